// round 1
// baseline (speedup 1.0000x reference)
#include <cuda_runtime.h>
#include <math.h>

#define BB   4
#define NT   2304      // 48*48 tokens
#define CD   256       // DIM
#define AGH  512       // agent hidden
#define NH   4
#define DH   64

// ---------------- scratch (static device globals; allocation-free at launch) ----------------
__device__ float g_xcat[(size_t)BB*NT*512];     // token-major [B,N,512] concat(ir,vis)
__device__ float g_h1  [(size_t)BB*NT*AGH];     // agent hidden
__device__ float g_logits[BB*NT];
__device__ float g_maskf [BB*NT];
__device__ int   g_list[BB*NT];
__device__ int   g_cnt [BB];
__device__ float g_x0 [(size_t)BB*NT*CD];       // ir mixer residual stream (compacted)
__device__ float g_x1 [(size_t)BB*NT*CD];       // vis mixer residual stream (compacted)
__device__ float g_xn [(size_t)BB*NT*CD];
__device__ float g_qkv[(size_t)BB*NT*3*CD];
__device__ float g_att[(size_t)BB*NT*CD];
__device__ float g_hid[(size_t)BB*NT*4*CD];

// ---------------- transpose [B,C,N] -> token-major concat [B,N,512] ----------------
__global__ void transpose_cat(const float* __restrict__ fir, const float* __restrict__ fvis,
                              float* __restrict__ xcat)
{
    int src = blockIdx.z & 1;
    int b   = blockIdx.z >> 1;
    const float* f = src ? fvis : fir;
    __shared__ float tile[32][33];
    int n0 = blockIdx.x * 32, c0 = blockIdx.y * 32;
    int tx = threadIdx.x, ty = threadIdx.y;   // (32,8)
    #pragma unroll
    for (int i = 0; i < 32; i += 8)
        tile[ty + i][tx] = f[((size_t)b*CD + c0 + ty + i)*NT + n0 + tx];
    __syncthreads();
    #pragma unroll
    for (int i = 0; i < 32; i += 8)
        xcat[((size_t)b*NT + n0 + ty + i)*512 + src*CD + c0 + tx] = tile[tx][ty + i];
}

// ---------------- generic fp32 GEMM:  C[b,m,o] = act( sum_k A[b,m,k]*W[o,k] + bias[o] ) (+resid) ----
// A: [B,NT,K] (rows valid up to counts[b], or NT if counts==null). W: [O,K] row-major.
#define BM 64
#define BO 64
#define BK 16
__global__ void gemm_nt(const float* __restrict__ A, const float* __restrict__ W,
                        const float* __restrict__ bias, float* __restrict__ Cmat,
                        const float* __restrict__ resid, const int* __restrict__ counts,
                        int K, int Ocols, int act)
{
    int b  = blockIdx.z;
    int Mb = counts ? counts[b] : NT;
    int m0 = blockIdx.y * BM;
    if (m0 >= Mb) return;
    int o0 = blockIdx.x * BO;
    const float* Ab = A + (size_t)b*NT*K;
    float*       Cb = Cmat + (size_t)b*NT*Ocols;
    const float* Rb = resid ? resid + (size_t)b*NT*Ocols : (const float*)0;

    __shared__ float As[BK][BM+1];
    __shared__ float Ws[BK][BO+1];

    int tid = threadIdx.x;          // 256
    int tx = tid & 15;              // o-group
    int ty = tid >> 4;              // m-group
    float acc[4][4];
    #pragma unroll
    for (int i=0;i<4;i++)
        #pragma unroll
        for (int j=0;j<4;j++) acc[i][j]=0.f;

    for (int k0 = 0; k0 < K; k0 += BK) {
        #pragma unroll
        for (int i = 0; i < 4; i++) {
            int idx = tid + i*256;
            int m = idx >> 4, k = idx & 15;
            float v = 0.f;
            if (m0 + m < Mb) v = Ab[(size_t)(m0+m)*K + k0 + k];
            As[k][m] = v;
        }
        #pragma unroll
        for (int i = 0; i < 4; i++) {
            int idx = tid + i*256;
            int o = idx >> 4, k = idx & 15;
            Ws[k][o] = W[(size_t)(o0+o)*K + k0 + k];
        }
        __syncthreads();
        #pragma unroll
        for (int k = 0; k < BK; k++) {
            float a[4], w[4];
            #pragma unroll
            for (int i=0;i<4;i++) a[i] = As[k][ty*4+i];
            #pragma unroll
            for (int j=0;j<4;j++) w[j] = Ws[k][tx*4+j];
            #pragma unroll
            for (int i=0;i<4;i++)
                #pragma unroll
                for (int j=0;j<4;j++) acc[i][j] = fmaf(a[i], w[j], acc[i][j]);
        }
        __syncthreads();
    }
    #pragma unroll
    for (int i=0;i<4;i++) {
        int m = m0 + ty*4 + i;
        if (m >= Mb) continue;
        #pragma unroll
        for (int j=0;j<4;j++) {
            int o = o0 + tx*4 + j;
            float v = acc[i][j] + bias[o];
            if (act == 1)      v = v / (1.f + expf(-v));                       // silu
            else if (act == 2) v = 0.5f*v*(1.f + erff(v*0.70710678118654752f)); // exact gelu
            if (Rb) v += Rb[(size_t)m*Ocols + o];
            Cb[(size_t)m*Ocols + o] = v;
        }
    }
}

// ---------------- agent logits reduce:  logits = h1 . aw2 + ab2 ;  maskf = logits>0 ----------------
__global__ void agent_logits(const float* __restrict__ h1, const float* __restrict__ aw2,
                             const float* __restrict__ ab2,
                             float* __restrict__ logits, float* __restrict__ maskf)
{
    int t = blockIdx.x * 8 + (threadIdx.x >> 5);
    if (t >= BB*NT) return;
    int lane = threadIdx.x & 31;
    const float* hr = h1 + (size_t)t*AGH;
    float s = 0.f;
    for (int i = lane; i < AGH; i += 32) s += hr[i]*aw2[i];
    #pragma unroll
    for (int off = 16; off; off >>= 1) s += __shfl_down_sync(0xffffffffu, s, off);
    if (lane == 0) {
        float lg = s + ab2[0];
        logits[t] = lg;
        maskf[t]  = (lg > 0.f) ? 1.f : 0.f;
    }
}

// ---------------- selection: deterministic compaction (prefix scan) + top-64 fallback --------------
__global__ void select_kernel(const float* __restrict__ logits,
                              int* __restrict__ list, int* __restrict__ cnt)
{
    int b = blockIdx.x, tid = threadIdx.x;
    const float* lg = logits + b*NT;
    const int PER = NT/256;  // 9
    __shared__ int cn[256];
    int base = tid*PER;
    float lv[PER];
    bool  sv[PER];
    int c = 0;
    #pragma unroll
    for (int i = 0; i < PER; i++) {
        float v = lg[base+i]; lv[i] = v;
        bool s = v > 0.f; sv[i] = s; c += s;
    }
    cn[tid] = c; __syncthreads();
    for (int off = 1; off < 256; off <<= 1) {
        int v = (tid >= off) ? cn[tid-off] : 0;
        __syncthreads();
        cn[tid] += v;
        __syncthreads();
    }
    int total = cn[255];
    int pos = cn[tid] - c;          // exclusive
    if (total >= 64) {
        #pragma unroll
        for (int i = 0; i < PER; i++)
            if (sv[i]) { list[b*NT + pos] = base + i; pos++; }
        if (tid == 0) cnt[b] = total;
    } else {
        __shared__ float sl[NT];
        #pragma unroll
        for (int i = 0; i < PER; i++) sl[base+i] = lv[i];
        __syncthreads();
        if (tid == 0) {
            for (int t = 0; t < 64; t++) {
                int am = 0; float mv = sl[0];
                for (int n = 1; n < NT; n++) if (sl[n] > mv) { mv = sl[n]; am = n; }
                list[b*NT + t] = am; sl[am] = -1e30f;
            }
            cnt[b] = 64;
        }
    }
}

// ---------------- gather selected tokens into compacted token-major buffers ----------------
__global__ void gather_tok(const float* __restrict__ xcat, const int* __restrict__ list,
                           const int* __restrict__ cnt,
                           float* __restrict__ x0, float* __restrict__ x1)
{
    int b = blockIdx.y, j = blockIdx.x;
    if (j >= cnt[b]) return;
    int idx = list[b*NT + j];
    int c = threadIdx.x;
    const float* src = xcat + ((size_t)b*NT + idx)*512;
    x0[((size_t)b*NT + j)*CD + c] = src[c];
    x1[((size_t)b*NT + j)*CD + c] = src[CD + c];
}

// ---------------- LayerNorm over C=256 (one block per token) ----------------
__global__ void ln_kernel(const float* __restrict__ X, float* __restrict__ Y,
                          const float* __restrict__ gw, const float* __restrict__ gb,
                          const int* __restrict__ cnt)
{
    int b = blockIdx.y, n = blockIdx.x;
    if (n >= cnt[b]) return;
    int tid = threadIdx.x;  // 256 == CD
    const float* xr = X + ((size_t)b*NT + n)*CD;
    float v = xr[tid];
    __shared__ float red[8];
    float s = v;
    #pragma unroll
    for (int o = 16; o; o >>= 1) s += __shfl_down_sync(0xffffffffu, s, o);
    if ((tid & 31) == 0) red[tid>>5] = s;
    __syncthreads();
    float mean = 0.f;
    #pragma unroll
    for (int i = 0; i < 8; i++) mean += red[i];
    mean *= (1.f/CD);
    __syncthreads();
    float d = v - mean;
    s = d*d;
    #pragma unroll
    for (int o = 16; o; o >>= 1) s += __shfl_down_sync(0xffffffffu, s, o);
    if ((tid & 31) == 0) red[tid>>5] = s;
    __syncthreads();
    float var = 0.f;
    #pragma unroll
    for (int i = 0; i < 8; i++) var += red[i];
    var *= (1.f/CD);
    Y[((size_t)b*NT + n)*CD + tid] = d * rsqrtf(var + 1e-5f) * gw[tid] + gb[tid];
}

// ---------------- flash attention over compacted tokens (keys == queries == selected set) ---------
// qkv: [B,NT,768] compacted rows. att: [B,NT,256].
#define APAD 65
#define ATTN_SMEM ((4*64*APAD + 128) * (int)sizeof(float))
__global__ void attn_kernel(const float* __restrict__ qkv, float* __restrict__ att,
                            const int* __restrict__ cnt)
{
    extern __shared__ float sm[];
    float* Qs = sm;
    float* Ks = Qs + 64*APAD;
    float* Vs = Ks + 64*APAD;
    float* Ss = Vs + 64*APAD;
    float* alphas = Ss + 64*APAD;   // 64
    float* llist  = alphas + 64;    // 64

    int b = blockIdx.z, h = blockIdx.y, q0 = blockIdx.x*64;
    int Mb = cnt[b];
    if (q0 >= Mb) return;
    int tid = threadIdx.x;
    int tq = tid >> 4, tc = tid & 15;
    const float* base = qkv + (size_t)b*NT*768;

    for (int idx = tid; idx < 64*64; idx += 256) {
        int r = idx >> 6, c = idx & 63;
        float v = 0.f;
        if (q0 + r < Mb) v = base[(size_t)(q0+r)*768 + h*DH + c];
        Qs[r*APAD + c] = v;
    }

    float m_run = -1e30f, l_run = 0.f;
    float acc[4][4];
    #pragma unroll
    for (int i=0;i<4;i++)
        #pragma unroll
        for (int j=0;j<4;j++) acc[i][j]=0.f;

    int nkt = (Mb + 63) >> 6;
    for (int kt = 0; kt < nkt; kt++) {
        int k0 = kt*64;
        int kval = min(64, Mb - k0);
        __syncthreads();   // previous-tile consumers done
        for (int idx = tid; idx < 64*64; idx += 256) {
            int r = idx >> 6, c = idx & 63;
            float kv = 0.f, vv = 0.f;
            if (r < kval) {
                kv = base[(size_t)(k0+r)*768 + 256 + h*DH + c];
                vv = base[(size_t)(k0+r)*768 + 512 + h*DH + c];
            }
            Ks[r*APAD + c] = kv;
            Vs[r*APAD + c] = vv;
        }
        __syncthreads();
        // S = (Q K^T) * 1/8
        {
            float s4[4][4];
            #pragma unroll
            for (int i=0;i<4;i++)
                #pragma unroll
                for (int j=0;j<4;j++) s4[i][j]=0.f;
            for (int d = 0; d < DH; d++) {
                float qv[4], kv[4];
                #pragma unroll
                for (int i=0;i<4;i++) qv[i] = Qs[(tq*4+i)*APAD + d];
                #pragma unroll
                for (int j=0;j<4;j++) kv[j] = Ks[(tc*4+j)*APAD + d];
                #pragma unroll
                for (int i=0;i<4;i++)
                    #pragma unroll
                    for (int j=0;j<4;j++) s4[i][j] = fmaf(qv[i], kv[j], s4[i][j]);
            }
            #pragma unroll
            for (int i=0;i<4;i++)
                #pragma unroll
                for (int j=0;j<4;j++) Ss[(tq*4+i)*APAD + tc*4+j] = s4[i][j]*0.125f;
        }
        __syncthreads();
        // online softmax row stats (one thread per row, rows 0..63)
        if (tid < 64) {
            float* row = Ss + tid*APAD;
            float mx = -1e30f;
            for (int k = 0; k < kval; k++) mx = fmaxf(mx, row[k]);
            float mnew = fmaxf(m_run, mx);
            float al = __expf(m_run - mnew);     // first tile: underflows to 0
            float ssum = 0.f;
            for (int k = 0; k < kval; k++) { float p = __expf(row[k]-mnew); row[k]=p; ssum+=p; }
            for (int k = kval; k < 64; k++) row[k] = 0.f;
            l_run = l_run*al + ssum;
            m_run = mnew;
            alphas[tid] = al;
        }
        __syncthreads();
        // O = O*alpha + P V
        #pragma unroll
        for (int i=0;i<4;i++) {
            float al = alphas[tq*4+i];
            #pragma unroll
            for (int j=0;j<4;j++) acc[i][j] *= al;
        }
        for (int k = 0; k < 64; k++) {
            float vv[4];
            #pragma unroll
            for (int j=0;j<4;j++) vv[j] = Vs[k*APAD + tc*4+j];
            #pragma unroll
            for (int i=0;i<4;i++) {
                float p = Ss[(tq*4+i)*APAD + k];
                #pragma unroll
                for (int j=0;j<4;j++) acc[i][j] = fmaf(p, vv[j], acc[i][j]);
            }
        }
    }
    __syncthreads();
    if (tid < 64) llist[tid] = l_run;
    __syncthreads();
    #pragma unroll
    for (int i=0;i<4;i++) {
        int q = tq*4+i;
        int qq = q0 + q;
        if (qq < Mb) {
            float inv = 1.f / llist[q];
            #pragma unroll
            for (int j=0;j<4;j++)
                att[((size_t)b*NT + qq)*CD + h*DH + tc*4+j] = acc[i][j]*inv;
        }
    }
}

// ---------------- output: base canvas then scatter refined tokens ----------------
__global__ void base_out(const float* __restrict__ fir, const float* __restrict__ fvis,
                         float* __restrict__ out)
{
    size_t i = (size_t)blockIdx.x*256 + threadIdx.x;
    out[i] = fir[i] + fvis[i];
}

__global__ void scatter_out(const float* __restrict__ x0, const float* __restrict__ x1,
                            const int* __restrict__ list, const float* __restrict__ maskf,
                            const int* __restrict__ cnt, float* __restrict__ out)
{
    int b = blockIdx.y, j = blockIdx.x;
    if (j >= cnt[b]) return;
    int idx = list[b*NT + j];
    float mv = maskf[b*NT + idx];
    int c = threadIdx.x;
    float v = (x0[((size_t)b*NT + j)*CD + c] + x1[((size_t)b*NT + j)*CD + c]) * mv;
    out[((size_t)b*CD + c)*NT + idx] = v;
}

// ---------------- host ----------------
extern "C" void kernel_launch(void* const* d_in, const int* in_sizes, int n_in,
                              void* d_out, int out_size)
{
    const float* f_ir  = (const float*)d_in[0];
    const float* f_vis = (const float*)d_in[1];
    const float* aw1   = (const float*)d_in[2];
    const float* ab1   = (const float*)d_in[3];
    const float* aw2   = (const float*)d_in[4];
    const float* ab2   = (const float*)d_in[5];
    float* out = (float*)d_out;

    float *xcat,*h1,*logits,*maskf,*x0,*x1,*xn,*qkv,*att,*hid;
    int *list,*cntp;
    cudaGetSymbolAddress((void**)&xcat,  g_xcat);
    cudaGetSymbolAddress((void**)&h1,    g_h1);
    cudaGetSymbolAddress((void**)&logits,g_logits);
    cudaGetSymbolAddress((void**)&maskf, g_maskf);
    cudaGetSymbolAddress((void**)&x0,    g_x0);
    cudaGetSymbolAddress((void**)&x1,    g_x1);
    cudaGetSymbolAddress((void**)&xn,    g_xn);
    cudaGetSymbolAddress((void**)&qkv,   g_qkv);
    cudaGetSymbolAddress((void**)&att,   g_att);
    cudaGetSymbolAddress((void**)&hid,   g_hid);
    cudaGetSymbolAddress((void**)&list,  g_list);
    cudaGetSymbolAddress((void**)&cntp,  g_cnt);

    cudaFuncSetAttribute(attn_kernel, cudaFuncAttributeMaxDynamicSharedMemorySize, ATTN_SMEM);

    // 1. token-major concat
    transpose_cat<<<dim3(NT/32, CD/32, BB*2), dim3(32,8)>>>(f_ir, f_vis, xcat);
    // 2. agent hidden (silu)
    gemm_nt<<<dim3(AGH/BO, NT/BM, BB), 256>>>(xcat, aw1, ab1, h1, 0, 0, 512, AGH, 1);
    // 3. agent logits + STE mask
    agent_logits<<<(BB*NT)/8, 256>>>(h1, aw2, ab2, logits, maskf);
    // 4. selection (compaction / top-64 fallback)
    select_kernel<<<BB, 256>>>(logits, list, cntp);
    // 5. gather selected tokens
    gather_tok<<<dim3(NT, BB), 256>>>(xcat, list, cntp, x0, x1);

    // 6. two mixers (ir -> x0, vis -> x1) on compacted tokens
    for (int s = 0; s < 2; s++) {
        int o = 6 + s*10;
        const float* lng  = (const float*)d_in[o+0];
        const float* lnb  = (const float*)d_in[o+1];
        const float* wqkv = (const float*)d_in[o+2];
        const float* bqkv = (const float*)d_in[o+3];
        const float* wo   = (const float*)d_in[o+4];
        const float* bo   = (const float*)d_in[o+5];
        const float* w1   = (const float*)d_in[o+6];
        const float* b1   = (const float*)d_in[o+7];
        const float* w2   = (const float*)d_in[o+8];
        const float* b2   = (const float*)d_in[o+9];
        float* x = s ? x1 : x0;

        ln_kernel<<<dim3(NT, BB), 256>>>(x, xn, lng, lnb, cntp);
        gemm_nt<<<dim3(768/BO, NT/BM, BB), 256>>>(xn, wqkv, bqkv, qkv, 0, cntp, 256, 768, 0);
        attn_kernel<<<dim3(NT/64, NH, BB), 256, ATTN_SMEM>>>(qkv, att, cntp);
        gemm_nt<<<dim3(CD/BO, NT/BM, BB), 256>>>(att, wo, bo, x, x, cntp, 256, CD, 0);
        ln_kernel<<<dim3(NT, BB), 256>>>(x, xn, lng, lnb, cntp);
        gemm_nt<<<dim3(1024/BO, NT/BM, BB), 256>>>(xn, w1, b1, hid, 0, cntp, 256, 1024, 2);
        gemm_nt<<<dim3(CD/BO, NT/BM, BB), 256>>>(hid, w2, b2, x, x, cntp, 1024, CD, 0);
    }

    // 7. output
    base_out<<<(BB*CD*NT)/256, 256>>>(f_ir, f_vis, out);
    scatter_out<<<dim3(NT, BB), 256>>>(x0, x1, list, maskf, cntp, out);
}

// round 2
// speedup vs baseline: 1.0058x; 1.0058x over previous
#include <cuda_runtime.h>
#include <math.h>

#define BB   4
#define NT   2304      // 48*48 tokens
#define CD   256       // DIM
#define AGH  512       // agent hidden
#define NH   4
#define DH   64

// ---------------- scratch (static device globals; allocation-free at launch) ----------------
__device__ float g_xcat[(size_t)BB*NT*512];     // token-major [B,N,512] concat(ir,vis)
__device__ float g_h1  [(size_t)BB*NT*AGH];     // agent hidden
__device__ float g_logits[BB*NT];
__device__ float g_maskf [BB*NT];
__device__ int   g_list[BB*NT];
__device__ int   g_cnt [BB];
__device__ float g_x0 [(size_t)BB*NT*CD];       // ir mixer residual stream (compacted)
__device__ float g_x1 [(size_t)BB*NT*CD];       // vis mixer residual stream (compacted)
__device__ float g_xn [(size_t)BB*NT*CD];
__device__ float g_qkv[(size_t)BB*NT*3*CD];
__device__ float g_att[(size_t)BB*NT*CD];
__device__ float g_hid[(size_t)BB*NT*4*CD];

// ---------------- transpose [B,C,N] -> token-major concat [B,N,512] ----------------
__global__ void transpose_cat(const float* __restrict__ fir, const float* __restrict__ fvis,
                              float* __restrict__ xcat)
{
    int src = blockIdx.z & 1;
    int b   = blockIdx.z >> 1;
    const float* f = src ? fvis : fir;
    __shared__ float tile[32][33];
    int n0 = blockIdx.x * 32, c0 = blockIdx.y * 32;
    int tx = threadIdx.x, ty = threadIdx.y;   // (32,8)
    #pragma unroll
    for (int i = 0; i < 32; i += 8)
        tile[ty + i][tx] = f[((size_t)b*CD + c0 + ty + i)*NT + n0 + tx];
    __syncthreads();
    #pragma unroll
    for (int i = 0; i < 32; i += 8)
        xcat[((size_t)b*NT + n0 + ty + i)*512 + src*CD + c0 + tx] = tile[tx][ty + i];
}

// ---------------- generic fp32 GEMM:  C[b,m,o] = act( sum_k A[b,m,k]*W[o,k] + bias[o] ) (+resid) ----
// A: [B,NT,K] (rows valid up to counts[b], or NT if counts==null). W: [O,K] row-major.
#define BM 64
#define BO 64
#define BK 16
__global__ void gemm_nt(const float* __restrict__ A, const float* __restrict__ W,
                        const float* __restrict__ bias, float* __restrict__ Cmat,
                        const float* __restrict__ resid, const int* __restrict__ counts,
                        int K, int Ocols, int act)
{
    int b  = blockIdx.z;
    int Mb = counts ? counts[b] : NT;
    int m0 = blockIdx.y * BM;
    if (m0 >= Mb) return;
    int o0 = blockIdx.x * BO;
    const float* Ab = A + (size_t)b*NT*K;
    float*       Cb = Cmat + (size_t)b*NT*Ocols;
    const float* Rb = resid ? resid + (size_t)b*NT*Ocols : (const float*)0;

    __shared__ float As[BK][BM+1];
    __shared__ float Ws[BK][BO+1];

    int tid = threadIdx.x;          // 256
    int tx = tid & 15;              // o-group
    int ty = tid >> 4;              // m-group
    float acc[4][4];
    #pragma unroll
    for (int i=0;i<4;i++)
        #pragma unroll
        for (int j=0;j<4;j++) acc[i][j]=0.f;

    for (int k0 = 0; k0 < K; k0 += BK) {
        #pragma unroll
        for (int i = 0; i < 4; i++) {
            int idx = tid + i*256;
            int m = idx >> 4, k = idx & 15;
            float v = 0.f;
            if (m0 + m < Mb) v = Ab[(size_t)(m0+m)*K + k0 + k];
            As[k][m] = v;
        }
        #pragma unroll
        for (int i = 0; i < 4; i++) {
            int idx = tid + i*256;
            int o = idx >> 4, k = idx & 15;
            Ws[k][o] = W[(size_t)(o0+o)*K + k0 + k];
        }
        __syncthreads();
        #pragma unroll
        for (int k = 0; k < BK; k++) {
            float a[4], w[4];
            #pragma unroll
            for (int i=0;i<4;i++) a[i] = As[k][ty*4+i];
            #pragma unroll
            for (int j=0;j<4;j++) w[j] = Ws[k][tx*4+j];
            #pragma unroll
            for (int i=0;i<4;i++)
                #pragma unroll
                for (int j=0;j<4;j++) acc[i][j] = fmaf(a[i], w[j], acc[i][j]);
        }
        __syncthreads();
    }
    #pragma unroll
    for (int i=0;i<4;i++) {
        int m = m0 + ty*4 + i;
        if (m >= Mb) continue;
        #pragma unroll
        for (int j=0;j<4;j++) {
            int o = o0 + tx*4 + j;
            float v = acc[i][j] + bias[o];
            if (act == 1)      v = v / (1.f + expf(-v));                       // silu
            else if (act == 2) v = 0.5f*v*(1.f + erff(v*0.70710678118654752f)); // exact gelu
            if (Rb) v += Rb[(size_t)m*Ocols + o];
            Cb[(size_t)m*Ocols + o] = v;
        }
    }
}

// ---------------- agent logits reduce:  logits = h1 . aw2 + ab2 ;  maskf = logits>0 ----------------
__global__ void agent_logits(const float* __restrict__ h1, const float* __restrict__ aw2,
                             const float* __restrict__ ab2,
                             float* __restrict__ logits, float* __restrict__ maskf)
{
    int t = blockIdx.x * 8 + (threadIdx.x >> 5);
    if (t >= BB*NT) return;
    int lane = threadIdx.x & 31;
    const float* hr = h1 + (size_t)t*AGH;
    float s = 0.f;
    for (int i = lane; i < AGH; i += 32) s += hr[i]*aw2[i];
    #pragma unroll
    for (int off = 16; off; off >>= 1) s += __shfl_down_sync(0xffffffffu, s, off);
    if (lane == 0) {
        float lg = s + ab2[0];
        logits[t] = lg;
        maskf[t]  = (lg > 0.f) ? 1.f : 0.f;
    }
}

// ---------------- selection: deterministic compaction (prefix scan) + top-64 fallback --------------
__global__ void select_kernel(const float* __restrict__ logits,
                              int* __restrict__ list, int* __restrict__ cnt)
{
    int b = blockIdx.x, tid = threadIdx.x;
    const float* lg = logits + b*NT;
    const int PER = NT/256;  // 9
    __shared__ int cn[256];
    int base = tid*PER;
    float lv[PER];
    bool  sv[PER];
    int c = 0;
    #pragma unroll
    for (int i = 0; i < PER; i++) {
        float v = lg[base+i]; lv[i] = v;
        bool s = v > 0.f; sv[i] = s; c += s;
    }
    cn[tid] = c; __syncthreads();
    for (int off = 1; off < 256; off <<= 1) {
        int v = (tid >= off) ? cn[tid-off] : 0;
        __syncthreads();
        cn[tid] += v;
        __syncthreads();
    }
    int total = cn[255];
    int pos = cn[tid] - c;          // exclusive
    if (total >= 64) {
        #pragma unroll
        for (int i = 0; i < PER; i++)
            if (sv[i]) { list[b*NT + pos] = base + i; pos++; }
        if (tid == 0) cnt[b] = total;
    } else {
        __shared__ float sl[NT];
        #pragma unroll
        for (int i = 0; i < PER; i++) sl[base+i] = lv[i];
        __syncthreads();
        if (tid == 0) {
            for (int t = 0; t < 64; t++) {
                int am = 0; float mv = sl[0];
                for (int n = 1; n < NT; n++) if (sl[n] > mv) { mv = sl[n]; am = n; }
                list[b*NT + t] = am; sl[am] = -1e30f;
            }
            cnt[b] = 64;
        }
    }
}

// ---------------- gather selected tokens into compacted token-major buffers ----------------
__global__ void gather_tok(const float* __restrict__ xcat, const int* __restrict__ list,
                           const int* __restrict__ cnt,
                           float* __restrict__ x0, float* __restrict__ x1)
{
    int b = blockIdx.y, j = blockIdx.x;
    if (j >= cnt[b]) return;
    int idx = list[b*NT + j];
    int c = threadIdx.x;
    const float* src = xcat + ((size_t)b*NT + idx)*512;
    x0[((size_t)b*NT + j)*CD + c] = src[c];
    x1[((size_t)b*NT + j)*CD + c] = src[CD + c];
}

// ---------------- LayerNorm over C=256 (one block per token) ----------------
__global__ void ln_kernel(const float* __restrict__ X, float* __restrict__ Y,
                          const float* __restrict__ gw, const float* __restrict__ gb,
                          const int* __restrict__ cnt)
{
    int b = blockIdx.y, n = blockIdx.x;
    if (n >= cnt[b]) return;
    int tid = threadIdx.x;  // 256 == CD
    const float* xr = X + ((size_t)b*NT + n)*CD;
    float v = xr[tid];
    __shared__ float red[8];
    float s = v;
    #pragma unroll
    for (int o = 16; o; o >>= 1) s += __shfl_down_sync(0xffffffffu, s, o);
    if ((tid & 31) == 0) red[tid>>5] = s;
    __syncthreads();
    float mean = 0.f;
    #pragma unroll
    for (int i = 0; i < 8; i++) mean += red[i];
    mean *= (1.f/CD);
    __syncthreads();
    float d = v - mean;
    s = d*d;
    #pragma unroll
    for (int o = 16; o; o >>= 1) s += __shfl_down_sync(0xffffffffu, s, o);
    if ((tid & 31) == 0) red[tid>>5] = s;
    __syncthreads();
    float var = 0.f;
    #pragma unroll
    for (int i = 0; i < 8; i++) var += red[i];
    var *= (1.f/CD);
    Y[((size_t)b*NT + n)*CD + tid] = d * rsqrtf(var + 1e-5f) * gw[tid] + gb[tid];
}

// ---------------- flash attention over compacted tokens (keys == queries == selected set) ---------
// qkv: [B,NT,768] compacted rows. att: [B,NT,256].
#define APAD 65
#define ATTN_SMEM ((4*64*APAD + 128) * (int)sizeof(float))
__global__ void attn_kernel(const float* __restrict__ qkv, float* __restrict__ att,
                            const int* __restrict__ cnt)
{
    extern __shared__ float sm[];
    float* Qs = sm;
    float* Ks = Qs + 64*APAD;
    float* Vs = Ks + 64*APAD;
    float* Ss = Vs + 64*APAD;
    float* alphas = Ss + 64*APAD;   // 64
    float* llist  = alphas + 64;    // 64

    int b = blockIdx.z, h = blockIdx.y, q0 = blockIdx.x*64;
    int Mb = cnt[b];
    if (q0 >= Mb) return;
    int tid = threadIdx.x;
    int tq = tid >> 4, tc = tid & 15;
    const float* base = qkv + (size_t)b*NT*768;

    for (int idx = tid; idx < 64*64; idx += 256) {
        int r = idx >> 6, c = idx & 63;
        float v = 0.f;
        if (q0 + r < Mb) v = base[(size_t)(q0+r)*768 + h*DH + c];
        Qs[r*APAD + c] = v;
    }

    float m_run = -1e30f, l_run = 0.f;
    float acc[4][4];
    #pragma unroll
    for (int i=0;i<4;i++)
        #pragma unroll
        for (int j=0;j<4;j++) acc[i][j]=0.f;

    int nkt = (Mb + 63) >> 6;
    for (int kt = 0; kt < nkt; kt++) {
        int k0 = kt*64;
        int kval = min(64, Mb - k0);
        __syncthreads();   // previous-tile consumers done
        for (int idx = tid; idx < 64*64; idx += 256) {
            int r = idx >> 6, c = idx & 63;
            float kv = 0.f, vv = 0.f;
            if (r < kval) {
                kv = base[(size_t)(k0+r)*768 + 256 + h*DH + c];
                vv = base[(size_t)(k0+r)*768 + 512 + h*DH + c];
            }
            Ks[r*APAD + c] = kv;
            Vs[r*APAD + c] = vv;
        }
        __syncthreads();
        // S = (Q K^T) * 1/8
        {
            float s4[4][4];
            #pragma unroll
            for (int i=0;i<4;i++)
                #pragma unroll
                for (int j=0;j<4;j++) s4[i][j]=0.f;
            for (int d = 0; d < DH; d++) {
                float qv[4], kv[4];
                #pragma unroll
                for (int i=0;i<4;i++) qv[i] = Qs[(tq*4+i)*APAD + d];
                #pragma unroll
                for (int j=0;j<4;j++) kv[j] = Ks[(tc*4+j)*APAD + d];
                #pragma unroll
                for (int i=0;i<4;i++)
                    #pragma unroll
                    for (int j=0;j<4;j++) s4[i][j] = fmaf(qv[i], kv[j], s4[i][j]);
            }
            #pragma unroll
            for (int i=0;i<4;i++)
                #pragma unroll
                for (int j=0;j<4;j++) Ss[(tq*4+i)*APAD + tc*4+j] = s4[i][j]*0.125f;
        }
        __syncthreads();
        // online softmax row stats (one thread per row, rows 0..63)
        if (tid < 64) {
            float* row = Ss + tid*APAD;
            float mx = -1e30f;
            for (int k = 0; k < kval; k++) mx = fmaxf(mx, row[k]);
            float mnew = fmaxf(m_run, mx);
            float al = __expf(m_run - mnew);     // first tile: underflows to 0
            float ssum = 0.f;
            for (int k = 0; k < kval; k++) { float p = __expf(row[k]-mnew); row[k]=p; ssum+=p; }
            for (int k = kval; k < 64; k++) row[k] = 0.f;
            l_run = l_run*al + ssum;
            m_run = mnew;
            alphas[tid] = al;
        }
        __syncthreads();
        // O = O*alpha + P V
        #pragma unroll
        for (int i=0;i<4;i++) {
            float al = alphas[tq*4+i];
            #pragma unroll
            for (int j=0;j<4;j++) acc[i][j] *= al;
        }
        for (int k = 0; k < 64; k++) {
            float vv[4];
            #pragma unroll
            for (int j=0;j<4;j++) vv[j] = Vs[k*APAD + tc*4+j];
            #pragma unroll
            for (int i=0;i<4;i++) {
                float p = Ss[(tq*4+i)*APAD + k];
                #pragma unroll
                for (int j=0;j<4;j++) acc[i][j] = fmaf(p, vv[j], acc[i][j]);
            }
        }
    }
    __syncthreads();
    if (tid < 64) llist[tid] = l_run;
    __syncthreads();
    #pragma unroll
    for (int i=0;i<4;i++) {
        int q = tq*4+i;
        int qq = q0 + q;
        if (qq < Mb) {
            float inv = 1.f / llist[q];
            #pragma unroll
            for (int j=0;j<4;j++)
                att[((size_t)b*NT + qq)*CD + h*DH + tc*4+j] = acc[i][j]*inv;
        }
    }
}

// ---------------- output: base canvas then scatter refined tokens ----------------
__global__ void base_out(const float* __restrict__ fir, const float* __restrict__ fvis,
                         float* __restrict__ out)
{
    size_t i = (size_t)blockIdx.x*256 + threadIdx.x;
    out[i] = fir[i] + fvis[i];
}

__global__ void scatter_out(const float* __restrict__ x0, const float* __restrict__ x1,
                            const int* __restrict__ list, const float* __restrict__ maskf,
                            const int* __restrict__ cnt, float* __restrict__ out)
{
    int b = blockIdx.y, j = blockIdx.x;
    if (j >= cnt[b]) return;
    int idx = list[b*NT + j];
    float mv = maskf[b*NT + idx];
    int c = threadIdx.x;
    float v = (x0[((size_t)b*NT + j)*CD + c] + x1[((size_t)b*NT + j)*CD + c]) * mv;
    out[((size_t)b*CD + c)*NT + idx] = v;
}

// ---------------- host ----------------
extern "C" void kernel_launch(void* const* d_in, const int* in_sizes, int n_in,
                              void* d_out, int out_size)
{
    const float* f_ir  = (const float*)d_in[0];
    const float* f_vis = (const float*)d_in[1];
    const float* aw1   = (const float*)d_in[2];
    const float* ab1   = (const float*)d_in[3];
    const float* aw2   = (const float*)d_in[4];
    const float* ab2   = (const float*)d_in[5];
    float* out = (float*)d_out;

    float *xcat,*h1,*logits,*maskf,*x0,*x1,*xn,*qkv,*att,*hid;
    int *list,*cntp;
    cudaGetSymbolAddress((void**)&xcat,  g_xcat);
    cudaGetSymbolAddress((void**)&h1,    g_h1);
    cudaGetSymbolAddress((void**)&logits,g_logits);
    cudaGetSymbolAddress((void**)&maskf, g_maskf);
    cudaGetSymbolAddress((void**)&x0,    g_x0);
    cudaGetSymbolAddress((void**)&x1,    g_x1);
    cudaGetSymbolAddress((void**)&xn,    g_xn);
    cudaGetSymbolAddress((void**)&qkv,   g_qkv);
    cudaGetSymbolAddress((void**)&att,   g_att);
    cudaGetSymbolAddress((void**)&hid,   g_hid);
    cudaGetSymbolAddress((void**)&list,  g_list);
    cudaGetSymbolAddress((void**)&cntp,  g_cnt);

    cudaFuncSetAttribute(attn_kernel, cudaFuncAttributeMaxDynamicSharedMemorySize, ATTN_SMEM);

    // 1. token-major concat
    transpose_cat<<<dim3(NT/32, CD/32, BB*2), dim3(32,8)>>>(f_ir, f_vis, xcat);
    // 2. agent hidden (silu)
    gemm_nt<<<dim3(AGH/BO, NT/BM, BB), 256>>>(xcat, aw1, ab1, h1, 0, 0, 512, AGH, 1);
    // 3. agent logits + STE mask
    agent_logits<<<(BB*NT)/8, 256>>>(h1, aw2, ab2, logits, maskf);
    // 4. selection (compaction / top-64 fallback)
    select_kernel<<<BB, 256>>>(logits, list, cntp);
    // 5. gather selected tokens
    gather_tok<<<dim3(NT, BB), 256>>>(xcat, list, cntp, x0, x1);

    // 6. two mixers (ir -> x0, vis -> x1) on compacted tokens
    for (int s = 0; s < 2; s++) {
        int o = 6 + s*10;
        const float* lng  = (const float*)d_in[o+0];
        const float* lnb  = (const float*)d_in[o+1];
        const float* wqkv = (const float*)d_in[o+2];
        const float* bqkv = (const float*)d_in[o+3];
        const float* wo   = (const float*)d_in[o+4];
        const float* bo   = (const float*)d_in[o+5];
        const float* w1   = (const float*)d_in[o+6];
        const float* b1   = (const float*)d_in[o+7];
        const float* w2   = (const float*)d_in[o+8];
        const float* b2   = (const float*)d_in[o+9];
        float* x = s ? x1 : x0;

        ln_kernel<<<dim3(NT, BB), 256>>>(x, xn, lng, lnb, cntp);
        gemm_nt<<<dim3(768/BO, NT/BM, BB), 256>>>(xn, wqkv, bqkv, qkv, 0, cntp, 256, 768, 0);
        attn_kernel<<<dim3(NT/64, NH, BB), 256, ATTN_SMEM>>>(qkv, att, cntp);
        gemm_nt<<<dim3(CD/BO, NT/BM, BB), 256>>>(att, wo, bo, x, x, cntp, 256, CD, 0);
        ln_kernel<<<dim3(NT, BB), 256>>>(x, xn, lng, lnb, cntp);
        gemm_nt<<<dim3(1024/BO, NT/BM, BB), 256>>>(xn, w1, b1, hid, 0, cntp, 256, 1024, 2);
        gemm_nt<<<dim3(CD/BO, NT/BM, BB), 256>>>(hid, w2, b2, x, x, cntp, 1024, CD, 0);
    }

    // 7. output
    base_out<<<(BB*CD*NT)/256, 256>>>(f_ir, f_vis, out);
    scatter_out<<<dim3(NT, BB), 256>>>(x0, x1, list, maskf, cntp, out);
}

// round 3
// speedup vs baseline: 1.8550x; 1.8443x over previous
#include <cuda_runtime.h>
#include <math.h>

#define BB   4
#define NT   2304      // 48*48 tokens
#define CD   256       // DIM
#define AGH  512       // agent hidden
#define NH   4
#define DH   64

// ---------------- packed f32x2 FMA (Blackwell; PTX-only) ----------------
__device__ __forceinline__ float2 ffma2(float2 a, float2 b, float2 c) {
    float2 d;
    asm("fma.rn.f32x2 %0, %1, %2, %3;"
        : "=l"(reinterpret_cast<unsigned long long&>(d))
        : "l"(reinterpret_cast<unsigned long long&>(a)),
          "l"(reinterpret_cast<unsigned long long&>(b)),
          "l"(reinterpret_cast<unsigned long long&>(c)));
    return d;
}

// ---------------- scratch (static device globals; allocation-free) ----------------
__device__ float g_xcat[(size_t)BB*NT*512];       // token-major [B,N,512] concat(ir,vis)
__device__ float g_h1  [(size_t)BB*NT*AGH];
__device__ float g_logits[BB*NT];
__device__ float g_maskf [BB*NT];
__device__ int   g_list[BB*NT];
__device__ int   g_cnt [BB];
__device__ float g_x  [(size_t)2*BB*NT*CD];       // [s][B][N][C] residual streams
__device__ float g_xn [(size_t)2*BB*NT*CD];
__device__ float g_qkv[(size_t)2*BB*NT*3*CD];
__device__ float g_att[(size_t)2*BB*NT*CD];
__device__ float g_hid[(size_t)2*BB*NT*4*CD];

// ---------------- transpose [B,C,N] -> token-major concat [B,N,512] ----------------
__global__ void transpose_cat(const float* __restrict__ fir, const float* __restrict__ fvis,
                              float* __restrict__ xcat)
{
    int src = blockIdx.z & 1;
    int b   = blockIdx.z >> 1;
    const float* f = src ? fvis : fir;
    __shared__ float tile[32][33];
    int n0 = blockIdx.x * 32, c0 = blockIdx.y * 32;
    int tx = threadIdx.x, ty = threadIdx.y;   // (32,8)
    #pragma unroll
    for (int i = 0; i < 32; i += 8)
        tile[ty + i][tx] = f[((size_t)b*CD + c0 + ty + i)*NT + n0 + tx];
    __syncthreads();
    #pragma unroll
    for (int i = 0; i < 32; i += 8)
        xcat[((size_t)b*NT + n0 + ty + i)*512 + src*CD + c0 + tx] = tile[tx][ty + i];
}

// ---------------- fp32 GEMM (f32x2 packed), dual-stream via gridDim.z = 2*BB ----------------
// C[s,b,m,o] = act( sum_k A[s,b,m,k]*W_s[o,k] + bias_s[o] ) (+resid)
#define BM 64
#define BO 64
#define BK 16
__global__ void __launch_bounds__(256)
gemm2(const float* __restrict__ A,
      const float* __restrict__ Wa, const float* __restrict__ Wb,
      const float* __restrict__ ba, const float* __restrict__ bbv,
      float* __restrict__ C, const float* __restrict__ R,
      const int* __restrict__ counts, int K, int Ocols, int act)
{
    int bz = blockIdx.z;
    int s = bz >> 2, b = bz & 3;
    int Mb = counts ? counts[b] : NT;
    int m0 = blockIdx.y * BM;
    if (m0 >= Mb) return;
    int o0 = blockIdx.x * BO;
    const float* W    = s ? Wb  : Wa;
    const float* bias = s ? bbv : ba;
    size_t rowbase = (size_t)(s*BB + b) * NT;
    const float* Ab = A + rowbase * K;
    float*       Cb = C + rowbase * Ocols;
    const float* Rb = R ? R + rowbase * Ocols : (const float*)0;

    __shared__ __align__(16) float As[BK][68];
    __shared__ __align__(16) float Ws[BK][68];

    int tid = threadIdx.x;                 // 256
    int tx = tid & 15, ty = tid >> 4;
    int lm = tid >> 2, lk = (tid & 3) * 4; // loader mapping: one float4 of A and W each

    float2 acc[4][2];
    #pragma unroll
    for (int i=0;i<4;i++){ acc[i][0]=make_float2(0.f,0.f); acc[i][1]=make_float2(0.f,0.f); }

    for (int k0 = 0; k0 < K; k0 += BK) {
        float4 av = make_float4(0.f,0.f,0.f,0.f);
        if (m0 + lm < Mb) av = *(const float4*)&Ab[(size_t)(m0+lm)*K + k0 + lk];
        float4 wv = *(const float4*)&W[(size_t)(o0+lm)*K + k0 + lk];
        As[lk+0][lm]=av.x; As[lk+1][lm]=av.y; As[lk+2][lm]=av.z; As[lk+3][lm]=av.w;
        Ws[lk+0][lm]=wv.x; Ws[lk+1][lm]=wv.y; Ws[lk+2][lm]=wv.z; Ws[lk+3][lm]=wv.w;
        __syncthreads();
        #pragma unroll
        for (int k = 0; k < BK; k++) {
            float4 a4 = *(const float4*)&As[k][ty*4];
            float4 w4 = *(const float4*)&Ws[k][tx*4];
            float2 w01 = make_float2(w4.x, w4.y);
            float2 w23 = make_float2(w4.z, w4.w);
            float aa[4] = {a4.x, a4.y, a4.z, a4.w};
            #pragma unroll
            for (int i=0;i<4;i++){
                float2 ad = make_float2(aa[i], aa[i]);
                acc[i][0] = ffma2(ad, w01, acc[i][0]);
                acc[i][1] = ffma2(ad, w23, acc[i][1]);
            }
        }
        __syncthreads();
    }
    #pragma unroll
    for (int i=0;i<4;i++) {
        int m = m0 + ty*4 + i;
        if (m >= Mb) continue;
        float v[4] = {acc[i][0].x, acc[i][0].y, acc[i][1].x, acc[i][1].y};
        float4 ov;
        float* po = &ov.x;
        #pragma unroll
        for (int j=0;j<4;j++) {
            int o = o0 + tx*4 + j;
            float t = v[j] + bias[o];
            if (act == 1)      t = t / (1.f + expf(-t));                          // silu
            else if (act == 2) t = 0.5f*t*(1.f + erff(t*0.70710678118654752f));   // exact gelu
            if (Rb) t += Rb[(size_t)m*Ocols + o];
            po[j] = t;
        }
        *(float4*)&Cb[(size_t)m*Ocols + o0 + tx*4] = ov;
    }
}

// ---------------- agent logits reduce ----------------
__global__ void agent_logits(const float* __restrict__ h1, const float* __restrict__ aw2,
                             const float* __restrict__ ab2,
                             float* __restrict__ logits, float* __restrict__ maskf)
{
    int t = blockIdx.x * 8 + (threadIdx.x >> 5);
    if (t >= BB*NT) return;
    int lane = threadIdx.x & 31;
    const float* hr = h1 + (size_t)t*AGH;
    float ssum = 0.f;
    for (int i = lane; i < AGH; i += 32) ssum += hr[i]*aw2[i];
    #pragma unroll
    for (int off = 16; off; off >>= 1) ssum += __shfl_down_sync(0xffffffffu, ssum, off);
    if (lane == 0) {
        float lg = ssum + ab2[0];
        logits[t] = lg;
        maskf[t]  = (lg > 0.f) ? 1.f : 0.f;
    }
}

// ---------------- selection: deterministic compaction + top-64 fallback ----------------
__global__ void select_kernel(const float* __restrict__ logits,
                              int* __restrict__ list, int* __restrict__ cnt)
{
    int b = blockIdx.x, tid = threadIdx.x;
    const float* lg = logits + b*NT;
    const int PER = NT/256;  // 9
    __shared__ int cn[256];
    int base = tid*PER;
    float lv[PER];
    bool  sv[PER];
    int c = 0;
    #pragma unroll
    for (int i = 0; i < PER; i++) {
        float v = lg[base+i]; lv[i] = v;
        bool sel = v > 0.f; sv[i] = sel; c += sel;
    }
    cn[tid] = c; __syncthreads();
    for (int off = 1; off < 256; off <<= 1) {
        int v = (tid >= off) ? cn[tid-off] : 0;
        __syncthreads();
        cn[tid] += v;
        __syncthreads();
    }
    int total = cn[255];
    int pos = cn[tid] - c;
    if (total >= 64) {
        #pragma unroll
        for (int i = 0; i < PER; i++)
            if (sv[i]) { list[b*NT + pos] = base + i; pos++; }
        if (tid == 0) cnt[b] = total;
    } else {
        __shared__ float sl[NT];
        #pragma unroll
        for (int i = 0; i < PER; i++) sl[base+i] = lv[i];
        __syncthreads();
        if (tid == 0) {
            for (int t = 0; t < 64; t++) {
                int am = 0; float mv = sl[0];
                for (int n = 1; n < NT; n++) if (sl[n] > mv) { mv = sl[n]; am = n; }
                list[b*NT + t] = am; sl[am] = -1e30f;
            }
            cnt[b] = 64;
        }
    }
}

// ---------------- gather selected tokens ----------------
__global__ void gather_tok(const float* __restrict__ xcat, const int* __restrict__ list,
                           const int* __restrict__ cnt,
                           float* __restrict__ x0, float* __restrict__ x1)
{
    int b = blockIdx.y, j = blockIdx.x;
    if (j >= cnt[b]) return;
    int idx = list[b*NT + j];
    int c = threadIdx.x;
    const float* src = xcat + ((size_t)b*NT + idx)*512;
    x0[((size_t)b*NT + j)*CD + c] = src[c];
    x1[((size_t)b*NT + j)*CD + c] = src[CD + c];
}

// ---------------- LayerNorm (dual-stream) ----------------
__global__ void ln2(const float* __restrict__ X, float* __restrict__ Y,
                    const float* __restrict__ ga, const float* __restrict__ bba,
                    const float* __restrict__ gb2, const float* __restrict__ bbb,
                    const int* __restrict__ cnt)
{
    int bz = blockIdx.y; int s = bz >> 2, b = bz & 3;
    int n = blockIdx.x;
    if (n >= cnt[b]) return;
    const float* gw = s ? gb2 : ga;
    const float* gb = s ? bbb : bba;
    int tid = threadIdx.x;  // 256 == CD
    size_t row = ((size_t)(s*BB+b)*NT + n)*CD;
    float v = X[row + tid];
    __shared__ float red[8];
    float ssum = v;
    #pragma unroll
    for (int o = 16; o; o >>= 1) ssum += __shfl_down_sync(0xffffffffu, ssum, o);
    if ((tid & 31) == 0) red[tid>>5] = ssum;
    __syncthreads();
    float mean = 0.f;
    #pragma unroll
    for (int i = 0; i < 8; i++) mean += red[i];
    mean *= (1.f/CD);
    __syncthreads();
    float d = v - mean;
    ssum = d*d;
    #pragma unroll
    for (int o = 16; o; o >>= 1) ssum += __shfl_down_sync(0xffffffffu, ssum, o);
    if ((tid & 31) == 0) red[tid>>5] = ssum;
    __syncthreads();
    float var = 0.f;
    #pragma unroll
    for (int i = 0; i < 8; i++) var += red[i];
    var *= (1.f/CD);
    Y[row + tid] = d * rsqrtf(var + 1e-5f) * gw[tid] + gb[tid];
}

// ---------------- flash attention (f32x2, transposed smem operands, dual-stream) ----------------
#define AP 68
#define ATTN_SMEM ((4*64*AP + 128) * (int)sizeof(float))
__global__ void __launch_bounds__(256)
attn2(const float* __restrict__ qkv, float* __restrict__ att, const int* __restrict__ cnt)
{
    extern __shared__ __align__(16) float sm[];
    float* QsT = sm;               // [d][q]  64 x AP
    float* KsT = QsT + 64*AP;      // [d][k]
    float* Vs  = KsT + 64*AP;      // [k][d]
    float* SsT = Vs  + 64*AP;      // [k][q]
    float* alph = SsT + 64*AP;     // 64
    float* lsum = alph + 64;       // 64

    int bz = blockIdx.z; int s = bz >> 2, b = bz & 3;
    int h = blockIdx.y, q0 = blockIdx.x*64;
    int Mb = cnt[b];
    if (q0 >= Mb) return;
    int tid = threadIdx.x;
    int tq = tid >> 4, tc = tid & 15;
    int sq = tid >> 2, sub = tid & 3;
    const float* base = qkv + (size_t)(s*BB+b)*NT*768;

    for (int idx = tid; idx < 4096; idx += 256) {
        int q = idx >> 6, d = idx & 63;
        float v = (q0 + q < Mb) ? base[(size_t)(q0+q)*768 + h*DH + d] : 0.f;
        QsT[d*AP + q] = v;
    }

    float m_run = -1e30f, l_run = 0.f;
    float2 acco[4][2];
    #pragma unroll
    for (int i=0;i<4;i++){ acco[i][0]=make_float2(0.f,0.f); acco[i][1]=make_float2(0.f,0.f); }

    int nkt = (Mb + 63) >> 6;
    for (int kt = 0; kt < nkt; kt++) {
        int k0t = kt*64;
        int kval = min(64, Mb - k0t);
        __syncthreads();
        for (int idx = tid; idx < 4096; idx += 256) {
            int r = idx >> 6, c = idx & 63;
            float kv = 0.f, vv = 0.f;
            if (r < kval) {
                kv = base[(size_t)(k0t+r)*768 + 256 + h*DH + c];
                vv = base[(size_t)(k0t+r)*768 + 512 + h*DH + c];
            }
            KsT[c*AP + r] = kv;
            Vs[r*AP + c]  = vv;
        }
        __syncthreads();
        // S = (Q K^T)/8 -> SsT[k][q]
        {
            float2 accs[2][4];
            #pragma unroll
            for (int ip=0;ip<2;ip++)
                #pragma unroll
                for (int j=0;j<4;j++) accs[ip][j] = make_float2(0.f,0.f);
            for (int d = 0; d < DH; d++) {
                float4 a4 = *(const float4*)&QsT[d*AP + tq*4];
                float4 b4 = *(const float4*)&KsT[d*AP + tc*4];
                float2 qp0 = make_float2(a4.x, a4.y);
                float2 qp1 = make_float2(a4.z, a4.w);
                float wj[4] = {b4.x, b4.y, b4.z, b4.w};
                #pragma unroll
                for (int j=0;j<4;j++){
                    float2 wd = make_float2(wj[j], wj[j]);
                    accs[0][j] = ffma2(qp0, wd, accs[0][j]);
                    accs[1][j] = ffma2(qp1, wd, accs[1][j]);
                }
            }
            #pragma unroll
            for (int j=0;j<4;j++)
                #pragma unroll
                for (int ip=0;ip<2;ip++){
                    float2 v = accs[ip][j];
                    v.x *= 0.125f; v.y *= 0.125f;
                    *(float2*)&SsT[(tc*4+j)*AP + tq*4 + 2*ip] = v;
                }
        }
        __syncthreads();
        // online softmax: one quad (4 lanes) per q-column
        {
            float mx = -1e30f;
            #pragma unroll
            for (int kk = 0; kk < 16; kk++) {
                int k = kk*4 + sub;
                if (k < kval) mx = fmaxf(mx, SsT[k*AP + sq]);
            }
            mx = fmaxf(mx, __shfl_xor_sync(0xffffffffu, mx, 1));
            mx = fmaxf(mx, __shfl_xor_sync(0xffffffffu, mx, 2));
            float mnew = fmaxf(m_run, mx);
            float al = __expf(m_run - mnew);
            float ssum = 0.f;
            #pragma unroll
            for (int kk = 0; kk < 16; kk++) {
                int k = kk*4 + sub;
                float p = 0.f;
                if (k < kval) p = __expf(SsT[k*AP + sq] - mnew);
                SsT[k*AP + sq] = p;
                ssum += p;
            }
            ssum += __shfl_xor_sync(0xffffffffu, ssum, 1);
            ssum += __shfl_xor_sync(0xffffffffu, ssum, 2);
            l_run = l_run*al + ssum;
            m_run = mnew;
            if (sub == 0) alph[sq] = al;
        }
        __syncthreads();
        // O = O*alpha + P V
        #pragma unroll
        for (int i=0;i<4;i++){
            float al = alph[tq*4+i];
            acco[i][0].x *= al; acco[i][0].y *= al;
            acco[i][1].x *= al; acco[i][1].y *= al;
        }
        for (int k = 0; k < 64; k++) {
            float4 p4 = *(const float4*)&SsT[k*AP + tq*4];
            float4 v4 = *(const float4*)&Vs[k*AP + tc*4];
            float2 vp0 = make_float2(v4.x, v4.y);
            float2 vp1 = make_float2(v4.z, v4.w);
            float pi[4] = {p4.x, p4.y, p4.z, p4.w};
            #pragma unroll
            for (int i=0;i<4;i++){
                float2 pd = make_float2(pi[i], pi[i]);
                acco[i][0] = ffma2(pd, vp0, acco[i][0]);
                acco[i][1] = ffma2(pd, vp1, acco[i][1]);
            }
        }
    }
    __syncthreads();
    if (sub == 0) lsum[sq] = l_run;
    __syncthreads();
    #pragma unroll
    for (int i=0;i<4;i++){
        int q = q0 + tq*4 + i;
        if (q < Mb) {
            float inv = 1.f / lsum[tq*4+i];
            float2 o0v = acco[i][0]; o0v.x *= inv; o0v.y *= inv;
            float2 o1v = acco[i][1]; o1v.x *= inv; o1v.y *= inv;
            float* dst = att + ((size_t)(s*BB+b)*NT + q)*CD + h*DH + tc*4;
            *(float2*)dst = o0v;
            *(float2*)(dst+2) = o1v;
        }
    }
}

// ---------------- output ----------------
__global__ void base_out(const float* __restrict__ fir, const float* __restrict__ fvis,
                         float* __restrict__ out)
{
    size_t i = (size_t)blockIdx.x*256 + threadIdx.x;
    out[i] = fir[i] + fvis[i];
}

__global__ void scatter_out(const float* __restrict__ x0, const float* __restrict__ x1,
                            const int* __restrict__ list, const float* __restrict__ maskf,
                            const int* __restrict__ cnt, float* __restrict__ out)
{
    int b = blockIdx.y, j = blockIdx.x;
    if (j >= cnt[b]) return;
    int idx = list[b*NT + j];
    float mv = maskf[b*NT + idx];
    int c = threadIdx.x;
    float v = (x0[((size_t)b*NT + j)*CD + c] + x1[((size_t)b*NT + j)*CD + c]) * mv;
    out[((size_t)b*CD + c)*NT + idx] = v;
}

// ---------------- host ----------------
extern "C" void kernel_launch(void* const* d_in, const int* in_sizes, int n_in,
                              void* d_out, int out_size)
{
    const float* f_ir  = (const float*)d_in[0];
    const float* f_vis = (const float*)d_in[1];
    const float* aw1   = (const float*)d_in[2];
    const float* ab1   = (const float*)d_in[3];
    const float* aw2   = (const float*)d_in[4];
    const float* ab2   = (const float*)d_in[5];
    const float* ir_lng  = (const float*)d_in[6];
    const float* ir_lnb  = (const float*)d_in[7];
    const float* ir_wqkv = (const float*)d_in[8];
    const float* ir_bqkv = (const float*)d_in[9];
    const float* ir_wo   = (const float*)d_in[10];
    const float* ir_bo   = (const float*)d_in[11];
    const float* ir_w1   = (const float*)d_in[12];
    const float* ir_b1   = (const float*)d_in[13];
    const float* ir_w2   = (const float*)d_in[14];
    const float* ir_b2   = (const float*)d_in[15];
    const float* vi_lng  = (const float*)d_in[16];
    const float* vi_lnb  = (const float*)d_in[17];
    const float* vi_wqkv = (const float*)d_in[18];
    const float* vi_bqkv = (const float*)d_in[19];
    const float* vi_wo   = (const float*)d_in[20];
    const float* vi_bo   = (const float*)d_in[21];
    const float* vi_w1   = (const float*)d_in[22];
    const float* vi_b1   = (const float*)d_in[23];
    const float* vi_w2   = (const float*)d_in[24];
    const float* vi_b2   = (const float*)d_in[25];
    float* out = (float*)d_out;

    float *xcat,*h1,*logits,*maskf,*x,*xn,*qkv,*att,*hid;
    int *list,*cntp;
    cudaGetSymbolAddress((void**)&xcat,  g_xcat);
    cudaGetSymbolAddress((void**)&h1,    g_h1);
    cudaGetSymbolAddress((void**)&logits,g_logits);
    cudaGetSymbolAddress((void**)&maskf, g_maskf);
    cudaGetSymbolAddress((void**)&x,     g_x);
    cudaGetSymbolAddress((void**)&xn,    g_xn);
    cudaGetSymbolAddress((void**)&qkv,   g_qkv);
    cudaGetSymbolAddress((void**)&att,   g_att);
    cudaGetSymbolAddress((void**)&hid,   g_hid);
    cudaGetSymbolAddress((void**)&list,  g_list);
    cudaGetSymbolAddress((void**)&cntp,  g_cnt);
    float* x0 = x;
    float* x1 = x + (size_t)BB*NT*CD;

    cudaFuncSetAttribute(attn2, cudaFuncAttributeMaxDynamicSharedMemorySize, ATTN_SMEM);

    // 1. token-major concat
    transpose_cat<<<dim3(NT/32, CD/32, BB*2), dim3(32,8)>>>(f_ir, f_vis, xcat);
    // 2. agent hidden (silu)  [z=BB -> s=0]
    gemm2<<<dim3(AGH/BO, NT/BM, BB), 256>>>(xcat, aw1, aw1, ab1, ab1, h1, 0, 0, 512, AGH, 1);
    // 3. agent logits + STE mask
    agent_logits<<<(BB*NT)/8, 256>>>(h1, aw2, ab2, logits, maskf);
    // 4. selection
    select_kernel<<<BB, 256>>>(logits, list, cntp);
    // 5. gather selected tokens
    gather_tok<<<dim3(NT, BB), 256>>>(xcat, list, cntp, x0, x1);

    // 6. both mixers fused per launch (z = 2*BB)
    ln2<<<dim3(NT, 2*BB), 256>>>(x, xn, ir_lng, ir_lnb, vi_lng, vi_lnb, cntp);
    gemm2<<<dim3(768/BO, NT/BM, 2*BB), 256>>>(xn, ir_wqkv, vi_wqkv, ir_bqkv, vi_bqkv, qkv, 0, cntp, 256, 768, 0);
    attn2<<<dim3(NT/64, NH, 2*BB), 256, ATTN_SMEM>>>(qkv, att, cntp);
    gemm2<<<dim3(CD/BO, NT/BM, 2*BB), 256>>>(att, ir_wo, vi_wo, ir_bo, vi_bo, x, x, cntp, 256, CD, 0);
    ln2<<<dim3(NT, 2*BB), 256>>>(x, xn, ir_lng, ir_lnb, vi_lng, vi_lnb, cntp);
    gemm2<<<dim3(1024/BO, NT/BM, 2*BB), 256>>>(xn, ir_w1, vi_w1, ir_b1, vi_b1, hid, 0, cntp, 256, 1024, 2);
    gemm2<<<dim3(CD/BO, NT/BM, 2*BB), 256>>>(hid, ir_w2, vi_w2, ir_b2, vi_b2, x, x, cntp, 1024, CD, 0);

    // 7. output
    base_out<<<(BB*CD*NT)/256, 256>>>(f_ir, f_vis, out);
    scatter_out<<<dim3(NT, BB), 256>>>(x0, x1, list, maskf, cntp, out);
}

// round 4
// speedup vs baseline: 1.9060x; 1.0275x over previous
#include <cuda_runtime.h>
#include <math.h>

#define BB   4
#define NT   2304      // 48*48 tokens
#define CD   256       // DIM
#define AGH  512       // agent hidden
#define NH   4
#define DH   64

// ---------------- packed f32x2 FMA (Blackwell; PTX-only) ----------------
__device__ __forceinline__ float2 ffma2(float2 a, float2 b, float2 c) {
    float2 d;
    asm("fma.rn.f32x2 %0, %1, %2, %3;"
        : "=l"(reinterpret_cast<unsigned long long&>(d))
        : "l"(reinterpret_cast<unsigned long long&>(a)),
          "l"(reinterpret_cast<unsigned long long&>(b)),
          "l"(reinterpret_cast<unsigned long long&>(c)));
    return d;
}

// ---------------- scratch (static device globals; allocation-free) ----------------
__device__ float g_xcat[(size_t)BB*NT*512];
__device__ float g_h1  [(size_t)BB*NT*AGH];
__device__ float g_logits[BB*NT];
__device__ float g_maskf [BB*NT];
__device__ int   g_list[BB*NT];
__device__ int   g_cnt [BB];
__device__ float g_x  [(size_t)2*BB*NT*CD];       // [s][B][N][C]
__device__ float g_xn [(size_t)2*BB*NT*CD];
__device__ float g_qkv[(size_t)2*BB*NT*3*CD];
__device__ float g_att[(size_t)2*BB*NT*CD];
__device__ float g_hid[(size_t)2*BB*NT*4*CD];

// ---------------- transpose [B,C,N] -> token-major concat [B,N,512] ----------------
__global__ void transpose_cat(const float* __restrict__ fir, const float* __restrict__ fvis,
                              float* __restrict__ xcat)
{
    int src = blockIdx.z & 1;
    int b   = blockIdx.z >> 1;
    const float* f = src ? fvis : fir;
    __shared__ float tile[32][33];
    int n0 = blockIdx.x * 32, c0 = blockIdx.y * 32;
    int tx = threadIdx.x, ty = threadIdx.y;   // (32,8)
    #pragma unroll
    for (int i = 0; i < 32; i += 8)
        tile[ty + i][tx] = f[((size_t)b*CD + c0 + ty + i)*NT + n0 + tx];
    __syncthreads();
    #pragma unroll
    for (int i = 0; i < 32; i += 8)
        xcat[((size_t)b*NT + n0 + ty + i)*512 + src*CD + c0 + tx] = tile[tx][ty + i];
}

// ---------------- fp32 GEMM 128x128 tile, 8x8 micro, f32x2, dual-stream ----------------
#define BM 128
#define BO 128
#define BK 16
#define GP 132   // padded smem row stride
__global__ void __launch_bounds__(256)
gemm2(const float* __restrict__ A,
      const float* __restrict__ Wa, const float* __restrict__ Wb,
      const float* __restrict__ ba, const float* __restrict__ bbv,
      float* __restrict__ C, const float* __restrict__ R,
      const int* __restrict__ counts, int K, int Ocols, int act)
{
    int bz = blockIdx.z;
    int s = bz >> 2, b = bz & 3;
    int Mb = counts ? counts[b] : NT;
    int m0 = blockIdx.y * BM;
    if (m0 >= Mb) return;
    int o0 = blockIdx.x * BO;
    const float* W    = s ? Wb  : Wa;
    const float* bias = s ? bbv : ba;
    size_t rowbase = (size_t)(s*BB + b) * NT;
    const float* Ab = A + rowbase * K;
    float*       Cb = C + rowbase * Ocols;
    const float* Rb = R ? R + rowbase * Ocols : (const float*)0;

    __shared__ __align__(16) float As[BK][GP];
    __shared__ __align__(16) float Ws[BK][GP];

    int tid = threadIdx.x;                 // 256
    int tx = tid & 15, ty = tid >> 4;      // 16 x 16 thread grid, 8x8 micro
    int lrow = tid >> 2, lk = (tid & 3) * 4;

    float2 acc[8][4];
    #pragma unroll
    for (int i=0;i<8;i++)
        #pragma unroll
        for (int j=0;j<4;j++) acc[i][j]=make_float2(0.f,0.f);

    for (int k0 = 0; k0 < K; k0 += BK) {
        #pragma unroll
        for (int li = 0; li < 2; li++) {
            int m = lrow + li*64;
            float4 av = make_float4(0.f,0.f,0.f,0.f);
            if (m0 + m < Mb) av = *(const float4*)&Ab[(size_t)(m0+m)*K + k0 + lk];
            As[lk+0][m]=av.x; As[lk+1][m]=av.y; As[lk+2][m]=av.z; As[lk+3][m]=av.w;
            float4 wv = *(const float4*)&W[(size_t)(o0+m)*K + k0 + lk];
            Ws[lk+0][m]=wv.x; Ws[lk+1][m]=wv.y; Ws[lk+2][m]=wv.z; Ws[lk+3][m]=wv.w;
        }
        __syncthreads();
        #pragma unroll
        for (int k = 0; k < BK; k++) {
            float4 a0 = *(const float4*)&As[k][ty*8];
            float4 a1 = *(const float4*)&As[k][ty*8+4];
            float4 w0 = *(const float4*)&Ws[k][tx*8];
            float4 w1 = *(const float4*)&Ws[k][tx*8+4];
            float2 wp[4] = { make_float2(w0.x,w0.y), make_float2(w0.z,w0.w),
                             make_float2(w1.x,w1.y), make_float2(w1.z,w1.w) };
            float aa[8] = {a0.x,a0.y,a0.z,a0.w,a1.x,a1.y,a1.z,a1.w};
            #pragma unroll
            for (int i=0;i<8;i++){
                float2 ad = make_float2(aa[i], aa[i]);
                #pragma unroll
                for (int j=0;j<4;j++)
                    acc[i][j] = ffma2(ad, wp[j], acc[i][j]);
            }
        }
        __syncthreads();
    }
    #pragma unroll
    for (int i=0;i<8;i++) {
        int m = m0 + ty*8 + i;
        if (m >= Mb) continue;
        float v[8] = {acc[i][0].x,acc[i][0].y,acc[i][1].x,acc[i][1].y,
                      acc[i][2].x,acc[i][2].y,acc[i][3].x,acc[i][3].y};
        float ov[8];
        #pragma unroll
        for (int j=0;j<8;j++) {
            int o = o0 + tx*8 + j;
            float t = v[j] + bias[o];
            if (act == 1)      t = t / (1.f + expf(-t));
            else if (act == 2) t = 0.5f*t*(1.f + erff(t*0.70710678118654752f));
            if (Rb) t += Rb[(size_t)m*Ocols + o];
            ov[j] = t;
        }
        *(float4*)&Cb[(size_t)m*Ocols + o0 + tx*8]     = make_float4(ov[0],ov[1],ov[2],ov[3]);
        *(float4*)&Cb[(size_t)m*Ocols + o0 + tx*8 + 4] = make_float4(ov[4],ov[5],ov[6],ov[7]);
    }
}

// ---------------- agent logits reduce ----------------
__global__ void agent_logits(const float* __restrict__ h1, const float* __restrict__ aw2,
                             const float* __restrict__ ab2,
                             float* __restrict__ logits, float* __restrict__ maskf)
{
    int t = blockIdx.x * 8 + (threadIdx.x >> 5);
    if (t >= BB*NT) return;
    int lane = threadIdx.x & 31;
    const float* hr = h1 + (size_t)t*AGH;
    float ssum = 0.f;
    for (int i = lane; i < AGH; i += 32) ssum += hr[i]*aw2[i];
    #pragma unroll
    for (int off = 16; off; off >>= 1) ssum += __shfl_down_sync(0xffffffffu, ssum, off);
    if (lane == 0) {
        float lg = ssum + ab2[0];
        logits[t] = lg;
        maskf[t]  = (lg > 0.f) ? 1.f : 0.f;
    }
}

// ---------------- selection ----------------
__global__ void select_kernel(const float* __restrict__ logits,
                              int* __restrict__ list, int* __restrict__ cnt)
{
    int b = blockIdx.x, tid = threadIdx.x;
    const float* lg = logits + b*NT;
    const int PER = NT/256;  // 9
    __shared__ int cn[256];
    int base = tid*PER;
    float lv[PER];
    bool  sv[PER];
    int c = 0;
    #pragma unroll
    for (int i = 0; i < PER; i++) {
        float v = lg[base+i]; lv[i] = v;
        bool sel = v > 0.f; sv[i] = sel; c += sel;
    }
    cn[tid] = c; __syncthreads();
    for (int off = 1; off < 256; off <<= 1) {
        int v = (tid >= off) ? cn[tid-off] : 0;
        __syncthreads();
        cn[tid] += v;
        __syncthreads();
    }
    int total = cn[255];
    int pos = cn[tid] - c;
    if (total >= 64) {
        #pragma unroll
        for (int i = 0; i < PER; i++)
            if (sv[i]) { list[b*NT + pos] = base + i; pos++; }
        if (tid == 0) cnt[b] = total;
    } else {
        __shared__ float sl[NT];
        #pragma unroll
        for (int i = 0; i < PER; i++) sl[base+i] = lv[i];
        __syncthreads();
        if (tid == 0) {
            for (int t = 0; t < 64; t++) {
                int am = 0; float mv = sl[0];
                for (int n = 1; n < NT; n++) if (sl[n] > mv) { mv = sl[n]; am = n; }
                list[b*NT + t] = am; sl[am] = -1e30f;
            }
            cnt[b] = 64;
        }
    }
}

// ---------------- gather selected tokens ----------------
__global__ void gather_tok(const float* __restrict__ xcat, const int* __restrict__ list,
                           const int* __restrict__ cnt,
                           float* __restrict__ x0, float* __restrict__ x1)
{
    int b = blockIdx.y, j = blockIdx.x;
    if (j >= cnt[b]) return;
    int idx = list[b*NT + j];
    int c = threadIdx.x;
    const float* src = xcat + ((size_t)b*NT + idx)*512;
    x0[((size_t)b*NT + j)*CD + c] = src[c];
    x1[((size_t)b*NT + j)*CD + c] = src[CD + c];
}

// ---------------- LayerNorm (dual-stream) ----------------
__global__ void ln2(const float* __restrict__ X, float* __restrict__ Y,
                    const float* __restrict__ ga, const float* __restrict__ bba,
                    const float* __restrict__ gb2, const float* __restrict__ bbb,
                    const int* __restrict__ cnt)
{
    int bz = blockIdx.y; int s = bz >> 2, b = bz & 3;
    int n = blockIdx.x;
    if (n >= cnt[b]) return;
    const float* gw = s ? gb2 : ga;
    const float* gb = s ? bbb : bba;
    int tid = threadIdx.x;  // 256 == CD
    size_t row = ((size_t)(s*BB+b)*NT + n)*CD;
    float v = X[row + tid];
    __shared__ float red[8];
    float ssum = v;
    #pragma unroll
    for (int o = 16; o; o >>= 1) ssum += __shfl_down_sync(0xffffffffu, ssum, o);
    if ((tid & 31) == 0) red[tid>>5] = ssum;
    __syncthreads();
    float mean = 0.f;
    #pragma unroll
    for (int i = 0; i < 8; i++) mean += red[i];
    mean *= (1.f/CD);
    __syncthreads();
    float d = v - mean;
    ssum = d*d;
    #pragma unroll
    for (int o = 16; o; o >>= 1) ssum += __shfl_down_sync(0xffffffffu, ssum, o);
    if ((tid & 31) == 0) red[tid>>5] = ssum;
    __syncthreads();
    float var = 0.f;
    #pragma unroll
    for (int i = 0; i < 8; i++) var += red[i];
    var *= (1.f/CD);
    Y[row + tid] = d * rsqrtf(var + 1e-5f) * gw[tid] + gb[tid];
}

// ---------------- flash attention: 128q x 64k tile, 8q x 4k micro, f32x2 ----------------
#define APQ 132   // stride for [*][q] arrays (q dim = 128)
#define APK 68    // stride for [*][k]/[k][*] arrays (64)
#define ATTN_SMEM ((64*APQ + 64*APK + 64*APK + 64*APQ + 256) * (int)sizeof(float))
__global__ void __launch_bounds__(256)
attn2(const float* __restrict__ qkv, float* __restrict__ att, const int* __restrict__ cnt)
{
    extern __shared__ __align__(16) float sm[];
    float* QsT = sm;               // [d][q]  64 x APQ
    float* KsT = QsT + 64*APQ;     // [d][k]  64 x APK
    float* Vs  = KsT + 64*APK;     // [k][d]  64 x APK
    float* SsT = Vs  + 64*APK;     // [k][q]  64 x APQ
    float* alph = SsT + 64*APQ;    // 128
    float* lsum = alph + 128;      // 128

    int bz = blockIdx.z; int s = bz >> 2, b = bz & 3;
    int h = blockIdx.y, q0 = blockIdx.x*128;
    int Mb = cnt[b];
    if (q0 >= Mb) return;
    int tid = threadIdx.x;
    int tx = tid & 15, ty = tid >> 4;       // tx: k-group(QK)/d-group(PV), ty: q-group of 8
    int sq = tid >> 1, sub = tid & 1;       // softmax: 2 lanes per q-row
    const float* base = qkv + (size_t)(s*BB+b)*NT*768;

    // load Q tile transposed [d][q]
    for (int idx = tid; idx < 128*64; idx += 256) {
        int q = idx >> 6, d = idx & 63;
        float v = (q0 + q < Mb) ? base[(size_t)(q0+q)*768 + h*DH + d] : 0.f;
        QsT[d*APQ + q] = v;
    }

    float m_run = -1e30f, l_run = 0.f;
    float2 acco[8][2];
    #pragma unroll
    for (int i=0;i<8;i++){ acco[i][0]=make_float2(0.f,0.f); acco[i][1]=make_float2(0.f,0.f); }

    int nkt = (Mb + 63) >> 6;
    for (int kt = 0; kt < nkt; kt++) {
        int k0t = kt*64;
        int kval = min(64, Mb - k0t);
        __syncthreads();   // prev-tile consumers done
        for (int idx = tid; idx < 64*64; idx += 256) {
            int r = idx >> 6, c = idx & 63;
            float kv = 0.f, vv = 0.f;
            if (r < kval) {
                kv = base[(size_t)(k0t+r)*768 + 256 + h*DH + c];
                vv = base[(size_t)(k0t+r)*768 + 512 + h*DH + c];
            }
            KsT[c*APK + r] = kv;
            Vs[r*APK + c]  = vv;
        }
        __syncthreads();
        // S = (Q K^T)/8 -> SsT[k][q]; per-thread 8q x 4k
        {
            float2 accs[4][4];   // [k][q-pair]
            #pragma unroll
            for (int j=0;j<4;j++)
                #pragma unroll
                for (int ip=0;ip<4;ip++) accs[j][ip] = make_float2(0.f,0.f);
            for (int d = 0; d < DH; d++) {
                float4 qa = *(const float4*)&QsT[d*APQ + ty*8];
                float4 qb = *(const float4*)&QsT[d*APQ + ty*8 + 4];
                float4 kk = *(const float4*)&KsT[d*APK + tx*4];
                float2 qp[4] = { make_float2(qa.x,qa.y), make_float2(qa.z,qa.w),
                                 make_float2(qb.x,qb.y), make_float2(qb.z,qb.w) };
                float kj[4] = {kk.x, kk.y, kk.z, kk.w};
                #pragma unroll
                for (int j=0;j<4;j++){
                    float2 kd = make_float2(kj[j], kj[j]);
                    #pragma unroll
                    for (int ip=0;ip<4;ip++)
                        accs[j][ip] = ffma2(qp[ip], kd, accs[j][ip]);
                }
            }
            #pragma unroll
            for (int j=0;j<4;j++){
                #pragma unroll
                for (int ip=0;ip<4;ip++){
                    float2 v = accs[j][ip];
                    v.x *= 0.125f; v.y *= 0.125f;
                    *(float2*)&SsT[(tx*4+j)*APQ + ty*8 + 2*ip] = v;
                }
            }
        }
        __syncthreads();
        // online softmax: 2 lanes per q-row (128 rows)
        {
            float mx = -1e30f;
            #pragma unroll
            for (int kk = 0; kk < 32; kk++) {
                int k = kk*2 + sub;
                if (k < kval) mx = fmaxf(mx, SsT[k*APQ + sq]);
            }
            mx = fmaxf(mx, __shfl_xor_sync(0xffffffffu, mx, 1));
            float mnew = fmaxf(m_run, mx);
            float al = __expf(m_run - mnew);
            float ssum = 0.f;
            #pragma unroll
            for (int kk = 0; kk < 32; kk++) {
                int k = kk*2 + sub;
                float p = 0.f;
                if (k < kval) p = __expf(SsT[k*APQ + sq] - mnew);
                SsT[k*APQ + sq] = p;
                ssum += p;
            }
            ssum += __shfl_xor_sync(0xffffffffu, ssum, 1);
            l_run = l_run*al + ssum;
            m_run = mnew;
            if (sub == 0) alph[sq] = al;
        }
        __syncthreads();
        // O = O*alpha + P V ; per-thread 8q x 4d
        #pragma unroll
        for (int i=0;i<8;i++){
            float al = alph[ty*8+i];
            acco[i][0].x *= al; acco[i][0].y *= al;
            acco[i][1].x *= al; acco[i][1].y *= al;
        }
        for (int k = 0; k < 64; k++) {
            float4 pa = *(const float4*)&SsT[k*APQ + ty*8];
            float4 pb = *(const float4*)&SsT[k*APQ + ty*8 + 4];
            float4 v4 = *(const float4*)&Vs[k*APK + tx*4];
            float2 vp0 = make_float2(v4.x, v4.y);
            float2 vp1 = make_float2(v4.z, v4.w);
            float pi[8] = {pa.x,pa.y,pa.z,pa.w,pb.x,pb.y,pb.z,pb.w};
            #pragma unroll
            for (int i=0;i<8;i++){
                float2 pd = make_float2(pi[i], pi[i]);
                acco[i][0] = ffma2(pd, vp0, acco[i][0]);
                acco[i][1] = ffma2(pd, vp1, acco[i][1]);
            }
        }
    }
    __syncthreads();
    if (sub == 0) lsum[sq] = l_run;
    __syncthreads();
    #pragma unroll
    for (int i=0;i<8;i++){
        int q = q0 + ty*8 + i;
        if (q < Mb) {
            float inv = 1.f / lsum[ty*8+i];
            float4 o4 = make_float4(acco[i][0].x*inv, acco[i][0].y*inv,
                                    acco[i][1].x*inv, acco[i][1].y*inv);
            *(float4*)&att[((size_t)(s*BB+b)*NT + q)*CD + h*DH + tx*4] = o4;
        }
    }
}

// ---------------- output ----------------
__global__ void base_out(const float* __restrict__ fir, const float* __restrict__ fvis,
                         float* __restrict__ out)
{
    size_t i = (size_t)blockIdx.x*256 + threadIdx.x;
    out[i] = fir[i] + fvis[i];
}

__global__ void scatter_out(const float* __restrict__ x0, const float* __restrict__ x1,
                            const int* __restrict__ list, const float* __restrict__ maskf,
                            const int* __restrict__ cnt, float* __restrict__ out)
{
    int b = blockIdx.y, j = blockIdx.x;
    if (j >= cnt[b]) return;
    int idx = list[b*NT + j];
    float mv = maskf[b*NT + idx];
    int c = threadIdx.x;
    float v = (x0[((size_t)b*NT + j)*CD + c] + x1[((size_t)b*NT + j)*CD + c]) * mv;
    out[((size_t)b*CD + c)*NT + idx] = v;
}

// ---------------- host ----------------
extern "C" void kernel_launch(void* const* d_in, const int* in_sizes, int n_in,
                              void* d_out, int out_size)
{
    const float* f_ir  = (const float*)d_in[0];
    const float* f_vis = (const float*)d_in[1];
    const float* aw1   = (const float*)d_in[2];
    const float* ab1   = (const float*)d_in[3];
    const float* aw2   = (const float*)d_in[4];
    const float* ab2   = (const float*)d_in[5];
    const float* ir_lng  = (const float*)d_in[6];
    const float* ir_lnb  = (const float*)d_in[7];
    const float* ir_wqkv = (const float*)d_in[8];
    const float* ir_bqkv = (const float*)d_in[9];
    const float* ir_wo   = (const float*)d_in[10];
    const float* ir_bo   = (const float*)d_in[11];
    const float* ir_w1   = (const float*)d_in[12];
    const float* ir_b1   = (const float*)d_in[13];
    const float* ir_w2   = (const float*)d_in[14];
    const float* ir_b2   = (const float*)d_in[15];
    const float* vi_lng  = (const float*)d_in[16];
    const float* vi_lnb  = (const float*)d_in[17];
    const float* vi_wqkv = (const float*)d_in[18];
    const float* vi_bqkv = (const float*)d_in[19];
    const float* vi_wo   = (const float*)d_in[20];
    const float* vi_bo   = (const float*)d_in[21];
    const float* vi_w1   = (const float*)d_in[22];
    const float* vi_b1   = (const float*)d_in[23];
    const float* vi_w2   = (const float*)d_in[24];
    const float* vi_b2   = (const float*)d_in[25];
    float* out = (float*)d_out;

    float *xcat,*h1,*logits,*maskf,*x,*xn,*qkv,*att,*hid;
    int *list,*cntp;
    cudaGetSymbolAddress((void**)&xcat,  g_xcat);
    cudaGetSymbolAddress((void**)&h1,    g_h1);
    cudaGetSymbolAddress((void**)&logits,g_logits);
    cudaGetSymbolAddress((void**)&maskf, g_maskf);
    cudaGetSymbolAddress((void**)&x,     g_x);
    cudaGetSymbolAddress((void**)&xn,    g_xn);
    cudaGetSymbolAddress((void**)&qkv,   g_qkv);
    cudaGetSymbolAddress((void**)&att,   g_att);
    cudaGetSymbolAddress((void**)&hid,   g_hid);
    cudaGetSymbolAddress((void**)&list,  g_list);
    cudaGetSymbolAddress((void**)&cntp,  g_cnt);
    float* x0 = x;
    float* x1 = x + (size_t)BB*NT*CD;

    cudaFuncSetAttribute(attn2, cudaFuncAttributeMaxDynamicSharedMemorySize, ATTN_SMEM);

    // 1. token-major concat
    transpose_cat<<<dim3(NT/32, CD/32, BB*2), dim3(32,8)>>>(f_ir, f_vis, xcat);
    // 2. agent hidden (silu)
    gemm2<<<dim3(AGH/BO, NT/BM, BB), 256>>>(xcat, aw1, aw1, ab1, ab1, h1, 0, 0, 512, AGH, 1);
    // 3. agent logits + STE mask
    agent_logits<<<(BB*NT)/8, 256>>>(h1, aw2, ab2, logits, maskf);
    // 4. selection
    select_kernel<<<BB, 256>>>(logits, list, cntp);
    // 5. gather selected tokens
    gather_tok<<<dim3(NT, BB), 256>>>(xcat, list, cntp, x0, x1);

    // 6. both mixers fused per launch (z = 2*BB)
    ln2<<<dim3(NT, 2*BB), 256>>>(x, xn, ir_lng, ir_lnb, vi_lng, vi_lnb, cntp);
    gemm2<<<dim3(768/BO, NT/BM, 2*BB), 256>>>(xn, ir_wqkv, vi_wqkv, ir_bqkv, vi_bqkv, qkv, 0, cntp, 256, 768, 0);
    attn2<<<dim3(NT/128, NH, 2*BB), 256, ATTN_SMEM>>>(qkv, att, cntp);
    gemm2<<<dim3(CD/BO, NT/BM, 2*BB), 256>>>(att, ir_wo, vi_wo, ir_bo, vi_bo, x, x, cntp, 256, CD, 0);
    ln2<<<dim3(NT, 2*BB), 256>>>(x, xn, ir_lng, ir_lnb, vi_lng, vi_lnb, cntp);
    gemm2<<<dim3(1024/BO, NT/BM, 2*BB), 256>>>(xn, ir_w1, vi_w1, ir_b1, vi_b1, hid, 0, cntp, 256, 1024, 2);
    gemm2<<<dim3(CD/BO, NT/BM, 2*BB), 256>>>(hid, ir_w2, vi_w2, ir_b2, vi_b2, x, x, cntp, 1024, CD, 0);

    // 7. output
    base_out<<<(BB*CD*NT)/256, 256>>>(f_ir, f_vis, out);
    scatter_out<<<dim3(NT, BB), 256>>>(x0, x1, list, maskf, cntp, out);
}

// round 6
// speedup vs baseline: 2.4309x; 1.2754x over previous
#include <cuda_runtime.h>
#include <cuda_bf16.h>
#include <math.h>
#include <stdint.h>

#define BB   4
#define NT   2304      // 48*48 tokens
#define CD   256       // DIM
#define AGH  512       // agent hidden
#define NH   4
#define DH   64

// ---------------- packed f32x2 FMA (attention path) ----------------
__device__ __forceinline__ float2 ffma2(float2 a, float2 b, float2 c) {
    float2 d;
    asm("fma.rn.f32x2 %0, %1, %2, %3;"
        : "=l"(reinterpret_cast<unsigned long long&>(d))
        : "l"(reinterpret_cast<unsigned long long&>(a)),
          "l"(reinterpret_cast<unsigned long long&>(b)),
          "l"(reinterpret_cast<unsigned long long&>(c)));
    return d;
}

// ---------------- bf16 HMMA m16n8k16 (sm_80+ path; works on compute_103) ----------------
__device__ __forceinline__ void mma16816(float* c, const uint32_t* a, uint32_t b0, uint32_t b1) {
    asm volatile("mma.sync.aligned.m16n8k16.row.col.f32.bf16.bf16.f32 "
        "{%0,%1,%2,%3}, {%4,%5,%6,%7}, {%8,%9}, {%0,%1,%2,%3};"
        : "+f"(c[0]), "+f"(c[1]), "+f"(c[2]), "+f"(c[3])
        : "r"(a[0]), "r"(a[1]), "r"(a[2]), "r"(a[3]), "r"(b0), "r"(b1));
}

// ---------------- scratch ----------------
__device__ float g_xcat[(size_t)BB*NT*512];
__device__ float g_h1  [(size_t)BB*NT*AGH];
__device__ float g_logits[BB*NT];
__device__ float g_maskf [BB*NT];
__device__ int   g_list[BB*NT];
__device__ int   g_cnt [BB];
__device__ float g_x  [(size_t)2*BB*NT*CD];
__device__ float g_xn [(size_t)2*BB*NT*CD];
__device__ float g_qkv[(size_t)2*BB*NT*3*CD];
__device__ float g_att[(size_t)2*BB*NT*CD];
__device__ float g_hid[(size_t)2*BB*NT*4*CD];

// ---------------- transpose [B,C,N] -> token-major concat [B,N,512] ----------------
__global__ void transpose_cat(const float* __restrict__ fir, const float* __restrict__ fvis,
                              float* __restrict__ xcat)
{
    int src = blockIdx.z & 1;
    int b   = blockIdx.z >> 1;
    const float* f = src ? fvis : fir;
    __shared__ float tile[32][33];
    int n0 = blockIdx.x * 32, c0 = blockIdx.y * 32;
    int tx = threadIdx.x, ty = threadIdx.y;
    #pragma unroll
    for (int i = 0; i < 32; i += 8)
        tile[ty + i][tx] = f[((size_t)b*CD + c0 + ty + i)*NT + n0 + tx];
    __syncthreads();
    #pragma unroll
    for (int i = 0; i < 32; i += 8)
        xcat[((size_t)b*NT + n0 + ty + i)*512 + src*CD + c0 + tx] = tile[tx][ty + i];
}

// ================= HMMA GEMM (bf16 hi/lo split, 3-term) =================
// C[m,o] = act( sum_k A[m,k]*W[o,k] + bias[o] ) (+resid)
// block tile 128m x 128o, K-chunks of 32, 2-stage smem pipeline.
#define RS    36                   // smem row stride in bf16 (72 B = 18 banks; conflict-free)
#define MATB  (128*RS*2)           // 9216 bytes per bf16 matrix
#define STAGE (4*MATB)             // Ahi, Alo, Whi, Wlo
#define GEMM_SMEM (2*STAGE)        // 73728 B

__device__ __forceinline__ float actf(float t, int act) {
    if (act == 1) return t / (1.f + expf(-t));
    if (act == 2) return 0.5f*t*(1.f + erff(t*0.70710678118654752f));
    return t;
}

__device__ __forceinline__ void cvt_pack(float4 v, uint2& h, uint2& l) {
    __nv_bfloat16 h0 = __float2bfloat16_rn(v.x);
    __nv_bfloat16 h1 = __float2bfloat16_rn(v.y);
    __nv_bfloat16 h2 = __float2bfloat16_rn(v.z);
    __nv_bfloat16 h3 = __float2bfloat16_rn(v.w);
    h.x = ((uint32_t)__bfloat16_as_ushort(h1) << 16) | (uint32_t)__bfloat16_as_ushort(h0);
    h.y = ((uint32_t)__bfloat16_as_ushort(h3) << 16) | (uint32_t)__bfloat16_as_ushort(h2);
    __nv_bfloat16 l0 = __float2bfloat16_rn(v.x - __bfloat162float(h0));
    __nv_bfloat16 l1 = __float2bfloat16_rn(v.y - __bfloat162float(h1));
    __nv_bfloat16 l2 = __float2bfloat16_rn(v.z - __bfloat162float(h2));
    __nv_bfloat16 l3 = __float2bfloat16_rn(v.w - __bfloat162float(h3));
    l.x = ((uint32_t)__bfloat16_as_ushort(l1) << 16) | (uint32_t)__bfloat16_as_ushort(l0);
    l.y = ((uint32_t)__bfloat16_as_ushort(l3) << 16) | (uint32_t)__bfloat16_as_ushort(l2);
}

__global__ void __launch_bounds__(256)
gemm_hm(const float* __restrict__ A,
        const float* __restrict__ Wa, const float* __restrict__ Wb,
        const float* __restrict__ ba, const float* __restrict__ bbv,
        float* __restrict__ C, const float* __restrict__ R,
        const int* __restrict__ counts, int K, int Ocols, int act)
{
    int bz = blockIdx.z;
    int s = (bz >= BB) ? 1 : 0;
    int b = bz & 3;
    int Mb = counts ? counts[b] : NT;
    int m0 = blockIdx.y * 128;
    if (m0 >= Mb) return;
    int o0 = blockIdx.x * 128;
    const float* W    = s ? Wb  : Wa;
    const float* bias = s ? bbv : ba;
    size_t rowbase = (size_t)(s*BB + b) * NT;
    const float* Ab = A + rowbase * K + (size_t)m0 * K;
    float*       Cb = C + rowbase * Ocols;
    const float* Rb = R ? R + rowbase * Ocols : (const float*)0;
    const float* Wt = W + (size_t)o0 * K;
    int arows = Mb - m0; if (arows > 128) arows = 128;

    extern __shared__ char smem[];
    int tid  = threadIdx.x;
    int lane = tid & 31, w = tid >> 5;
    int wm = w & 3, wn = w >> 2;          // 4 m-warps x 2 n-warps
    int gid = lane >> 2, tig = lane & 3;

    float acc[2][8][4];
    #pragma unroll
    for (int mt=0; mt<2; mt++)
        #pragma unroll
        for (int nt=0; nt<8; nt++)
            #pragma unroll
            for (int q=0; q<4; q++) acc[mt][nt][q] = 0.f;

    // pipeline regs: per-thread 4 float4 of A and W
    int lr = tid >> 1;
    int lc = (tid & 1) * 16;
    float4 ra[4], rw[4];

    int nchunk = K >> 5;

    // prefetch chunk 0
    #pragma unroll
    for (int i = 0; i < 4; i++) {
        ra[i] = make_float4(0.f,0.f,0.f,0.f);
        if (lr < arows) ra[i] = *(const float4*)&Ab[(size_t)lr*K + lc + i*4];
        rw[i] = *(const float4*)&Wt[(size_t)lr*K + lc + i*4];
    }
    {
        char* st = smem;
        #pragma unroll
        for (int i = 0; i < 4; i++) {
            uint32_t off = (uint32_t)(lr*(RS*2) + (lc + i*4)*2);
            uint2 h, l;
            cvt_pack(ra[i], h, l);
            *(uint2*)(st + off) = h;
            *(uint2*)(st + MATB + off) = l;
            cvt_pack(rw[i], h, l);
            *(uint2*)(st + 2*MATB + off) = h;
            *(uint2*)(st + 3*MATB + off) = l;
        }
    }
    __syncthreads();

    for (int c = 0; c < nchunk; c++) {
        if (c + 1 < nchunk) {
            int k0 = (c + 1) << 5;
            #pragma unroll
            for (int i = 0; i < 4; i++) {
                ra[i] = make_float4(0.f,0.f,0.f,0.f);
                if (lr < arows) ra[i] = *(const float4*)&Ab[(size_t)lr*K + k0 + lc + i*4];
                rw[i] = *(const float4*)&Wt[(size_t)lr*K + k0 + lc + i*4];
            }
        }
        // compute on stage c&1
        {
            char* st  = smem + (c & 1) * STAGE;
            char* ahi = st;
            char* alo = st + MATB;
            char* whi = st + 2*MATB;
            char* wlo = st + 3*MATB;
            #pragma unroll
            for (int ks = 0; ks < 2; ks++) {
                int kb = ks * 32;   // byte offset of k-step within row (16 bf16 = 32 B)
                uint32_t Ah[2][4], Al[2][4];
                #pragma unroll
                for (int mt = 0; mt < 2; mt++) {
                    uint32_t base = (uint32_t)((wm*32 + mt*16 + gid)*(RS*2) + kb + tig*4);
                    Ah[mt][0] = *(const uint32_t*)(ahi + base);
                    Ah[mt][1] = *(const uint32_t*)(ahi + base + 8*RS*2);
                    Ah[mt][2] = *(const uint32_t*)(ahi + base + 16);
                    Ah[mt][3] = *(const uint32_t*)(ahi + base + 8*RS*2 + 16);
                    Al[mt][0] = *(const uint32_t*)(alo + base);
                    Al[mt][1] = *(const uint32_t*)(alo + base + 8*RS*2);
                    Al[mt][2] = *(const uint32_t*)(alo + base + 16);
                    Al[mt][3] = *(const uint32_t*)(alo + base + 8*RS*2 + 16);
                }
                #pragma unroll
                for (int nt = 0; nt < 8; nt++) {
                    uint32_t bb = (uint32_t)((wn*64 + nt*8 + gid)*(RS*2) + kb + tig*4);
                    uint32_t Bh0 = *(const uint32_t*)(whi + bb);
                    uint32_t Bh1 = *(const uint32_t*)(whi + bb + 16);
                    uint32_t Bl0 = *(const uint32_t*)(wlo + bb);
                    uint32_t Bl1 = *(const uint32_t*)(wlo + bb + 16);
                    #pragma unroll
                    for (int mt = 0; mt < 2; mt++) {
                        mma16816(acc[mt][nt], Ah[mt], Bh0, Bh1);
                        mma16816(acc[mt][nt], Ah[mt], Bl0, Bl1);
                        mma16816(acc[mt][nt], Al[mt], Bh0, Bh1);
                    }
                }
            }
        }
        if (c + 1 < nchunk) {
            __syncthreads();
            char* st = smem + ((c + 1) & 1) * STAGE;
            #pragma unroll
            for (int i = 0; i < 4; i++) {
                uint32_t off = (uint32_t)(lr*(RS*2) + (lc + i*4)*2);
                uint2 h, l;
                cvt_pack(ra[i], h, l);
                *(uint2*)(st + off) = h;
                *(uint2*)(st + MATB + off) = l;
                cvt_pack(rw[i], h, l);
                *(uint2*)(st + 2*MATB + off) = h;
                *(uint2*)(st + 3*MATB + off) = l;
            }
            __syncthreads();
        }
    }

    // epilogue
    #pragma unroll
    for (int mt = 0; mt < 2; mt++) {
        int r0 = m0 + wm*32 + mt*16 + gid;
        int r1 = r0 + 8;
        #pragma unroll
        for (int nt = 0; nt < 8; nt++) {
            int col = o0 + wn*64 + nt*8 + 2*tig;
            float b0v = bias[col], b1v = bias[col+1];
            if (r0 < Mb) {
                float t0 = actf(acc[mt][nt][0] + b0v, act);
                float t1 = actf(acc[mt][nt][1] + b1v, act);
                if (Rb) { t0 += Rb[(size_t)(r0 - m0 + m0)*Ocols + col]; t1 += Rb[(size_t)r0*Ocols + col + 1]; }
                *(float2*)&Cb[(size_t)r0*Ocols + col] = make_float2(t0, t1);
            }
            if (r1 < Mb) {
                float t2 = actf(acc[mt][nt][2] + b0v, act);
                float t3 = actf(acc[mt][nt][3] + b1v, act);
                if (Rb) { t2 += Rb[(size_t)r1*Ocols + col]; t3 += Rb[(size_t)r1*Ocols + col + 1]; }
                *(float2*)&Cb[(size_t)r1*Ocols + col] = make_float2(t2, t3);
            }
        }
    }
}

// ---------------- agent logits reduce ----------------
__global__ void agent_logits(const float* __restrict__ h1, const float* __restrict__ aw2,
                             const float* __restrict__ ab2,
                             float* __restrict__ logits, float* __restrict__ maskf)
{
    int t = blockIdx.x * 8 + (threadIdx.x >> 5);
    if (t >= BB*NT) return;
    int lane = threadIdx.x & 31;
    const float* hr = h1 + (size_t)t*AGH;
    float ssum = 0.f;
    for (int i = lane; i < AGH; i += 32) ssum += hr[i]*aw2[i];
    #pragma unroll
    for (int off = 16; off; off >>= 1) ssum += __shfl_down_sync(0xffffffffu, ssum, off);
    if (lane == 0) {
        float lg = ssum + ab2[0];
        logits[t] = lg;
        maskf[t]  = (lg > 0.f) ? 1.f : 0.f;
    }
}

// ---------------- selection ----------------
__global__ void select_kernel(const float* __restrict__ logits,
                              int* __restrict__ list, int* __restrict__ cnt)
{
    int b = blockIdx.x, tid = threadIdx.x;
    const float* lg = logits + b*NT;
    const int PER = NT/256;  // 9
    __shared__ int cn[256];
    int base = tid*PER;
    float lv[PER];
    bool  sv[PER];
    int c = 0;
    #pragma unroll
    for (int i = 0; i < PER; i++) {
        float v = lg[base+i]; lv[i] = v;
        bool sel = v > 0.f; sv[i] = sel; c += sel;
    }
    cn[tid] = c; __syncthreads();
    for (int off = 1; off < 256; off <<= 1) {
        int v = (tid >= off) ? cn[tid-off] : 0;
        __syncthreads();
        cn[tid] += v;
        __syncthreads();
    }
    int total = cn[255];
    int pos = cn[tid] - c;
    if (total >= 64) {
        #pragma unroll
        for (int i = 0; i < PER; i++)
            if (sv[i]) { list[b*NT + pos] = base + i; pos++; }
        if (tid == 0) cnt[b] = total;
    } else {
        __shared__ float sl[NT];
        #pragma unroll
        for (int i = 0; i < PER; i++) sl[base+i] = lv[i];
        __syncthreads();
        if (tid == 0) {
            for (int t = 0; t < 64; t++) {
                int am = 0; float mv = sl[0];
                for (int n = 1; n < NT; n++) if (sl[n] > mv) { mv = sl[n]; am = n; }
                list[b*NT + t] = am; sl[am] = -1e30f;
            }
            cnt[b] = 64;
        }
    }
}

// ---------------- gather selected tokens ----------------
__global__ void gather_tok(const float* __restrict__ xcat, const int* __restrict__ list,
                           const int* __restrict__ cnt,
                           float* __restrict__ x0, float* __restrict__ x1)
{
    int b = blockIdx.y, j = blockIdx.x;
    if (j >= cnt[b]) return;
    int idx = list[b*NT + j];
    int c = threadIdx.x;
    const float* src = xcat + ((size_t)b*NT + idx)*512;
    x0[((size_t)b*NT + j)*CD + c] = src[c];
    x1[((size_t)b*NT + j)*CD + c] = src[CD + c];
}

// ---------------- LayerNorm (dual-stream) ----------------
__global__ void ln2(const float* __restrict__ X, float* __restrict__ Y,
                    const float* __restrict__ ga, const float* __restrict__ bba,
                    const float* __restrict__ gb2, const float* __restrict__ bbb,
                    const int* __restrict__ cnt)
{
    int bz = blockIdx.y; int s = bz >> 2, b = bz & 3;
    int n = blockIdx.x;
    if (n >= cnt[b]) return;
    const float* gw = s ? gb2 : ga;
    const float* gb = s ? bbb : bba;
    int tid = threadIdx.x;
    size_t row = ((size_t)(s*BB+b)*NT + n)*CD;
    float v = X[row + tid];
    __shared__ float red[8];
    float ssum = v;
    #pragma unroll
    for (int o = 16; o; o >>= 1) ssum += __shfl_down_sync(0xffffffffu, ssum, o);
    if ((tid & 31) == 0) red[tid>>5] = ssum;
    __syncthreads();
    float mean = 0.f;
    #pragma unroll
    for (int i = 0; i < 8; i++) mean += red[i];
    mean *= (1.f/CD);
    __syncthreads();
    float d = v - mean;
    ssum = d*d;
    #pragma unroll
    for (int o = 16; o; o >>= 1) ssum += __shfl_down_sync(0xffffffffu, ssum, o);
    if ((tid & 31) == 0) red[tid>>5] = ssum;
    __syncthreads();
    float var = 0.f;
    #pragma unroll
    for (int i = 0; i < 8; i++) var += red[i];
    var *= (1.f/CD);
    Y[row + tid] = d * rsqrtf(var + 1e-5f) * gw[tid] + gb[tid];
}

// ---------------- flash attention: 128q x 64k tile, 8q x 4k micro, f32x2 ----------------
#define APQ 132
#define APK 68
#define ATTN_SMEM ((64*APQ + 64*APK + 64*APK + 64*APQ + 256) * (int)sizeof(float))
__global__ void __launch_bounds__(256)
attn2(const float* __restrict__ qkv, float* __restrict__ att, const int* __restrict__ cnt)
{
    extern __shared__ __align__(16) float sm[];
    float* QsT = sm;
    float* KsT = QsT + 64*APQ;
    float* Vs  = KsT + 64*APK;
    float* SsT = Vs  + 64*APK;
    float* alph = SsT + 64*APQ;
    float* lsum = alph + 128;

    int bz = blockIdx.z; int s = bz >> 2, b = bz & 3;
    int h = blockIdx.y, q0 = blockIdx.x*128;
    int Mb = cnt[b];
    if (q0 >= Mb) return;
    int tid = threadIdx.x;
    int tx = tid & 15, ty = tid >> 4;
    int sq = tid >> 1, sub = tid & 1;
    const float* base = qkv + (size_t)(s*BB+b)*NT*768;

    for (int idx = tid; idx < 128*64; idx += 256) {
        int q = idx >> 6, d = idx & 63;
        float v = (q0 + q < Mb) ? base[(size_t)(q0+q)*768 + h*DH + d] : 0.f;
        QsT[d*APQ + q] = v;
    }

    float m_run = -1e30f, l_run = 0.f;
    float2 acco[8][2];
    #pragma unroll
    for (int i=0;i<8;i++){ acco[i][0]=make_float2(0.f,0.f); acco[i][1]=make_float2(0.f,0.f); }

    int nkt = (Mb + 63) >> 6;
    for (int kt = 0; kt < nkt; kt++) {
        int k0t = kt*64;
        int kval = min(64, Mb - k0t);
        __syncthreads();
        for (int idx = tid; idx < 64*64; idx += 256) {
            int r = idx >> 6, c = idx & 63;
            float kv = 0.f, vv = 0.f;
            if (r < kval) {
                kv = base[(size_t)(k0t+r)*768 + 256 + h*DH + c];
                vv = base[(size_t)(k0t+r)*768 + 512 + h*DH + c];
            }
            KsT[c*APK + r] = kv;
            Vs[r*APK + c]  = vv;
        }
        __syncthreads();
        {
            float2 accs[4][4];
            #pragma unroll
            for (int j=0;j<4;j++)
                #pragma unroll
                for (int ip=0;ip<4;ip++) accs[j][ip] = make_float2(0.f,0.f);
            for (int d = 0; d < DH; d++) {
                float4 qa = *(const float4*)&QsT[d*APQ + ty*8];
                float4 qb = *(const float4*)&QsT[d*APQ + ty*8 + 4];
                float4 kk = *(const float4*)&KsT[d*APK + tx*4];
                float2 qp[4] = { make_float2(qa.x,qa.y), make_float2(qa.z,qa.w),
                                 make_float2(qb.x,qb.y), make_float2(qb.z,qb.w) };
                float kj[4] = {kk.x, kk.y, kk.z, kk.w};
                #pragma unroll
                for (int j=0;j<4;j++){
                    float2 kd = make_float2(kj[j], kj[j]);
                    #pragma unroll
                    for (int ip=0;ip<4;ip++)
                        accs[j][ip] = ffma2(qp[ip], kd, accs[j][ip]);
                }
            }
            #pragma unroll
            for (int j=0;j<4;j++){
                #pragma unroll
                for (int ip=0;ip<4;ip++){
                    float2 v = accs[j][ip];
                    v.x *= 0.125f; v.y *= 0.125f;
                    *(float2*)&SsT[(tx*4+j)*APQ + ty*8 + 2*ip] = v;
                }
            }
        }
        __syncthreads();
        {
            float mx = -1e30f;
            #pragma unroll
            for (int kk = 0; kk < 32; kk++) {
                int k = kk*2 + sub;
                if (k < kval) mx = fmaxf(mx, SsT[k*APQ + sq]);
            }
            mx = fmaxf(mx, __shfl_xor_sync(0xffffffffu, mx, 1));
            float mnew = fmaxf(m_run, mx);
            float al = __expf(m_run - mnew);
            float ssum = 0.f;
            #pragma unroll
            for (int kk = 0; kk < 32; kk++) {
                int k = kk*2 + sub;
                float p = 0.f;
                if (k < kval) p = __expf(SsT[k*APQ + sq] - mnew);
                SsT[k*APQ + sq] = p;
                ssum += p;
            }
            ssum += __shfl_xor_sync(0xffffffffu, ssum, 1);
            l_run = l_run*al + ssum;
            m_run = mnew;
            if (sub == 0) alph[sq] = al;
        }
        __syncthreads();
        #pragma unroll
        for (int i=0;i<8;i++){
            float al = alph[ty*8+i];
            acco[i][0].x *= al; acco[i][0].y *= al;
            acco[i][1].x *= al; acco[i][1].y *= al;
        }
        for (int k = 0; k < 64; k++) {
            float4 pa = *(const float4*)&SsT[k*APQ + ty*8];
            float4 pb = *(const float4*)&SsT[k*APQ + ty*8 + 4];
            float4 v4 = *(const float4*)&Vs[k*APK + tx*4];
            float2 vp0 = make_float2(v4.x, v4.y);
            float2 vp1 = make_float2(v4.z, v4.w);
            float pi[8] = {pa.x,pa.y,pa.z,pa.w,pb.x,pb.y,pb.z,pb.w};
            #pragma unroll
            for (int i=0;i<8;i++){
                float2 pd = make_float2(pi[i], pi[i]);
                acco[i][0] = ffma2(pd, vp0, acco[i][0]);
                acco[i][1] = ffma2(pd, vp1, acco[i][1]);
            }
        }
    }
    __syncthreads();
    if (sub == 0) lsum[sq] = l_run;
    __syncthreads();
    #pragma unroll
    for (int i=0;i<8;i++){
        int q = q0 + ty*8 + i;
        if (q < Mb) {
            float inv = 1.f / lsum[ty*8+i];
            float4 o4 = make_float4(acco[i][0].x*inv, acco[i][0].y*inv,
                                    acco[i][1].x*inv, acco[i][1].y*inv);
            *(float4*)&att[((size_t)(s*BB+b)*NT + q)*CD + h*DH + tx*4] = o4;
        }
    }
}

// ---------------- output ----------------
__global__ void base_out(const float* __restrict__ fir, const float* __restrict__ fvis,
                         float* __restrict__ out)
{
    size_t i = (size_t)blockIdx.x*256 + threadIdx.x;
    out[i] = fir[i] + fvis[i];
}

__global__ void scatter_out(const float* __restrict__ x0, const float* __restrict__ x1,
                            const int* __restrict__ list, const float* __restrict__ maskf,
                            const int* __restrict__ cnt, float* __restrict__ out)
{
    int b = blockIdx.y, j = blockIdx.x;
    if (j >= cnt[b]) return;
    int idx = list[b*NT + j];
    float mv = maskf[b*NT + idx];
    int c = threadIdx.x;
    float v = (x0[((size_t)b*NT + j)*CD + c] + x1[((size_t)b*NT + j)*CD + c]) * mv;
    out[((size_t)b*CD + c)*NT + idx] = v;
}

// ---------------- host ----------------
extern "C" void kernel_launch(void* const* d_in, const int* in_sizes, int n_in,
                              void* d_out, int out_size)
{
    const float* f_ir  = (const float*)d_in[0];
    const float* f_vis = (const float*)d_in[1];
    const float* aw1   = (const float*)d_in[2];
    const float* ab1   = (const float*)d_in[3];
    const float* aw2   = (const float*)d_in[4];
    const float* ab2   = (const float*)d_in[5];
    const float* ir_lng  = (const float*)d_in[6];
    const float* ir_lnb  = (const float*)d_in[7];
    const float* ir_wqkv = (const float*)d_in[8];
    const float* ir_bqkv = (const float*)d_in[9];
    const float* ir_wo   = (const float*)d_in[10];
    const float* ir_bo   = (const float*)d_in[11];
    const float* ir_w1   = (const float*)d_in[12];
    const float* ir_b1   = (const float*)d_in[13];
    const float* ir_w2   = (const float*)d_in[14];
    const float* ir_b2   = (const float*)d_in[15];
    const float* vi_lng  = (const float*)d_in[16];
    const float* vi_lnb  = (const float*)d_in[17];
    const float* vi_wqkv = (const float*)d_in[18];
    const float* vi_bqkv = (const float*)d_in[19];
    const float* vi_wo   = (const float*)d_in[20];
    const float* vi_bo   = (const float*)d_in[21];
    const float* vi_w1   = (const float*)d_in[22];
    const float* vi_b1   = (const float*)d_in[23];
    const float* vi_w2   = (const float*)d_in[24];
    const float* vi_b2   = (const float*)d_in[25];
    float* out = (float*)d_out;

    float *xcat,*h1,*logits,*maskf,*x,*xn,*qkv,*att,*hid;
    int *list,*cntp;
    cudaGetSymbolAddress((void**)&xcat,  g_xcat);
    cudaGetSymbolAddress((void**)&h1,    g_h1);
    cudaGetSymbolAddress((void**)&logits,g_logits);
    cudaGetSymbolAddress((void**)&maskf, g_maskf);
    cudaGetSymbolAddress((void**)&x,     g_x);
    cudaGetSymbolAddress((void**)&xn,    g_xn);
    cudaGetSymbolAddress((void**)&qkv,   g_qkv);
    cudaGetSymbolAddress((void**)&att,   g_att);
    cudaGetSymbolAddress((void**)&hid,   g_hid);
    cudaGetSymbolAddress((void**)&list,  g_list);
    cudaGetSymbolAddress((void**)&cntp,  g_cnt);
    float* x0 = x;
    float* x1 = x + (size_t)BB*NT*CD;

    cudaFuncSetAttribute(attn2, cudaFuncAttributeMaxDynamicSharedMemorySize, ATTN_SMEM);
    cudaFuncSetAttribute(gemm_hm, cudaFuncAttributeMaxDynamicSharedMemorySize, GEMM_SMEM);

    // 1. token-major concat
    transpose_cat<<<dim3(NT/32, CD/32, BB*2), dim3(32,8)>>>(f_ir, f_vis, xcat);
    // 2. agent hidden (silu), K=512, O=512
    gemm_hm<<<dim3(AGH/128, NT/128, BB), 256, GEMM_SMEM>>>(xcat, aw1, aw1, ab1, ab1, h1, 0, 0, 512, AGH, 1);
    // 3. agent logits + STE mask
    agent_logits<<<(BB*NT)/8, 256>>>(h1, aw2, ab2, logits, maskf);
    // 4. selection
    select_kernel<<<BB, 256>>>(logits, list, cntp);
    // 5. gather selected tokens
    gather_tok<<<dim3(NT, BB), 256>>>(xcat, list, cntp, x0, x1);

    // 6. both mixers fused per launch (z = 2*BB)
    ln2<<<dim3(NT, 2*BB), 256>>>(x, xn, ir_lng, ir_lnb, vi_lng, vi_lnb, cntp);
    gemm_hm<<<dim3(768/128, NT/128, 2*BB), 256, GEMM_SMEM>>>(xn, ir_wqkv, vi_wqkv, ir_bqkv, vi_bqkv, qkv, 0, cntp, 256, 768, 0);
    attn2<<<dim3(NT/128, NH, 2*BB), 256, ATTN_SMEM>>>(qkv, att, cntp);
    gemm_hm<<<dim3(CD/128, NT/128, 2*BB), 256, GEMM_SMEM>>>(att, ir_wo, vi_wo, ir_bo, vi_bo, x, x, cntp, 256, CD, 0);
    ln2<<<dim3(NT, 2*BB), 256>>>(x, xn, ir_lng, ir_lnb, vi_lng, vi_lnb, cntp);
    gemm_hm<<<dim3(1024/128, NT/128, 2*BB), 256, GEMM_SMEM>>>(xn, ir_w1, vi_w1, ir_b1, vi_b1, hid, 0, cntp, 256, 1024, 2);
    gemm_hm<<<dim3(CD/128, NT/128, 2*BB), 256, GEMM_SMEM>>>(hid, ir_w2, vi_w2, ir_b2, vi_b2, x, x, cntp, 1024, CD, 0);

    // 7. output
    base_out<<<(BB*CD*NT)/256, 256>>>(f_ir, f_vis, out);
    scatter_out<<<dim3(NT, BB), 256>>>(x0, x1, list, maskf, cntp, out);
}

// round 7
// speedup vs baseline: 2.8523x; 1.1733x over previous
#include <cuda_runtime.h>
#include <cuda_bf16.h>
#include <math.h>
#include <stdint.h>

#define BB   4
#define NT   2304      // 48*48 tokens
#define CD   256       // DIM
#define AGH  512       // agent hidden
#define NH   4
#define DH   64

// plane sizes (elements)
#define XCAT_PLANE ((size_t)BB*NT*512)
#define XN_PLANE   ((size_t)2*BB*NT*CD)
#define ATT_PLANE  ((size_t)2*BB*NT*CD)
#define HID_PLANE  ((size_t)2*BB*NT*1024)
#define WHL_TOTAL  3670016

// ---------------- packed f32x2 FMA (attention path) ----------------
__device__ __forceinline__ float2 ffma2(float2 a, float2 b, float2 c) {
    float2 d;
    asm("fma.rn.f32x2 %0, %1, %2, %3;"
        : "=l"(reinterpret_cast<unsigned long long&>(d))
        : "l"(reinterpret_cast<unsigned long long&>(a)),
          "l"(reinterpret_cast<unsigned long long&>(b)),
          "l"(reinterpret_cast<unsigned long long&>(c)));
    return d;
}

// ---------------- bf16 HMMA m16n8k16 ----------------
__device__ __forceinline__ void mma16816(float* c, const uint32_t* a, uint32_t b0, uint32_t b1) {
    asm volatile("mma.sync.aligned.m16n8k16.row.col.f32.bf16.bf16.f32 "
        "{%0,%1,%2,%3}, {%4,%5,%6,%7}, {%8,%9}, {%0,%1,%2,%3};"
        : "+f"(c[0]), "+f"(c[1]), "+f"(c[2]), "+f"(c[3])
        : "r"(a[0]), "r"(a[1]), "r"(a[2]), "r"(a[3]), "r"(b0), "r"(b1));
}

__device__ __forceinline__ uint32_t smem_u32(const void* p) {
    uint32_t a;
    asm("{ .reg .u64 t; cvta.to.shared.u64 t, %1; cvt.u32.u64 %0, t; }" : "=r"(a) : "l"(p));
    return a;
}
#define CP16(dst, src) asm volatile("cp.async.cg.shared.global [%0], [%1], 16;" :: "r"(dst), "l"(src))
#define CPCOMMIT()     asm volatile("cp.async.commit_group;" ::: "memory")
#define CPWAIT(n)      asm volatile("cp.async.wait_group %0;" :: "n"(n) : "memory")
#define LDSM4(r, a) asm volatile("ldmatrix.sync.aligned.m8n8.x4.shared.b16 {%0,%1,%2,%3}, [%4];" \
    : "=r"((r)[0]), "=r"((r)[1]), "=r"((r)[2]), "=r"((r)[3]) : "r"(a))

__device__ __forceinline__ uint32_t packbf(float a, float b) {
    return ((uint32_t)__bfloat16_as_ushort(__float2bfloat16_rn(b)) << 16)
         |  (uint32_t)__bfloat16_as_ushort(__float2bfloat16_rn(a));
}
__device__ __forceinline__ void split_hl(float v, __nv_bfloat16& h, __nv_bfloat16& l) {
    h = __float2bfloat16_rn(v);
    l = __float2bfloat16_rn(v - __bfloat162float(h));
}
__device__ __forceinline__ void cvt_pack(float4 v, uint2& h, uint2& l) {
    __nv_bfloat16 h0, h1, h2, h3, l0, l1, l2, l3;
    split_hl(v.x, h0, l0); split_hl(v.y, h1, l1);
    split_hl(v.z, h2, l2); split_hl(v.w, h3, l3);
    h.x = ((uint32_t)__bfloat16_as_ushort(h1) << 16) | (uint32_t)__bfloat16_as_ushort(h0);
    h.y = ((uint32_t)__bfloat16_as_ushort(h3) << 16) | (uint32_t)__bfloat16_as_ushort(h2);
    l.x = ((uint32_t)__bfloat16_as_ushort(l1) << 16) | (uint32_t)__bfloat16_as_ushort(l0);
    l.y = ((uint32_t)__bfloat16_as_ushort(l3) << 16) | (uint32_t)__bfloat16_as_ushort(l2);
}

// ---------------- scratch ----------------
__device__ float g_xcat[(size_t)BB*NT*512];
__device__ float g_h1  [(size_t)BB*NT*AGH];
__device__ float g_logits[BB*NT];
__device__ float g_maskf [BB*NT];
__device__ int   g_list[BB*NT];
__device__ int   g_cnt [BB];
__device__ float g_x  [(size_t)2*BB*NT*CD];
__device__ float g_qkv[(size_t)2*BB*NT*3*CD];
__device__ __align__(16) __nv_bfloat16 g_w_hl  [WHL_TOTAL];
__device__ __align__(16) __nv_bfloat16 g_xcat_hl[2*XCAT_PLANE];
__device__ __align__(16) __nv_bfloat16 g_xn_hl [2*XN_PLANE];
__device__ __align__(16) __nv_bfloat16 g_att_hl[2*ATT_PLANE];
__device__ __align__(16) __nv_bfloat16 g_hid_hl[2*HID_PLANE];

// ---------------- weight convert (all 9 weights, once per launch) ----------------
struct WArgs { const float* src[9]; int start[9]; int n[9]; };
__global__ void conv_w(WArgs a, __nv_bfloat16* __restrict__ dst)
{
    int w = blockIdx.y;
    int n = a.n[w];
    const float4* s = (const float4*)a.src[w];
    __nv_bfloat16* dh = dst + a.start[w];
    __nv_bfloat16* dl = dh + n;
    int n4 = n >> 2;
    for (int i = blockIdx.x*256 + threadIdx.x; i < n4; i += gridDim.x*256) {
        float4 v = s[i];
        uint2 h, l; cvt_pack(v, h, l);
        *(uint2*)&dh[i*4] = h;
        *(uint2*)&dl[i*4] = l;
    }
}

// ---------------- transpose [B,C,N] -> token-major concat [B,N,512] + hi/lo ----------------
__global__ void transpose_cat(const float* __restrict__ fir, const float* __restrict__ fvis,
                              float* __restrict__ xcat, __nv_bfloat16* __restrict__ xcat_hl)
{
    int src = blockIdx.z & 1;
    int b   = blockIdx.z >> 1;
    const float* f = src ? fvis : fir;
    __shared__ float tile[32][33];
    int n0 = blockIdx.x * 32, c0 = blockIdx.y * 32;
    int tx = threadIdx.x, ty = threadIdx.y;
    #pragma unroll
    for (int i = 0; i < 32; i += 8)
        tile[ty + i][tx] = f[((size_t)b*CD + c0 + ty + i)*NT + n0 + tx];
    __syncthreads();
    #pragma unroll
    for (int i = 0; i < 32; i += 8) {
        float v = tile[tx][ty + i];
        size_t idx = ((size_t)b*NT + n0 + ty + i)*512 + src*CD + c0 + tx;
        xcat[idx] = v;
        __nv_bfloat16 h, l; split_hl(v, h, l);
        xcat_hl[idx] = h;
        xcat_hl[XCAT_PLANE + idx] = l;
    }
}

// ================= HMMA GEMM: bf16 hi/lo inputs, cp.async + ldmatrix =================
#define RSB   80                   // smem row stride bytes (20 banks; conflict-free, 16B-aligned)
#define MATB  (128*RSB)            // 10240
#define STAGE (4*MATB)             // Ahi, Alo, Whi, Wlo
#define GEMM_SMEM (2*STAGE)        // 81920

__device__ __forceinline__ float actf(float t, int act) {
    if (act == 1) return t / (1.f + expf(-t));
    if (act == 2) return 0.5f*t*(1.f + erff(t*0.70710678118654752f));
    return t;
}

__global__ void __launch_bounds__(256)
gemm_hm(const __nv_bfloat16* __restrict__ Ahl, size_t aplane,
        const __nv_bfloat16* __restrict__ Wah, const __nv_bfloat16* __restrict__ Wbh, size_t wplane,
        const float* __restrict__ ba, const float* __restrict__ bbv,
        float* __restrict__ Cf, __nv_bfloat16* __restrict__ Chl, size_t cplane,
        const float* __restrict__ R,
        const int* __restrict__ counts, int K, int Ocols, int act)
{
    int bz = blockIdx.z;
    int s = (bz >= BB) ? 1 : 0;
    int b = bz & 3;
    int Mb = counts ? counts[b] : NT;
    int m0 = blockIdx.y * 128;
    if (m0 >= Mb) return;
    int o0 = blockIdx.x * 128;
    const __nv_bfloat16* Wsel = s ? Wbh : Wah;
    const float* bias = s ? bbv : ba;
    size_t rowbase = (size_t)(s*BB + b) * NT;
    const __nv_bfloat16* Ah_g = Ahl + (rowbase + m0) * K;
    const __nv_bfloat16* Al_g = Ah_g + aplane;
    const __nv_bfloat16* Wh_g = Wsel + (size_t)o0 * K;
    const __nv_bfloat16* Wl_g = Wh_g + wplane;
    float* Cfb = Cf ? Cf + rowbase * Ocols : (float*)0;
    __nv_bfloat16* Chb = Chl ? Chl + rowbase * Ocols : (__nv_bfloat16*)0;
    const float* Rb = R ? R + rowbase * Ocols : (const float*)0;

    extern __shared__ char smem[];
    uint32_t sbase = smem_u32(smem);
    int tid = threadIdx.x, lane = tid & 31, w = tid >> 5;
    int wm = w & 3, wn = w >> 2;
    int gid = lane >> 2, tig = lane & 3;

    float acc[2][8][4];
    #pragma unroll
    for (int mt=0; mt<2; mt++)
        #pragma unroll
        for (int nt=0; nt<8; nt++)
            #pragma unroll
            for (int q=0; q<4; q++) acc[mt][nt][q] = 0.f;

#define PREFETCH(cc, st) do { \
    uint32_t sb_ = sbase + (st)*STAGE; \
    _Pragma("unroll") \
    for (int i_ = 0; i_ < 2; i_++) { \
        int f_ = tid + i_*256; int row_ = f_ >> 2; int jb_ = (f_ & 3) * 16; \
        size_t go_ = (size_t)row_*K + (size_t)(cc)*32; \
        const char* pah = (const char*)(Ah_g + go_) + jb_; \
        const char* pal = (const char*)(Al_g + go_) + jb_; \
        const char* pwh = (const char*)(Wh_g + go_) + jb_; \
        const char* pwl = (const char*)(Wl_g + go_) + jb_; \
        uint32_t so_ = sb_ + (uint32_t)(row_*RSB + jb_); \
        CP16(so_, pah); CP16(so_ + MATB, pal); \
        CP16(so_ + 2*MATB, pwh); CP16(so_ + 3*MATB, pwl); \
    } } while (0)

    int nchunk = K >> 5;
    PREFETCH(0, 0);
    CPCOMMIT();

    for (int c = 0; c < nchunk; c++) {
        if (c + 1 < nchunk) {
            PREFETCH(c+1, (c+1)&1);
            CPCOMMIT();
            CPWAIT(1);
        } else {
            CPWAIT(0);
        }
        __syncthreads();
        uint32_t stg = sbase + (c & 1) * STAGE;
        #pragma unroll
        for (int ks = 0; ks < 2; ks++) {
            int kb = ks * 32;
            uint32_t colb = (uint32_t)(kb + ((lane >> 4) << 4));
            uint32_t Ahf[2][4], Alf[2][4];
            #pragma unroll
            for (int mt = 0; mt < 2; mt++) {
                uint32_t sa = stg + (uint32_t)((wm*32 + mt*16 + (lane & 15)) * RSB) + colb;
                LDSM4(Ahf[mt], sa);
                LDSM4(Alf[mt], sa + MATB);
            }
            #pragma unroll
            for (int np = 0; np < 4; np++) {
                uint32_t sb = stg + 2*MATB + (uint32_t)((wn*64 + np*16 + (lane & 15)) * RSB) + colb;
                uint32_t Bh[4], Bl[4];
                LDSM4(Bh, sb);
                LDSM4(Bl, sb + MATB);
                #pragma unroll
                for (int mt = 0; mt < 2; mt++) {
                    mma16816(acc[mt][2*np],   Ahf[mt], Bh[0], Bh[2]);
                    mma16816(acc[mt][2*np],   Ahf[mt], Bl[0], Bl[2]);
                    mma16816(acc[mt][2*np],   Alf[mt], Bh[0], Bh[2]);
                    mma16816(acc[mt][2*np+1], Ahf[mt], Bh[1], Bh[3]);
                    mma16816(acc[mt][2*np+1], Ahf[mt], Bl[1], Bl[3]);
                    mma16816(acc[mt][2*np+1], Alf[mt], Bh[1], Bh[3]);
                }
            }
        }
        __syncthreads();
    }
#undef PREFETCH

    // epilogue
    #pragma unroll
    for (int mt = 0; mt < 2; mt++) {
        int r0 = m0 + wm*32 + mt*16 + gid;
        int r1 = r0 + 8;
        #pragma unroll
        for (int nt = 0; nt < 8; nt++) {
            int col = o0 + wn*64 + nt*8 + 2*tig;
            float b0v = bias[col], b1v = bias[col+1];
            float t0 = actf(acc[mt][nt][0] + b0v, act);
            float t1 = actf(acc[mt][nt][1] + b1v, act);
            float t2 = actf(acc[mt][nt][2] + b0v, act);
            float t3 = actf(acc[mt][nt][3] + b1v, act);
            if (Cfb) {
                if (r0 < Mb) {
                    if (Rb) { t0 += Rb[(size_t)r0*Ocols + col]; t1 += Rb[(size_t)r0*Ocols + col + 1]; }
                    *(float2*)&Cfb[(size_t)r0*Ocols + col] = make_float2(t0, t1);
                }
                if (r1 < Mb) {
                    if (Rb) { t2 += Rb[(size_t)r1*Ocols + col]; t3 += Rb[(size_t)r1*Ocols + col + 1]; }
                    *(float2*)&Cfb[(size_t)r1*Ocols + col] = make_float2(t2, t3);
                }
            } else {
                if (r0 < Mb) {
                    __nv_bfloat16 h0,l0,h1,l1;
                    split_hl(t0,h0,l0); split_hl(t1,h1,l1);
                    *(uint32_t*)&Chb[(size_t)r0*Ocols + col] =
                        ((uint32_t)__bfloat16_as_ushort(h1)<<16)|(uint32_t)__bfloat16_as_ushort(h0);
                    *(uint32_t*)&Chb[cplane + (size_t)r0*Ocols + col] =
                        ((uint32_t)__bfloat16_as_ushort(l1)<<16)|(uint32_t)__bfloat16_as_ushort(l0);
                }
                if (r1 < Mb) {
                    __nv_bfloat16 h2,l2,h3,l3;
                    split_hl(t2,h2,l2); split_hl(t3,h3,l3);
                    *(uint32_t*)&Chb[(size_t)r1*Ocols + col] =
                        ((uint32_t)__bfloat16_as_ushort(h3)<<16)|(uint32_t)__bfloat16_as_ushort(h2);
                    *(uint32_t*)&Chb[cplane + (size_t)r1*Ocols + col] =
                        ((uint32_t)__bfloat16_as_ushort(l3)<<16)|(uint32_t)__bfloat16_as_ushort(l2);
                }
            }
        }
    }
}

// ---------------- agent logits reduce ----------------
__global__ void agent_logits(const float* __restrict__ h1, const float* __restrict__ aw2,
                             const float* __restrict__ ab2,
                             float* __restrict__ logits, float* __restrict__ maskf)
{
    int t = blockIdx.x * 8 + (threadIdx.x >> 5);
    if (t >= BB*NT) return;
    int lane = threadIdx.x & 31;
    const float* hr = h1 + (size_t)t*AGH;
    float ssum = 0.f;
    for (int i = lane; i < AGH; i += 32) ssum += hr[i]*aw2[i];
    #pragma unroll
    for (int off = 16; off; off >>= 1) ssum += __shfl_down_sync(0xffffffffu, ssum, off);
    if (lane == 0) {
        float lg = ssum + ab2[0];
        logits[t] = lg;
        maskf[t]  = (lg > 0.f) ? 1.f : 0.f;
    }
}

// ---------------- selection ----------------
__global__ void select_kernel(const float* __restrict__ logits,
                              int* __restrict__ list, int* __restrict__ cnt)
{
    int b = blockIdx.x, tid = threadIdx.x;
    const float* lg = logits + b*NT;
    const int PER = NT/256;  // 9
    __shared__ int cn[256];
    int base = tid*PER;
    float lv[PER];
    bool  sv[PER];
    int c = 0;
    #pragma unroll
    for (int i = 0; i < PER; i++) {
        float v = lg[base+i]; lv[i] = v;
        bool sel = v > 0.f; sv[i] = sel; c += sel;
    }
    cn[tid] = c; __syncthreads();
    for (int off = 1; off < 256; off <<= 1) {
        int v = (tid >= off) ? cn[tid-off] : 0;
        __syncthreads();
        cn[tid] += v;
        __syncthreads();
    }
    int total = cn[255];
    int pos = cn[tid] - c;
    if (total >= 64) {
        #pragma unroll
        for (int i = 0; i < PER; i++)
            if (sv[i]) { list[b*NT + pos] = base + i; pos++; }
        if (tid == 0) cnt[b] = total;
    } else {
        __shared__ float sl[NT];
        #pragma unroll
        for (int i = 0; i < PER; i++) sl[base+i] = lv[i];
        __syncthreads();
        if (tid == 0) {
            for (int t = 0; t < 64; t++) {
                int am = 0; float mv = sl[0];
                for (int n = 1; n < NT; n++) if (sl[n] > mv) { mv = sl[n]; am = n; }
                list[b*NT + t] = am; sl[am] = -1e30f;
            }
            cnt[b] = 64;
        }
    }
}

// ---------------- gather selected tokens ----------------
__global__ void gather_tok(const float* __restrict__ xcat, const int* __restrict__ list,
                           const int* __restrict__ cnt,
                           float* __restrict__ x0, float* __restrict__ x1)
{
    int b = blockIdx.y, j = blockIdx.x;
    if (j >= cnt[b]) return;
    int idx = list[b*NT + j];
    int c = threadIdx.x;
    const float* src = xcat + ((size_t)b*NT + idx)*512;
    x0[((size_t)b*NT + j)*CD + c] = src[c];
    x1[((size_t)b*NT + j)*CD + c] = src[CD + c];
}

// ---------------- LayerNorm (dual-stream) -> bf16 hi/lo ----------------
__global__ void ln2(const float* __restrict__ X, __nv_bfloat16* __restrict__ Yhl,
                    const float* __restrict__ ga, const float* __restrict__ bba,
                    const float* __restrict__ gb2, const float* __restrict__ bbb,
                    const int* __restrict__ cnt)
{
    int bz = blockIdx.y; int s = bz >> 2, b = bz & 3;
    int n = blockIdx.x;
    if (n >= cnt[b]) return;
    const float* gw = s ? gb2 : ga;
    const float* gb = s ? bbb : bba;
    int tid = threadIdx.x;
    size_t row = ((size_t)(s*BB+b)*NT + n)*CD;
    float v = X[row + tid];
    __shared__ float red[8];
    float ssum = v;
    #pragma unroll
    for (int o = 16; o; o >>= 1) ssum += __shfl_down_sync(0xffffffffu, ssum, o);
    if ((tid & 31) == 0) red[tid>>5] = ssum;
    __syncthreads();
    float mean = 0.f;
    #pragma unroll
    for (int i = 0; i < 8; i++) mean += red[i];
    mean *= (1.f/CD);
    __syncthreads();
    float d = v - mean;
    ssum = d*d;
    #pragma unroll
    for (int o = 16; o; o >>= 1) ssum += __shfl_down_sync(0xffffffffu, ssum, o);
    if ((tid & 31) == 0) red[tid>>5] = ssum;
    __syncthreads();
    float var = 0.f;
    #pragma unroll
    for (int i = 0; i < 8; i++) var += red[i];
    var *= (1.f/CD);
    float yv = d * rsqrtf(var + 1e-5f) * gw[tid] + gb[tid];
    __nv_bfloat16 h, l; split_hl(yv, h, l);
    Yhl[row + tid] = h;
    Yhl[XN_PLANE + row + tid] = l;
}

// ---------------- flash attention: 128q x 64k tile, f32x2; epilogue -> bf16 hi/lo ----------------
#define APQ 132
#define APK 68
#define ATTN_SMEM ((64*APQ + 64*APK + 64*APK + 64*APQ + 256) * (int)sizeof(float))
__global__ void __launch_bounds__(256)
attn2(const float* __restrict__ qkv, __nv_bfloat16* __restrict__ att_hl,
      const int* __restrict__ cnt)
{
    extern __shared__ __align__(16) float sm[];
    float* QsT = sm;
    float* KsT = QsT + 64*APQ;
    float* Vs  = KsT + 64*APK;
    float* SsT = Vs  + 64*APK;
    float* alph = SsT + 64*APQ;
    float* lsum = alph + 128;

    int bz = blockIdx.z; int s = bz >> 2, b = bz & 3;
    int h = blockIdx.y, q0 = blockIdx.x*128;
    int Mb = cnt[b];
    if (q0 >= Mb) return;
    int tid = threadIdx.x;
    int tx = tid & 15, ty = tid >> 4;
    int sq = tid >> 1, sub = tid & 1;
    const float* base = qkv + (size_t)(s*BB+b)*NT*768;

    for (int idx = tid; idx < 128*64; idx += 256) {
        int q = idx >> 6, d = idx & 63;
        float v = (q0 + q < Mb) ? base[(size_t)(q0+q)*768 + h*DH + d] : 0.f;
        QsT[d*APQ + q] = v;
    }

    float m_run = -1e30f, l_run = 0.f;
    float2 acco[8][2];
    #pragma unroll
    for (int i=0;i<8;i++){ acco[i][0]=make_float2(0.f,0.f); acco[i][1]=make_float2(0.f,0.f); }

    int nkt = (Mb + 63) >> 6;
    for (int kt = 0; kt < nkt; kt++) {
        int k0t = kt*64;
        int kval = min(64, Mb - k0t);
        __syncthreads();
        for (int idx = tid; idx < 64*64; idx += 256) {
            int r = idx >> 6, c = idx & 63;
            float kv = 0.f, vv = 0.f;
            if (r < kval) {
                kv = base[(size_t)(k0t+r)*768 + 256 + h*DH + c];
                vv = base[(size_t)(k0t+r)*768 + 512 + h*DH + c];
            }
            KsT[c*APK + r] = kv;
            Vs[r*APK + c]  = vv;
        }
        __syncthreads();
        {
            float2 accs[4][4];
            #pragma unroll
            for (int j=0;j<4;j++)
                #pragma unroll
                for (int ip=0;ip<4;ip++) accs[j][ip] = make_float2(0.f,0.f);
            for (int d = 0; d < DH; d++) {
                float4 qa = *(const float4*)&QsT[d*APQ + ty*8];
                float4 qb = *(const float4*)&QsT[d*APQ + ty*8 + 4];
                float4 kk = *(const float4*)&KsT[d*APK + tx*4];
                float2 qp[4] = { make_float2(qa.x,qa.y), make_float2(qa.z,qa.w),
                                 make_float2(qb.x,qb.y), make_float2(qb.z,qb.w) };
                float kj[4] = {kk.x, kk.y, kk.z, kk.w};
                #pragma unroll
                for (int j=0;j<4;j++){
                    float2 kd = make_float2(kj[j], kj[j]);
                    #pragma unroll
                    for (int ip=0;ip<4;ip++)
                        accs[j][ip] = ffma2(qp[ip], kd, accs[j][ip]);
                }
            }
            #pragma unroll
            for (int j=0;j<4;j++){
                #pragma unroll
                for (int ip=0;ip<4;ip++){
                    float2 v = accs[j][ip];
                    v.x *= 0.125f; v.y *= 0.125f;
                    *(float2*)&SsT[(tx*4+j)*APQ + ty*8 + 2*ip] = v;
                }
            }
        }
        __syncthreads();
        {
            float mx = -1e30f;
            #pragma unroll
            for (int kk = 0; kk < 32; kk++) {
                int k = kk*2 + sub;
                if (k < kval) mx = fmaxf(mx, SsT[k*APQ + sq]);
            }
            mx = fmaxf(mx, __shfl_xor_sync(0xffffffffu, mx, 1));
            float mnew = fmaxf(m_run, mx);
            float al = __expf(m_run - mnew);
            float ssum = 0.f;
            #pragma unroll
            for (int kk = 0; kk < 32; kk++) {
                int k = kk*2 + sub;
                float p = 0.f;
                if (k < kval) p = __expf(SsT[k*APQ + sq] - mnew);
                SsT[k*APQ + sq] = p;
                ssum += p;
            }
            ssum += __shfl_xor_sync(0xffffffffu, ssum, 1);
            l_run = l_run*al + ssum;
            m_run = mnew;
            if (sub == 0) alph[sq] = al;
        }
        __syncthreads();
        #pragma unroll
        for (int i=0;i<8;i++){
            float al = alph[ty*8+i];
            acco[i][0].x *= al; acco[i][0].y *= al;
            acco[i][1].x *= al; acco[i][1].y *= al;
        }
        for (int k = 0; k < 64; k++) {
            float4 pa = *(const float4*)&SsT[k*APQ + ty*8];
            float4 pb = *(const float4*)&SsT[k*APQ + ty*8 + 4];
            float4 v4 = *(const float4*)&Vs[k*APK + tx*4];
            float2 vp0 = make_float2(v4.x, v4.y);
            float2 vp1 = make_float2(v4.z, v4.w);
            float pi[8] = {pa.x,pa.y,pa.z,pa.w,pb.x,pb.y,pb.z,pb.w};
            #pragma unroll
            for (int i=0;i<8;i++){
                float2 pd = make_float2(pi[i], pi[i]);
                acco[i][0] = ffma2(pd, vp0, acco[i][0]);
                acco[i][1] = ffma2(pd, vp1, acco[i][1]);
            }
        }
    }
    __syncthreads();
    if (sub == 0) lsum[sq] = l_run;
    __syncthreads();
    #pragma unroll
    for (int i=0;i<8;i++){
        int q = q0 + ty*8 + i;
        if (q < Mb) {
            float inv = 1.f / lsum[ty*8+i];
            float o0v = acco[i][0].x*inv, o1v = acco[i][0].y*inv;
            float o2v = acco[i][1].x*inv, o3v = acco[i][1].y*inv;
            __nv_bfloat16 h0,l0,h1,l1,h2,l2,h3,l3;
            split_hl(o0v,h0,l0); split_hl(o1v,h1,l1);
            split_hl(o2v,h2,l2); split_hl(o3v,h3,l3);
            size_t idx = ((size_t)(s*BB+b)*NT + q)*CD + h*DH + tx*4;
            *(uint32_t*)&att_hl[idx] =
                ((uint32_t)__bfloat16_as_ushort(h1)<<16)|(uint32_t)__bfloat16_as_ushort(h0);
            *(uint32_t*)&att_hl[idx+2] =
                ((uint32_t)__bfloat16_as_ushort(h3)<<16)|(uint32_t)__bfloat16_as_ushort(h2);
            *(uint32_t*)&att_hl[ATT_PLANE+idx] =
                ((uint32_t)__bfloat16_as_ushort(l1)<<16)|(uint32_t)__bfloat16_as_ushort(l0);
            *(uint32_t*)&att_hl[ATT_PLANE+idx+2] =
                ((uint32_t)__bfloat16_as_ushort(l3)<<16)|(uint32_t)__bfloat16_as_ushort(l2);
        }
    }
}

// ---------------- output ----------------
__global__ void base_out(const float* __restrict__ fir, const float* __restrict__ fvis,
                         float* __restrict__ out)
{
    size_t i = (size_t)blockIdx.x*256 + threadIdx.x;
    out[i] = fir[i] + fvis[i];
}

__global__ void scatter_out(const float* __restrict__ x0, const float* __restrict__ x1,
                            const int* __restrict__ list, const float* __restrict__ maskf,
                            const int* __restrict__ cnt, float* __restrict__ out)
{
    int b = blockIdx.y, j = blockIdx.x;
    if (j >= cnt[b]) return;
    int idx = list[b*NT + j];
    float mv = maskf[b*NT + idx];
    int c = threadIdx.x;
    float v = (x0[((size_t)b*NT + j)*CD + c] + x1[((size_t)b*NT + j)*CD + c]) * mv;
    out[((size_t)b*CD + c)*NT + idx] = v;
}

// ---------------- host ----------------
extern "C" void kernel_launch(void* const* d_in, const int* in_sizes, int n_in,
                              void* d_out, int out_size)
{
    const float* f_ir  = (const float*)d_in[0];
    const float* f_vis = (const float*)d_in[1];
    const float* aw1   = (const float*)d_in[2];
    const float* ab1   = (const float*)d_in[3];
    const float* aw2   = (const float*)d_in[4];
    const float* ab2   = (const float*)d_in[5];
    const float* ir_lng  = (const float*)d_in[6];
    const float* ir_lnb  = (const float*)d_in[7];
    const float* ir_wqkv = (const float*)d_in[8];
    const float* ir_bqkv = (const float*)d_in[9];
    const float* ir_wo   = (const float*)d_in[10];
    const float* ir_bo   = (const float*)d_in[11];
    const float* ir_w1   = (const float*)d_in[12];
    const float* ir_b1   = (const float*)d_in[13];
    const float* ir_w2   = (const float*)d_in[14];
    const float* ir_b2   = (const float*)d_in[15];
    const float* vi_lng  = (const float*)d_in[16];
    const float* vi_lnb  = (const float*)d_in[17];
    const float* vi_wqkv = (const float*)d_in[18];
    const float* vi_bqkv = (const float*)d_in[19];
    const float* vi_wo   = (const float*)d_in[20];
    const float* vi_bo   = (const float*)d_in[21];
    const float* vi_w1   = (const float*)d_in[22];
    const float* vi_b1   = (const float*)d_in[23];
    const float* vi_w2   = (const float*)d_in[24];
    const float* vi_b2   = (const float*)d_in[25];
    float* out = (float*)d_out;

    float *xcat,*h1,*logits,*maskf,*x,*qkv;
    __nv_bfloat16 *whl,*xcathl,*xnhl,*atthl,*hidhl;
    int *list,*cntp;
    cudaGetSymbolAddress((void**)&xcat,  g_xcat);
    cudaGetSymbolAddress((void**)&h1,    g_h1);
    cudaGetSymbolAddress((void**)&logits,g_logits);
    cudaGetSymbolAddress((void**)&maskf, g_maskf);
    cudaGetSymbolAddress((void**)&x,     g_x);
    cudaGetSymbolAddress((void**)&qkv,   g_qkv);
    cudaGetSymbolAddress((void**)&whl,   g_w_hl);
    cudaGetSymbolAddress((void**)&xcathl,g_xcat_hl);
    cudaGetSymbolAddress((void**)&xnhl,  g_xn_hl);
    cudaGetSymbolAddress((void**)&atthl, g_att_hl);
    cudaGetSymbolAddress((void**)&hidhl, g_hid_hl);
    cudaGetSymbolAddress((void**)&list,  g_list);
    cudaGetSymbolAddress((void**)&cntp,  g_cnt);
    float* x0 = x;
    float* x1 = x + (size_t)BB*NT*CD;

    cudaFuncSetAttribute(attn2, cudaFuncAttributeMaxDynamicSharedMemorySize, ATTN_SMEM);
    cudaFuncSetAttribute(gemm_hm, cudaFuncAttributeMaxDynamicSharedMemorySize, GEMM_SMEM);

    // weight hi/lo offsets (elements; each block = [hi(n), lo(n)])
    WArgs ws;
    const float* wsrc[9] = {aw1, ir_wqkv, vi_wqkv, ir_wo, vi_wo, ir_w1, vi_w1, ir_w2, vi_w2};
    const int    wn[9]   = {262144, 196608, 196608, 65536, 65536, 262144, 262144, 262144, 262144};
    int start = 0;
    for (int i = 0; i < 9; i++) { ws.src[i] = wsrc[i]; ws.n[i] = wn[i]; ws.start[i] = start; start += 2*wn[i]; }
    conv_w<<<dim3(64, 9), 256>>>(ws, whl);

    // 1. token-major concat (+hi/lo)
    transpose_cat<<<dim3(NT/32, CD/32, BB*2), dim3(32,8)>>>(f_ir, f_vis, xcat, xcathl);
    // 2. agent hidden (silu), K=512, O=512
    gemm_hm<<<dim3(AGH/128, NT/128, BB), 256, GEMM_SMEM>>>(
        xcathl, XCAT_PLANE, whl + 0, whl + 0, 262144,
        ab1, ab1, h1, (__nv_bfloat16*)0, 0, (const float*)0, (const int*)0, 512, AGH, 1);
    // 3. agent logits + STE mask
    agent_logits<<<(BB*NT)/8, 256>>>(h1, aw2, ab2, logits, maskf);
    // 4. selection
    select_kernel<<<BB, 256>>>(logits, list, cntp);
    // 5. gather selected tokens
    gather_tok<<<dim3(NT, BB), 256>>>(xcat, list, cntp, x0, x1);

    // 6. both mixers fused per launch (z = 2*BB)
    ln2<<<dim3(NT, 2*BB), 256>>>(x, xnhl, ir_lng, ir_lnb, vi_lng, vi_lnb, cntp);
    gemm_hm<<<dim3(768/128, NT/128, 2*BB), 256, GEMM_SMEM>>>(
        xnhl, XN_PLANE, whl + 524288, whl + 917504, 196608,
        ir_bqkv, vi_bqkv, qkv, (__nv_bfloat16*)0, 0, (const float*)0, cntp, 256, 768, 0);
    attn2<<<dim3(NT/128, NH, 2*BB), 256, ATTN_SMEM>>>(qkv, atthl, cntp);
    gemm_hm<<<dim3(CD/128, NT/128, 2*BB), 256, GEMM_SMEM>>>(
        atthl, ATT_PLANE, whl + 1310720, whl + 1441792, 65536,
        ir_bo, vi_bo, x, (__nv_bfloat16*)0, 0, x, cntp, 256, CD, 0);
    ln2<<<dim3(NT, 2*BB), 256>>>(x, xnhl, ir_lng, ir_lnb, vi_lng, vi_lnb, cntp);
    gemm_hm<<<dim3(1024/128, NT/128, 2*BB), 256, GEMM_SMEM>>>(
        xnhl, XN_PLANE, whl + 1572864, whl + 2097152, 262144,
        ir_b1, vi_b1, (float*)0, hidhl, HID_PLANE, (const float*)0, cntp, 256, 1024, 2);
    gemm_hm<<<dim3(CD/128, NT/128, 2*BB), 256, GEMM_SMEM>>>(
        hidhl, HID_PLANE, whl + 2621440, whl + 3145728, 262144,
        ir_b2, vi_b2, x, (__nv_bfloat16*)0, 0, x, cntp, 1024, CD, 0);

    // 7. output
    base_out<<<(BB*CD*NT)/256, 256>>>(f_ir, f_vis, out);
    scatter_out<<<dim3(NT, BB), 256>>>(x0, x1, list, maskf, cntp, out);
}

// round 8
// speedup vs baseline: 3.8989x; 1.3669x over previous
#include <cuda_runtime.h>
#include <cuda_bf16.h>
#include <math.h>
#include <stdint.h>

#define BB   4
#define NT   2304      // 48*48 tokens
#define CD   256       // DIM
#define AGH  512       // agent hidden
#define NH   4
#define DH   64

// plane sizes (elements)
#define XCAT_PLANE ((size_t)BB*NT*512)
#define XN_PLANE   ((size_t)2*BB*NT*CD)
#define ATT_PLANE  ((size_t)2*BB*NT*CD)
#define HID_PLANE  ((size_t)2*BB*NT*1024)
#define QKV_PLANE  ((size_t)2*BB*NT*768)
#define WHL_TOTAL  3670016

// ---------------- bf16 HMMA m16n8k16 ----------------
__device__ __forceinline__ void mma16816(float* c, const uint32_t* a, uint32_t b0, uint32_t b1) {
    asm volatile("mma.sync.aligned.m16n8k16.row.col.f32.bf16.bf16.f32 "
        "{%0,%1,%2,%3}, {%4,%5,%6,%7}, {%8,%9}, {%0,%1,%2,%3};"
        : "+f"(c[0]), "+f"(c[1]), "+f"(c[2]), "+f"(c[3])
        : "r"(a[0]), "r"(a[1]), "r"(a[2]), "r"(a[3]), "r"(b0), "r"(b1));
}

__device__ __forceinline__ uint32_t smem_u32(const void* p) {
    uint32_t a;
    asm("{ .reg .u64 t; cvta.to.shared.u64 t, %1; cvt.u32.u64 %0, t; }" : "=r"(a) : "l"(p));
    return a;
}
#define CP16(dst, src) asm volatile("cp.async.cg.shared.global [%0], [%1], 16;" :: "r"(dst), "l"(src))
#define CP16P(dst, src, p) asm volatile("cp.async.cg.shared.global [%0], [%1], 16, %2;" :: "r"(dst), "l"(src), "r"((p)?16:0))
#define CPCOMMIT()     asm volatile("cp.async.commit_group;" ::: "memory")
#define CPWAIT(n)      asm volatile("cp.async.wait_group %0;" :: "n"(n) : "memory")
#define LDSM4(r, a) asm volatile("ldmatrix.sync.aligned.m8n8.x4.shared.b16 {%0,%1,%2,%3}, [%4];" \
    : "=r"((r)[0]), "=r"((r)[1]), "=r"((r)[2]), "=r"((r)[3]) : "r"(a))
#define LDSM4T(r, a) asm volatile("ldmatrix.sync.aligned.m8n8.x4.trans.shared.b16 {%0,%1,%2,%3}, [%4];" \
    : "=r"((r)[0]), "=r"((r)[1]), "=r"((r)[2]), "=r"((r)[3]) : "r"(a))

__device__ __forceinline__ void split_hl(float v, __nv_bfloat16& h, __nv_bfloat16& l) {
    h = __float2bfloat16_rn(v);
    l = __float2bfloat16_rn(v - __bfloat162float(h));
}
__device__ __forceinline__ void pack_hl2(float a, float b, uint32_t& ph, uint32_t& pl) {
    __nv_bfloat16 ha, la, hb, lb;
    split_hl(a, ha, la); split_hl(b, hb, lb);
    ph = ((uint32_t)__bfloat16_as_ushort(hb) << 16) | (uint32_t)__bfloat16_as_ushort(ha);
    pl = ((uint32_t)__bfloat16_as_ushort(lb) << 16) | (uint32_t)__bfloat16_as_ushort(la);
}
__device__ __forceinline__ void cvt_pack(float4 v, uint2& h, uint2& l) {
    uint32_t h0, l0, h1, l1;
    pack_hl2(v.x, v.y, h0, l0);
    pack_hl2(v.z, v.w, h1, l1);
    h.x = h0; h.y = h1; l.x = l0; l.y = l1;
}

// ---------------- scratch ----------------
__device__ float g_xcat[(size_t)BB*NT*512];
__device__ float g_h1  [(size_t)BB*NT*AGH];
__device__ float g_logits[BB*NT];
__device__ float g_maskf [BB*NT];
__device__ int   g_list[BB*NT];
__device__ int   g_cnt [BB];
__device__ float g_x  [(size_t)2*BB*NT*CD];
__device__ __align__(16) __nv_bfloat16 g_w_hl  [WHL_TOTAL];
__device__ __align__(16) __nv_bfloat16 g_xcat_hl[2*XCAT_PLANE];
__device__ __align__(16) __nv_bfloat16 g_xn_hl [2*XN_PLANE];
__device__ __align__(16) __nv_bfloat16 g_att_hl[2*ATT_PLANE];
__device__ __align__(16) __nv_bfloat16 g_hid_hl[2*HID_PLANE];
__device__ __align__(16) __nv_bfloat16 g_qkv_hl[2*QKV_PLANE];

// ---------------- weight convert ----------------
struct WArgs { const float* src[9]; int start[9]; int n[9]; };
__global__ void conv_w(WArgs a, __nv_bfloat16* __restrict__ dst)
{
    int w = blockIdx.y;
    int n = a.n[w];
    const float4* s = (const float4*)a.src[w];
    __nv_bfloat16* dh = dst + a.start[w];
    __nv_bfloat16* dl = dh + n;
    int n4 = n >> 2;
    for (int i = blockIdx.x*256 + threadIdx.x; i < n4; i += gridDim.x*256) {
        float4 v = s[i];
        uint2 h, l; cvt_pack(v, h, l);
        *(uint2*)&dh[i*4] = h;
        *(uint2*)&dl[i*4] = l;
    }
}

// ---------------- transpose [B,C,N] -> token-major concat + hi/lo ----------------
__global__ void transpose_cat(const float* __restrict__ fir, const float* __restrict__ fvis,
                              float* __restrict__ xcat, __nv_bfloat16* __restrict__ xcat_hl)
{
    int src = blockIdx.z & 1;
    int b   = blockIdx.z >> 1;
    const float* f = src ? fvis : fir;
    __shared__ float tile[32][33];
    int n0 = blockIdx.x * 32, c0 = blockIdx.y * 32;
    int tx = threadIdx.x, ty = threadIdx.y;
    #pragma unroll
    for (int i = 0; i < 32; i += 8)
        tile[ty + i][tx] = f[((size_t)b*CD + c0 + ty + i)*NT + n0 + tx];
    __syncthreads();
    #pragma unroll
    for (int i = 0; i < 32; i += 8) {
        float v = tile[tx][ty + i];
        size_t idx = ((size_t)b*NT + n0 + ty + i)*512 + src*CD + c0 + tx;
        xcat[idx] = v;
        __nv_bfloat16 h, l; split_hl(v, h, l);
        xcat_hl[idx] = h;
        xcat_hl[XCAT_PLANE + idx] = l;
    }
}

// ================= HMMA GEMM: bf16 hi/lo inputs, cp.async + ldmatrix =================
#define RSB   80
#define MATB  (128*RSB)
#define STAGE (4*MATB)
#define GEMM_SMEM (2*STAGE)

__device__ __forceinline__ float actf(float t, int act) {
    if (act == 1) return t / (1.f + expf(-t));
    if (act == 2) return 0.5f*t*(1.f + erff(t*0.70710678118654752f));
    return t;
}

__global__ void __launch_bounds__(256)
gemm_hm(const __nv_bfloat16* __restrict__ Ahl, size_t aplane,
        const __nv_bfloat16* __restrict__ Wah, const __nv_bfloat16* __restrict__ Wbh, size_t wplane,
        const float* __restrict__ ba, const float* __restrict__ bbv,
        float* __restrict__ Cf, __nv_bfloat16* __restrict__ Chl, size_t cplane,
        const float* __restrict__ R,
        const int* __restrict__ counts, int K, int Ocols, int act)
{
    int bz = blockIdx.z;
    int s = (bz >= BB) ? 1 : 0;
    int b = bz & 3;
    int Mb = counts ? counts[b] : NT;
    int m0 = blockIdx.y * 128;
    if (m0 >= Mb) return;
    int o0 = blockIdx.x * 128;
    const __nv_bfloat16* Wsel = s ? Wbh : Wah;
    const float* bias = s ? bbv : ba;
    size_t rowbase = (size_t)(s*BB + b) * NT;
    const __nv_bfloat16* Ah_g = Ahl + (rowbase + m0) * K;
    const __nv_bfloat16* Al_g = Ah_g + aplane;
    const __nv_bfloat16* Wh_g = Wsel + (size_t)o0 * K;
    const __nv_bfloat16* Wl_g = Wh_g + wplane;
    float* Cfb = Cf ? Cf + rowbase * Ocols : (float*)0;
    __nv_bfloat16* Chb = Chl ? Chl + rowbase * Ocols : (__nv_bfloat16*)0;
    const float* Rb = R ? R + rowbase * Ocols : (const float*)0;

    extern __shared__ char smem[];
    uint32_t sbase = smem_u32(smem);
    int tid = threadIdx.x, lane = tid & 31, w = tid >> 5;
    int wm = w & 3, wn = w >> 2;
    int gid = lane >> 2, tig = lane & 3;

    float acc[2][8][4];
    #pragma unroll
    for (int mt=0; mt<2; mt++)
        #pragma unroll
        for (int nt=0; nt<8; nt++)
            #pragma unroll
            for (int q=0; q<4; q++) acc[mt][nt][q] = 0.f;

#define PREFETCH(cc, st) do { \
    uint32_t sb_ = sbase + (st)*STAGE; \
    _Pragma("unroll") \
    for (int i_ = 0; i_ < 2; i_++) { \
        int f_ = tid + i_*256; int row_ = f_ >> 2; int jb_ = (f_ & 3) * 16; \
        size_t go_ = (size_t)row_*K + (size_t)(cc)*32; \
        const char* pah = (const char*)(Ah_g + go_) + jb_; \
        const char* pal = (const char*)(Al_g + go_) + jb_; \
        const char* pwh = (const char*)(Wh_g + go_) + jb_; \
        const char* pwl = (const char*)(Wl_g + go_) + jb_; \
        uint32_t so_ = sb_ + (uint32_t)(row_*RSB + jb_); \
        CP16(so_, pah); CP16(so_ + MATB, pal); \
        CP16(so_ + 2*MATB, pwh); CP16(so_ + 3*MATB, pwl); \
    } } while (0)

    int nchunk = K >> 5;
    PREFETCH(0, 0);
    CPCOMMIT();

    for (int c = 0; c < nchunk; c++) {
        if (c + 1 < nchunk) {
            PREFETCH(c+1, (c+1)&1);
            CPCOMMIT();
            CPWAIT(1);
        } else {
            CPWAIT(0);
        }
        __syncthreads();
        uint32_t stg = sbase + (c & 1) * STAGE;
        #pragma unroll
        for (int ks = 0; ks < 2; ks++) {
            int kb = ks * 32;
            uint32_t colb = (uint32_t)(kb + ((lane >> 4) << 4));
            uint32_t Ahf[2][4], Alf[2][4];
            #pragma unroll
            for (int mt = 0; mt < 2; mt++) {
                uint32_t sa = stg + (uint32_t)((wm*32 + mt*16 + (lane & 15)) * RSB) + colb;
                LDSM4(Ahf[mt], sa);
                LDSM4(Alf[mt], sa + MATB);
            }
            #pragma unroll
            for (int np = 0; np < 4; np++) {
                uint32_t sb = stg + 2*MATB + (uint32_t)((wn*64 + np*16 + (lane & 15)) * RSB) + colb;
                uint32_t Bh[4], Bl[4];
                LDSM4(Bh, sb);
                LDSM4(Bl, sb + MATB);
                #pragma unroll
                for (int mt = 0; mt < 2; mt++) {
                    mma16816(acc[mt][2*np],   Ahf[mt], Bh[0], Bh[2]);
                    mma16816(acc[mt][2*np],   Ahf[mt], Bl[0], Bl[2]);
                    mma16816(acc[mt][2*np],   Alf[mt], Bh[0], Bh[2]);
                    mma16816(acc[mt][2*np+1], Ahf[mt], Bh[1], Bh[3]);
                    mma16816(acc[mt][2*np+1], Ahf[mt], Bl[1], Bl[3]);
                    mma16816(acc[mt][2*np+1], Alf[mt], Bh[1], Bh[3]);
                }
            }
        }
        __syncthreads();
    }
#undef PREFETCH

    #pragma unroll
    for (int mt = 0; mt < 2; mt++) {
        int r0 = m0 + wm*32 + mt*16 + gid;
        int r1 = r0 + 8;
        #pragma unroll
        for (int nt = 0; nt < 8; nt++) {
            int col = o0 + wn*64 + nt*8 + 2*tig;
            float b0v = bias[col], b1v = bias[col+1];
            float t0 = actf(acc[mt][nt][0] + b0v, act);
            float t1 = actf(acc[mt][nt][1] + b1v, act);
            float t2 = actf(acc[mt][nt][2] + b0v, act);
            float t3 = actf(acc[mt][nt][3] + b1v, act);
            if (Cfb) {
                if (r0 < Mb) {
                    if (Rb) { t0 += Rb[(size_t)r0*Ocols + col]; t1 += Rb[(size_t)r0*Ocols + col + 1]; }
                    *(float2*)&Cfb[(size_t)r0*Ocols + col] = make_float2(t0, t1);
                }
                if (r1 < Mb) {
                    if (Rb) { t2 += Rb[(size_t)r1*Ocols + col]; t3 += Rb[(size_t)r1*Ocols + col + 1]; }
                    *(float2*)&Cfb[(size_t)r1*Ocols + col] = make_float2(t2, t3);
                }
            } else {
                if (r0 < Mb) {
                    uint32_t ph, pl; pack_hl2(t0, t1, ph, pl);
                    *(uint32_t*)&Chb[(size_t)r0*Ocols + col] = ph;
                    *(uint32_t*)&Chb[cplane + (size_t)r0*Ocols + col] = pl;
                }
                if (r1 < Mb) {
                    uint32_t ph, pl; pack_hl2(t2, t3, ph, pl);
                    *(uint32_t*)&Chb[(size_t)r1*Ocols + col] = ph;
                    *(uint32_t*)&Chb[cplane + (size_t)r1*Ocols + col] = pl;
                }
            }
        }
    }
}

// ---------------- agent logits reduce ----------------
__global__ void agent_logits(const float* __restrict__ h1, const float* __restrict__ aw2,
                             const float* __restrict__ ab2,
                             float* __restrict__ logits, float* __restrict__ maskf)
{
    int t = blockIdx.x * 8 + (threadIdx.x >> 5);
    if (t >= BB*NT) return;
    int lane = threadIdx.x & 31;
    const float* hr = h1 + (size_t)t*AGH;
    float ssum = 0.f;
    for (int i = lane; i < AGH; i += 32) ssum += hr[i]*aw2[i];
    #pragma unroll
    for (int off = 16; off; off >>= 1) ssum += __shfl_down_sync(0xffffffffu, ssum, off);
    if (lane == 0) {
        float lg = ssum + ab2[0];
        logits[t] = lg;
        maskf[t]  = (lg > 0.f) ? 1.f : 0.f;
    }
}

// ---------------- selection ----------------
__global__ void select_kernel(const float* __restrict__ logits,
                              int* __restrict__ list, int* __restrict__ cnt)
{
    int b = blockIdx.x, tid = threadIdx.x;
    const float* lg = logits + b*NT;
    const int PER = NT/256;  // 9
    __shared__ int cn[256];
    int base = tid*PER;
    float lv[PER];
    bool  sv[PER];
    int c = 0;
    #pragma unroll
    for (int i = 0; i < PER; i++) {
        float v = lg[base+i]; lv[i] = v;
        bool sel = v > 0.f; sv[i] = sel; c += sel;
    }
    cn[tid] = c; __syncthreads();
    for (int off = 1; off < 256; off <<= 1) {
        int v = (tid >= off) ? cn[tid-off] : 0;
        __syncthreads();
        cn[tid] += v;
        __syncthreads();
    }
    int total = cn[255];
    int pos = cn[tid] - c;
    if (total >= 64) {
        #pragma unroll
        for (int i = 0; i < PER; i++)
            if (sv[i]) { list[b*NT + pos] = base + i; pos++; }
        if (tid == 0) cnt[b] = total;
    } else {
        __shared__ float sl[NT];
        #pragma unroll
        for (int i = 0; i < PER; i++) sl[base+i] = lv[i];
        __syncthreads();
        if (tid == 0) {
            for (int t = 0; t < 64; t++) {
                int am = 0; float mv = sl[0];
                for (int n = 1; n < NT; n++) if (sl[n] > mv) { mv = sl[n]; am = n; }
                list[b*NT + t] = am; sl[am] = -1e30f;
            }
            cnt[b] = 64;
        }
    }
}

// ---------------- gather selected tokens ----------------
__global__ void gather_tok(const float* __restrict__ xcat, const int* __restrict__ list,
                           const int* __restrict__ cnt,
                           float* __restrict__ x0, float* __restrict__ x1)
{
    int b = blockIdx.y, j = blockIdx.x;
    if (j >= cnt[b]) return;
    int idx = list[b*NT + j];
    int c = threadIdx.x;
    const float* src = xcat + ((size_t)b*NT + idx)*512;
    x0[((size_t)b*NT + j)*CD + c] = src[c];
    x1[((size_t)b*NT + j)*CD + c] = src[CD + c];
}

// ---------------- LayerNorm (dual-stream) -> bf16 hi/lo ----------------
__global__ void ln2(const float* __restrict__ X, __nv_bfloat16* __restrict__ Yhl,
                    const float* __restrict__ ga, const float* __restrict__ bba,
                    const float* __restrict__ gb2, const float* __restrict__ bbb,
                    const int* __restrict__ cnt)
{
    int bz = blockIdx.y; int s = bz >> 2, b = bz & 3;
    int n = blockIdx.x;
    if (n >= cnt[b]) return;
    const float* gw = s ? gb2 : ga;
    const float* gb = s ? bbb : bba;
    int tid = threadIdx.x;
    size_t row = ((size_t)(s*BB+b)*NT + n)*CD;
    float v = X[row + tid];
    __shared__ float red[8];
    float ssum = v;
    #pragma unroll
    for (int o = 16; o; o >>= 1) ssum += __shfl_down_sync(0xffffffffu, ssum, o);
    if ((tid & 31) == 0) red[tid>>5] = ssum;
    __syncthreads();
    float mean = 0.f;
    #pragma unroll
    for (int i = 0; i < 8; i++) mean += red[i];
    mean *= (1.f/CD);
    __syncthreads();
    float d = v - mean;
    ssum = d*d;
    #pragma unroll
    for (int o = 16; o; o >>= 1) ssum += __shfl_down_sync(0xffffffffu, ssum, o);
    if ((tid & 31) == 0) red[tid>>5] = ssum;
    __syncthreads();
    float var = 0.f;
    #pragma unroll
    for (int i = 0; i < 8; i++) var += red[i];
    var *= (1.f/CD);
    float yv = d * rsqrtf(var + 1e-5f) * gw[tid] + gb[tid];
    __nv_bfloat16 h, l; split_hl(yv, h, l);
    Yhl[row + tid] = h;
    Yhl[XN_PLANE + row + tid] = l;
}

// ================= flash attention on HMMA (bf16 hi/lo, register softmax) =================
// 128 q rows per CTA, 64-token k-tiles. qkv_hl: [row][768] hi plane + lo plane.
#define AQR 144                         // row stride bytes for 64-col bf16 tiles
#define AT_QH 0
#define AT_QL (128*AQR)                 // 18432
#define AT_KV (2*128*AQR)               // 36864 : stage base
#define AT_STG (4*64*AQR)               // 36864 per stage (Kh,Kl,Vh,Vl)
#define ATTN_SMEM (AT_KV + 2*AT_STG)    // 110592

__global__ void __launch_bounds__(256)
attn_mma(const __nv_bfloat16* __restrict__ qkvhl, __nv_bfloat16* __restrict__ att_hl,
         const int* __restrict__ cnt)
{
    extern __shared__ char smc[];
    uint32_t sb = smem_u32(smc);
    int bz = blockIdx.z; int s = bz >> 2, b = bz & 3;
    int h = blockIdx.y, q0 = blockIdx.x*128;
    int Mb = cnt[b];
    if (q0 >= Mb) return;
    int tid = threadIdx.x, lane = tid & 31, w = tid >> 5;
    int gid = lane >> 2, tig = lane & 3;
    size_t rowbase = (size_t)(s*BB + b) * NT;
    const __nv_bfloat16* qg = qkvhl;   // element indexing below

    // ---- Q prefetch (once): 2 planes x 128 rows x 8x16B ----
    {
        #pragma unroll
        for (int i = 0; i < 8; i++) {
            int f = tid + i*256;
            int pl = f >> 10, rem = f & 1023;
            int row = rem >> 3, c16 = rem & 7;
            const char* src = (const char*)(qg + (rowbase + q0 + row)*768 + h*64
                                            + (size_t)pl*QKV_PLANE) + c16*16;
            uint32_t dst = sb + pl*AT_QL + row*AQR + c16*16;
            CP16P(dst, src, (q0 + row) < Mb);
        }
    }
#define KV_PREFETCH(kt, st) do { \
    int k0_ = (kt)*64; \
    _Pragma("unroll") \
    for (int i_ = 0; i_ < 8; i_++) { \
        int f_ = tid + i_*256; \
        int pl_ = f_ >> 9, rem_ = f_ & 511; \
        int row_ = rem_ >> 3, c16_ = rem_ & 7; \
        int ko_ = (pl_ < 2) ? 256 : 512;  /* K or V */ \
        size_t hp_ = (pl_ & 1) ? QKV_PLANE : 0; \
        const char* src_ = (const char*)(qg + (rowbase + k0_ + row_)*768 + ko_ + h*64 + hp_) + c16_*16; \
        uint32_t dst_ = sb + AT_KV + (st)*AT_STG + pl_*(64*AQR) + row_*AQR + c16_*16; \
        CP16P(dst_, src_, (k0_ + row_) < Mb); \
    } } while (0)

    int nkt = (Mb + 63) >> 6;
    KV_PREFETCH(0, 0);
    CPCOMMIT();

    uint32_t Qh[4][4], Ql[4][4];
    float oacc[8][4];
    #pragma unroll
    for (int j=0;j<8;j++)
        #pragma unroll
        for (int q=0;q<4;q++) oacc[j][q] = 0.f;
    float m0 = -1e30f, m1 = -1e30f, l0 = 0.f, l1 = 0.f;
    bool qload = false;

    for (int c = 0; c < nkt; c++) {
        if (c + 1 < nkt) {
            KV_PREFETCH(c+1, (c+1)&1);
            CPCOMMIT();
            CPWAIT(1);
        } else {
            CPWAIT(0);
        }
        __syncthreads();
        if (!qload) {
            qload = true;
            #pragma unroll
            for (int ks = 0; ks < 4; ks++) {
                uint32_t qa = sb + (uint32_t)((w*16 + (lane & 15)) * AQR) + ks*32 + ((lane >> 4) << 4);
                LDSM4(Qh[ks], qa);
                LDSM4(Ql[ks], qa + AT_QL);
            }
        }
        uint32_t kb = sb + AT_KV + (c & 1)*AT_STG;
        uint32_t vb = kb + 2*(64*AQR);

        // ---- S = Q K^T (3-term) ----
        float sacc[8][4];
        #pragma unroll
        for (int j=0;j<8;j++)
            #pragma unroll
            for (int q=0;q<4;q++) sacc[j][q] = 0.f;
        #pragma unroll
        for (int ks = 0; ks < 4; ks++) {
            #pragma unroll
            for (int np = 0; np < 4; np++) {
                uint32_t ka = kb + (uint32_t)((np*16 + ((lane >> 4) << 3) + (lane & 7)) * AQR)
                            + ks*32 + (((lane >> 3) & 1) << 4);
                uint32_t Kh4[4], Kl4[4];
                LDSM4(Kh4, ka);
                LDSM4(Kl4, ka + 64*AQR);
                mma16816(sacc[2*np],   Qh[ks], Kh4[0], Kh4[1]);
                mma16816(sacc[2*np],   Qh[ks], Kl4[0], Kl4[1]);
                mma16816(sacc[2*np],   Ql[ks], Kh4[0], Kh4[1]);
                mma16816(sacc[2*np+1], Qh[ks], Kh4[2], Kh4[3]);
                mma16816(sacc[2*np+1], Qh[ks], Kl4[2], Kl4[3]);
                mma16816(sacc[2*np+1], Ql[ks], Kh4[2], Kh4[3]);
            }
        }
        // ---- scale + token mask ----
        int kvb = c*64;
        #pragma unroll
        for (int j = 0; j < 8; j++) {
            int t0 = kvb + j*8 + 2*tig;
            bool v0 = t0 < Mb, v1 = (t0 + 1) < Mb;
            sacc[j][0] = v0 ? sacc[j][0]*0.125f : -1e30f;
            sacc[j][1] = v1 ? sacc[j][1]*0.125f : -1e30f;
            sacc[j][2] = v0 ? sacc[j][2]*0.125f : -1e30f;
            sacc[j][3] = v1 ? sacc[j][3]*0.125f : -1e30f;
        }
        // ---- register online softmax (rows gid / gid+8) ----
        float mx0 = -1e30f, mx1 = -1e30f;
        #pragma unroll
        for (int j = 0; j < 8; j++) {
            mx0 = fmaxf(mx0, fmaxf(sacc[j][0], sacc[j][1]));
            mx1 = fmaxf(mx1, fmaxf(sacc[j][2], sacc[j][3]));
        }
        mx0 = fmaxf(mx0, __shfl_xor_sync(0xffffffffu, mx0, 1));
        mx0 = fmaxf(mx0, __shfl_xor_sync(0xffffffffu, mx0, 2));
        mx1 = fmaxf(mx1, __shfl_xor_sync(0xffffffffu, mx1, 1));
        mx1 = fmaxf(mx1, __shfl_xor_sync(0xffffffffu, mx1, 2));
        float mn0 = fmaxf(m0, mx0), mn1 = fmaxf(m1, mx1);
        float al0 = __expf(m0 - mn0), al1 = __expf(m1 - mn1);
        float s0 = 0.f, s1 = 0.f;
        #pragma unroll
        for (int j = 0; j < 8; j++) {
            sacc[j][0] = __expf(sacc[j][0] - mn0);
            sacc[j][1] = __expf(sacc[j][1] - mn0);
            sacc[j][2] = __expf(sacc[j][2] - mn1);
            sacc[j][3] = __expf(sacc[j][3] - mn1);
            s0 += sacc[j][0] + sacc[j][1];
            s1 += sacc[j][2] + sacc[j][3];
        }
        s0 += __shfl_xor_sync(0xffffffffu, s0, 1);
        s0 += __shfl_xor_sync(0xffffffffu, s0, 2);
        s1 += __shfl_xor_sync(0xffffffffu, s1, 1);
        s1 += __shfl_xor_sync(0xffffffffu, s1, 2);
        l0 = l0*al0 + s0; l1 = l1*al1 + s1;
        m0 = mn0; m1 = mn1;
        #pragma unroll
        for (int j = 0; j < 8; j++) {
            oacc[j][0] *= al0; oacc[j][1] *= al0;
            oacc[j][2] *= al1; oacc[j][3] *= al1;
        }
        // ---- O += P V (3-term; P fragments from S accumulators) ----
        #pragma unroll
        for (int kt = 0; kt < 4; kt++) {
            uint32_t aPh[4], aPl[4];
            pack_hl2(sacc[2*kt][0],   sacc[2*kt][1],   aPh[0], aPl[0]);
            pack_hl2(sacc[2*kt][2],   sacc[2*kt][3],   aPh[1], aPl[1]);
            pack_hl2(sacc[2*kt+1][0], sacc[2*kt+1][1], aPh[2], aPl[2]);
            pack_hl2(sacc[2*kt+1][2], sacc[2*kt+1][3], aPh[3], aPl[3]);
            #pragma unroll
            for (int np = 0; np < 4; np++) {
                uint32_t va = vb + (uint32_t)((kt*16 + (((lane >> 3) & 1) << 3) + (lane & 7)) * AQR)
                            + (2*np + (lane >> 4))*16;
                uint32_t Vh4[4], Vl4[4];
                LDSM4T(Vh4, va);
                LDSM4T(Vl4, va + 64*AQR);
                mma16816(oacc[2*np],   aPh, Vh4[0], Vh4[1]);
                mma16816(oacc[2*np],   aPh, Vl4[0], Vl4[1]);
                mma16816(oacc[2*np],   aPl, Vh4[0], Vh4[1]);
                mma16816(oacc[2*np+1], aPh, Vh4[2], Vh4[3]);
                mma16816(oacc[2*np+1], aPh, Vl4[2], Vl4[3]);
                mma16816(oacc[2*np+1], aPl, Vh4[2], Vh4[3]);
            }
        }
        __syncthreads();
    }
#undef KV_PREFETCH

    // ---- normalize + store hi/lo bf16 ----
    float inv0 = 1.f / l0, inv1 = 1.f / l1;
    int qr0 = q0 + w*16 + gid;
    int qr1 = qr0 + 8;
    #pragma unroll
    for (int j = 0; j < 8; j++) {
        int col = h*64 + j*8 + 2*tig;
        if (qr0 < Mb) {
            uint32_t ph, pl;
            pack_hl2(oacc[j][0]*inv0, oacc[j][1]*inv0, ph, pl);
            *(uint32_t*)&att_hl[(rowbase + qr0)*CD + col] = ph;
            *(uint32_t*)&att_hl[ATT_PLANE + (rowbase + qr0)*CD + col] = pl;
        }
        if (qr1 < Mb) {
            uint32_t ph, pl;
            pack_hl2(oacc[j][2]*inv1, oacc[j][3]*inv1, ph, pl);
            *(uint32_t*)&att_hl[(rowbase + qr1)*CD + col] = ph;
            *(uint32_t*)&att_hl[ATT_PLANE + (rowbase + qr1)*CD + col] = pl;
        }
    }
}

// ---------------- output ----------------
__global__ void base_out(const float* __restrict__ fir, const float* __restrict__ fvis,
                         float* __restrict__ out)
{
    size_t i = (size_t)blockIdx.x*256 + threadIdx.x;
    out[i] = fir[i] + fvis[i];
}

__global__ void scatter_out(const float* __restrict__ x0, const float* __restrict__ x1,
                            const int* __restrict__ list, const float* __restrict__ maskf,
                            const int* __restrict__ cnt, float* __restrict__ out)
{
    int b = blockIdx.y, j = blockIdx.x;
    if (j >= cnt[b]) return;
    int idx = list[b*NT + j];
    float mv = maskf[b*NT + idx];
    int c = threadIdx.x;
    float v = (x0[((size_t)b*NT + j)*CD + c] + x1[((size_t)b*NT + j)*CD + c]) * mv;
    out[((size_t)b*CD + c)*NT + idx] = v;
}

// ---------------- host ----------------
extern "C" void kernel_launch(void* const* d_in, const int* in_sizes, int n_in,
                              void* d_out, int out_size)
{
    const float* f_ir  = (const float*)d_in[0];
    const float* f_vis = (const float*)d_in[1];
    const float* aw1   = (const float*)d_in[2];
    const float* ab1   = (const float*)d_in[3];
    const float* aw2   = (const float*)d_in[4];
    const float* ab2   = (const float*)d_in[5];
    const float* ir_lng  = (const float*)d_in[6];
    const float* ir_lnb  = (const float*)d_in[7];
    const float* ir_wqkv = (const float*)d_in[8];
    const float* ir_bqkv = (const float*)d_in[9];
    const float* ir_wo   = (const float*)d_in[10];
    const float* ir_bo   = (const float*)d_in[11];
    const float* ir_w1   = (const float*)d_in[12];
    const float* ir_b1   = (const float*)d_in[13];
    const float* ir_w2   = (const float*)d_in[14];
    const float* ir_b2   = (const float*)d_in[15];
    const float* vi_lng  = (const float*)d_in[16];
    const float* vi_lnb  = (const float*)d_in[17];
    const float* vi_wqkv = (const float*)d_in[18];
    const float* vi_bqkv = (const float*)d_in[19];
    const float* vi_wo   = (const float*)d_in[20];
    const float* vi_bo   = (const float*)d_in[21];
    const float* vi_w1   = (const float*)d_in[22];
    const float* vi_b1   = (const float*)d_in[23];
    const float* vi_w2   = (const float*)d_in[24];
    const float* vi_b2   = (const float*)d_in[25];
    float* out = (float*)d_out;

    float *xcat,*h1,*logits,*maskf,*x;
    __nv_bfloat16 *whl,*xcathl,*xnhl,*atthl,*hidhl,*qkvhl;
    int *list,*cntp;
    cudaGetSymbolAddress((void**)&xcat,  g_xcat);
    cudaGetSymbolAddress((void**)&h1,    g_h1);
    cudaGetSymbolAddress((void**)&logits,g_logits);
    cudaGetSymbolAddress((void**)&maskf, g_maskf);
    cudaGetSymbolAddress((void**)&x,     g_x);
    cudaGetSymbolAddress((void**)&whl,   g_w_hl);
    cudaGetSymbolAddress((void**)&xcathl,g_xcat_hl);
    cudaGetSymbolAddress((void**)&xnhl,  g_xn_hl);
    cudaGetSymbolAddress((void**)&atthl, g_att_hl);
    cudaGetSymbolAddress((void**)&hidhl, g_hid_hl);
    cudaGetSymbolAddress((void**)&qkvhl, g_qkv_hl);
    cudaGetSymbolAddress((void**)&list,  g_list);
    cudaGetSymbolAddress((void**)&cntp,  g_cnt);
    float* x0 = x;
    float* x1 = x + (size_t)BB*NT*CD;

    cudaFuncSetAttribute(attn_mma, cudaFuncAttributeMaxDynamicSharedMemorySize, ATTN_SMEM);
    cudaFuncSetAttribute(gemm_hm, cudaFuncAttributeMaxDynamicSharedMemorySize, GEMM_SMEM);

    // weight hi/lo offsets (elements; each block = [hi(n), lo(n)])
    WArgs ws;
    const float* wsrc[9] = {aw1, ir_wqkv, vi_wqkv, ir_wo, vi_wo, ir_w1, vi_w1, ir_w2, vi_w2};
    const int    wn[9]   = {262144, 196608, 196608, 65536, 65536, 262144, 262144, 262144, 262144};
    int start = 0;
    for (int i = 0; i < 9; i++) { ws.src[i] = wsrc[i]; ws.n[i] = wn[i]; ws.start[i] = start; start += 2*wn[i]; }
    conv_w<<<dim3(64, 9), 256>>>(ws, whl);

    // 1. token-major concat (+hi/lo)
    transpose_cat<<<dim3(NT/32, CD/32, BB*2), dim3(32,8)>>>(f_ir, f_vis, xcat, xcathl);
    // 2. agent hidden (silu)
    gemm_hm<<<dim3(AGH/128, NT/128, BB), 256, GEMM_SMEM>>>(
        xcathl, XCAT_PLANE, whl + 0, whl + 0, 262144,
        ab1, ab1, h1, (__nv_bfloat16*)0, 0, (const float*)0, (const int*)0, 512, AGH, 1);
    // 3. agent logits + STE mask
    agent_logits<<<(BB*NT)/8, 256>>>(h1, aw2, ab2, logits, maskf);
    // 4. selection
    select_kernel<<<BB, 256>>>(logits, list, cntp);
    // 5. gather selected tokens
    gather_tok<<<dim3(NT, BB), 256>>>(xcat, list, cntp, x0, x1);

    // 6. both mixers fused per launch (z = 2*BB)
    ln2<<<dim3(NT, 2*BB), 256>>>(x, xnhl, ir_lng, ir_lnb, vi_lng, vi_lnb, cntp);
    gemm_hm<<<dim3(768/128, NT/128, 2*BB), 256, GEMM_SMEM>>>(
        xnhl, XN_PLANE, whl + 524288, whl + 917504, 196608,
        ir_bqkv, vi_bqkv, (float*)0, qkvhl, QKV_PLANE, (const float*)0, cntp, 256, 768, 0);
    attn_mma<<<dim3(NT/128, NH, 2*BB), 256, ATTN_SMEM>>>(qkvhl, atthl, cntp);
    gemm_hm<<<dim3(CD/128, NT/128, 2*BB), 256, GEMM_SMEM>>>(
        atthl, ATT_PLANE, whl + 1310720, whl + 1441792, 65536,
        ir_bo, vi_bo, x, (__nv_bfloat16*)0, 0, x, cntp, 256, CD, 0);
    ln2<<<dim3(NT, 2*BB), 256>>>(x, xnhl, ir_lng, ir_lnb, vi_lng, vi_lnb, cntp);
    gemm_hm<<<dim3(1024/128, NT/128, 2*BB), 256, GEMM_SMEM>>>(
        xnhl, XN_PLANE, whl + 1572864, whl + 2097152, 262144,
        ir_b1, vi_b1, (float*)0, hidhl, HID_PLANE, (const float*)0, cntp, 256, 1024, 2);
    gemm_hm<<<dim3(CD/128, NT/128, 2*BB), 256, GEMM_SMEM>>>(
        hidhl, HID_PLANE, whl + 2621440, whl + 3145728, 262144,
        ir_b2, vi_b2, x, (__nv_bfloat16*)0, 0, x, cntp, 1024, CD, 0);

    // 7. output
    base_out<<<(BB*CD*NT)/256, 256>>>(f_ir, f_vis, out);
    scatter_out<<<dim3(NT, BB), 256>>>(x0, x1, list, maskf, cntp, out);
}

// round 9
// speedup vs baseline: 4.1740x; 1.0705x over previous
#include <cuda_runtime.h>
#include <cuda_bf16.h>
#include <math.h>
#include <stdint.h>

#define BB   4
#define NT   2304      // 48*48 tokens
#define CD   256       // DIM
#define AGH  512       // agent hidden
#define NH   4
#define DH   64

// plane sizes (elements)
#define XCAT_PLANE ((size_t)BB*NT*512)
#define XN_PLANE   ((size_t)2*BB*NT*CD)
#define ATT_PLANE  ((size_t)2*BB*NT*CD)
#define HID_PLANE  ((size_t)2*BB*NT*1024)
#define QKV_PLANE  ((size_t)2*BB*NT*768)
#define WHL_TOTAL  3670016

// ---------------- bf16 HMMA m16n8k16 ----------------
__device__ __forceinline__ void mma16816(float* c, const uint32_t* a, uint32_t b0, uint32_t b1) {
    asm volatile("mma.sync.aligned.m16n8k16.row.col.f32.bf16.bf16.f32 "
        "{%0,%1,%2,%3}, {%4,%5,%6,%7}, {%8,%9}, {%0,%1,%2,%3};"
        : "+f"(c[0]), "+f"(c[1]), "+f"(c[2]), "+f"(c[3])
        : "r"(a[0]), "r"(a[1]), "r"(a[2]), "r"(a[3]), "r"(b0), "r"(b1));
}

__device__ __forceinline__ uint32_t smem_u32(const void* p) {
    uint32_t a;
    asm("{ .reg .u64 t; cvta.to.shared.u64 t, %1; cvt.u32.u64 %0, t; }" : "=r"(a) : "l"(p));
    return a;
}
#define CP16(dst, src) asm volatile("cp.async.cg.shared.global [%0], [%1], 16;" :: "r"(dst), "l"(src))
#define CP16P(dst, src, p) asm volatile("cp.async.cg.shared.global [%0], [%1], 16, %2;" :: "r"(dst), "l"(src), "r"((p)?16:0))
#define CPCOMMIT()     asm volatile("cp.async.commit_group;" ::: "memory")
#define CPWAIT(n)      asm volatile("cp.async.wait_group %0;" :: "n"(n) : "memory")
#define LDSM4(r, a) asm volatile("ldmatrix.sync.aligned.m8n8.x4.shared.b16 {%0,%1,%2,%3}, [%4];" \
    : "=r"((r)[0]), "=r"((r)[1]), "=r"((r)[2]), "=r"((r)[3]) : "r"(a))
#define LDSM4T(r, a) asm volatile("ldmatrix.sync.aligned.m8n8.x4.trans.shared.b16 {%0,%1,%2,%3}, [%4];" \
    : "=r"((r)[0]), "=r"((r)[1]), "=r"((r)[2]), "=r"((r)[3]) : "r"(a))

__device__ __forceinline__ void split_hl(float v, __nv_bfloat16& h, __nv_bfloat16& l) {
    h = __float2bfloat16_rn(v);
    l = __float2bfloat16_rn(v - __bfloat162float(h));
}
__device__ __forceinline__ void pack_hl2(float a, float b, uint32_t& ph, uint32_t& pl) {
    __nv_bfloat16 ha, la, hb, lb;
    split_hl(a, ha, la); split_hl(b, hb, lb);
    ph = ((uint32_t)__bfloat16_as_ushort(hb) << 16) | (uint32_t)__bfloat16_as_ushort(ha);
    pl = ((uint32_t)__bfloat16_as_ushort(lb) << 16) | (uint32_t)__bfloat16_as_ushort(la);
}
__device__ __forceinline__ void cvt_pack(float4 v, uint2& h, uint2& l) {
    uint32_t h0, l0, h1, l1;
    pack_hl2(v.x, v.y, h0, l0);
    pack_hl2(v.z, v.w, h1, l1);
    h.x = h0; h.y = h1; l.x = l0; l.y = l1;
}

// ---------------- scratch ----------------
__device__ float g_xcat[(size_t)BB*NT*512];
__device__ float g_part[(size_t)BB*NT*4];
__device__ float g_maskf [BB*NT];
__device__ int   g_list[BB*NT];
__device__ int   g_cnt [BB];
__device__ float g_x  [(size_t)2*BB*NT*CD];
__device__ __align__(16) __nv_bfloat16 g_w_hl  [WHL_TOTAL];
__device__ __align__(16) __nv_bfloat16 g_xcat_hl[2*XCAT_PLANE];
__device__ __align__(16) __nv_bfloat16 g_xn_hl [2*XN_PLANE];
__device__ __align__(16) __nv_bfloat16 g_att_hl[2*ATT_PLANE];
__device__ __align__(16) __nv_bfloat16 g_hid_hl[2*HID_PLANE];
__device__ __align__(16) __nv_bfloat16 g_qkv_hl[2*QKV_PLANE];

// ---------------- weight convert ----------------
struct WArgs { const float* src[9]; int start[9]; int n[9]; };
__global__ void conv_w(WArgs a, __nv_bfloat16* __restrict__ dst)
{
    int w = blockIdx.y;
    int n = a.n[w];
    const float4* s = (const float4*)a.src[w];
    __nv_bfloat16* dh = dst + a.start[w];
    __nv_bfloat16* dl = dh + n;
    int n4 = n >> 2;
    for (int i = blockIdx.x*256 + threadIdx.x; i < n4; i += gridDim.x*256) {
        float4 v = s[i];
        uint2 h, l; cvt_pack(v, h, l);
        *(uint2*)&dh[i*4] = h;
        *(uint2*)&dl[i*4] = l;
    }
}

// ---------------- transpose [B,C,N] -> token-major concat + hi/lo ----------------
__global__ void transpose_cat(const float* __restrict__ fir, const float* __restrict__ fvis,
                              float* __restrict__ xcat, __nv_bfloat16* __restrict__ xcat_hl)
{
    int src = blockIdx.z & 1;
    int b   = blockIdx.z >> 1;
    const float* f = src ? fvis : fir;
    __shared__ float tile[32][33];
    int n0 = blockIdx.x * 32, c0 = blockIdx.y * 32;
    int tx = threadIdx.x, ty = threadIdx.y;
    #pragma unroll
    for (int i = 0; i < 32; i += 8)
        tile[ty + i][tx] = f[((size_t)b*CD + c0 + ty + i)*NT + n0 + tx];
    __syncthreads();
    #pragma unroll
    for (int i = 0; i < 32; i += 8) {
        float v = tile[tx][ty + i];
        size_t idx = ((size_t)b*NT + n0 + ty + i)*512 + src*CD + c0 + tx;
        xcat[idx] = v;
        __nv_bfloat16 h, l; split_hl(v, h, l);
        xcat_hl[idx] = h;
        xcat_hl[XCAT_PLANE + idx] = l;
    }
}

// ================= HMMA GEMM: bf16 hi/lo inputs, 3-stage cp.async + ldmatrix =================
#define RSB   80
#define MATB  (128*RSB)
#define STAGE (4*MATB)
#define GEMM_SMEM (3*STAGE)

__device__ __forceinline__ float actf(float t, int act) {
    if (act == 1) return t / (1.f + expf(-t));
    if (act == 2) return 0.5f*t*(1.f + erff(t*0.70710678118654752f));
    return t;
}

__global__ void __launch_bounds__(256)
gemm_hm(const __nv_bfloat16* __restrict__ Ahl, size_t aplane,
        const __nv_bfloat16* __restrict__ Wah, const __nv_bfloat16* __restrict__ Wbh, size_t wplane,
        const float* __restrict__ ba, const float* __restrict__ bbv,
        float* __restrict__ Cf, __nv_bfloat16* __restrict__ Chl, size_t cplane,
        const float* __restrict__ R,
        const int* __restrict__ counts, int K, int Ocols, int act,
        const float* __restrict__ logit_w, float* __restrict__ part)
{
    int bz = blockIdx.z;
    int s = (bz >= BB) ? 1 : 0;
    int b = bz & 3;
    int Mb = counts ? counts[b] : NT;
    int m0 = blockIdx.y * 128;
    if (m0 >= Mb) return;
    int o0 = blockIdx.x * 128;
    const __nv_bfloat16* Wsel = s ? Wbh : Wah;
    const float* bias = s ? bbv : ba;
    size_t rowbase = (size_t)(s*BB + b) * NT;
    const __nv_bfloat16* Ah_g = Ahl + (rowbase + m0) * K;
    const __nv_bfloat16* Al_g = Ah_g + aplane;
    const __nv_bfloat16* Wh_g = Wsel + (size_t)o0 * K;
    const __nv_bfloat16* Wl_g = Wh_g + wplane;
    float* Cfb = Cf ? Cf + rowbase * Ocols : (float*)0;
    __nv_bfloat16* Chb = Chl ? Chl + rowbase * Ocols : (__nv_bfloat16*)0;
    const float* Rb = R ? R + rowbase * Ocols : (const float*)0;

    extern __shared__ char smem[];
    uint32_t sbase = smem_u32(smem);
    int tid = threadIdx.x, lane = tid & 31, w = tid >> 5;
    int wm = w & 3, wn = w >> 2;
    int gid = lane >> 2, tig = lane & 3;

    float acc[2][8][4];
    #pragma unroll
    for (int mt=0; mt<2; mt++)
        #pragma unroll
        for (int nt=0; nt<8; nt++)
            #pragma unroll
            for (int q=0; q<4; q++) acc[mt][nt][q] = 0.f;

#define PREFETCH(cc, st) do { \
    uint32_t sb_ = sbase + (st)*STAGE; \
    _Pragma("unroll") \
    for (int i_ = 0; i_ < 2; i_++) { \
        int f_ = tid + i_*256; int row_ = f_ >> 2; int jb_ = (f_ & 3) * 16; \
        size_t go_ = (size_t)row_*K + (size_t)(cc)*32; \
        const char* pah = (const char*)(Ah_g + go_) + jb_; \
        const char* pal = (const char*)(Al_g + go_) + jb_; \
        const char* pwh = (const char*)(Wh_g + go_) + jb_; \
        const char* pwl = (const char*)(Wl_g + go_) + jb_; \
        uint32_t so_ = sb_ + (uint32_t)(row_*RSB + jb_); \
        CP16(so_, pah); CP16(so_ + MATB, pal); \
        CP16(so_ + 2*MATB, pwh); CP16(so_ + 3*MATB, pwl); \
    } } while (0)

    int nchunk = K >> 5;
    PREFETCH(0, 0);
    CPCOMMIT();
    if (nchunk > 1) { PREFETCH(1, 1); CPCOMMIT(); }

    for (int c = 0; c < nchunk; c++) {
        if (c == nchunk - 1) { CPWAIT(0); } else { CPWAIT(1); }
        __syncthreads();
        int st3 = c % 3;
        uint32_t stg = sbase + st3 * STAGE;
        #pragma unroll
        for (int ks = 0; ks < 2; ks++) {
            int kb = ks * 32;
            uint32_t colb = (uint32_t)(kb + ((lane >> 4) << 4));
            uint32_t Ahf[2][4], Alf[2][4];
            #pragma unroll
            for (int mt = 0; mt < 2; mt++) {
                uint32_t sa = stg + (uint32_t)((wm*32 + mt*16 + (lane & 15)) * RSB) + colb;
                LDSM4(Ahf[mt], sa);
                LDSM4(Alf[mt], sa + MATB);
            }
            #pragma unroll
            for (int np = 0; np < 4; np++) {
                uint32_t sb = stg + 2*MATB + (uint32_t)((wn*64 + np*16 + (lane & 15)) * RSB) + colb;
                uint32_t Bh[4], Bl[4];
                LDSM4(Bh, sb);
                LDSM4(Bl, sb + MATB);
                #pragma unroll
                for (int mt = 0; mt < 2; mt++) {
                    mma16816(acc[mt][2*np],   Ahf[mt], Bh[0], Bh[2]);
                    mma16816(acc[mt][2*np],   Ahf[mt], Bl[0], Bl[2]);
                    mma16816(acc[mt][2*np],   Alf[mt], Bh[0], Bh[2]);
                    mma16816(acc[mt][2*np+1], Ahf[mt], Bh[1], Bh[3]);
                    mma16816(acc[mt][2*np+1], Ahf[mt], Bl[1], Bl[3]);
                    mma16816(acc[mt][2*np+1], Alf[mt], Bh[1], Bh[3]);
                }
            }
        }
        if (c + 2 < nchunk) { PREFETCH(c+2, (c+2) % 3); CPCOMMIT(); }
    }
#undef PREFETCH

    if (logit_w) {
        // fused agent-logit partial: pr = sum_cols silu(v)*aw2[col], deterministic reduce
        float pr[4] = {0.f, 0.f, 0.f, 0.f};
        #pragma unroll
        for (int mt = 0; mt < 2; mt++) {
            #pragma unroll
            for (int nt = 0; nt < 8; nt++) {
                int col = o0 + wn*64 + nt*8 + 2*tig;
                float b0v = bias[col], b1v = bias[col+1];
                float w0 = logit_w[col], w1 = logit_w[col+1];
                float t0 = actf(acc[mt][nt][0] + b0v, act);
                float t1 = actf(acc[mt][nt][1] + b1v, act);
                float t2 = actf(acc[mt][nt][2] + b0v, act);
                float t3 = actf(acc[mt][nt][3] + b1v, act);
                pr[mt*2+0] += t0*w0 + t1*w1;
                pr[mt*2+1] += t2*w0 + t3*w1;
            }
        }
        #pragma unroll
        for (int i = 0; i < 4; i++) {
            pr[i] += __shfl_xor_sync(0xffffffffu, pr[i], 1);
            pr[i] += __shfl_xor_sync(0xffffffffu, pr[i], 2);
        }
        __syncthreads();           // all warps done reading smem stages
        float* red = (float*)smem; // 256 floats
        if (tig == 0) {
            #pragma unroll
            for (int mt = 0; mt < 2; mt++) {
                red[wn*128 + wm*32 + mt*16 + gid]     = pr[mt*2+0];
                red[wn*128 + wm*32 + mt*16 + gid + 8] = pr[mt*2+1];
            }
        }
        __syncthreads();
        if (tid < 128)
            part[((size_t)b*NT + m0 + tid)*4 + blockIdx.x] = red[tid] + red[128 + tid];
        return;
    }

    #pragma unroll
    for (int mt = 0; mt < 2; mt++) {
        int r0 = m0 + wm*32 + mt*16 + gid;
        int r1 = r0 + 8;
        #pragma unroll
        for (int nt = 0; nt < 8; nt++) {
            int col = o0 + wn*64 + nt*8 + 2*tig;
            float b0v = bias[col], b1v = bias[col+1];
            float t0 = actf(acc[mt][nt][0] + b0v, act);
            float t1 = actf(acc[mt][nt][1] + b1v, act);
            float t2 = actf(acc[mt][nt][2] + b0v, act);
            float t3 = actf(acc[mt][nt][3] + b1v, act);
            if (Cfb) {
                if (r0 < Mb) {
                    if (Rb) { t0 += Rb[(size_t)r0*Ocols + col]; t1 += Rb[(size_t)r0*Ocols + col + 1]; }
                    *(float2*)&Cfb[(size_t)r0*Ocols + col] = make_float2(t0, t1);
                }
                if (r1 < Mb) {
                    if (Rb) { t2 += Rb[(size_t)r1*Ocols + col]; t3 += Rb[(size_t)r1*Ocols + col + 1]; }
                    *(float2*)&Cfb[(size_t)r1*Ocols + col] = make_float2(t2, t3);
                }
            } else {
                if (r0 < Mb) {
                    uint32_t ph, pl; pack_hl2(t0, t1, ph, pl);
                    *(uint32_t*)&Chb[(size_t)r0*Ocols + col] = ph;
                    *(uint32_t*)&Chb[cplane + (size_t)r0*Ocols + col] = pl;
                }
                if (r1 < Mb) {
                    uint32_t ph, pl; pack_hl2(t2, t3, ph, pl);
                    *(uint32_t*)&Chb[(size_t)r1*Ocols + col] = ph;
                    *(uint32_t*)&Chb[cplane + (size_t)r1*Ocols + col] = pl;
                }
            }
        }
    }
}

// ---------------- selection (logits from partials) ----------------
__global__ void select_kernel(const float* __restrict__ part, const float* __restrict__ ab2,
                              int* __restrict__ list, int* __restrict__ cnt,
                              float* __restrict__ maskf)
{
    int b = blockIdx.x, tid = threadIdx.x;
    const int PER = NT/256;  // 9
    __shared__ int cn[256];
    float ab2v = ab2[0];
    int base = tid*PER;
    float lv[PER];
    bool  sv[PER];
    int c = 0;
    #pragma unroll
    for (int i = 0; i < PER; i++) {
        size_t t4 = ((size_t)b*NT + base + i)*4;
        float lg = ((part[t4] + part[t4+1]) + (part[t4+2] + part[t4+3])) + ab2v;
        lv[i] = lg;
        bool sel = lg > 0.f; sv[i] = sel; c += sel;
        maskf[b*NT + base + i] = sel ? 1.f : 0.f;
    }
    cn[tid] = c; __syncthreads();
    for (int off = 1; off < 256; off <<= 1) {
        int v = (tid >= off) ? cn[tid-off] : 0;
        __syncthreads();
        cn[tid] += v;
        __syncthreads();
    }
    int total = cn[255];
    int pos = cn[tid] - c;
    if (total >= 64) {
        #pragma unroll
        for (int i = 0; i < PER; i++)
            if (sv[i]) { list[b*NT + pos] = base + i; pos++; }
        if (tid == 0) cnt[b] = total;
    } else {
        __shared__ float sl[NT];
        #pragma unroll
        for (int i = 0; i < PER; i++) sl[base+i] = lv[i];
        __syncthreads();
        if (tid == 0) {
            for (int t = 0; t < 64; t++) {
                int am = 0; float mv = sl[0];
                for (int n = 1; n < NT; n++) if (sl[n] > mv) { mv = sl[n]; am = n; }
                list[b*NT + t] = am; sl[am] = -1e30f;
            }
            cnt[b] = 64;
        }
    }
}

// ---------------- fused gather + LayerNorm (both streams) ----------------
__global__ void gather_ln(const float* __restrict__ xcat, const int* __restrict__ list,
                          const int* __restrict__ cnt,
                          float* __restrict__ x, __nv_bfloat16* __restrict__ Yhl,
                          const float* __restrict__ ga, const float* __restrict__ bba,
                          const float* __restrict__ gb2, const float* __restrict__ bbb)
{
    int b = blockIdx.y, j = blockIdx.x;
    if (j >= cnt[b]) return;
    int idx = list[b*NT + j];
    int tid = threadIdx.x;
    const float* src = xcat + ((size_t)b*NT + idx)*512;
    __shared__ float red[8];
    #pragma unroll
    for (int s = 0; s < 2; s++) {
        const float* gw = s ? gb2 : ga;
        const float* gb = s ? bbb : bba;
        float v = src[s*CD + tid];
        size_t row = ((size_t)(s*BB + b)*NT + j)*CD;
        x[row + tid] = v;
        float ssum = v;
        #pragma unroll
        for (int o = 16; o; o >>= 1) ssum += __shfl_down_sync(0xffffffffu, ssum, o);
        if ((tid & 31) == 0) red[tid>>5] = ssum;
        __syncthreads();
        float mean = 0.f;
        #pragma unroll
        for (int i = 0; i < 8; i++) mean += red[i];
        mean *= (1.f/CD);
        __syncthreads();
        float d = v - mean;
        ssum = d*d;
        #pragma unroll
        for (int o = 16; o; o >>= 1) ssum += __shfl_down_sync(0xffffffffu, ssum, o);
        if ((tid & 31) == 0) red[tid>>5] = ssum;
        __syncthreads();
        float var = 0.f;
        #pragma unroll
        for (int i = 0; i < 8; i++) var += red[i];
        var *= (1.f/CD);
        float yv = d * rsqrtf(var + 1e-5f) * gw[tid] + gb[tid];
        __nv_bfloat16 h, l; split_hl(yv, h, l);
        Yhl[row + tid] = h;
        Yhl[XN_PLANE + row + tid] = l;
        __syncthreads();
    }
}

// ---------------- LayerNorm (dual-stream) -> bf16 hi/lo ----------------
__global__ void ln2(const float* __restrict__ X, __nv_bfloat16* __restrict__ Yhl,
                    const float* __restrict__ ga, const float* __restrict__ bba,
                    const float* __restrict__ gb2, const float* __restrict__ bbb,
                    const int* __restrict__ cnt)
{
    int bz = blockIdx.y; int s = bz >> 2, b = bz & 3;
    int n = blockIdx.x;
    if (n >= cnt[b]) return;
    const float* gw = s ? gb2 : ga;
    const float* gb = s ? bbb : bba;
    int tid = threadIdx.x;
    size_t row = ((size_t)(s*BB+b)*NT + n)*CD;
    float v = X[row + tid];
    __shared__ float red[8];
    float ssum = v;
    #pragma unroll
    for (int o = 16; o; o >>= 1) ssum += __shfl_down_sync(0xffffffffu, ssum, o);
    if ((tid & 31) == 0) red[tid>>5] = ssum;
    __syncthreads();
    float mean = 0.f;
    #pragma unroll
    for (int i = 0; i < 8; i++) mean += red[i];
    mean *= (1.f/CD);
    __syncthreads();
    float d = v - mean;
    ssum = d*d;
    #pragma unroll
    for (int o = 16; o; o >>= 1) ssum += __shfl_down_sync(0xffffffffu, ssum, o);
    if ((tid & 31) == 0) red[tid>>5] = ssum;
    __syncthreads();
    float var = 0.f;
    #pragma unroll
    for (int i = 0; i < 8; i++) var += red[i];
    var *= (1.f/CD);
    float yv = d * rsqrtf(var + 1e-5f) * gw[tid] + gb[tid];
    __nv_bfloat16 h, l; split_hl(yv, h, l);
    Yhl[row + tid] = h;
    Yhl[XN_PLANE + row + tid] = l;
}

// ================= flash attention on HMMA (3-stage pipeline) =================
#define AQR 144
#define AT_QL (128*AQR)
#define AT_KV (2*128*AQR)
#define AT_STG (4*64*AQR)
#define ATTN_SMEM (AT_KV + 3*AT_STG)

__global__ void __launch_bounds__(256)
attn_mma(const __nv_bfloat16* __restrict__ qkvhl, __nv_bfloat16* __restrict__ att_hl,
         const int* __restrict__ cnt)
{
    extern __shared__ char smc[];
    uint32_t sb = smem_u32(smc);
    int bz = blockIdx.z; int s = bz >> 2, b = bz & 3;
    int h = blockIdx.y, q0 = blockIdx.x*128;
    int Mb = cnt[b];
    if (q0 >= Mb) return;
    int tid = threadIdx.x, lane = tid & 31, w = tid >> 5;
    int gid = lane >> 2, tig = lane & 3;
    size_t rowbase = (size_t)(s*BB + b) * NT;
    const __nv_bfloat16* qg = qkvhl;

    {
        #pragma unroll
        for (int i = 0; i < 8; i++) {
            int f = tid + i*256;
            int pl = f >> 10, rem = f & 1023;
            int row = rem >> 3, c16 = rem & 7;
            const char* src = (const char*)(qg + (rowbase + q0 + row)*768 + h*64
                                            + (size_t)pl*QKV_PLANE) + c16*16;
            uint32_t dst = sb + pl*AT_QL + row*AQR + c16*16;
            CP16P(dst, src, (q0 + row) < Mb);
        }
    }
#define KV_PREFETCH(kt, st) do { \
    int k0_ = (kt)*64; \
    _Pragma("unroll") \
    for (int i_ = 0; i_ < 8; i_++) { \
        int f_ = tid + i_*256; \
        int pl_ = f_ >> 9, rem_ = f_ & 511; \
        int row_ = rem_ >> 3, c16_ = rem_ & 7; \
        int ko_ = (pl_ < 2) ? 256 : 512; \
        size_t hp_ = (pl_ & 1) ? QKV_PLANE : 0; \
        const char* src_ = (const char*)(qg + (rowbase + k0_ + row_)*768 + ko_ + h*64 + hp_) + c16_*16; \
        uint32_t dst_ = sb + AT_KV + (st)*AT_STG + pl_*(64*AQR) + row_*AQR + c16_*16; \
        CP16P(dst_, src_, (k0_ + row_) < Mb); \
    } } while (0)

    int nkt = (Mb + 63) >> 6;
    KV_PREFETCH(0, 0);
    CPCOMMIT();
    if (nkt > 1) { KV_PREFETCH(1, 1); CPCOMMIT(); }

    uint32_t Qh[4][4], Ql[4][4];
    float oacc[8][4];
    #pragma unroll
    for (int j=0;j<8;j++)
        #pragma unroll
        for (int q=0;q<4;q++) oacc[j][q] = 0.f;
    float m0 = -1e30f, m1 = -1e30f, l0 = 0.f, l1 = 0.f;
    bool qload = false;

    for (int c = 0; c < nkt; c++) {
        if (c == nkt - 1) { CPWAIT(0); } else { CPWAIT(1); }
        __syncthreads();
        if (!qload) {
            qload = true;
            #pragma unroll
            for (int ks = 0; ks < 4; ks++) {
                uint32_t qa = sb + (uint32_t)((w*16 + (lane & 15)) * AQR) + ks*32 + ((lane >> 4) << 4);
                LDSM4(Qh[ks], qa);
                LDSM4(Ql[ks], qa + AT_QL);
            }
        }
        uint32_t kb = sb + AT_KV + (c % 3)*AT_STG;
        uint32_t vb = kb + 2*(64*AQR);

        float sacc[8][4];
        #pragma unroll
        for (int j=0;j<8;j++)
            #pragma unroll
            for (int q=0;q<4;q++) sacc[j][q] = 0.f;
        #pragma unroll
        for (int ks = 0; ks < 4; ks++) {
            #pragma unroll
            for (int np = 0; np < 4; np++) {
                uint32_t ka = kb + (uint32_t)((np*16 + ((lane >> 4) << 3) + (lane & 7)) * AQR)
                            + ks*32 + (((lane >> 3) & 1) << 4);
                uint32_t Kh4[4], Kl4[4];
                LDSM4(Kh4, ka);
                LDSM4(Kl4, ka + 64*AQR);
                mma16816(sacc[2*np],   Qh[ks], Kh4[0], Kh4[1]);
                mma16816(sacc[2*np],   Qh[ks], Kl4[0], Kl4[1]);
                mma16816(sacc[2*np],   Ql[ks], Kh4[0], Kh4[1]);
                mma16816(sacc[2*np+1], Qh[ks], Kh4[2], Kh4[3]);
                mma16816(sacc[2*np+1], Qh[ks], Kl4[2], Kl4[3]);
                mma16816(sacc[2*np+1], Ql[ks], Kh4[2], Kh4[3]);
            }
        }
        int kvb = c*64;
        #pragma unroll
        for (int j = 0; j < 8; j++) {
            int t0 = kvb + j*8 + 2*tig;
            bool v0 = t0 < Mb, v1 = (t0 + 1) < Mb;
            sacc[j][0] = v0 ? sacc[j][0]*0.125f : -1e30f;
            sacc[j][1] = v1 ? sacc[j][1]*0.125f : -1e30f;
            sacc[j][2] = v0 ? sacc[j][2]*0.125f : -1e30f;
            sacc[j][3] = v1 ? sacc[j][3]*0.125f : -1e30f;
        }
        float mx0 = -1e30f, mx1 = -1e30f;
        #pragma unroll
        for (int j = 0; j < 8; j++) {
            mx0 = fmaxf(mx0, fmaxf(sacc[j][0], sacc[j][1]));
            mx1 = fmaxf(mx1, fmaxf(sacc[j][2], sacc[j][3]));
        }
        mx0 = fmaxf(mx0, __shfl_xor_sync(0xffffffffu, mx0, 1));
        mx0 = fmaxf(mx0, __shfl_xor_sync(0xffffffffu, mx0, 2));
        mx1 = fmaxf(mx1, __shfl_xor_sync(0xffffffffu, mx1, 1));
        mx1 = fmaxf(mx1, __shfl_xor_sync(0xffffffffu, mx1, 2));
        float mn0 = fmaxf(m0, mx0), mn1 = fmaxf(m1, mx1);
        float al0 = __expf(m0 - mn0), al1 = __expf(m1 - mn1);
        float s0 = 0.f, s1 = 0.f;
        #pragma unroll
        for (int j = 0; j < 8; j++) {
            sacc[j][0] = __expf(sacc[j][0] - mn0);
            sacc[j][1] = __expf(sacc[j][1] - mn0);
            sacc[j][2] = __expf(sacc[j][2] - mn1);
            sacc[j][3] = __expf(sacc[j][3] - mn1);
            s0 += sacc[j][0] + sacc[j][1];
            s1 += sacc[j][2] + sacc[j][3];
        }
        s0 += __shfl_xor_sync(0xffffffffu, s0, 1);
        s0 += __shfl_xor_sync(0xffffffffu, s0, 2);
        s1 += __shfl_xor_sync(0xffffffffu, s1, 1);
        s1 += __shfl_xor_sync(0xffffffffu, s1, 2);
        l0 = l0*al0 + s0; l1 = l1*al1 + s1;
        m0 = mn0; m1 = mn1;
        #pragma unroll
        for (int j = 0; j < 8; j++) {
            oacc[j][0] *= al0; oacc[j][1] *= al0;
            oacc[j][2] *= al1; oacc[j][3] *= al1;
        }
        #pragma unroll
        for (int kt = 0; kt < 4; kt++) {
            uint32_t aPh[4], aPl[4];
            pack_hl2(sacc[2*kt][0],   sacc[2*kt][1],   aPh[0], aPl[0]);
            pack_hl2(sacc[2*kt][2],   sacc[2*kt][3],   aPh[1], aPl[1]);
            pack_hl2(sacc[2*kt+1][0], sacc[2*kt+1][1], aPh[2], aPl[2]);
            pack_hl2(sacc[2*kt+1][2], sacc[2*kt+1][3], aPh[3], aPl[3]);
            #pragma unroll
            for (int np = 0; np < 4; np++) {
                uint32_t va = vb + (uint32_t)((kt*16 + (((lane >> 3) & 1) << 3) + (lane & 7)) * AQR)
                            + (2*np + (lane >> 4))*16;
                uint32_t Vh4[4], Vl4[4];
                LDSM4T(Vh4, va);
                LDSM4T(Vl4, va + 64*AQR);
                mma16816(oacc[2*np],   aPh, Vh4[0], Vh4[1]);
                mma16816(oacc[2*np],   aPh, Vl4[0], Vl4[1]);
                mma16816(oacc[2*np],   aPl, Vh4[0], Vh4[1]);
                mma16816(oacc[2*np+1], aPh, Vh4[2], Vh4[3]);
                mma16816(oacc[2*np+1], aPh, Vl4[2], Vl4[3]);
                mma16816(oacc[2*np+1], aPl, Vh4[2], Vh4[3]);
            }
        }
        if (c + 2 < nkt) { KV_PREFETCH(c+2, (c+2) % 3); CPCOMMIT(); }
    }
#undef KV_PREFETCH

    float inv0 = 1.f / l0, inv1 = 1.f / l1;
    int qr0 = q0 + w*16 + gid;
    int qr1 = qr0 + 8;
    #pragma unroll
    for (int j = 0; j < 8; j++) {
        int col = h*64 + j*8 + 2*tig;
        if (qr0 < Mb) {
            uint32_t ph, pl;
            pack_hl2(oacc[j][0]*inv0, oacc[j][1]*inv0, ph, pl);
            *(uint32_t*)&att_hl[(rowbase + qr0)*CD + col] = ph;
            *(uint32_t*)&att_hl[ATT_PLANE + (rowbase + qr0)*CD + col] = pl;
        }
        if (qr1 < Mb) {
            uint32_t ph, pl;
            pack_hl2(oacc[j][2]*inv1, oacc[j][3]*inv1, ph, pl);
            *(uint32_t*)&att_hl[(rowbase + qr1)*CD + col] = ph;
            *(uint32_t*)&att_hl[ATT_PLANE + (rowbase + qr1)*CD + col] = pl;
        }
    }
}

// ---------------- output ----------------
__global__ void base_out(const float* __restrict__ fir, const float* __restrict__ fvis,
                         float* __restrict__ out)
{
    size_t i = (size_t)blockIdx.x*256 + threadIdx.x;
    out[i] = fir[i] + fvis[i];
}

__global__ void scatter_out(const float* __restrict__ x0, const float* __restrict__ x1,
                            const int* __restrict__ list, const float* __restrict__ maskf,
                            const int* __restrict__ cnt, float* __restrict__ out)
{
    int b = blockIdx.y, j = blockIdx.x;
    if (j >= cnt[b]) return;
    int idx = list[b*NT + j];
    float mv = maskf[b*NT + idx];
    int c = threadIdx.x;
    float v = (x0[((size_t)b*NT + j)*CD + c] + x1[((size_t)b*NT + j)*CD + c]) * mv;
    out[((size_t)b*CD + c)*NT + idx] = v;
}

// ---------------- host ----------------
extern "C" void kernel_launch(void* const* d_in, const int* in_sizes, int n_in,
                              void* d_out, int out_size)
{
    const float* f_ir  = (const float*)d_in[0];
    const float* f_vis = (const float*)d_in[1];
    const float* aw1   = (const float*)d_in[2];
    const float* ab1   = (const float*)d_in[3];
    const float* aw2   = (const float*)d_in[4];
    const float* ab2   = (const float*)d_in[5];
    const float* ir_lng  = (const float*)d_in[6];
    const float* ir_lnb  = (const float*)d_in[7];
    const float* ir_wqkv = (const float*)d_in[8];
    const float* ir_bqkv = (const float*)d_in[9];
    const float* ir_wo   = (const float*)d_in[10];
    const float* ir_bo   = (const float*)d_in[11];
    const float* ir_w1   = (const float*)d_in[12];
    const float* ir_b1   = (const float*)d_in[13];
    const float* ir_w2   = (const float*)d_in[14];
    const float* ir_b2   = (const float*)d_in[15];
    const float* vi_lng  = (const float*)d_in[16];
    const float* vi_lnb  = (const float*)d_in[17];
    const float* vi_wqkv = (const float*)d_in[18];
    const float* vi_bqkv = (const float*)d_in[19];
    const float* vi_wo   = (const float*)d_in[20];
    const float* vi_bo   = (const float*)d_in[21];
    const float* vi_w1   = (const float*)d_in[22];
    const float* vi_b1   = (const float*)d_in[23];
    const float* vi_w2   = (const float*)d_in[24];
    const float* vi_b2   = (const float*)d_in[25];
    float* out = (float*)d_out;

    float *xcat,*partp,*maskf,*x;
    __nv_bfloat16 *whl,*xcathl,*xnhl,*atthl,*hidhl,*qkvhl;
    int *list,*cntp;
    cudaGetSymbolAddress((void**)&xcat,  g_xcat);
    cudaGetSymbolAddress((void**)&partp, g_part);
    cudaGetSymbolAddress((void**)&maskf, g_maskf);
    cudaGetSymbolAddress((void**)&x,     g_x);
    cudaGetSymbolAddress((void**)&whl,   g_w_hl);
    cudaGetSymbolAddress((void**)&xcathl,g_xcat_hl);
    cudaGetSymbolAddress((void**)&xnhl,  g_xn_hl);
    cudaGetSymbolAddress((void**)&atthl, g_att_hl);
    cudaGetSymbolAddress((void**)&hidhl, g_hid_hl);
    cudaGetSymbolAddress((void**)&qkvhl, g_qkv_hl);
    cudaGetSymbolAddress((void**)&list,  g_list);
    cudaGetSymbolAddress((void**)&cntp,  g_cnt);
    float* x0 = x;
    float* x1 = x + (size_t)BB*NT*CD;

    cudaFuncSetAttribute(attn_mma, cudaFuncAttributeMaxDynamicSharedMemorySize, ATTN_SMEM);
    cudaFuncSetAttribute(gemm_hm, cudaFuncAttributeMaxDynamicSharedMemorySize, GEMM_SMEM);

    WArgs ws;
    const float* wsrc[9] = {aw1, ir_wqkv, vi_wqkv, ir_wo, vi_wo, ir_w1, vi_w1, ir_w2, vi_w2};
    const int    wn[9]   = {262144, 196608, 196608, 65536, 65536, 262144, 262144, 262144, 262144};
    int start = 0;
    for (int i = 0; i < 9; i++) { ws.src[i] = wsrc[i]; ws.n[i] = wn[i]; ws.start[i] = start; start += 2*wn[i]; }
    conv_w<<<dim3(64, 9), 256>>>(ws, whl);

    // 1. token-major concat (+hi/lo)
    transpose_cat<<<dim3(NT/32, CD/32, BB*2), dim3(32,8)>>>(f_ir, f_vis, xcat, xcathl);
    // 2. agent hidden GEMM with fused logit partials
    gemm_hm<<<dim3(AGH/128, NT/128, BB), 256, GEMM_SMEM>>>(
        xcathl, XCAT_PLANE, whl + 0, whl + 0, 262144,
        ab1, ab1, (float*)0, (__nv_bfloat16*)0, 0, (const float*)0, (const int*)0, 512, AGH, 1,
        aw2, partp);
    // 3. selection (computes logits from partials; writes mask)
    select_kernel<<<BB, 256>>>(partp, ab2, list, cntp, maskf);
    // 4. fused gather + first LN
    gather_ln<<<dim3(NT, BB), 256>>>(xcat, list, cntp, x, xnhl,
                                     ir_lng, ir_lnb, vi_lng, vi_lnb);

    // 5. both mixers fused per launch (z = 2*BB)
    gemm_hm<<<dim3(768/128, NT/128, 2*BB), 256, GEMM_SMEM>>>(
        xnhl, XN_PLANE, whl + 524288, whl + 917504, 196608,
        ir_bqkv, vi_bqkv, (float*)0, qkvhl, QKV_PLANE, (const float*)0, cntp, 256, 768, 0,
        (const float*)0, (float*)0);
    attn_mma<<<dim3(NT/128, NH, 2*BB), 256, ATTN_SMEM>>>(qkvhl, atthl, cntp);
    gemm_hm<<<dim3(CD/128, NT/128, 2*BB), 256, GEMM_SMEM>>>(
        atthl, ATT_PLANE, whl + 1310720, whl + 1441792, 65536,
        ir_bo, vi_bo, x, (__nv_bfloat16*)0, 0, x, cntp, 256, CD, 0,
        (const float*)0, (float*)0);
    ln2<<<dim3(NT, 2*BB), 256>>>(x, xnhl, ir_lng, ir_lnb, vi_lng, vi_lnb, cntp);
    gemm_hm<<<dim3(1024/128, NT/128, 2*BB), 256, GEMM_SMEM>>>(
        xnhl, XN_PLANE, whl + 1572864, whl + 2097152, 262144,
        ir_b1, vi_b1, (float*)0, hidhl, HID_PLANE, (const float*)0, cntp, 256, 1024, 2,
        (const float*)0, (float*)0);
    gemm_hm<<<dim3(CD/128, NT/128, 2*BB), 256, GEMM_SMEM>>>(
        hidhl, HID_PLANE, whl + 2621440, whl + 3145728, 262144,
        ir_b2, vi_b2, x, (__nv_bfloat16*)0, 0, x, cntp, 1024, CD, 0,
        (const float*)0, (float*)0);

    // 6. output
    base_out<<<(BB*CD*NT)/256, 256>>>(f_ir, f_vis, out);
    scatter_out<<<dim3(NT, BB), 256>>>(x0, x1, list, maskf, cntp, out);
}

// round 10
// speedup vs baseline: 4.7498x; 1.1380x over previous
#include <cuda_runtime.h>
#include <cuda_bf16.h>
#include <cuda_fp16.h>
#include <math.h>
#include <stdint.h>

#define BB   4
#define NT   2304      // 48*48 tokens
#define CD   256       // DIM
#define AGH  512       // agent hidden
#define NH   4
#define DH   64

// plane sizes (elements)
#define XCAT_PLANE ((size_t)BB*NT*512)
#define XN_PLANE   ((size_t)2*BB*NT*CD)
#define ATT_PLANE  ((size_t)2*BB*NT*CD)
#define HID_PLANE  ((size_t)2*BB*NT*1024)
#define QKV_PLANE  ((size_t)2*BB*NT*768)

// ---------------- HMMA m16n8k16 (bf16 + fp16 variants) ----------------
__device__ __forceinline__ void mma16816(float* c, const uint32_t* a, uint32_t b0, uint32_t b1) {
    asm volatile("mma.sync.aligned.m16n8k16.row.col.f32.bf16.bf16.f32 "
        "{%0,%1,%2,%3}, {%4,%5,%6,%7}, {%8,%9}, {%0,%1,%2,%3};"
        : "+f"(c[0]), "+f"(c[1]), "+f"(c[2]), "+f"(c[3])
        : "r"(a[0]), "r"(a[1]), "r"(a[2]), "r"(a[3]), "r"(b0), "r"(b1));
}
__device__ __forceinline__ void mma16816h(float* c, const uint32_t* a, uint32_t b0, uint32_t b1) {
    asm volatile("mma.sync.aligned.m16n8k16.row.col.f32.f16.f16.f32 "
        "{%0,%1,%2,%3}, {%4,%5,%6,%7}, {%8,%9}, {%0,%1,%2,%3};"
        : "+f"(c[0]), "+f"(c[1]), "+f"(c[2]), "+f"(c[3])
        : "r"(a[0]), "r"(a[1]), "r"(a[2]), "r"(a[3]), "r"(b0), "r"(b1));
}

__device__ __forceinline__ uint32_t smem_u32(const void* p) {
    uint32_t a;
    asm("{ .reg .u64 t; cvta.to.shared.u64 t, %1; cvt.u32.u64 %0, t; }" : "=r"(a) : "l"(p));
    return a;
}
#define CP16(dst, src) asm volatile("cp.async.cg.shared.global [%0], [%1], 16;" :: "r"(dst), "l"(src))
#define CP16P(dst, src, p) asm volatile("cp.async.cg.shared.global [%0], [%1], 16, %2;" :: "r"(dst), "l"(src), "r"((p)?16:0))
#define CPCOMMIT()     asm volatile("cp.async.commit_group;" ::: "memory")
#define CPWAIT(n)      asm volatile("cp.async.wait_group %0;" :: "n"(n) : "memory")
#define LDSM4(r, a) asm volatile("ldmatrix.sync.aligned.m8n8.x4.shared.b16 {%0,%1,%2,%3}, [%4];" \
    : "=r"((r)[0]), "=r"((r)[1]), "=r"((r)[2]), "=r"((r)[3]) : "r"(a))
#define LDSM4T(r, a) asm volatile("ldmatrix.sync.aligned.m8n8.x4.trans.shared.b16 {%0,%1,%2,%3}, [%4];" \
    : "=r"((r)[0]), "=r"((r)[1]), "=r"((r)[2]), "=r"((r)[3]) : "r"(a))

// bf16 helpers (agent path — bit-identical to R8)
__device__ __forceinline__ void split_hl(float v, __nv_bfloat16& h, __nv_bfloat16& l) {
    h = __float2bfloat16_rn(v);
    l = __float2bfloat16_rn(v - __bfloat162float(h));
}
__device__ __forceinline__ void cvt_pack(float4 v, uint2& h, uint2& l) {
    __nv_bfloat16 h0,l0,h1,l1,h2,l2,h3,l3;
    split_hl(v.x,h0,l0); split_hl(v.y,h1,l1); split_hl(v.z,h2,l2); split_hl(v.w,h3,l3);
    h.x = ((uint32_t)__bfloat16_as_ushort(h1)<<16)|(uint32_t)__bfloat16_as_ushort(h0);
    h.y = ((uint32_t)__bfloat16_as_ushort(h3)<<16)|(uint32_t)__bfloat16_as_ushort(h2);
    l.x = ((uint32_t)__bfloat16_as_ushort(l1)<<16)|(uint32_t)__bfloat16_as_ushort(l0);
    l.y = ((uint32_t)__bfloat16_as_ushort(l3)<<16)|(uint32_t)__bfloat16_as_ushort(l2);
}
// fp16 helpers
__device__ __forceinline__ uint32_t packh2(float a, float b) {
    __half2 h2 = __floats2half2_rn(a, b);
    return *reinterpret_cast<uint32_t*>(&h2);
}
__device__ __forceinline__ void pack_hl2h(float a, float b, uint32_t& ph, uint32_t& pl) {
    __half ha = __float2half_rn(a), hb = __float2half_rn(b);
    float la = a - __half2float(ha), lb = b - __half2float(hb);
    ph = ((uint32_t)__half_as_ushort(hb)<<16)|(uint32_t)__half_as_ushort(ha);
    pl = ((uint32_t)__half_as_ushort(__float2half_rn(lb))<<16)
       | (uint32_t)__half_as_ushort(__float2half_rn(la));
}

// ---------------- scratch ----------------
__device__ float g_xcat[(size_t)BB*NT*512];
__device__ float g_part[(size_t)BB*NT*4];
__device__ float g_maskf [BB*NT];
__device__ int   g_list[BB*NT];
__device__ int   g_cnt [BB];
__device__ float g_x  [(size_t)2*BB*NT*CD];
__device__ __align__(16) __nv_bfloat16 g_w_ag [2*262144];          // agent aw1 hi/lo (bf16)
__device__ __align__(16) __nv_bfloat16 g_xcat_hl[2*XCAT_PLANE];    // agent A (bf16)
__device__ __align__(16) __half g_w16  [3145728];                  // 8 mixer weights hi/lo (fp16)
__device__ __align__(16) __half g_xn_h [XN_PLANE];
__device__ __align__(16) __half g_att_h[ATT_PLANE];
__device__ __align__(16) __half g_hid_h[HID_PLANE];
__device__ __align__(16) __half g_qkv_hl[2*QKV_PLANE];

// ---------------- weight converts ----------------
__global__ void conv_wag(const float* __restrict__ src, __nv_bfloat16* __restrict__ dst, int n)
{
    __nv_bfloat16* dh = dst;
    __nv_bfloat16* dl = dst + n;
    int n4 = n >> 2;
    for (int i = blockIdx.x*256 + threadIdx.x; i < n4; i += gridDim.x*256) {
        float4 v = ((const float4*)src)[i];
        uint2 h, l; cvt_pack(v, h, l);
        *(uint2*)&dh[i*4] = h;
        *(uint2*)&dl[i*4] = l;
    }
}
struct W8 { const float* src[8]; int start[8]; int n[8]; };
__global__ void conv_w16(W8 a, __half* __restrict__ dst)
{
    int w = blockIdx.y;
    int n = a.n[w];
    const float4* s = (const float4*)a.src[w];
    __half* dh = dst + a.start[w];
    __half* dl = dh + n;
    int n4 = n >> 2;
    for (int i = blockIdx.x*256 + threadIdx.x; i < n4; i += gridDim.x*256) {
        float4 v = s[i];
        uint32_t h0,l0,h1,l1;
        pack_hl2h(v.x, v.y, h0, l0);
        pack_hl2h(v.z, v.w, h1, l1);
        *(uint2*)&dh[i*4] = make_uint2(h0, h1);
        *(uint2*)&dl[i*4] = make_uint2(l0, l1);
    }
}

// ---------------- transpose [B,C,N] -> token-major concat + bf16 hi/lo (agent) ----------------
__global__ void transpose_cat(const float* __restrict__ fir, const float* __restrict__ fvis,
                              float* __restrict__ xcat, __nv_bfloat16* __restrict__ xcat_hl)
{
    int src = blockIdx.z & 1;
    int b   = blockIdx.z >> 1;
    const float* f = src ? fvis : fir;
    __shared__ float tile[32][33];
    int n0 = blockIdx.x * 32, c0 = blockIdx.y * 32;
    int tx = threadIdx.x, ty = threadIdx.y;
    #pragma unroll
    for (int i = 0; i < 32; i += 8)
        tile[ty + i][tx] = f[((size_t)b*CD + c0 + ty + i)*NT + n0 + tx];
    __syncthreads();
    #pragma unroll
    for (int i = 0; i < 32; i += 8) {
        float v = tile[tx][ty + i];
        size_t idx = ((size_t)b*NT + n0 + ty + i)*512 + src*CD + c0 + tx;
        xcat[idx] = v;
        __nv_bfloat16 h, l; split_hl(v, h, l);
        xcat_hl[idx] = h;
        xcat_hl[XCAT_PLANE + idx] = l;
    }
}

#define RSB   80
#define MATB  (128*RSB)

__device__ __forceinline__ float actf(float t, int act) {
    if (act == 1) return t / (1.f + expf(-t));
    if (act == 2) return 0.5f*t*(1.f + erff(t*0.70710678118654752f));
    return t;
}

// ================= agent GEMM: bf16 3-term (bit-identical to R8), logit partials only ==========
#define STAGEA (4*MATB)
#define AGEMM_SMEM (3*STAGEA)
__global__ void __launch_bounds__(256)
gemm_agent(const __nv_bfloat16* __restrict__ Ahl, size_t aplane,
           const __nv_bfloat16* __restrict__ Wh, size_t wplane,
           const float* __restrict__ bias, int K,
           const float* __restrict__ logit_w, float* __restrict__ part)
{
    int b = blockIdx.z;
    int m0 = blockIdx.y * 128;
    int o0 = blockIdx.x * 128;
    size_t rowbase = (size_t)b * NT;
    const __nv_bfloat16* Ah_g = Ahl + (rowbase + m0) * K;
    const __nv_bfloat16* Al_g = Ah_g + aplane;
    const __nv_bfloat16* Wh_g = Wh + (size_t)o0 * K;
    const __nv_bfloat16* Wl_g = Wh_g + wplane;

    extern __shared__ char smem[];
    uint32_t sbase = smem_u32(smem);
    int tid = threadIdx.x, lane = tid & 31, w = tid >> 5;
    int wm = w & 3, wn = w >> 2;
    int gid = lane >> 2, tig = lane & 3;

    float acc[2][8][4];
    #pragma unroll
    for (int mt=0; mt<2; mt++)
        #pragma unroll
        for (int nt=0; nt<8; nt++)
            #pragma unroll
            for (int q=0; q<4; q++) acc[mt][nt][q] = 0.f;

#define PREFA(cc, st) do { \
    uint32_t sb_ = sbase + (st)*STAGEA; \
    _Pragma("unroll") \
    for (int i_ = 0; i_ < 2; i_++) { \
        int f_ = tid + i_*256; int row_ = f_ >> 2; int jb_ = (f_ & 3) * 16; \
        size_t go_ = (size_t)row_*K + (size_t)(cc)*32; \
        uint32_t so_ = sb_ + (uint32_t)(row_*RSB + jb_); \
        CP16(so_, (const char*)(Ah_g + go_) + jb_); \
        CP16(so_ + MATB, (const char*)(Al_g + go_) + jb_); \
        CP16(so_ + 2*MATB, (const char*)(Wh_g + go_) + jb_); \
        CP16(so_ + 3*MATB, (const char*)(Wl_g + go_) + jb_); \
    } } while (0)

    int nchunk = K >> 5;
    PREFA(0, 0);
    CPCOMMIT();
    if (nchunk > 1) { PREFA(1, 1); CPCOMMIT(); }

    for (int c = 0; c < nchunk; c++) {
        if (c == nchunk - 1) { CPWAIT(0); } else { CPWAIT(1); }
        __syncthreads();
        uint32_t stg = sbase + (c % 3) * STAGEA;
        #pragma unroll
        for (int ks = 0; ks < 2; ks++) {
            uint32_t colb = (uint32_t)(ks*32 + ((lane >> 4) << 4));
            uint32_t Ahf[2][4], Alf[2][4];
            #pragma unroll
            for (int mt = 0; mt < 2; mt++) {
                uint32_t sa = stg + (uint32_t)((wm*32 + mt*16 + (lane & 15)) * RSB) + colb;
                LDSM4(Ahf[mt], sa);
                LDSM4(Alf[mt], sa + MATB);
            }
            #pragma unroll
            for (int np = 0; np < 4; np++) {
                uint32_t sb = stg + 2*MATB + (uint32_t)((wn*64 + np*16 + (lane & 15)) * RSB) + colb;
                uint32_t Bh[4], Bl[4];
                LDSM4(Bh, sb);
                LDSM4(Bl, sb + MATB);
                #pragma unroll
                for (int mt = 0; mt < 2; mt++) {
                    mma16816(acc[mt][2*np],   Ahf[mt], Bh[0], Bh[2]);
                    mma16816(acc[mt][2*np],   Ahf[mt], Bl[0], Bl[2]);
                    mma16816(acc[mt][2*np],   Alf[mt], Bh[0], Bh[2]);
                    mma16816(acc[mt][2*np+1], Ahf[mt], Bh[1], Bh[3]);
                    mma16816(acc[mt][2*np+1], Ahf[mt], Bl[1], Bl[3]);
                    mma16816(acc[mt][2*np+1], Alf[mt], Bh[1], Bh[3]);
                }
            }
        }
        if (c + 2 < nchunk) { PREFA(c+2, (c+2) % 3); CPCOMMIT(); }
    }
#undef PREFA

    // fused agent-logit partials (identical math/order to R8)
    float pr[4] = {0.f, 0.f, 0.f, 0.f};
    #pragma unroll
    for (int mt = 0; mt < 2; mt++) {
        #pragma unroll
        for (int nt = 0; nt < 8; nt++) {
            int col = o0 + wn*64 + nt*8 + 2*tig;
            float b0v = bias[col], b1v = bias[col+1];
            float w0 = logit_w[col], w1 = logit_w[col+1];
            float t0 = actf(acc[mt][nt][0] + b0v, 1);
            float t1 = actf(acc[mt][nt][1] + b1v, 1);
            float t2 = actf(acc[mt][nt][2] + b0v, 1);
            float t3 = actf(acc[mt][nt][3] + b1v, 1);
            pr[mt*2+0] += t0*w0 + t1*w1;
            pr[mt*2+1] += t2*w0 + t3*w1;
        }
    }
    #pragma unroll
    for (int i = 0; i < 4; i++) {
        pr[i] += __shfl_xor_sync(0xffffffffu, pr[i], 1);
        pr[i] += __shfl_xor_sync(0xffffffffu, pr[i], 2);
    }
    __syncthreads();
    float* red = (float*)smem;
    if (tig == 0) {
        #pragma unroll
        for (int mt = 0; mt < 2; mt++) {
            red[wn*128 + wm*32 + mt*16 + gid]     = pr[mt*2+0];
            red[wn*128 + wm*32 + mt*16 + gid + 8] = pr[mt*2+1];
        }
    }
    __syncthreads();
    if (tid < 128)
        part[((size_t)b*NT + m0 + tid)*4 + blockIdx.x] = red[tid] + red[128 + tid];
}

// ================= fp16 2-term GEMM: A single plane, W hi/lo =================
#define STAGE3 (3*MATB)
#define GEMM16_SMEM (3*STAGE3)   // 92160
__global__ void __launch_bounds__(256)
gemm_f16(const __half* __restrict__ Aall,
         const __half* __restrict__ Wah, const __half* __restrict__ Wbh, size_t wplane,
         const float* __restrict__ ba, const float* __restrict__ bbv,
         float* __restrict__ Cf, __half* __restrict__ Ch, size_t cplane,
         const float* __restrict__ R,
         const int* __restrict__ counts, int K, int Ocols, int act)
{
    int bz = blockIdx.z;
    int s = (bz >= BB) ? 1 : 0;
    int b = bz & 3;
    int Mb = counts[b];
    int m0 = blockIdx.y * 128;
    if (m0 >= Mb) return;
    int o0 = blockIdx.x * 128;
    const __half* Wsel = s ? Wbh : Wah;
    const float* bias = s ? bbv : ba;
    size_t rowbase = (size_t)(s*BB + b) * NT;
    const __half* Ah_g = Aall + (rowbase + m0) * K;
    const __half* Wh_g = Wsel + (size_t)o0 * K;
    const __half* Wl_g = Wh_g + wplane;
    float* Cfb = Cf ? Cf + rowbase * Ocols : (float*)0;
    __half* Chb = Ch ? Ch + rowbase * Ocols : (__half*)0;
    const float* Rb = R ? R + rowbase * Ocols : (const float*)0;

    extern __shared__ char smem[];
    uint32_t sbase = smem_u32(smem);
    int tid = threadIdx.x, lane = tid & 31, w = tid >> 5;
    int wm = w & 3, wn = w >> 2;
    int gid = lane >> 2, tig = lane & 3;

    float acc[2][8][4];
    #pragma unroll
    for (int mt=0; mt<2; mt++)
        #pragma unroll
        for (int nt=0; nt<8; nt++)
            #pragma unroll
            for (int q=0; q<4; q++) acc[mt][nt][q] = 0.f;

#define PREF16(cc, st) do { \
    uint32_t sb_ = sbase + (st)*STAGE3; \
    _Pragma("unroll") \
    for (int i_ = 0; i_ < 6; i_++) { \
        int f_ = tid + i_*256; int mat_ = f_ >> 9; int rem_ = f_ & 511; \
        int row_ = rem_ >> 2; int jb_ = (rem_ & 3) * 16; \
        size_t go_ = (size_t)row_*K + (size_t)(cc)*32; \
        const char* p_ = (mat_ == 0) ? (const char*)(Ah_g + go_) \
                       : (mat_ == 1) ? (const char*)(Wh_g + go_) \
                                     : (const char*)(Wl_g + go_); \
        CP16(sb_ + (uint32_t)(mat_*MATB + row_*RSB + jb_), p_ + jb_); \
    } } while (0)

    int nchunk = K >> 5;
    PREF16(0, 0);
    CPCOMMIT();
    if (nchunk > 1) { PREF16(1, 1); CPCOMMIT(); }

    for (int c = 0; c < nchunk; c++) {
        if (c == nchunk - 1) { CPWAIT(0); } else { CPWAIT(1); }
        __syncthreads();
        uint32_t stg = sbase + (c % 3) * STAGE3;
        #pragma unroll
        for (int ks = 0; ks < 2; ks++) {
            uint32_t colb = (uint32_t)(ks*32 + ((lane >> 4) << 4));
            uint32_t Ahf[2][4];
            #pragma unroll
            for (int mt = 0; mt < 2; mt++) {
                uint32_t sa = stg + (uint32_t)((wm*32 + mt*16 + (lane & 15)) * RSB) + colb;
                LDSM4(Ahf[mt], sa);
            }
            #pragma unroll
            for (int np = 0; np < 4; np++) {
                uint32_t sb = stg + MATB + (uint32_t)((wn*64 + np*16 + (lane & 15)) * RSB) + colb;
                uint32_t Bh[4], Bl[4];
                LDSM4(Bh, sb);
                LDSM4(Bl, sb + MATB);
                #pragma unroll
                for (int mt = 0; mt < 2; mt++) {
                    mma16816h(acc[mt][2*np],   Ahf[mt], Bh[0], Bh[2]);
                    mma16816h(acc[mt][2*np],   Ahf[mt], Bl[0], Bl[2]);
                    mma16816h(acc[mt][2*np+1], Ahf[mt], Bh[1], Bh[3]);
                    mma16816h(acc[mt][2*np+1], Ahf[mt], Bl[1], Bl[3]);
                }
            }
        }
        if (c + 2 < nchunk) { PREF16(c+2, (c+2) % 3); CPCOMMIT(); }
    }
#undef PREF16

    #pragma unroll
    for (int mt = 0; mt < 2; mt++) {
        int r0 = m0 + wm*32 + mt*16 + gid;
        int r1 = r0 + 8;
        #pragma unroll
        for (int nt = 0; nt < 8; nt++) {
            int col = o0 + wn*64 + nt*8 + 2*tig;
            float b0v = bias[col], b1v = bias[col+1];
            float t0 = actf(acc[mt][nt][0] + b0v, act);
            float t1 = actf(acc[mt][nt][1] + b1v, act);
            float t2 = actf(acc[mt][nt][2] + b0v, act);
            float t3 = actf(acc[mt][nt][3] + b1v, act);
            if (Cfb) {
                if (r0 < Mb) {
                    if (Rb) { t0 += Rb[(size_t)r0*Ocols + col]; t1 += Rb[(size_t)r0*Ocols + col + 1]; }
                    *(float2*)&Cfb[(size_t)r0*Ocols + col] = make_float2(t0, t1);
                }
                if (r1 < Mb) {
                    if (Rb) { t2 += Rb[(size_t)r1*Ocols + col]; t3 += Rb[(size_t)r1*Ocols + col + 1]; }
                    *(float2*)&Cfb[(size_t)r1*Ocols + col] = make_float2(t2, t3);
                }
            } else if (cplane) {
                if (r0 < Mb) {
                    uint32_t ph, pl; pack_hl2h(t0, t1, ph, pl);
                    *(uint32_t*)&Chb[(size_t)r0*Ocols + col] = ph;
                    *(uint32_t*)&Chb[cplane + (size_t)r0*Ocols + col] = pl;
                }
                if (r1 < Mb) {
                    uint32_t ph, pl; pack_hl2h(t2, t3, ph, pl);
                    *(uint32_t*)&Chb[(size_t)r1*Ocols + col] = ph;
                    *(uint32_t*)&Chb[cplane + (size_t)r1*Ocols + col] = pl;
                }
            } else {
                if (r0 < Mb) *(uint32_t*)&Chb[(size_t)r0*Ocols + col] = packh2(t0, t1);
                if (r1 < Mb) *(uint32_t*)&Chb[(size_t)r1*Ocols + col] = packh2(t2, t3);
            }
        }
    }
}

// ---------------- selection (logits from partials) ----------------
__global__ void select_kernel(const float* __restrict__ part, const float* __restrict__ ab2,
                              int* __restrict__ list, int* __restrict__ cnt,
                              float* __restrict__ maskf)
{
    int b = blockIdx.x, tid = threadIdx.x;
    const int PER = NT/256;  // 9
    __shared__ int cn[256];
    float ab2v = ab2[0];
    int base = tid*PER;
    float lv[PER];
    bool  sv[PER];
    int c = 0;
    #pragma unroll
    for (int i = 0; i < PER; i++) {
        size_t t4 = ((size_t)b*NT + base + i)*4;
        float lg = ((part[t4] + part[t4+1]) + (part[t4+2] + part[t4+3])) + ab2v;
        lv[i] = lg;
        bool sel = lg > 0.f; sv[i] = sel; c += sel;
        maskf[b*NT + base + i] = sel ? 1.f : 0.f;
    }
    cn[tid] = c; __syncthreads();
    for (int off = 1; off < 256; off <<= 1) {
        int v = (tid >= off) ? cn[tid-off] : 0;
        __syncthreads();
        cn[tid] += v;
        __syncthreads();
    }
    int total = cn[255];
    int pos = cn[tid] - c;
    if (total >= 64) {
        #pragma unroll
        for (int i = 0; i < PER; i++)
            if (sv[i]) { list[b*NT + pos] = base + i; pos++; }
        if (tid == 0) cnt[b] = total;
    } else {
        __shared__ float sl[NT];
        #pragma unroll
        for (int i = 0; i < PER; i++) sl[base+i] = lv[i];
        __syncthreads();
        if (tid == 0) {
            for (int t = 0; t < 64; t++) {
                int am = 0; float mv = sl[0];
                for (int n = 1; n < NT; n++) if (sl[n] > mv) { mv = sl[n]; am = n; }
                list[b*NT + t] = am; sl[am] = -1e30f;
            }
            cnt[b] = 64;
        }
    }
}

// ---------------- fused gather + LayerNorm (both streams) -> fp16 ----------------
__global__ void gather_ln(const float* __restrict__ xcat, const int* __restrict__ list,
                          const int* __restrict__ cnt,
                          float* __restrict__ x, __half* __restrict__ Yh,
                          const float* __restrict__ ga, const float* __restrict__ bba,
                          const float* __restrict__ gb2, const float* __restrict__ bbb)
{
    int b = blockIdx.y, j = blockIdx.x;
    if (j >= cnt[b]) return;
    int idx = list[b*NT + j];
    int tid = threadIdx.x;
    const float* src = xcat + ((size_t)b*NT + idx)*512;
    __shared__ float red[8];
    #pragma unroll
    for (int s = 0; s < 2; s++) {
        const float* gw = s ? gb2 : ga;
        const float* gb = s ? bbb : bba;
        float v = src[s*CD + tid];
        size_t row = ((size_t)(s*BB + b)*NT + j)*CD;
        x[row + tid] = v;
        float ssum = v;
        #pragma unroll
        for (int o = 16; o; o >>= 1) ssum += __shfl_down_sync(0xffffffffu, ssum, o);
        if ((tid & 31) == 0) red[tid>>5] = ssum;
        __syncthreads();
        float mean = 0.f;
        #pragma unroll
        for (int i = 0; i < 8; i++) mean += red[i];
        mean *= (1.f/CD);
        __syncthreads();
        float d = v - mean;
        ssum = d*d;
        #pragma unroll
        for (int o = 16; o; o >>= 1) ssum += __shfl_down_sync(0xffffffffu, ssum, o);
        if ((tid & 31) == 0) red[tid>>5] = ssum;
        __syncthreads();
        float var = 0.f;
        #pragma unroll
        for (int i = 0; i < 8; i++) var += red[i];
        var *= (1.f/CD);
        Yh[row + tid] = __float2half_rn(d * rsqrtf(var + 1e-5f) * gw[tid] + gb[tid]);
        __syncthreads();
    }
}

// ---------------- LayerNorm (dual-stream) -> fp16 ----------------
__global__ void ln2(const float* __restrict__ X, __half* __restrict__ Yh,
                    const float* __restrict__ ga, const float* __restrict__ bba,
                    const float* __restrict__ gb2, const float* __restrict__ bbb,
                    const int* __restrict__ cnt)
{
    int bz = blockIdx.y; int s = bz >> 2, b = bz & 3;
    int n = blockIdx.x;
    if (n >= cnt[b]) return;
    const float* gw = s ? gb2 : ga;
    const float* gb = s ? bbb : bba;
    int tid = threadIdx.x;
    size_t row = ((size_t)(s*BB+b)*NT + n)*CD;
    float v = X[row + tid];
    __shared__ float red[8];
    float ssum = v;
    #pragma unroll
    for (int o = 16; o; o >>= 1) ssum += __shfl_down_sync(0xffffffffu, ssum, o);
    if ((tid & 31) == 0) red[tid>>5] = ssum;
    __syncthreads();
    float mean = 0.f;
    #pragma unroll
    for (int i = 0; i < 8; i++) mean += red[i];
    mean *= (1.f/CD);
    __syncthreads();
    float d = v - mean;
    ssum = d*d;
    #pragma unroll
    for (int o = 16; o; o >>= 1) ssum += __shfl_down_sync(0xffffffffu, ssum, o);
    if ((tid & 31) == 0) red[tid>>5] = ssum;
    __syncthreads();
    float var = 0.f;
    #pragma unroll
    for (int i = 0; i < 8; i++) var += red[i];
    var *= (1.f/CD);
    Yh[row + tid] = __float2half_rn(d * rsqrtf(var + 1e-5f) * gw[tid] + gb[tid]);
}

// ================= flash attention on fp16 HMMA (Q/P hi-only, K/V hi+lo) =================
#define AQR 144
#define AT_KVOFF (128*AQR)              // Q hi plane only
#define AT_STG (4*64*AQR)               // Kh,Kl,Vh,Vl
#define ATTN_SMEM (AT_KVOFF + 3*AT_STG) // 129024

__global__ void __launch_bounds__(256)
attn_mma(const __half* __restrict__ qkvhl, __half* __restrict__ att_h,
         const int* __restrict__ cnt)
{
    extern __shared__ char smc[];
    uint32_t sb = smem_u32(smc);
    int bz = blockIdx.z; int s = bz >> 2, b = bz & 3;
    int h = blockIdx.y, q0 = blockIdx.x*128;
    int Mb = cnt[b];
    if (q0 >= Mb) return;
    int tid = threadIdx.x, lane = tid & 31, w = tid >> 5;
    int gid = lane >> 2, tig = lane & 3;
    size_t rowbase = (size_t)(s*BB + b) * NT;
    const __half* qg = qkvhl;

    // Q hi prefetch: 128 rows x 8x16B
    {
        #pragma unroll
        for (int i = 0; i < 4; i++) {
            int f = tid + i*256;
            int row = f >> 3, c16 = f & 7;
            const char* src = (const char*)(qg + (rowbase + q0 + row)*768 + h*64) + c16*16;
            CP16P(sb + row*AQR + c16*16, src, (q0 + row) < Mb);
        }
    }
#define KV_PREFETCH(kt, st) do { \
    int k0_ = (kt)*64; \
    _Pragma("unroll") \
    for (int i_ = 0; i_ < 8; i_++) { \
        int f_ = tid + i_*256; \
        int pl_ = f_ >> 9, rem_ = f_ & 511; \
        int row_ = rem_ >> 3, c16_ = rem_ & 7; \
        int ko_ = (pl_ < 2) ? 256 : 512; \
        size_t hp_ = (pl_ & 1) ? QKV_PLANE : 0; \
        const char* src_ = (const char*)(qg + (rowbase + k0_ + row_)*768 + ko_ + h*64 + hp_) + c16_*16; \
        uint32_t dst_ = sb + AT_KVOFF + (st)*AT_STG + pl_*(64*AQR) + row_*AQR + c16_*16; \
        CP16P(dst_, src_, (k0_ + row_) < Mb); \
    } } while (0)

    int nkt = (Mb + 63) >> 6;
    KV_PREFETCH(0, 0);
    CPCOMMIT();
    if (nkt > 1) { KV_PREFETCH(1, 1); CPCOMMIT(); }

    uint32_t Qh[4][4];
    float oacc[8][4];
    #pragma unroll
    for (int j=0;j<8;j++)
        #pragma unroll
        for (int q=0;q<4;q++) oacc[j][q] = 0.f;
    float m0 = -1e30f, m1 = -1e30f, l0 = 0.f, l1 = 0.f;
    bool qload = false;

    for (int c = 0; c < nkt; c++) {
        if (c == nkt - 1) { CPWAIT(0); } else { CPWAIT(1); }
        __syncthreads();
        if (!qload) {
            qload = true;
            #pragma unroll
            for (int ks = 0; ks < 4; ks++) {
                uint32_t qa = sb + (uint32_t)((w*16 + (lane & 15)) * AQR) + ks*32 + ((lane >> 4) << 4);
                LDSM4(Qh[ks], qa);
            }
        }
        uint32_t kb = sb + AT_KVOFF + (c % 3)*AT_STG;
        uint32_t vb = kb + 2*(64*AQR);

        float sacc[8][4];
        #pragma unroll
        for (int j=0;j<8;j++)
            #pragma unroll
            for (int q=0;q<4;q++) sacc[j][q] = 0.f;
        #pragma unroll
        for (int ks = 0; ks < 4; ks++) {
            #pragma unroll
            for (int np = 0; np < 4; np++) {
                uint32_t ka = kb + (uint32_t)((np*16 + ((lane >> 4) << 3) + (lane & 7)) * AQR)
                            + ks*32 + (((lane >> 3) & 1) << 4);
                uint32_t Kh4[4], Kl4[4];
                LDSM4(Kh4, ka);
                LDSM4(Kl4, ka + 64*AQR);
                mma16816h(sacc[2*np],   Qh[ks], Kh4[0], Kh4[1]);
                mma16816h(sacc[2*np],   Qh[ks], Kl4[0], Kl4[1]);
                mma16816h(sacc[2*np+1], Qh[ks], Kh4[2], Kh4[3]);
                mma16816h(sacc[2*np+1], Qh[ks], Kl4[2], Kl4[3]);
            }
        }
        int kvb = c*64;
        #pragma unroll
        for (int j = 0; j < 8; j++) {
            int t0 = kvb + j*8 + 2*tig;
            bool v0 = t0 < Mb, v1 = (t0 + 1) < Mb;
            sacc[j][0] = v0 ? sacc[j][0]*0.125f : -1e30f;
            sacc[j][1] = v1 ? sacc[j][1]*0.125f : -1e30f;
            sacc[j][2] = v0 ? sacc[j][2]*0.125f : -1e30f;
            sacc[j][3] = v1 ? sacc[j][3]*0.125f : -1e30f;
        }
        float mx0 = -1e30f, mx1 = -1e30f;
        #pragma unroll
        for (int j = 0; j < 8; j++) {
            mx0 = fmaxf(mx0, fmaxf(sacc[j][0], sacc[j][1]));
            mx1 = fmaxf(mx1, fmaxf(sacc[j][2], sacc[j][3]));
        }
        mx0 = fmaxf(mx0, __shfl_xor_sync(0xffffffffu, mx0, 1));
        mx0 = fmaxf(mx0, __shfl_xor_sync(0xffffffffu, mx0, 2));
        mx1 = fmaxf(mx1, __shfl_xor_sync(0xffffffffu, mx1, 1));
        mx1 = fmaxf(mx1, __shfl_xor_sync(0xffffffffu, mx1, 2));
        float mn0 = fmaxf(m0, mx0), mn1 = fmaxf(m1, mx1);
        float al0 = __expf(m0 - mn0), al1 = __expf(m1 - mn1);
        float s0 = 0.f, s1 = 0.f;
        #pragma unroll
        for (int j = 0; j < 8; j++) {
            sacc[j][0] = __expf(sacc[j][0] - mn0);
            sacc[j][1] = __expf(sacc[j][1] - mn0);
            sacc[j][2] = __expf(sacc[j][2] - mn1);
            sacc[j][3] = __expf(sacc[j][3] - mn1);
            s0 += sacc[j][0] + sacc[j][1];
            s1 += sacc[j][2] + sacc[j][3];
        }
        s0 += __shfl_xor_sync(0xffffffffu, s0, 1);
        s0 += __shfl_xor_sync(0xffffffffu, s0, 2);
        s1 += __shfl_xor_sync(0xffffffffu, s1, 1);
        s1 += __shfl_xor_sync(0xffffffffu, s1, 2);
        l0 = l0*al0 + s0; l1 = l1*al1 + s1;
        m0 = mn0; m1 = mn1;
        #pragma unroll
        for (int j = 0; j < 8; j++) {
            oacc[j][0] *= al0; oacc[j][1] *= al0;
            oacc[j][2] *= al1; oacc[j][3] *= al1;
        }
        #pragma unroll
        for (int kt = 0; kt < 4; kt++) {
            uint32_t aP[4];
            aP[0] = packh2(sacc[2*kt][0],   sacc[2*kt][1]);
            aP[1] = packh2(sacc[2*kt][2],   sacc[2*kt][3]);
            aP[2] = packh2(sacc[2*kt+1][0], sacc[2*kt+1][1]);
            aP[3] = packh2(sacc[2*kt+1][2], sacc[2*kt+1][3]);
            #pragma unroll
            for (int np = 0; np < 4; np++) {
                uint32_t va = vb + (uint32_t)((kt*16 + (((lane >> 3) & 1) << 3) + (lane & 7)) * AQR)
                            + (2*np + (lane >> 4))*16;
                uint32_t Vh4[4], Vl4[4];
                LDSM4T(Vh4, va);
                LDSM4T(Vl4, va + 64*AQR);
                mma16816h(oacc[2*np],   aP, Vh4[0], Vh4[1]);
                mma16816h(oacc[2*np],   aP, Vl4[0], Vl4[1]);
                mma16816h(oacc[2*np+1], aP, Vh4[2], Vh4[3]);
                mma16816h(oacc[2*np+1], aP, Vl4[2], Vl4[3]);
            }
        }
        if (c + 2 < nkt) { KV_PREFETCH(c+2, (c+2) % 3); CPCOMMIT(); }
    }
#undef KV_PREFETCH

    float inv0 = 1.f / l0, inv1 = 1.f / l1;
    int qr0 = q0 + w*16 + gid;
    int qr1 = qr0 + 8;
    #pragma unroll
    for (int j = 0; j < 8; j++) {
        int col = h*64 + j*8 + 2*tig;
        if (qr0 < Mb)
            *(uint32_t*)&att_h[(rowbase + qr0)*CD + col] = packh2(oacc[j][0]*inv0, oacc[j][1]*inv0);
        if (qr1 < Mb)
            *(uint32_t*)&att_h[(rowbase + qr1)*CD + col] = packh2(oacc[j][2]*inv1, oacc[j][3]*inv1);
    }
}

// ---------------- output ----------------
__global__ void base_out(const float* __restrict__ fir, const float* __restrict__ fvis,
                         float* __restrict__ out)
{
    size_t i = (size_t)blockIdx.x*256 + threadIdx.x;
    out[i] = fir[i] + fvis[i];
}

__global__ void scatter_out(const float* __restrict__ x0, const float* __restrict__ x1,
                            const int* __restrict__ list, const float* __restrict__ maskf,
                            const int* __restrict__ cnt, float* __restrict__ out)
{
    int b = blockIdx.y, j = blockIdx.x;
    if (j >= cnt[b]) return;
    int idx = list[b*NT + j];
    float mv = maskf[b*NT + idx];
    int c = threadIdx.x;
    float v = (x0[((size_t)b*NT + j)*CD + c] + x1[((size_t)b*NT + j)*CD + c]) * mv;
    out[((size_t)b*CD + c)*NT + idx] = v;
}

// ---------------- host ----------------
extern "C" void kernel_launch(void* const* d_in, const int* in_sizes, int n_in,
                              void* d_out, int out_size)
{
    const float* f_ir  = (const float*)d_in[0];
    const float* f_vis = (const float*)d_in[1];
    const float* aw1   = (const float*)d_in[2];
    const float* ab1   = (const float*)d_in[3];
    const float* aw2   = (const float*)d_in[4];
    const float* ab2   = (const float*)d_in[5];
    const float* ir_lng  = (const float*)d_in[6];
    const float* ir_lnb  = (const float*)d_in[7];
    const float* ir_wqkv = (const float*)d_in[8];
    const float* ir_bqkv = (const float*)d_in[9];
    const float* ir_wo   = (const float*)d_in[10];
    const float* ir_bo   = (const float*)d_in[11];
    const float* ir_w1   = (const float*)d_in[12];
    const float* ir_b1   = (const float*)d_in[13];
    const float* ir_w2   = (const float*)d_in[14];
    const float* ir_b2   = (const float*)d_in[15];
    const float* vi_lng  = (const float*)d_in[16];
    const float* vi_lnb  = (const float*)d_in[17];
    const float* vi_wqkv = (const float*)d_in[18];
    const float* vi_bqkv = (const float*)d_in[19];
    const float* vi_wo   = (const float*)d_in[20];
    const float* vi_bo   = (const float*)d_in[21];
    const float* vi_w1   = (const float*)d_in[22];
    const float* vi_b1   = (const float*)d_in[23];
    const float* vi_w2   = (const float*)d_in[24];
    const float* vi_b2   = (const float*)d_in[25];
    float* out = (float*)d_out;

    float *xcat,*partp,*maskf,*x;
    __nv_bfloat16 *wag,*xcathl;
    __half *w16,*xnh,*atth,*hidh,*qkvhl;
    int *list,*cntp;
    cudaGetSymbolAddress((void**)&xcat,  g_xcat);
    cudaGetSymbolAddress((void**)&partp, g_part);
    cudaGetSymbolAddress((void**)&maskf, g_maskf);
    cudaGetSymbolAddress((void**)&x,     g_x);
    cudaGetSymbolAddress((void**)&wag,   g_w_ag);
    cudaGetSymbolAddress((void**)&xcathl,g_xcat_hl);
    cudaGetSymbolAddress((void**)&w16,   g_w16);
    cudaGetSymbolAddress((void**)&xnh,   g_xn_h);
    cudaGetSymbolAddress((void**)&atth,  g_att_h);
    cudaGetSymbolAddress((void**)&hidh,  g_hid_h);
    cudaGetSymbolAddress((void**)&qkvhl, g_qkv_hl);
    cudaGetSymbolAddress((void**)&list,  g_list);
    cudaGetSymbolAddress((void**)&cntp,  g_cnt);
    float* x0 = x;
    float* x1 = x + (size_t)BB*NT*CD;

    cudaFuncSetAttribute(attn_mma, cudaFuncAttributeMaxDynamicSharedMemorySize, ATTN_SMEM);
    cudaFuncSetAttribute(gemm_agent, cudaFuncAttributeMaxDynamicSharedMemorySize, AGEMM_SMEM);
    cudaFuncSetAttribute(gemm_f16, cudaFuncAttributeMaxDynamicSharedMemorySize, GEMM16_SMEM);

    // weight conversions
    conv_wag<<<64, 256>>>(aw1, wag, 262144);
    W8 ws;
    const float* wsrc[8] = {ir_wqkv, vi_wqkv, ir_wo, vi_wo, ir_w1, vi_w1, ir_w2, vi_w2};
    const int    wn[8]   = {196608, 196608, 65536, 65536, 262144, 262144, 262144, 262144};
    int start = 0;
    for (int i = 0; i < 8; i++) { ws.src[i] = wsrc[i]; ws.n[i] = wn[i]; ws.start[i] = start; start += 2*wn[i]; }
    conv_w16<<<dim3(64, 8), 256>>>(ws, w16);

    // 1. token-major concat (+bf16 hi/lo for agent)
    transpose_cat<<<dim3(NT/32, CD/32, BB*2), dim3(32,8)>>>(f_ir, f_vis, xcat, xcathl);
    // 2. agent GEMM (bf16 3-term, bit-identical logits)
    gemm_agent<<<dim3(AGH/128, NT/128, BB), 256, AGEMM_SMEM>>>(
        xcathl, XCAT_PLANE, wag, 262144, ab1, 512, aw2, partp);
    // 3. selection
    select_kernel<<<BB, 256>>>(partp, ab2, list, cntp, maskf);
    // 4. fused gather + first LN (fp16 out)
    gather_ln<<<dim3(NT, BB), 256>>>(xcat, list, cntp, x, xnh,
                                     ir_lng, ir_lnb, vi_lng, vi_lnb);

    // 5. both mixers (fp16 2-term)
    gemm_f16<<<dim3(768/128, NT/128, 2*BB), 256, GEMM16_SMEM>>>(
        xnh, w16 + 0, w16 + 393216, 196608,
        ir_bqkv, vi_bqkv, (float*)0, qkvhl, QKV_PLANE, (const float*)0, cntp, 256, 768, 0);
    attn_mma<<<dim3(NT/128, NH, 2*BB), 256, ATTN_SMEM>>>(qkvhl, atth, cntp);
    gemm_f16<<<dim3(CD/128, NT/128, 2*BB), 256, GEMM16_SMEM>>>(
        atth, w16 + 786432, w16 + 917504, 65536,
        ir_bo, vi_bo, x, (__half*)0, 0, x, cntp, 256, CD, 0);
    ln2<<<dim3(NT, 2*BB), 256>>>(x, xnh, ir_lng, ir_lnb, vi_lng, vi_lnb, cntp);
    gemm_f16<<<dim3(1024/128, NT/128, 2*BB), 256, GEMM16_SMEM>>>(
        xnh, w16 + 1048576, w16 + 1572864, 262144,
        ir_b1, vi_b1, (float*)0, hidh, 0, (const float*)0, cntp, 256, 1024, 2);
    gemm_f16<<<dim3(CD/128, NT/128, 2*BB), 256, GEMM16_SMEM>>>(
        hidh, w16 + 2097152, w16 + 2621440, 262144,
        ir_b2, vi_b2, x, (__half*)0, 0, x, cntp, 1024, CD, 0);

    // 6. output
    base_out<<<(BB*CD*NT)/256, 256>>>(f_ir, f_vis, out);
    scatter_out<<<dim3(NT, BB), 256>>>(x0, x1, list, maskf, cntp, out);
}

// round 11
// speedup vs baseline: 5.1218x; 1.0783x over previous
#include <cuda_runtime.h>
#include <cuda_bf16.h>
#include <cuda_fp16.h>
#include <math.h>
#include <stdint.h>

#define BB   4
#define NT   2304      // 48*48 tokens
#define CD   256       // DIM
#define AGH  512       // agent hidden
#define NH   4
#define DH   64

// plane sizes (elements)
#define XCAT_PLANE ((size_t)BB*NT*512)
#define XN_PLANE   ((size_t)2*BB*NT*CD)
#define ATT_PLANE  ((size_t)2*BB*NT*CD)
#define HID_PLANE  ((size_t)2*BB*NT*1024)
#define QKV_PLANE  ((size_t)2*BB*NT*768)

// ---------------- HMMA m16n8k16 (bf16 + fp16 variants) ----------------
__device__ __forceinline__ void mma16816(float* c, const uint32_t* a, uint32_t b0, uint32_t b1) {
    asm volatile("mma.sync.aligned.m16n8k16.row.col.f32.bf16.bf16.f32 "
        "{%0,%1,%2,%3}, {%4,%5,%6,%7}, {%8,%9}, {%0,%1,%2,%3};"
        : "+f"(c[0]), "+f"(c[1]), "+f"(c[2]), "+f"(c[3])
        : "r"(a[0]), "r"(a[1]), "r"(a[2]), "r"(a[3]), "r"(b0), "r"(b1));
}
__device__ __forceinline__ void mma16816h(float* c, const uint32_t* a, uint32_t b0, uint32_t b1) {
    asm volatile("mma.sync.aligned.m16n8k16.row.col.f32.f16.f16.f32 "
        "{%0,%1,%2,%3}, {%4,%5,%6,%7}, {%8,%9}, {%0,%1,%2,%3};"
        : "+f"(c[0]), "+f"(c[1]), "+f"(c[2]), "+f"(c[3])
        : "r"(a[0]), "r"(a[1]), "r"(a[2]), "r"(a[3]), "r"(b0), "r"(b1));
}

__device__ __forceinline__ uint32_t smem_u32(const void* p) {
    uint32_t a;
    asm("{ .reg .u64 t; cvta.to.shared.u64 t, %1; cvt.u32.u64 %0, t; }" : "=r"(a) : "l"(p));
    return a;
}
#define CP16(dst, src) asm volatile("cp.async.cg.shared.global [%0], [%1], 16;" :: "r"(dst), "l"(src))
#define CP16P(dst, src, p) asm volatile("cp.async.cg.shared.global [%0], [%1], 16, %2;" :: "r"(dst), "l"(src), "r"((p)?16:0))
#define CPCOMMIT()     asm volatile("cp.async.commit_group;" ::: "memory")
#define CPWAIT(n)      asm volatile("cp.async.wait_group %0;" :: "n"(n) : "memory")
#define LDSM4(r, a) asm volatile("ldmatrix.sync.aligned.m8n8.x4.shared.b16 {%0,%1,%2,%3}, [%4];" \
    : "=r"((r)[0]), "=r"((r)[1]), "=r"((r)[2]), "=r"((r)[3]) : "r"(a))
#define LDSM4T(r, a) asm volatile("ldmatrix.sync.aligned.m8n8.x4.trans.shared.b16 {%0,%1,%2,%3}, [%4];" \
    : "=r"((r)[0]), "=r"((r)[1]), "=r"((r)[2]), "=r"((r)[3]) : "r"(a))

// bf16 helpers (agent path — bit-identical mask)
__device__ __forceinline__ void split_hl(float v, __nv_bfloat16& h, __nv_bfloat16& l) {
    h = __float2bfloat16_rn(v);
    l = __float2bfloat16_rn(v - __bfloat162float(h));
}
__device__ __forceinline__ void cvt_pack(float4 v, uint2& h, uint2& l) {
    __nv_bfloat16 h0,l0,h1,l1,h2,l2,h3,l3;
    split_hl(v.x,h0,l0); split_hl(v.y,h1,l1); split_hl(v.z,h2,l2); split_hl(v.w,h3,l3);
    h.x = ((uint32_t)__bfloat16_as_ushort(h1)<<16)|(uint32_t)__bfloat16_as_ushort(h0);
    h.y = ((uint32_t)__bfloat16_as_ushort(h3)<<16)|(uint32_t)__bfloat16_as_ushort(h2);
    l.x = ((uint32_t)__bfloat16_as_ushort(l1)<<16)|(uint32_t)__bfloat16_as_ushort(l0);
    l.y = ((uint32_t)__bfloat16_as_ushort(l3)<<16)|(uint32_t)__bfloat16_as_ushort(l2);
}
// fp16 helpers
__device__ __forceinline__ uint32_t packh2(float a, float b) {
    __half2 h2 = __floats2half2_rn(a, b);
    return *reinterpret_cast<uint32_t*>(&h2);
}
__device__ __forceinline__ void pack_hl2h(float a, float b, uint32_t& ph, uint32_t& pl) {
    __half ha = __float2half_rn(a), hb = __float2half_rn(b);
    float la = a - __half2float(ha), lb = b - __half2float(hb);
    ph = ((uint32_t)__half_as_ushort(hb)<<16)|(uint32_t)__half_as_ushort(ha);
    pl = ((uint32_t)__half_as_ushort(__float2half_rn(lb))<<16)
       | (uint32_t)__half_as_ushort(__float2half_rn(la));
}

// ---------------- scratch ----------------
__device__ float g_xcat[(size_t)BB*NT*512];
__device__ float g_part[(size_t)BB*NT*4];
__device__ float g_maskf [BB*NT];
__device__ int   g_list[BB*NT];
__device__ int   g_cnt [BB];
__device__ float g_x  [(size_t)2*BB*NT*CD];
__device__ __align__(16) __nv_bfloat16 g_w_ag [2*262144];
__device__ __align__(16) __nv_bfloat16 g_xcat_hl[2*XCAT_PLANE];
__device__ __align__(16) __half g_w16  [3145728];
__device__ __align__(16) __half g_xn_h [XN_PLANE];
__device__ __align__(16) __half g_att_h[ATT_PLANE];
__device__ __align__(16) __half g_hid_h[HID_PLANE];
__device__ __align__(16) __half g_qkv_hl[2*QKV_PLANE];

// ---------------- weight converts ----------------
__global__ void conv_wag(const float* __restrict__ src, __nv_bfloat16* __restrict__ dst, int n)
{
    __nv_bfloat16* dh = dst;
    __nv_bfloat16* dl = dst + n;
    int n4 = n >> 2;
    for (int i = blockIdx.x*256 + threadIdx.x; i < n4; i += gridDim.x*256) {
        float4 v = ((const float4*)src)[i];
        uint2 h, l; cvt_pack(v, h, l);
        *(uint2*)&dh[i*4] = h;
        *(uint2*)&dl[i*4] = l;
    }
}
struct W8 { const float* src[8]; int start[8]; int n[8]; };
__global__ void conv_w16(W8 a, __half* __restrict__ dst)
{
    int w = blockIdx.y;
    int n = a.n[w];
    const float4* s = (const float4*)a.src[w];
    __half* dh = dst + a.start[w];
    __half* dl = dh + n;
    int n4 = n >> 2;
    for (int i = blockIdx.x*256 + threadIdx.x; i < n4; i += gridDim.x*256) {
        float4 v = s[i];
        uint32_t h0,l0,h1,l1;
        pack_hl2h(v.x, v.y, h0, l0);
        pack_hl2h(v.z, v.w, h1, l1);
        *(uint2*)&dh[i*4] = make_uint2(h0, h1);
        *(uint2*)&dl[i*4] = make_uint2(l0, l1);
    }
}

// ---------------- transpose [B,C,N] -> token-major concat + bf16 hi/lo (agent) ----------------
__global__ void transpose_cat(const float* __restrict__ fir, const float* __restrict__ fvis,
                              float* __restrict__ xcat, __nv_bfloat16* __restrict__ xcat_hl)
{
    int src = blockIdx.z & 1;
    int b   = blockIdx.z >> 1;
    const float* f = src ? fvis : fir;
    __shared__ float tile[32][33];
    int n0 = blockIdx.x * 32, c0 = blockIdx.y * 32;
    int tx = threadIdx.x, ty = threadIdx.y;
    #pragma unroll
    for (int i = 0; i < 32; i += 8)
        tile[ty + i][tx] = f[((size_t)b*CD + c0 + ty + i)*NT + n0 + tx];
    __syncthreads();
    #pragma unroll
    for (int i = 0; i < 32; i += 8) {
        float v = tile[tx][ty + i];
        size_t idx = ((size_t)b*NT + n0 + ty + i)*512 + src*CD + c0 + tx;
        xcat[idx] = v;
        __nv_bfloat16 h, l; split_hl(v, h, l);
        xcat_hl[idx] = h;
        xcat_hl[XCAT_PLANE + idx] = l;
    }
}

#define RSB   80
#define MATB  (128*RSB)

__device__ __forceinline__ float actf(float t, int act) {
    if (act == 1) return t / (1.f + expf(-t));
    if (act == 2) return 0.5f*t*(1.f + erff(t*0.70710678118654752f));
    return t;
}

// ================= agent GEMM: bf16 3-term, 2-stage, 2 CTAs/SM =================
#define STAGEA (4*MATB)
#define AGEMM_SMEM (2*STAGEA)   // 81920
__global__ void __launch_bounds__(256, 2)
gemm_agent(const __nv_bfloat16* __restrict__ Ahl, size_t aplane,
           const __nv_bfloat16* __restrict__ Wh, size_t wplane,
           const float* __restrict__ bias, int K,
           const float* __restrict__ logit_w, float* __restrict__ part)
{
    int b = blockIdx.z;
    int m0 = blockIdx.y * 128;
    int o0 = blockIdx.x * 128;
    size_t rowbase = (size_t)b * NT;
    const __nv_bfloat16* Ah_g = Ahl + (rowbase + m0) * K;
    const __nv_bfloat16* Al_g = Ah_g + aplane;
    const __nv_bfloat16* Wh_g = Wh + (size_t)o0 * K;
    const __nv_bfloat16* Wl_g = Wh_g + wplane;

    extern __shared__ char smem[];
    uint32_t sbase = smem_u32(smem);
    int tid = threadIdx.x, lane = tid & 31, w = tid >> 5;
    int wm = w & 3, wn = w >> 2;
    int gid = lane >> 2, tig = lane & 3;

    float acc[2][8][4];
    #pragma unroll
    for (int mt=0; mt<2; mt++)
        #pragma unroll
        for (int nt=0; nt<8; nt++)
            #pragma unroll
            for (int q=0; q<4; q++) acc[mt][nt][q] = 0.f;

#define PREFA(cc, st) do { \
    uint32_t sb_ = sbase + (st)*STAGEA; \
    _Pragma("unroll") \
    for (int i_ = 0; i_ < 2; i_++) { \
        int f_ = tid + i_*256; int row_ = f_ >> 2; int jb_ = (f_ & 3) * 16; \
        size_t go_ = (size_t)row_*K + (size_t)(cc)*32; \
        uint32_t so_ = sb_ + (uint32_t)(row_*RSB + jb_); \
        CP16(so_, (const char*)(Ah_g + go_) + jb_); \
        CP16(so_ + MATB, (const char*)(Al_g + go_) + jb_); \
        CP16(so_ + 2*MATB, (const char*)(Wh_g + go_) + jb_); \
        CP16(so_ + 3*MATB, (const char*)(Wl_g + go_) + jb_); \
    } } while (0)

    int nchunk = K >> 5;
    PREFA(0, 0);
    CPCOMMIT();

    for (int c = 0; c < nchunk; c++) {
        if (c + 1 < nchunk) { PREFA(c+1, (c+1)&1); CPCOMMIT(); CPWAIT(1); }
        else { CPWAIT(0); }
        __syncthreads();
        uint32_t stg = sbase + (c & 1) * STAGEA;
        #pragma unroll
        for (int ks = 0; ks < 2; ks++) {
            uint32_t colb = (uint32_t)(ks*32 + ((lane >> 4) << 4));
            uint32_t Ahf[2][4], Alf[2][4];
            #pragma unroll
            for (int mt = 0; mt < 2; mt++) {
                uint32_t sa = stg + (uint32_t)((wm*32 + mt*16 + (lane & 15)) * RSB) + colb;
                LDSM4(Ahf[mt], sa);
                LDSM4(Alf[mt], sa + MATB);
            }
            #pragma unroll
            for (int np = 0; np < 4; np++) {
                uint32_t sb = stg + 2*MATB + (uint32_t)((wn*64 + np*16 + (lane & 15)) * RSB) + colb;
                uint32_t Bh[4], Bl[4];
                LDSM4(Bh, sb);
                LDSM4(Bl, sb + MATB);
                #pragma unroll
                for (int mt = 0; mt < 2; mt++) {
                    mma16816(acc[mt][2*np],   Ahf[mt], Bh[0], Bh[2]);
                    mma16816(acc[mt][2*np],   Ahf[mt], Bl[0], Bl[2]);
                    mma16816(acc[mt][2*np],   Alf[mt], Bh[0], Bh[2]);
                    mma16816(acc[mt][2*np+1], Ahf[mt], Bh[1], Bh[3]);
                    mma16816(acc[mt][2*np+1], Ahf[mt], Bl[1], Bl[3]);
                    mma16816(acc[mt][2*np+1], Alf[mt], Bh[1], Bh[3]);
                }
            }
        }
        __syncthreads();
    }
#undef PREFA

    // fused agent-logit partials (identical math/order to R8/R9)
    float pr[4] = {0.f, 0.f, 0.f, 0.f};
    #pragma unroll
    for (int mt = 0; mt < 2; mt++) {
        #pragma unroll
        for (int nt = 0; nt < 8; nt++) {
            int col = o0 + wn*64 + nt*8 + 2*tig;
            float b0v = bias[col], b1v = bias[col+1];
            float w0 = logit_w[col], w1 = logit_w[col+1];
            float t0 = actf(acc[mt][nt][0] + b0v, 1);
            float t1 = actf(acc[mt][nt][1] + b1v, 1);
            float t2 = actf(acc[mt][nt][2] + b0v, 1);
            float t3 = actf(acc[mt][nt][3] + b1v, 1);
            pr[mt*2+0] += t0*w0 + t1*w1;
            pr[mt*2+1] += t2*w0 + t3*w1;
        }
    }
    #pragma unroll
    for (int i = 0; i < 4; i++) {
        pr[i] += __shfl_xor_sync(0xffffffffu, pr[i], 1);
        pr[i] += __shfl_xor_sync(0xffffffffu, pr[i], 2);
    }
    __syncthreads();
    float* red = (float*)smem;
    if (tig == 0) {
        #pragma unroll
        for (int mt = 0; mt < 2; mt++) {
            red[wn*128 + wm*32 + mt*16 + gid]     = pr[mt*2+0];
            red[wn*128 + wm*32 + mt*16 + gid + 8] = pr[mt*2+1];
        }
    }
    __syncthreads();
    if (tid < 128)
        part[((size_t)b*NT + m0 + tid)*4 + blockIdx.x] = red[tid] + red[128 + tid];
}

// ================= fp16 2-term GEMM: 2-stage, 2 CTAs/SM =================
#define STAGE3 (3*MATB)
#define GEMM16_SMEM (2*STAGE3)   // 61440
__global__ void __launch_bounds__(256, 2)
gemm_f16(const __half* __restrict__ Aall,
         const __half* __restrict__ Wah, const __half* __restrict__ Wbh, size_t wplane,
         const float* __restrict__ ba, const float* __restrict__ bbv,
         float* __restrict__ Cf, __half* __restrict__ Ch, size_t cplane,
         const float* __restrict__ R,
         const int* __restrict__ counts, int K, int Ocols, int act)
{
    int bz = blockIdx.z;
    int s = (bz >= BB) ? 1 : 0;
    int b = bz & 3;
    int Mb = counts[b];
    int m0 = blockIdx.y * 128;
    if (m0 >= Mb) return;
    int o0 = blockIdx.x * 128;
    const __half* Wsel = s ? Wbh : Wah;
    const float* bias = s ? bbv : ba;
    size_t rowbase = (size_t)(s*BB + b) * NT;
    const __half* Ah_g = Aall + (rowbase + m0) * K;
    const __half* Wh_g = Wsel + (size_t)o0 * K;
    const __half* Wl_g = Wh_g + wplane;
    float* Cfb = Cf ? Cf + rowbase * Ocols : (float*)0;
    __half* Chb = Ch ? Ch + rowbase * Ocols : (__half*)0;
    const float* Rb = R ? R + rowbase * Ocols : (const float*)0;

    extern __shared__ char smem[];
    uint32_t sbase = smem_u32(smem);
    int tid = threadIdx.x, lane = tid & 31, w = tid >> 5;
    int wm = w & 3, wn = w >> 2;
    int gid = lane >> 2, tig = lane & 3;

    float acc[2][8][4];
    #pragma unroll
    for (int mt=0; mt<2; mt++)
        #pragma unroll
        for (int nt=0; nt<8; nt++)
            #pragma unroll
            for (int q=0; q<4; q++) acc[mt][nt][q] = 0.f;

#define PREF16(cc, st) do { \
    uint32_t sb_ = sbase + (st)*STAGE3; \
    _Pragma("unroll") \
    for (int i_ = 0; i_ < 6; i_++) { \
        int f_ = tid + i_*256; int mat_ = f_ >> 9; int rem_ = f_ & 511; \
        int row_ = rem_ >> 2; int jb_ = (rem_ & 3) * 16; \
        size_t go_ = (size_t)row_*K + (size_t)(cc)*32; \
        const char* p_ = (mat_ == 0) ? (const char*)(Ah_g + go_) \
                       : (mat_ == 1) ? (const char*)(Wh_g + go_) \
                                     : (const char*)(Wl_g + go_); \
        CP16(sb_ + (uint32_t)(mat_*MATB + row_*RSB + jb_), p_ + jb_); \
    } } while (0)

    int nchunk = K >> 5;
    PREF16(0, 0);
    CPCOMMIT();

    for (int c = 0; c < nchunk; c++) {
        if (c + 1 < nchunk) { PREF16(c+1, (c+1)&1); CPCOMMIT(); CPWAIT(1); }
        else { CPWAIT(0); }
        __syncthreads();
        uint32_t stg = sbase + (c & 1) * STAGE3;
        #pragma unroll
        for (int ks = 0; ks < 2; ks++) {
            uint32_t colb = (uint32_t)(ks*32 + ((lane >> 4) << 4));
            uint32_t Ahf[2][4];
            #pragma unroll
            for (int mt = 0; mt < 2; mt++) {
                uint32_t sa = stg + (uint32_t)((wm*32 + mt*16 + (lane & 15)) * RSB) + colb;
                LDSM4(Ahf[mt], sa);
            }
            #pragma unroll
            for (int np = 0; np < 4; np++) {
                uint32_t sb = stg + MATB + (uint32_t)((wn*64 + np*16 + (lane & 15)) * RSB) + colb;
                uint32_t Bh[4], Bl[4];
                LDSM4(Bh, sb);
                LDSM4(Bl, sb + MATB);
                #pragma unroll
                for (int mt = 0; mt < 2; mt++) {
                    mma16816h(acc[mt][2*np],   Ahf[mt], Bh[0], Bh[2]);
                    mma16816h(acc[mt][2*np],   Ahf[mt], Bl[0], Bl[2]);
                    mma16816h(acc[mt][2*np+1], Ahf[mt], Bh[1], Bh[3]);
                    mma16816h(acc[mt][2*np+1], Ahf[mt], Bl[1], Bl[3]);
                }
            }
        }
        __syncthreads();
    }
#undef PREF16

    #pragma unroll
    for (int mt = 0; mt < 2; mt++) {
        int r0 = m0 + wm*32 + mt*16 + gid;
        int r1 = r0 + 8;
        #pragma unroll
        for (int nt = 0; nt < 8; nt++) {
            int col = o0 + wn*64 + nt*8 + 2*tig;
            float b0v = bias[col], b1v = bias[col+1];
            float t0 = actf(acc[mt][nt][0] + b0v, act);
            float t1 = actf(acc[mt][nt][1] + b1v, act);
            float t2 = actf(acc[mt][nt][2] + b0v, act);
            float t3 = actf(acc[mt][nt][3] + b1v, act);
            if (Cfb) {
                if (r0 < Mb) {
                    if (Rb) { t0 += Rb[(size_t)r0*Ocols + col]; t1 += Rb[(size_t)r0*Ocols + col + 1]; }
                    *(float2*)&Cfb[(size_t)r0*Ocols + col] = make_float2(t0, t1);
                }
                if (r1 < Mb) {
                    if (Rb) { t2 += Rb[(size_t)r1*Ocols + col]; t3 += Rb[(size_t)r1*Ocols + col + 1]; }
                    *(float2*)&Cfb[(size_t)r1*Ocols + col] = make_float2(t2, t3);
                }
            } else if (cplane) {
                if (r0 < Mb) {
                    uint32_t ph, pl; pack_hl2h(t0, t1, ph, pl);
                    *(uint32_t*)&Chb[(size_t)r0*Ocols + col] = ph;
                    *(uint32_t*)&Chb[cplane + (size_t)r0*Ocols + col] = pl;
                }
                if (r1 < Mb) {
                    uint32_t ph, pl; pack_hl2h(t2, t3, ph, pl);
                    *(uint32_t*)&Chb[(size_t)r1*Ocols + col] = ph;
                    *(uint32_t*)&Chb[cplane + (size_t)r1*Ocols + col] = pl;
                }
            } else {
                if (r0 < Mb) *(uint32_t*)&Chb[(size_t)r0*Ocols + col] = packh2(t0, t1);
                if (r1 < Mb) *(uint32_t*)&Chb[(size_t)r1*Ocols + col] = packh2(t2, t3);
            }
        }
    }
}

// ---------------- selection (logits from partials) ----------------
__global__ void select_kernel(const float* __restrict__ part, const float* __restrict__ ab2,
                              int* __restrict__ list, int* __restrict__ cnt,
                              float* __restrict__ maskf)
{
    int b = blockIdx.x, tid = threadIdx.x;
    const int PER = NT/256;  // 9
    __shared__ int cn[256];
    float ab2v = ab2[0];
    int base = tid*PER;
    float lv[PER];
    bool  sv[PER];
    int c = 0;
    #pragma unroll
    for (int i = 0; i < PER; i++) {
        size_t t4 = ((size_t)b*NT + base + i)*4;
        float lg = ((part[t4] + part[t4+1]) + (part[t4+2] + part[t4+3])) + ab2v;
        lv[i] = lg;
        bool sel = lg > 0.f; sv[i] = sel; c += sel;
        maskf[b*NT + base + i] = sel ? 1.f : 0.f;
    }
    cn[tid] = c; __syncthreads();
    for (int off = 1; off < 256; off <<= 1) {
        int v = (tid >= off) ? cn[tid-off] : 0;
        __syncthreads();
        cn[tid] += v;
        __syncthreads();
    }
    int total = cn[255];
    int pos = cn[tid] - c;
    if (total >= 64) {
        #pragma unroll
        for (int i = 0; i < PER; i++)
            if (sv[i]) { list[b*NT + pos] = base + i; pos++; }
        if (tid == 0) cnt[b] = total;
    } else {
        __shared__ float sl[NT];
        #pragma unroll
        for (int i = 0; i < PER; i++) sl[base+i] = lv[i];
        __syncthreads();
        if (tid == 0) {
            for (int t = 0; t < 64; t++) {
                int am = 0; float mv = sl[0];
                for (int n = 1; n < NT; n++) if (sl[n] > mv) { mv = sl[n]; am = n; }
                list[b*NT + t] = am; sl[am] = -1e30f;
            }
            cnt[b] = 64;
        }
    }
}

// ---------------- fused gather + LayerNorm (both streams) -> fp16 ----------------
__global__ void gather_ln(const float* __restrict__ xcat, const int* __restrict__ list,
                          const int* __restrict__ cnt,
                          float* __restrict__ x, __half* __restrict__ Yh,
                          const float* __restrict__ ga, const float* __restrict__ bba,
                          const float* __restrict__ gb2, const float* __restrict__ bbb)
{
    int b = blockIdx.y, j = blockIdx.x;
    if (j >= cnt[b]) return;
    int idx = list[b*NT + j];
    int tid = threadIdx.x;
    const float* src = xcat + ((size_t)b*NT + idx)*512;
    __shared__ float red[8];
    #pragma unroll
    for (int s = 0; s < 2; s++) {
        const float* gw = s ? gb2 : ga;
        const float* gb = s ? bbb : bba;
        float v = src[s*CD + tid];
        size_t row = ((size_t)(s*BB + b)*NT + j)*CD;
        x[row + tid] = v;
        float ssum = v;
        #pragma unroll
        for (int o = 16; o; o >>= 1) ssum += __shfl_down_sync(0xffffffffu, ssum, o);
        if ((tid & 31) == 0) red[tid>>5] = ssum;
        __syncthreads();
        float mean = 0.f;
        #pragma unroll
        for (int i = 0; i < 8; i++) mean += red[i];
        mean *= (1.f/CD);
        __syncthreads();
        float d = v - mean;
        ssum = d*d;
        #pragma unroll
        for (int o = 16; o; o >>= 1) ssum += __shfl_down_sync(0xffffffffu, ssum, o);
        if ((tid & 31) == 0) red[tid>>5] = ssum;
        __syncthreads();
        float var = 0.f;
        #pragma unroll
        for (int i = 0; i < 8; i++) var += red[i];
        var *= (1.f/CD);
        Yh[row + tid] = __float2half_rn(d * rsqrtf(var + 1e-5f) * gw[tid] + gb[tid]);
        __syncthreads();
    }
}

// ---------------- LayerNorm (dual-stream) -> fp16 ----------------
__global__ void ln2(const float* __restrict__ X, __half* __restrict__ Yh,
                    const float* __restrict__ ga, const float* __restrict__ bba,
                    const float* __restrict__ gb2, const float* __restrict__ bbb,
                    const int* __restrict__ cnt)
{
    int bz = blockIdx.y; int s = bz >> 2, b = bz & 3;
    int n = blockIdx.x;
    if (n >= cnt[b]) return;
    const float* gw = s ? gb2 : ga;
    const float* gb = s ? bbb : bba;
    int tid = threadIdx.x;
    size_t row = ((size_t)(s*BB+b)*NT + n)*CD;
    float v = X[row + tid];
    __shared__ float red[8];
    float ssum = v;
    #pragma unroll
    for (int o = 16; o; o >>= 1) ssum += __shfl_down_sync(0xffffffffu, ssum, o);
    if ((tid & 31) == 0) red[tid>>5] = ssum;
    __syncthreads();
    float mean = 0.f;
    #pragma unroll
    for (int i = 0; i < 8; i++) mean += red[i];
    mean *= (1.f/CD);
    __syncthreads();
    float d = v - mean;
    ssum = d*d;
    #pragma unroll
    for (int o = 16; o; o >>= 1) ssum += __shfl_down_sync(0xffffffffu, ssum, o);
    if ((tid & 31) == 0) red[tid>>5] = ssum;
    __syncthreads();
    float var = 0.f;
    #pragma unroll
    for (int i = 0; i < 8; i++) var += red[i];
    var *= (1.f/CD);
    Yh[row + tid] = __float2half_rn(d * rsqrtf(var + 1e-5f) * gw[tid] + gb[tid]);
}

// ================= flash attention fp16 (Q/P hi, K hi+lo, V hi only), 2-stage, 2 CTAs/SM =======
#define AQR 144
#define AT_KVOFF (128*AQR)              // Q hi plane only
#define AT_STG (3*64*AQR)               // Kh,Kl,Vh
#define ATTN_SMEM (AT_KVOFF + 2*AT_STG) // 73728

__global__ void __launch_bounds__(256, 2)
attn_mma(const __half* __restrict__ qkvhl, __half* __restrict__ att_h,
         const int* __restrict__ cnt)
{
    extern __shared__ char smc[];
    uint32_t sb = smem_u32(smc);
    int bz = blockIdx.z; int s = bz >> 2, b = bz & 3;
    int h = blockIdx.y, q0 = blockIdx.x*128;
    int Mb = cnt[b];
    if (q0 >= Mb) return;
    int tid = threadIdx.x, lane = tid & 31, w = tid >> 5;
    int gid = lane >> 2, tig = lane & 3;
    size_t rowbase = (size_t)(s*BB + b) * NT;
    const __half* qg = qkvhl;

    // Q hi prefetch
    {
        #pragma unroll
        for (int i = 0; i < 4; i++) {
            int f = tid + i*256;
            int row = f >> 3, c16 = f & 7;
            const char* src = (const char*)(qg + (rowbase + q0 + row)*768 + h*64) + c16*16;
            CP16P(sb + row*AQR + c16*16, src, (q0 + row) < Mb);
        }
    }
#define KV_PREFETCH(kt, st) do { \
    int k0_ = (kt)*64; \
    _Pragma("unroll") \
    for (int i_ = 0; i_ < 6; i_++) { \
        int f_ = tid + i_*256; \
        int pl_ = f_ >> 9, rem_ = f_ & 511; \
        int row_ = rem_ >> 3, c16_ = rem_ & 7; \
        int ko_ = (pl_ < 2) ? 256 : 512; \
        size_t hp_ = (pl_ == 1) ? QKV_PLANE : 0; \
        const char* src_ = (const char*)(qg + (rowbase + k0_ + row_)*768 + ko_ + h*64 + hp_) + c16_*16; \
        uint32_t dst_ = sb + AT_KVOFF + (st)*AT_STG + pl_*(64*AQR) + row_*AQR + c16_*16; \
        CP16P(dst_, src_, (k0_ + row_) < Mb); \
    } } while (0)

    int nkt = (Mb + 63) >> 6;
    KV_PREFETCH(0, 0);
    CPCOMMIT();

    uint32_t Qh[4][4];
    float oacc[8][4];
    #pragma unroll
    for (int j=0;j<8;j++)
        #pragma unroll
        for (int q=0;q<4;q++) oacc[j][q] = 0.f;
    float m0 = -1e30f, m1 = -1e30f, l0 = 0.f, l1 = 0.f;
    bool qload = false;

    for (int c = 0; c < nkt; c++) {
        if (c + 1 < nkt) { KV_PREFETCH(c+1, (c+1)&1); CPCOMMIT(); CPWAIT(1); }
        else { CPWAIT(0); }
        __syncthreads();
        if (!qload) {
            qload = true;
            #pragma unroll
            for (int ks = 0; ks < 4; ks++) {
                uint32_t qa = sb + (uint32_t)((w*16 + (lane & 15)) * AQR) + ks*32 + ((lane >> 4) << 4);
                LDSM4(Qh[ks], qa);
            }
        }
        uint32_t kb = sb + AT_KVOFF + (c & 1)*AT_STG;
        uint32_t vb = kb + 2*(64*AQR);

        float sacc[8][4];
        #pragma unroll
        for (int j=0;j<8;j++)
            #pragma unroll
            for (int q=0;q<4;q++) sacc[j][q] = 0.f;
        #pragma unroll
        for (int ks = 0; ks < 4; ks++) {
            #pragma unroll
            for (int np = 0; np < 4; np++) {
                uint32_t ka = kb + (uint32_t)((np*16 + ((lane >> 4) << 3) + (lane & 7)) * AQR)
                            + ks*32 + (((lane >> 3) & 1) << 4);
                uint32_t Kh4[4], Kl4[4];
                LDSM4(Kh4, ka);
                LDSM4(Kl4, ka + 64*AQR);
                mma16816h(sacc[2*np],   Qh[ks], Kh4[0], Kh4[1]);
                mma16816h(sacc[2*np],   Qh[ks], Kl4[0], Kl4[1]);
                mma16816h(sacc[2*np+1], Qh[ks], Kh4[2], Kh4[3]);
                mma16816h(sacc[2*np+1], Qh[ks], Kl4[2], Kl4[3]);
            }
        }
        int kvb = c*64;
        #pragma unroll
        for (int j = 0; j < 8; j++) {
            int t0 = kvb + j*8 + 2*tig;
            bool v0 = t0 < Mb, v1 = (t0 + 1) < Mb;
            sacc[j][0] = v0 ? sacc[j][0]*0.125f : -1e30f;
            sacc[j][1] = v1 ? sacc[j][1]*0.125f : -1e30f;
            sacc[j][2] = v0 ? sacc[j][2]*0.125f : -1e30f;
            sacc[j][3] = v1 ? sacc[j][3]*0.125f : -1e30f;
        }
        float mx0 = -1e30f, mx1 = -1e30f;
        #pragma unroll
        for (int j = 0; j < 8; j++) {
            mx0 = fmaxf(mx0, fmaxf(sacc[j][0], sacc[j][1]));
            mx1 = fmaxf(mx1, fmaxf(sacc[j][2], sacc[j][3]));
        }
        mx0 = fmaxf(mx0, __shfl_xor_sync(0xffffffffu, mx0, 1));
        mx0 = fmaxf(mx0, __shfl_xor_sync(0xffffffffu, mx0, 2));
        mx1 = fmaxf(mx1, __shfl_xor_sync(0xffffffffu, mx1, 1));
        mx1 = fmaxf(mx1, __shfl_xor_sync(0xffffffffu, mx1, 2));
        float mn0 = fmaxf(m0, mx0), mn1 = fmaxf(m1, mx1);
        float al0 = __expf(m0 - mn0), al1 = __expf(m1 - mn1);
        float s0 = 0.f, s1 = 0.f;
        #pragma unroll
        for (int j = 0; j < 8; j++) {
            sacc[j][0] = __expf(sacc[j][0] - mn0);
            sacc[j][1] = __expf(sacc[j][1] - mn0);
            sacc[j][2] = __expf(sacc[j][2] - mn1);
            sacc[j][3] = __expf(sacc[j][3] - mn1);
            s0 += sacc[j][0] + sacc[j][1];
            s1 += sacc[j][2] + sacc[j][3];
        }
        s0 += __shfl_xor_sync(0xffffffffu, s0, 1);
        s0 += __shfl_xor_sync(0xffffffffu, s0, 2);
        s1 += __shfl_xor_sync(0xffffffffu, s1, 1);
        s1 += __shfl_xor_sync(0xffffffffu, s1, 2);
        l0 = l0*al0 + s0; l1 = l1*al1 + s1;
        m0 = mn0; m1 = mn1;
        #pragma unroll
        for (int j = 0; j < 8; j++) {
            oacc[j][0] *= al0; oacc[j][1] *= al0;
            oacc[j][2] *= al1; oacc[j][3] *= al1;
        }
        #pragma unroll
        for (int kt = 0; kt < 4; kt++) {
            uint32_t aP[4];
            aP[0] = packh2(sacc[2*kt][0],   sacc[2*kt][1]);
            aP[1] = packh2(sacc[2*kt][2],   sacc[2*kt][3]);
            aP[2] = packh2(sacc[2*kt+1][0], sacc[2*kt+1][1]);
            aP[3] = packh2(sacc[2*kt+1][2], sacc[2*kt+1][3]);
            #pragma unroll
            for (int np = 0; np < 4; np++) {
                uint32_t va = vb + (uint32_t)((kt*16 + (((lane >> 3) & 1) << 3) + (lane & 7)) * AQR)
                            + (2*np + (lane >> 4))*16;
                uint32_t Vh4[4];
                LDSM4T(Vh4, va);
                mma16816h(oacc[2*np],   aP, Vh4[0], Vh4[1]);
                mma16816h(oacc[2*np+1], aP, Vh4[2], Vh4[3]);
            }
        }
        __syncthreads();
    }
#undef KV_PREFETCH

    float inv0 = 1.f / l0, inv1 = 1.f / l1;
    int qr0 = q0 + w*16 + gid;
    int qr1 = qr0 + 8;
    #pragma unroll
    for (int j = 0; j < 8; j++) {
        int col = h*64 + j*8 + 2*tig;
        if (qr0 < Mb)
            *(uint32_t*)&att_h[(rowbase + qr0)*CD + col] = packh2(oacc[j][0]*inv0, oacc[j][1]*inv0);
        if (qr1 < Mb)
            *(uint32_t*)&att_h[(rowbase + qr1)*CD + col] = packh2(oacc[j][2]*inv1, oacc[j][3]*inv1);
    }
}

// ---------------- output ----------------
__global__ void base_out(const float* __restrict__ fir, const float* __restrict__ fvis,
                         float* __restrict__ out)
{
    size_t i = (size_t)blockIdx.x*256 + threadIdx.x;
    float4 a = ((const float4*)fir)[i];
    float4 b = ((const float4*)fvis)[i];
    ((float4*)out)[i] = make_float4(a.x+b.x, a.y+b.y, a.z+b.z, a.w+b.w);
}

__global__ void scatter_out(const float* __restrict__ x0, const float* __restrict__ x1,
                            const int* __restrict__ list, const float* __restrict__ maskf,
                            const int* __restrict__ cnt, float* __restrict__ out)
{
    int b = blockIdx.y, j = blockIdx.x;
    if (j >= cnt[b]) return;
    int idx = list[b*NT + j];
    float mv = maskf[b*NT + idx];
    int c = threadIdx.x;
    float v = (x0[((size_t)b*NT + j)*CD + c] + x1[((size_t)b*NT + j)*CD + c]) * mv;
    out[((size_t)b*CD + c)*NT + idx] = v;
}

// ---------------- host ----------------
extern "C" void kernel_launch(void* const* d_in, const int* in_sizes, int n_in,
                              void* d_out, int out_size)
{
    const float* f_ir  = (const float*)d_in[0];
    const float* f_vis = (const float*)d_in[1];
    const float* aw1   = (const float*)d_in[2];
    const float* ab1   = (const float*)d_in[3];
    const float* aw2   = (const float*)d_in[4];
    const float* ab2   = (const float*)d_in[5];
    const float* ir_lng  = (const float*)d_in[6];
    const float* ir_lnb  = (const float*)d_in[7];
    const float* ir_wqkv = (const float*)d_in[8];
    const float* ir_bqkv = (const float*)d_in[9];
    const float* ir_wo   = (const float*)d_in[10];
    const float* ir_bo   = (const float*)d_in[11];
    const float* ir_w1   = (const float*)d_in[12];
    const float* ir_b1   = (const float*)d_in[13];
    const float* ir_w2   = (const float*)d_in[14];
    const float* ir_b2   = (const float*)d_in[15];
    const float* vi_lng  = (const float*)d_in[16];
    const float* vi_lnb  = (const float*)d_in[17];
    const float* vi_wqkv = (const float*)d_in[18];
    const float* vi_bqkv = (const float*)d_in[19];
    const float* vi_wo   = (const float*)d_in[20];
    const float* vi_bo   = (const float*)d_in[21];
    const float* vi_w1   = (const float*)d_in[22];
    const float* vi_b1   = (const float*)d_in[23];
    const float* vi_w2   = (const float*)d_in[24];
    const float* vi_b2   = (const float*)d_in[25];
    float* out = (float*)d_out;

    float *xcat,*partp,*maskf,*x;
    __nv_bfloat16 *wag,*xcathl;
    __half *w16,*xnh,*atth,*hidh,*qkvhl;
    int *list,*cntp;
    cudaGetSymbolAddress((void**)&xcat,  g_xcat);
    cudaGetSymbolAddress((void**)&partp, g_part);
    cudaGetSymbolAddress((void**)&maskf, g_maskf);
    cudaGetSymbolAddress((void**)&x,     g_x);
    cudaGetSymbolAddress((void**)&wag,   g_w_ag);
    cudaGetSymbolAddress((void**)&xcathl,g_xcat_hl);
    cudaGetSymbolAddress((void**)&w16,   g_w16);
    cudaGetSymbolAddress((void**)&xnh,   g_xn_h);
    cudaGetSymbolAddress((void**)&atth,  g_att_h);
    cudaGetSymbolAddress((void**)&hidh,  g_hid_h);
    cudaGetSymbolAddress((void**)&qkvhl, g_qkv_hl);
    cudaGetSymbolAddress((void**)&list,  g_list);
    cudaGetSymbolAddress((void**)&cntp,  g_cnt);
    float* x0 = x;
    float* x1 = x + (size_t)BB*NT*CD;

    cudaFuncSetAttribute(attn_mma, cudaFuncAttributeMaxDynamicSharedMemorySize, ATTN_SMEM);
    cudaFuncSetAttribute(gemm_agent, cudaFuncAttributeMaxDynamicSharedMemorySize, AGEMM_SMEM);
    cudaFuncSetAttribute(gemm_f16, cudaFuncAttributeMaxDynamicSharedMemorySize, GEMM16_SMEM);

    // weight conversions
    conv_wag<<<64, 256>>>(aw1, wag, 262144);
    W8 ws;
    const float* wsrc[8] = {ir_wqkv, vi_wqkv, ir_wo, vi_wo, ir_w1, vi_w1, ir_w2, vi_w2};
    const int    wn[8]   = {196608, 196608, 65536, 65536, 262144, 262144, 262144, 262144};
    int start = 0;
    for (int i = 0; i < 8; i++) { ws.src[i] = wsrc[i]; ws.n[i] = wn[i]; ws.start[i] = start; start += 2*wn[i]; }
    conv_w16<<<dim3(64, 8), 256>>>(ws, w16);

    // 1. token-major concat (+bf16 hi/lo for agent)
    transpose_cat<<<dim3(NT/32, CD/32, BB*2), dim3(32,8)>>>(f_ir, f_vis, xcat, xcathl);
    // 2. agent GEMM (bf16 3-term, bit-identical logits)
    gemm_agent<<<dim3(AGH/128, NT/128, BB), 256, AGEMM_SMEM>>>(
        xcathl, XCAT_PLANE, wag, 262144, ab1, 512, aw2, partp);
    // 3. selection
    select_kernel<<<BB, 256>>>(partp, ab2, list, cntp, maskf);
    // 4. fused gather + first LN (fp16 out)
    gather_ln<<<dim3(NT, BB), 256>>>(xcat, list, cntp, x, xnh,
                                     ir_lng, ir_lnb, vi_lng, vi_lnb);

    // 5. both mixers (fp16 2-term)
    gemm_f16<<<dim3(768/128, NT/128, 2*BB), 256, GEMM16_SMEM>>>(
        xnh, w16 + 0, w16 + 393216, 196608,
        ir_bqkv, vi_bqkv, (float*)0, qkvhl, QKV_PLANE, (const float*)0, cntp, 256, 768, 0);
    attn_mma<<<dim3(NT/128, NH, 2*BB), 256, ATTN_SMEM>>>(qkvhl, atth, cntp);
    gemm_f16<<<dim3(CD/128, NT/128, 2*BB), 256, GEMM16_SMEM>>>(
        atth, w16 + 786432, w16 + 917504, 65536,
        ir_bo, vi_bo, x, (__half*)0, 0, x, cntp, 256, CD, 0);
    ln2<<<dim3(NT, 2*BB), 256>>>(x, xnh, ir_lng, ir_lnb, vi_lng, vi_lnb, cntp);
    gemm_f16<<<dim3(1024/128, NT/128, 2*BB), 256, GEMM16_SMEM>>>(
        xnh, w16 + 1048576, w16 + 1572864, 262144,
        ir_b1, vi_b1, (float*)0, hidh, 0, (const float*)0, cntp, 256, 1024, 2);
    gemm_f16<<<dim3(CD/128, NT/128, 2*BB), 256, GEMM16_SMEM>>>(
        hidh, w16 + 2097152, w16 + 2621440, 262144,
        ir_b2, vi_b2, x, (__half*)0, 0, x, cntp, 1024, CD, 0);

    // 6. output
    base_out<<<(BB*CD*NT)/1024, 256>>>(f_ir, f_vis, out);
    scatter_out<<<dim3(NT, BB), 256>>>(x0, x1, list, maskf, cntp, out);
}

// round 12
// speedup vs baseline: 5.1602x; 1.0075x over previous
#include <cuda_runtime.h>
#include <cuda_bf16.h>
#include <cuda_fp16.h>
#include <math.h>
#include <stdint.h>

#define BB   4
#define NT   2304      // 48*48 tokens
#define CD   256       // DIM
#define AGH  512       // agent hidden
#define NH   4
#define DH   64

// plane sizes (elements)
#define XCAT_PLANE ((size_t)BB*NT*512)
#define XN_PLANE   ((size_t)2*BB*NT*CD)
#define ATT_PLANE  ((size_t)2*BB*NT*CD)
#define HID_PLANE  ((size_t)2*BB*NT*1024)
#define QKV_PLANE  ((size_t)2*BB*NT*768)

// ---------------- HMMA m16n8k16 (bf16 + fp16 variants) ----------------
__device__ __forceinline__ void mma16816(float* c, const uint32_t* a, uint32_t b0, uint32_t b1) {
    asm volatile("mma.sync.aligned.m16n8k16.row.col.f32.bf16.bf16.f32 "
        "{%0,%1,%2,%3}, {%4,%5,%6,%7}, {%8,%9}, {%0,%1,%2,%3};"
        : "+f"(c[0]), "+f"(c[1]), "+f"(c[2]), "+f"(c[3])
        : "r"(a[0]), "r"(a[1]), "r"(a[2]), "r"(a[3]), "r"(b0), "r"(b1));
}
__device__ __forceinline__ void mma16816h(float* c, const uint32_t* a, uint32_t b0, uint32_t b1) {
    asm volatile("mma.sync.aligned.m16n8k16.row.col.f32.f16.f16.f32 "
        "{%0,%1,%2,%3}, {%4,%5,%6,%7}, {%8,%9}, {%0,%1,%2,%3};"
        : "+f"(c[0]), "+f"(c[1]), "+f"(c[2]), "+f"(c[3])
        : "r"(a[0]), "r"(a[1]), "r"(a[2]), "r"(a[3]), "r"(b0), "r"(b1));
}

__device__ __forceinline__ uint32_t smem_u32(const void* p) {
    uint32_t a;
    asm("{ .reg .u64 t; cvta.to.shared.u64 t, %1; cvt.u32.u64 %0, t; }" : "=r"(a) : "l"(p));
    return a;
}
#define CP16(dst, src) asm volatile("cp.async.cg.shared.global [%0], [%1], 16;" :: "r"(dst), "l"(src))
#define CP16P(dst, src, p) asm volatile("cp.async.cg.shared.global [%0], [%1], 16, %2;" :: "r"(dst), "l"(src), "r"((p)?16:0))
#define CPCOMMIT()     asm volatile("cp.async.commit_group;" ::: "memory")
#define CPWAIT(n)      asm volatile("cp.async.wait_group %0;" :: "n"(n) : "memory")
#define LDSM4(r, a) asm volatile("ldmatrix.sync.aligned.m8n8.x4.shared.b16 {%0,%1,%2,%3}, [%4];" \
    : "=r"((r)[0]), "=r"((r)[1]), "=r"((r)[2]), "=r"((r)[3]) : "r"(a))
#define LDSM4T(r, a) asm volatile("ldmatrix.sync.aligned.m8n8.x4.trans.shared.b16 {%0,%1,%2,%3}, [%4];" \
    : "=r"((r)[0]), "=r"((r)[1]), "=r"((r)[2]), "=r"((r)[3]) : "r"(a))

// bf16 helpers (agent path — bit-identical mask)
__device__ __forceinline__ void split_hl(float v, __nv_bfloat16& h, __nv_bfloat16& l) {
    h = __float2bfloat16_rn(v);
    l = __float2bfloat16_rn(v - __bfloat162float(h));
}
__device__ __forceinline__ void cvt_pack(float4 v, uint2& h, uint2& l) {
    __nv_bfloat16 h0,l0,h1,l1,h2,l2,h3,l3;
    split_hl(v.x,h0,l0); split_hl(v.y,h1,l1); split_hl(v.z,h2,l2); split_hl(v.w,h3,l3);
    h.x = ((uint32_t)__bfloat16_as_ushort(h1)<<16)|(uint32_t)__bfloat16_as_ushort(h0);
    h.y = ((uint32_t)__bfloat16_as_ushort(h3)<<16)|(uint32_t)__bfloat16_as_ushort(h2);
    l.x = ((uint32_t)__bfloat16_as_ushort(l1)<<16)|(uint32_t)__bfloat16_as_ushort(l0);
    l.y = ((uint32_t)__bfloat16_as_ushort(l3)<<16)|(uint32_t)__bfloat16_as_ushort(l2);
}
// fp16 helpers
__device__ __forceinline__ uint32_t packh2(float a, float b) {
    __half2 h2 = __floats2half2_rn(a, b);
    return *reinterpret_cast<uint32_t*>(&h2);
}
__device__ __forceinline__ void pack_hl2h(float a, float b, uint32_t& ph, uint32_t& pl) {
    __half ha = __float2half_rn(a), hb = __float2half_rn(b);
    float la = a - __half2float(ha), lb = b - __half2float(hb);
    ph = ((uint32_t)__half_as_ushort(hb)<<16)|(uint32_t)__half_as_ushort(ha);
    pl = ((uint32_t)__half_as_ushort(__float2half_rn(lb))<<16)
       | (uint32_t)__half_as_ushort(__float2half_rn(la));
}

// ---------------- scratch ----------------
__device__ float g_xcat[(size_t)BB*NT*512];
__device__ float g_part[(size_t)BB*NT*4];
__device__ float g_maskf [BB*NT];
__device__ int   g_list[BB*NT];
__device__ int   g_cnt [BB];
__device__ float g_x  [(size_t)2*BB*NT*CD];
__device__ __align__(16) __nv_bfloat16 g_w_ag [2*262144];
__device__ __align__(16) __nv_bfloat16 g_xcat_hl[2*XCAT_PLANE];
__device__ __align__(16) __half g_w16  [3145728];
__device__ __align__(16) __half g_xn_h [XN_PLANE];
__device__ __align__(16) __half g_att_h[ATT_PLANE];
__device__ __align__(16) __half g_hid_h[HID_PLANE];
__device__ __align__(16) __half g_qkv_hl[2*QKV_PLANE];

// ---------------- weight converts ----------------
__global__ void conv_wag(const float* __restrict__ src, __nv_bfloat16* __restrict__ dst, int n)
{
    __nv_bfloat16* dh = dst;
    __nv_bfloat16* dl = dst + n;
    int n4 = n >> 2;
    for (int i = blockIdx.x*256 + threadIdx.x; i < n4; i += gridDim.x*256) {
        float4 v = ((const float4*)src)[i];
        uint2 h, l; cvt_pack(v, h, l);
        *(uint2*)&dh[i*4] = h;
        *(uint2*)&dl[i*4] = l;
    }
}
struct W8 { const float* src[8]; int start[8]; int n[8]; };
__global__ void conv_w16(W8 a, __half* __restrict__ dst)
{
    int w = blockIdx.y;
    int n = a.n[w];
    const float4* s = (const float4*)a.src[w];
    __half* dh = dst + a.start[w];
    __half* dl = dh + n;
    int n4 = n >> 2;
    for (int i = blockIdx.x*256 + threadIdx.x; i < n4; i += gridDim.x*256) {
        float4 v = s[i];
        uint32_t h0,l0,h1,l1;
        pack_hl2h(v.x, v.y, h0, l0);
        pack_hl2h(v.z, v.w, h1, l1);
        *(uint2*)&dh[i*4] = make_uint2(h0, h1);
        *(uint2*)&dl[i*4] = make_uint2(l0, l1);
    }
}

// ---------------- transpose [B,C,N] -> token-major concat + bf16 hi/lo (agent) ----------------
__global__ void transpose_cat(const float* __restrict__ fir, const float* __restrict__ fvis,
                              float* __restrict__ xcat, __nv_bfloat16* __restrict__ xcat_hl)
{
    int src = blockIdx.z & 1;
    int b   = blockIdx.z >> 1;
    const float* f = src ? fvis : fir;
    __shared__ float tile[32][33];
    int n0 = blockIdx.x * 32, c0 = blockIdx.y * 32;
    int tx = threadIdx.x, ty = threadIdx.y;
    #pragma unroll
    for (int i = 0; i < 32; i += 8)
        tile[ty + i][tx] = f[((size_t)b*CD + c0 + ty + i)*NT + n0 + tx];
    __syncthreads();
    #pragma unroll
    for (int i = 0; i < 32; i += 8) {
        float v = tile[tx][ty + i];
        size_t idx = ((size_t)b*NT + n0 + ty + i)*512 + src*CD + c0 + tx;
        xcat[idx] = v;
        __nv_bfloat16 h, l; split_hl(v, h, l);
        xcat_hl[idx] = h;
        xcat_hl[XCAT_PLANE + idx] = l;
    }
}

#define RSB   80
#define MATB  (128*RSB)

__device__ __forceinline__ float actf(float t, int act) {
    if (act == 1) return t / (1.f + expf(-t));
    if (act == 2) return 0.5f*t*(1.f + erff(t*0.70710678118654752f));
    return t;
}

// ================= agent GEMM: bf16 3-term, 2-stage, 2 CTAs/SM =================
#define STAGEA (4*MATB)
#define AGEMM_SMEM (2*STAGEA)   // 81920
__global__ void __launch_bounds__(256, 2)
gemm_agent(const __nv_bfloat16* __restrict__ Ahl, size_t aplane,
           const __nv_bfloat16* __restrict__ Wh, size_t wplane,
           const float* __restrict__ bias, int K,
           const float* __restrict__ logit_w, float* __restrict__ part)
{
    int b = blockIdx.z;
    int m0 = blockIdx.y * 128;
    int o0 = blockIdx.x * 128;
    size_t rowbase = (size_t)b * NT;
    const __nv_bfloat16* Ah_g = Ahl + (rowbase + m0) * K;
    const __nv_bfloat16* Al_g = Ah_g + aplane;
    const __nv_bfloat16* Wh_g = Wh + (size_t)o0 * K;
    const __nv_bfloat16* Wl_g = Wh_g + wplane;

    extern __shared__ char smem[];
    uint32_t sbase = smem_u32(smem);
    int tid = threadIdx.x, lane = tid & 31, w = tid >> 5;
    int wm = w & 3, wn = w >> 2;
    int gid = lane >> 2, tig = lane & 3;

    float acc[2][8][4];
    #pragma unroll
    for (int mt=0; mt<2; mt++)
        #pragma unroll
        for (int nt=0; nt<8; nt++)
            #pragma unroll
            for (int q=0; q<4; q++) acc[mt][nt][q] = 0.f;

#define PREFA(cc, st) do { \
    uint32_t sb_ = sbase + (st)*STAGEA; \
    _Pragma("unroll") \
    for (int i_ = 0; i_ < 2; i_++) { \
        int f_ = tid + i_*256; int row_ = f_ >> 2; int jb_ = (f_ & 3) * 16; \
        size_t go_ = (size_t)row_*K + (size_t)(cc)*32; \
        uint32_t so_ = sb_ + (uint32_t)(row_*RSB + jb_); \
        CP16(so_, (const char*)(Ah_g + go_) + jb_); \
        CP16(so_ + MATB, (const char*)(Al_g + go_) + jb_); \
        CP16(so_ + 2*MATB, (const char*)(Wh_g + go_) + jb_); \
        CP16(so_ + 3*MATB, (const char*)(Wl_g + go_) + jb_); \
    } } while (0)

    int nchunk = K >> 5;
    PREFA(0, 0);
    CPCOMMIT();

    for (int c = 0; c < nchunk; c++) {
        if (c + 1 < nchunk) { PREFA(c+1, (c+1)&1); CPCOMMIT(); CPWAIT(1); }
        else { CPWAIT(0); }
        __syncthreads();
        uint32_t stg = sbase + (c & 1) * STAGEA;
        #pragma unroll
        for (int ks = 0; ks < 2; ks++) {
            uint32_t colb = (uint32_t)(ks*32 + ((lane >> 4) << 4));
            uint32_t Ahf[2][4], Alf[2][4];
            #pragma unroll
            for (int mt = 0; mt < 2; mt++) {
                uint32_t sa = stg + (uint32_t)((wm*32 + mt*16 + (lane & 15)) * RSB) + colb;
                LDSM4(Ahf[mt], sa);
                LDSM4(Alf[mt], sa + MATB);
            }
            #pragma unroll
            for (int np = 0; np < 4; np++) {
                uint32_t sb = stg + 2*MATB + (uint32_t)((wn*64 + np*16 + (lane & 15)) * RSB) + colb;
                uint32_t Bh[4], Bl[4];
                LDSM4(Bh, sb);
                LDSM4(Bl, sb + MATB);
                #pragma unroll
                for (int mt = 0; mt < 2; mt++) {
                    mma16816(acc[mt][2*np],   Ahf[mt], Bh[0], Bh[2]);
                    mma16816(acc[mt][2*np],   Ahf[mt], Bl[0], Bl[2]);
                    mma16816(acc[mt][2*np],   Alf[mt], Bh[0], Bh[2]);
                    mma16816(acc[mt][2*np+1], Ahf[mt], Bh[1], Bh[3]);
                    mma16816(acc[mt][2*np+1], Ahf[mt], Bl[1], Bl[3]);
                    mma16816(acc[mt][2*np+1], Alf[mt], Bh[1], Bh[3]);
                }
            }
        }
        __syncthreads();
    }
#undef PREFA

    // fused agent-logit partials (identical math/order to R8-R10)
    float pr[4] = {0.f, 0.f, 0.f, 0.f};
    #pragma unroll
    for (int mt = 0; mt < 2; mt++) {
        #pragma unroll
        for (int nt = 0; nt < 8; nt++) {
            int col = o0 + wn*64 + nt*8 + 2*tig;
            float b0v = bias[col], b1v = bias[col+1];
            float w0 = logit_w[col], w1 = logit_w[col+1];
            float t0 = actf(acc[mt][nt][0] + b0v, 1);
            float t1 = actf(acc[mt][nt][1] + b1v, 1);
            float t2 = actf(acc[mt][nt][2] + b0v, 1);
            float t3 = actf(acc[mt][nt][3] + b1v, 1);
            pr[mt*2+0] += t0*w0 + t1*w1;
            pr[mt*2+1] += t2*w0 + t3*w1;
        }
    }
    #pragma unroll
    for (int i = 0; i < 4; i++) {
        pr[i] += __shfl_xor_sync(0xffffffffu, pr[i], 1);
        pr[i] += __shfl_xor_sync(0xffffffffu, pr[i], 2);
    }
    __syncthreads();
    float* red = (float*)smem;
    if (tig == 0) {
        #pragma unroll
        for (int mt = 0; mt < 2; mt++) {
            red[wn*128 + wm*32 + mt*16 + gid]     = pr[mt*2+0];
            red[wn*128 + wm*32 + mt*16 + gid + 8] = pr[mt*2+1];
        }
    }
    __syncthreads();
    if (tid < 128)
        part[((size_t)b*NT + m0 + tid)*4 + blockIdx.x] = red[tid] + red[128 + tid];
}

// ================= fp16 2-term GEMM: 3-stage single-sync, 2 CTAs/SM =================
#define STAGE3 (3*MATB)
#define GEMM16_SMEM (3*STAGE3)   // 92160 (x2 CTAs = 184320 <= 228KB)
__global__ void __launch_bounds__(256, 2)
gemm_f16(const __half* __restrict__ Aall,
         const __half* __restrict__ Wah, const __half* __restrict__ Wbh, size_t wplane,
         const float* __restrict__ ba, const float* __restrict__ bbv,
         float* __restrict__ Cf, __half* __restrict__ Ch, size_t cplane,
         const float* __restrict__ R,
         const int* __restrict__ counts, int K, int Ocols, int act)
{
    int bz = blockIdx.z;
    int s = (bz >= BB) ? 1 : 0;
    int b = bz & 3;
    int Mb = counts[b];
    int m0 = blockIdx.y * 128;
    if (m0 >= Mb) return;
    int o0 = blockIdx.x * 128;
    const __half* Wsel = s ? Wbh : Wah;
    const float* bias = s ? bbv : ba;
    size_t rowbase = (size_t)(s*BB + b) * NT;
    const __half* Ah_g = Aall + (rowbase + m0) * K;
    const __half* Wh_g = Wsel + (size_t)o0 * K;
    const __half* Wl_g = Wh_g + wplane;
    float* Cfb = Cf ? Cf + rowbase * Ocols : (float*)0;
    __half* Chb = Ch ? Ch + rowbase * Ocols : (__half*)0;
    const float* Rb = R ? R + rowbase * Ocols : (const float*)0;

    extern __shared__ char smem[];
    uint32_t sbase = smem_u32(smem);
    int tid = threadIdx.x, lane = tid & 31, w = tid >> 5;
    int wm = w & 3, wn = w >> 2;
    int gid = lane >> 2, tig = lane & 3;

    float acc[2][8][4];
    #pragma unroll
    for (int mt=0; mt<2; mt++)
        #pragma unroll
        for (int nt=0; nt<8; nt++)
            #pragma unroll
            for (int q=0; q<4; q++) acc[mt][nt][q] = 0.f;

#define PREF16(cc, st) do { \
    uint32_t sb_ = sbase + (st)*STAGE3; \
    _Pragma("unroll") \
    for (int i_ = 0; i_ < 6; i_++) { \
        int f_ = tid + i_*256; int mat_ = f_ >> 9; int rem_ = f_ & 511; \
        int row_ = rem_ >> 2; int jb_ = (rem_ & 3) * 16; \
        size_t go_ = (size_t)row_*K + (size_t)(cc)*32; \
        const char* p_ = (mat_ == 0) ? (const char*)(Ah_g + go_) \
                       : (mat_ == 1) ? (const char*)(Wh_g + go_) \
                                     : (const char*)(Wl_g + go_); \
        CP16(sb_ + (uint32_t)(mat_*MATB + row_*RSB + jb_), p_ + jb_); \
    } } while (0)

    int nchunk = K >> 5;
    PREF16(0, 0);
    CPCOMMIT();
    if (nchunk > 1) { PREF16(1, 1); CPCOMMIT(); }

    for (int c = 0; c < nchunk; c++) {
        if (c == nchunk - 1) { CPWAIT(0); } else { CPWAIT(1); }
        __syncthreads();
        uint32_t stg = sbase + (c % 3) * STAGE3;
        #pragma unroll
        for (int ks = 0; ks < 2; ks++) {
            uint32_t colb = (uint32_t)(ks*32 + ((lane >> 4) << 4));
            uint32_t Ahf[2][4];
            #pragma unroll
            for (int mt = 0; mt < 2; mt++) {
                uint32_t sa = stg + (uint32_t)((wm*32 + mt*16 + (lane & 15)) * RSB) + colb;
                LDSM4(Ahf[mt], sa);
            }
            #pragma unroll
            for (int np = 0; np < 4; np++) {
                uint32_t sb = stg + MATB + (uint32_t)((wn*64 + np*16 + (lane & 15)) * RSB) + colb;
                uint32_t Bh[4], Bl[4];
                LDSM4(Bh, sb);
                LDSM4(Bl, sb + MATB);
                #pragma unroll
                for (int mt = 0; mt < 2; mt++) {
                    mma16816h(acc[mt][2*np],   Ahf[mt], Bh[0], Bh[2]);
                    mma16816h(acc[mt][2*np],   Ahf[mt], Bl[0], Bl[2]);
                    mma16816h(acc[mt][2*np+1], Ahf[mt], Bh[1], Bh[3]);
                    mma16816h(acc[mt][2*np+1], Ahf[mt], Bl[1], Bl[3]);
                }
            }
        }
        if (c + 2 < nchunk) { PREF16(c+2, (c+2) % 3); CPCOMMIT(); }
    }
#undef PREF16

    #pragma unroll
    for (int mt = 0; mt < 2; mt++) {
        int r0 = m0 + wm*32 + mt*16 + gid;
        int r1 = r0 + 8;
        #pragma unroll
        for (int nt = 0; nt < 8; nt++) {
            int col = o0 + wn*64 + nt*8 + 2*tig;
            float b0v = bias[col], b1v = bias[col+1];
            float t0 = actf(acc[mt][nt][0] + b0v, act);
            float t1 = actf(acc[mt][nt][1] + b1v, act);
            float t2 = actf(acc[mt][nt][2] + b0v, act);
            float t3 = actf(acc[mt][nt][3] + b1v, act);
            if (Cfb) {
                if (r0 < Mb) {
                    if (Rb) { t0 += Rb[(size_t)r0*Ocols + col]; t1 += Rb[(size_t)r0*Ocols + col + 1]; }
                    *(float2*)&Cfb[(size_t)r0*Ocols + col] = make_float2(t0, t1);
                }
                if (r1 < Mb) {
                    if (Rb) { t2 += Rb[(size_t)r1*Ocols + col]; t3 += Rb[(size_t)r1*Ocols + col + 1]; }
                    *(float2*)&Cfb[(size_t)r1*Ocols + col] = make_float2(t2, t3);
                }
            } else if (cplane) {
                // qkv path: lo plane only needed for K columns [256, 512)
                bool wantlo = (col >= 256) && (col < 512);
                if (r0 < Mb) {
                    if (wantlo) {
                        uint32_t ph, pl; pack_hl2h(t0, t1, ph, pl);
                        *(uint32_t*)&Chb[(size_t)r0*Ocols + col] = ph;
                        *(uint32_t*)&Chb[cplane + (size_t)r0*Ocols + col] = pl;
                    } else {
                        *(uint32_t*)&Chb[(size_t)r0*Ocols + col] = packh2(t0, t1);
                    }
                }
                if (r1 < Mb) {
                    if (wantlo) {
                        uint32_t ph, pl; pack_hl2h(t2, t3, ph, pl);
                        *(uint32_t*)&Chb[(size_t)r1*Ocols + col] = ph;
                        *(uint32_t*)&Chb[cplane + (size_t)r1*Ocols + col] = pl;
                    } else {
                        *(uint32_t*)&Chb[(size_t)r1*Ocols + col] = packh2(t2, t3);
                    }
                }
            } else {
                if (r0 < Mb) *(uint32_t*)&Chb[(size_t)r0*Ocols + col] = packh2(t0, t1);
                if (r1 < Mb) *(uint32_t*)&Chb[(size_t)r1*Ocols + col] = packh2(t2, t3);
            }
        }
    }
}

// ---------------- selection (logits from partials) ----------------
__global__ void select_kernel(const float* __restrict__ part, const float* __restrict__ ab2,
                              int* __restrict__ list, int* __restrict__ cnt,
                              float* __restrict__ maskf)
{
    int b = blockIdx.x, tid = threadIdx.x;
    const int PER = NT/256;  // 9
    __shared__ int cn[256];
    float ab2v = ab2[0];
    int base = tid*PER;
    float lv[PER];
    bool  sv[PER];
    int c = 0;
    #pragma unroll
    for (int i = 0; i < PER; i++) {
        size_t t4 = ((size_t)b*NT + base + i)*4;
        float lg = ((part[t4] + part[t4+1]) + (part[t4+2] + part[t4+3])) + ab2v;
        lv[i] = lg;
        bool sel = lg > 0.f; sv[i] = sel; c += sel;
        maskf[b*NT + base + i] = sel ? 1.f : 0.f;
    }
    cn[tid] = c; __syncthreads();
    for (int off = 1; off < 256; off <<= 1) {
        int v = (tid >= off) ? cn[tid-off] : 0;
        __syncthreads();
        cn[tid] += v;
        __syncthreads();
    }
    int total = cn[255];
    int pos = cn[tid] - c;
    if (total >= 64) {
        #pragma unroll
        for (int i = 0; i < PER; i++)
            if (sv[i]) { list[b*NT + pos] = base + i; pos++; }
        if (tid == 0) cnt[b] = total;
    } else {
        __shared__ float sl[NT];
        #pragma unroll
        for (int i = 0; i < PER; i++) sl[base+i] = lv[i];
        __syncthreads();
        if (tid == 0) {
            for (int t = 0; t < 64; t++) {
                int am = 0; float mv = sl[0];
                for (int n = 1; n < NT; n++) if (sl[n] > mv) { mv = sl[n]; am = n; }
                list[b*NT + t] = am; sl[am] = -1e30f;
            }
            cnt[b] = 64;
        }
    }
}

// ---------------- fused gather + LayerNorm (both streams) -> fp16 ----------------
__global__ void gather_ln(const float* __restrict__ xcat, const int* __restrict__ list,
                          const int* __restrict__ cnt,
                          float* __restrict__ x, __half* __restrict__ Yh,
                          const float* __restrict__ ga, const float* __restrict__ bba,
                          const float* __restrict__ gb2, const float* __restrict__ bbb)
{
    int b = blockIdx.y, j = blockIdx.x;
    if (j >= cnt[b]) return;
    int idx = list[b*NT + j];
    int tid = threadIdx.x;
    const float* src = xcat + ((size_t)b*NT + idx)*512;
    __shared__ float red[8];
    #pragma unroll
    for (int s = 0; s < 2; s++) {
        const float* gw = s ? gb2 : ga;
        const float* gb = s ? bbb : bba;
        float v = src[s*CD + tid];
        size_t row = ((size_t)(s*BB + b)*NT + j)*CD;
        x[row + tid] = v;
        float ssum = v;
        #pragma unroll
        for (int o = 16; o; o >>= 1) ssum += __shfl_down_sync(0xffffffffu, ssum, o);
        if ((tid & 31) == 0) red[tid>>5] = ssum;
        __syncthreads();
        float mean = 0.f;
        #pragma unroll
        for (int i = 0; i < 8; i++) mean += red[i];
        mean *= (1.f/CD);
        __syncthreads();
        float d = v - mean;
        ssum = d*d;
        #pragma unroll
        for (int o = 16; o; o >>= 1) ssum += __shfl_down_sync(0xffffffffu, ssum, o);
        if ((tid & 31) == 0) red[tid>>5] = ssum;
        __syncthreads();
        float var = 0.f;
        #pragma unroll
        for (int i = 0; i < 8; i++) var += red[i];
        var *= (1.f/CD);
        Yh[row + tid] = __float2half_rn(d * rsqrtf(var + 1e-5f) * gw[tid] + gb[tid]);
        __syncthreads();
    }
}

// ---------------- LayerNorm (dual-stream) -> fp16 ----------------
__global__ void ln2(const float* __restrict__ X, __half* __restrict__ Yh,
                    const float* __restrict__ ga, const float* __restrict__ bba,
                    const float* __restrict__ gb2, const float* __restrict__ bbb,
                    const int* __restrict__ cnt)
{
    int bz = blockIdx.y; int s = bz >> 2, b = bz & 3;
    int n = blockIdx.x;
    if (n >= cnt[b]) return;
    const float* gw = s ? gb2 : ga;
    const float* gb = s ? bbb : bba;
    int tid = threadIdx.x;
    size_t row = ((size_t)(s*BB+b)*NT + n)*CD;
    float v = X[row + tid];
    __shared__ float red[8];
    float ssum = v;
    #pragma unroll
    for (int o = 16; o; o >>= 1) ssum += __shfl_down_sync(0xffffffffu, ssum, o);
    if ((tid & 31) == 0) red[tid>>5] = ssum;
    __syncthreads();
    float mean = 0.f;
    #pragma unroll
    for (int i = 0; i < 8; i++) mean += red[i];
    mean *= (1.f/CD);
    __syncthreads();
    float d = v - mean;
    ssum = d*d;
    #pragma unroll
    for (int o = 16; o; o >>= 1) ssum += __shfl_down_sync(0xffffffffu, ssum, o);
    if ((tid & 31) == 0) red[tid>>5] = ssum;
    __syncthreads();
    float var = 0.f;
    #pragma unroll
    for (int i = 0; i < 8; i++) var += red[i];
    var *= (1.f/CD);
    Yh[row + tid] = __float2half_rn(d * rsqrtf(var + 1e-5f) * gw[tid] + gb[tid]);
}

// ================= flash attention fp16 (max-free softmax), 3-stage single-sync, 2 CTAs/SM ======
// scores are tiny (|S| << 1): exp(S) is range-safe without running-max; masked -> exp(-1e30)=0.
#define AQR 144
#define AT_KVOFF (128*AQR)               // Q hi plane only
#define AT_STG (3*64*AQR)                // Kh,Kl,Vh
#define ATTN_SMEM (AT_KVOFF + 3*AT_STG)  // 101376 (x2 CTAs = 202752 <= 228KB)

__global__ void __launch_bounds__(256, 2)
attn_mma(const __half* __restrict__ qkvhl, __half* __restrict__ att_h,
         const int* __restrict__ cnt)
{
    extern __shared__ char smc[];
    uint32_t sb = smem_u32(smc);
    int bz = blockIdx.z; int s = bz >> 2, b = bz & 3;
    int h = blockIdx.y, q0 = blockIdx.x*128;
    int Mb = cnt[b];
    if (q0 >= Mb) return;
    int tid = threadIdx.x, lane = tid & 31, w = tid >> 5;
    int gid = lane >> 2, tig = lane & 3;
    size_t rowbase = (size_t)(s*BB + b) * NT;
    const __half* qg = qkvhl;

    // Q hi prefetch
    {
        #pragma unroll
        for (int i = 0; i < 4; i++) {
            int f = tid + i*256;
            int row = f >> 3, c16 = f & 7;
            const char* src = (const char*)(qg + (rowbase + q0 + row)*768 + h*64) + c16*16;
            CP16P(sb + row*AQR + c16*16, src, (q0 + row) < Mb);
        }
    }
#define KV_PREFETCH(kt, st) do { \
    int k0_ = (kt)*64; \
    _Pragma("unroll") \
    for (int i_ = 0; i_ < 6; i_++) { \
        int f_ = tid + i_*256; \
        int pl_ = f_ >> 9, rem_ = f_ & 511; \
        int row_ = rem_ >> 3, c16_ = rem_ & 7; \
        int ko_ = (pl_ < 2) ? 256 : 512; \
        size_t hp_ = (pl_ == 1) ? QKV_PLANE : 0; \
        const char* src_ = (const char*)(qg + (rowbase + k0_ + row_)*768 + ko_ + h*64 + hp_) + c16_*16; \
        uint32_t dst_ = sb + AT_KVOFF + (st)*AT_STG + pl_*(64*AQR) + row_*AQR + c16_*16; \
        CP16P(dst_, src_, (k0_ + row_) < Mb); \
    } } while (0)

    int nkt = (Mb + 63) >> 6;
    KV_PREFETCH(0, 0);
    CPCOMMIT();
    if (nkt > 1) { KV_PREFETCH(1, 1); CPCOMMIT(); }

    uint32_t Qh[4][4];
    float oacc[8][4];
    #pragma unroll
    for (int j=0;j<8;j++)
        #pragma unroll
        for (int q=0;q<4;q++) oacc[j][q] = 0.f;
    float l0 = 0.f, l1 = 0.f;
    bool qload = false;

    for (int c = 0; c < nkt; c++) {
        if (c == nkt - 1) { CPWAIT(0); } else { CPWAIT(1); }
        __syncthreads();
        if (!qload) {
            qload = true;
            #pragma unroll
            for (int ks = 0; ks < 4; ks++) {
                uint32_t qa = sb + (uint32_t)((w*16 + (lane & 15)) * AQR) + ks*32 + ((lane >> 4) << 4);
                LDSM4(Qh[ks], qa);
            }
        }
        uint32_t kb = sb + AT_KVOFF + (c % 3)*AT_STG;
        uint32_t vb = kb + 2*(64*AQR);

        float sacc[8][4];
        #pragma unroll
        for (int j=0;j<8;j++)
            #pragma unroll
            for (int q=0;q<4;q++) sacc[j][q] = 0.f;
        #pragma unroll
        for (int ks = 0; ks < 4; ks++) {
            #pragma unroll
            for (int np = 0; np < 4; np++) {
                uint32_t ka = kb + (uint32_t)((np*16 + ((lane >> 4) << 3) + (lane & 7)) * AQR)
                            + ks*32 + (((lane >> 3) & 1) << 4);
                uint32_t Kh4[4], Kl4[4];
                LDSM4(Kh4, ka);
                LDSM4(Kl4, ka + 64*AQR);
                mma16816h(sacc[2*np],   Qh[ks], Kh4[0], Kh4[1]);
                mma16816h(sacc[2*np],   Qh[ks], Kl4[0], Kl4[1]);
                mma16816h(sacc[2*np+1], Qh[ks], Kh4[2], Kh4[3]);
                mma16816h(sacc[2*np+1], Qh[ks], Kl4[2], Kl4[3]);
            }
        }
        // max-free softmax: P = exp(S/8) (masked -> 0), accumulate row sums
        int kvb = c*64;
        float s0 = 0.f, s1 = 0.f;
        #pragma unroll
        for (int j = 0; j < 8; j++) {
            int t0 = kvb + j*8 + 2*tig;
            bool v0 = t0 < Mb, v1 = (t0 + 1) < Mb;
            sacc[j][0] = v0 ? __expf(sacc[j][0]*0.125f) : 0.f;
            sacc[j][1] = v1 ? __expf(sacc[j][1]*0.125f) : 0.f;
            sacc[j][2] = v0 ? __expf(sacc[j][2]*0.125f) : 0.f;
            sacc[j][3] = v1 ? __expf(sacc[j][3]*0.125f) : 0.f;
            s0 += sacc[j][0] + sacc[j][1];
            s1 += sacc[j][2] + sacc[j][3];
        }
        s0 += __shfl_xor_sync(0xffffffffu, s0, 1);
        s0 += __shfl_xor_sync(0xffffffffu, s0, 2);
        s1 += __shfl_xor_sync(0xffffffffu, s1, 1);
        s1 += __shfl_xor_sync(0xffffffffu, s1, 2);
        l0 += s0; l1 += s1;
        // O += P V (P hi-only fp16, V hi-only)
        #pragma unroll
        for (int kt = 0; kt < 4; kt++) {
            uint32_t aP[4];
            aP[0] = packh2(sacc[2*kt][0],   sacc[2*kt][1]);
            aP[1] = packh2(sacc[2*kt][2],   sacc[2*kt][3]);
            aP[2] = packh2(sacc[2*kt+1][0], sacc[2*kt+1][1]);
            aP[3] = packh2(sacc[2*kt+1][2], sacc[2*kt+1][3]);
            #pragma unroll
            for (int np = 0; np < 4; np++) {
                uint32_t va = vb + (uint32_t)((kt*16 + (((lane >> 3) & 1) << 3) + (lane & 7)) * AQR)
                            + (2*np + (lane >> 4))*16;
                uint32_t Vh4[4];
                LDSM4T(Vh4, va);
                mma16816h(oacc[2*np],   aP, Vh4[0], Vh4[1]);
                mma16816h(oacc[2*np+1], aP, Vh4[2], Vh4[3]);
            }
        }
        if (c + 2 < nkt) { KV_PREFETCH(c+2, (c+2) % 3); CPCOMMIT(); }
    }
#undef KV_PREFETCH

    float inv0 = 1.f / l0, inv1 = 1.f / l1;
    int qr0 = q0 + w*16 + gid;
    int qr1 = qr0 + 8;
    #pragma unroll
    for (int j = 0; j < 8; j++) {
        int col = h*64 + j*8 + 2*tig;
        if (qr0 < Mb)
            *(uint32_t*)&att_h[(rowbase + qr0)*CD + col] = packh2(oacc[j][0]*inv0, oacc[j][1]*inv0);
        if (qr1 < Mb)
            *(uint32_t*)&att_h[(rowbase + qr1)*CD + col] = packh2(oacc[j][2]*inv1, oacc[j][3]*inv1);
    }
}

// ---------------- output ----------------
__global__ void base_out(const float* __restrict__ fir, const float* __restrict__ fvis,
                         float* __restrict__ out)
{
    size_t i = (size_t)blockIdx.x*256 + threadIdx.x;
    float4 a = ((const float4*)fir)[i];
    float4 b = ((const float4*)fvis)[i];
    ((float4*)out)[i] = make_float4(a.x+b.x, a.y+b.y, a.z+b.z, a.w+b.w);
}

__global__ void scatter_out(const float* __restrict__ x0, const float* __restrict__ x1,
                            const int* __restrict__ list, const float* __restrict__ maskf,
                            const int* __restrict__ cnt, float* __restrict__ out)
{
    int b = blockIdx.y, j = blockIdx.x;
    if (j >= cnt[b]) return;
    int idx = list[b*NT + j];
    float mv = maskf[b*NT + idx];
    int c = threadIdx.x;
    float v = (x0[((size_t)b*NT + j)*CD + c] + x1[((size_t)b*NT + j)*CD + c]) * mv;
    out[((size_t)b*CD + c)*NT + idx] = v;
}

// ---------------- host ----------------
extern "C" void kernel_launch(void* const* d_in, const int* in_sizes, int n_in,
                              void* d_out, int out_size)
{
    const float* f_ir  = (const float*)d_in[0];
    const float* f_vis = (const float*)d_in[1];
    const float* aw1   = (const float*)d_in[2];
    const float* ab1   = (const float*)d_in[3];
    const float* aw2   = (const float*)d_in[4];
    const float* ab2   = (const float*)d_in[5];
    const float* ir_lng  = (const float*)d_in[6];
    const float* ir_lnb  = (const float*)d_in[7];
    const float* ir_wqkv = (const float*)d_in[8];
    const float* ir_bqkv = (const float*)d_in[9];
    const float* ir_wo   = (const float*)d_in[10];
    const float* ir_bo   = (const float*)d_in[11];
    const float* ir_w1   = (const float*)d_in[12];
    const float* ir_b1   = (const float*)d_in[13];
    const float* ir_w2   = (const float*)d_in[14];
    const float* ir_b2   = (const float*)d_in[15];
    const float* vi_lng  = (const float*)d_in[16];
    const float* vi_lnb  = (const float*)d_in[17];
    const float* vi_wqkv = (const float*)d_in[18];
    const float* vi_bqkv = (const float*)d_in[19];
    const float* vi_wo   = (const float*)d_in[20];
    const float* vi_bo   = (const float*)d_in[21];
    const float* vi_w1   = (const float*)d_in[22];
    const float* vi_b1   = (const float*)d_in[23];
    const float* vi_w2   = (const float*)d_in[24];
    const float* vi_b2   = (const float*)d_in[25];
    float* out = (float*)d_out;

    float *xcat,*partp,*maskf,*x;
    __nv_bfloat16 *wag,*xcathl;
    __half *w16,*xnh,*atth,*hidh,*qkvhl;
    int *list,*cntp;
    cudaGetSymbolAddress((void**)&xcat,  g_xcat);
    cudaGetSymbolAddress((void**)&partp, g_part);
    cudaGetSymbolAddress((void**)&maskf, g_maskf);
    cudaGetSymbolAddress((void**)&x,     g_x);
    cudaGetSymbolAddress((void**)&wag,   g_w_ag);
    cudaGetSymbolAddress((void**)&xcathl,g_xcat_hl);
    cudaGetSymbolAddress((void**)&w16,   g_w16);
    cudaGetSymbolAddress((void**)&xnh,   g_xn_h);
    cudaGetSymbolAddress((void**)&atth,  g_att_h);
    cudaGetSymbolAddress((void**)&hidh,  g_hid_h);
    cudaGetSymbolAddress((void**)&qkvhl, g_qkv_hl);
    cudaGetSymbolAddress((void**)&list,  g_list);
    cudaGetSymbolAddress((void**)&cntp,  g_cnt);
    float* x0 = x;
    float* x1 = x + (size_t)BB*NT*CD;

    cudaFuncSetAttribute(attn_mma, cudaFuncAttributeMaxDynamicSharedMemorySize, ATTN_SMEM);
    cudaFuncSetAttribute(gemm_agent, cudaFuncAttributeMaxDynamicSharedMemorySize, AGEMM_SMEM);
    cudaFuncSetAttribute(gemm_f16, cudaFuncAttributeMaxDynamicSharedMemorySize, GEMM16_SMEM);

    // weight conversions
    conv_wag<<<64, 256>>>(aw1, wag, 262144);
    W8 ws;
    const float* wsrc[8] = {ir_wqkv, vi_wqkv, ir_wo, vi_wo, ir_w1, vi_w1, ir_w2, vi_w2};
    const int    wn[8]   = {196608, 196608, 65536, 65536, 262144, 262144, 262144, 262144};
    int start = 0;
    for (int i = 0; i < 8; i++) { ws.src[i] = wsrc[i]; ws.n[i] = wn[i]; ws.start[i] = start; start += 2*wn[i]; }
    conv_w16<<<dim3(64, 8), 256>>>(ws, w16);

    // 1. token-major concat (+bf16 hi/lo for agent)
    transpose_cat<<<dim3(NT/32, CD/32, BB*2), dim3(32,8)>>>(f_ir, f_vis, xcat, xcathl);
    // 2. agent GEMM (bf16 3-term, bit-identical logits)
    gemm_agent<<<dim3(AGH/128, NT/128, BB), 256, AGEMM_SMEM>>>(
        xcathl, XCAT_PLANE, wag, 262144, ab1, 512, aw2, partp);
    // 3. selection
    select_kernel<<<BB, 256>>>(partp, ab2, list, cntp, maskf);
    // 4. fused gather + first LN (fp16 out)
    gather_ln<<<dim3(NT, BB), 256>>>(xcat, list, cntp, x, xnh,
                                     ir_lng, ir_lnb, vi_lng, vi_lnb);

    // 5. both mixers (fp16 2-term)
    gemm_f16<<<dim3(768/128, NT/128, 2*BB), 256, GEMM16_SMEM>>>(
        xnh, w16 + 0, w16 + 393216, 196608,
        ir_bqkv, vi_bqkv, (float*)0, qkvhl, QKV_PLANE, (const float*)0, cntp, 256, 768, 0);
    attn_mma<<<dim3(NT/128, NH, 2*BB), 256, ATTN_SMEM>>>(qkvhl, atth, cntp);
    gemm_f16<<<dim3(CD/128, NT/128, 2*BB), 256, GEMM16_SMEM>>>(
        atth, w16 + 786432, w16 + 917504, 65536,
        ir_bo, vi_bo, x, (__half*)0, 0, x, cntp, 256, CD, 0);
    ln2<<<dim3(NT, 2*BB), 256>>>(x, xnh, ir_lng, ir_lnb, vi_lng, vi_lnb, cntp);
    gemm_f16<<<dim3(1024/128, NT/128, 2*BB), 256, GEMM16_SMEM>>>(
        xnh, w16 + 1048576, w16 + 1572864, 262144,
        ir_b1, vi_b1, (float*)0, hidh, 0, (const float*)0, cntp, 256, 1024, 2);
    gemm_f16<<<dim3(CD/128, NT/128, 2*BB), 256, GEMM16_SMEM>>>(
        hidh, w16 + 2097152, w16 + 2621440, 262144,
        ir_b2, vi_b2, x, (__half*)0, 0, x, cntp, 1024, CD, 0);

    // 6. output
    base_out<<<(BB*CD*NT)/1024, 256>>>(f_ir, f_vis, out);
    scatter_out<<<dim3(NT, BB), 256>>>(x0, x1, list, maskf, cntp, out);
}

// round 13
// speedup vs baseline: 5.7234x; 1.1092x over previous
#include <cuda_runtime.h>
#include <cuda_bf16.h>
#include <cuda_fp16.h>
#include <math.h>
#include <stdint.h>

#define BB   4
#define NT   2304      // 48*48 tokens
#define CD   256       // DIM
#define AGH  512       // agent hidden
#define NH   4
#define DH   64

// plane sizes (elements)
#define XCAT_PLANE ((size_t)BB*NT*512)
#define XN_PLANE   ((size_t)2*BB*NT*CD)
#define ATT_PLANE  ((size_t)2*BB*NT*CD)
#define HID_PLANE  ((size_t)2*BB*NT*1024)
#define QKV_PLANE  ((size_t)2*BB*NT*768)

// ---------------- HMMA m16n8k16 (bf16 + fp16 variants) ----------------
__device__ __forceinline__ void mma16816(float* c, const uint32_t* a, uint32_t b0, uint32_t b1) {
    asm volatile("mma.sync.aligned.m16n8k16.row.col.f32.bf16.bf16.f32 "
        "{%0,%1,%2,%3}, {%4,%5,%6,%7}, {%8,%9}, {%0,%1,%2,%3};"
        : "+f"(c[0]), "+f"(c[1]), "+f"(c[2]), "+f"(c[3])
        : "r"(a[0]), "r"(a[1]), "r"(a[2]), "r"(a[3]), "r"(b0), "r"(b1));
}
__device__ __forceinline__ void mma16816h(float* c, const uint32_t* a, uint32_t b0, uint32_t b1) {
    asm volatile("mma.sync.aligned.m16n8k16.row.col.f32.f16.f16.f32 "
        "{%0,%1,%2,%3}, {%4,%5,%6,%7}, {%8,%9}, {%0,%1,%2,%3};"
        : "+f"(c[0]), "+f"(c[1]), "+f"(c[2]), "+f"(c[3])
        : "r"(a[0]), "r"(a[1]), "r"(a[2]), "r"(a[3]), "r"(b0), "r"(b1));
}

__device__ __forceinline__ uint32_t smem_u32(const void* p) {
    uint32_t a;
    asm("{ .reg .u64 t; cvta.to.shared.u64 t, %1; cvt.u32.u64 %0, t; }" : "=r"(a) : "l"(p));
    return a;
}
#define CP16(dst, src) asm volatile("cp.async.cg.shared.global [%0], [%1], 16;" :: "r"(dst), "l"(src))
#define CP16P(dst, src, p) asm volatile("cp.async.cg.shared.global [%0], [%1], 16, %2;" :: "r"(dst), "l"(src), "r"((p)?16:0))
#define CPCOMMIT()     asm volatile("cp.async.commit_group;" ::: "memory")
#define CPWAIT(n)      asm volatile("cp.async.wait_group %0;" :: "n"(n) : "memory")
#define LDSM4(r, a) asm volatile("ldmatrix.sync.aligned.m8n8.x4.shared.b16 {%0,%1,%2,%3}, [%4];" \
    : "=r"((r)[0]), "=r"((r)[1]), "=r"((r)[2]), "=r"((r)[3]) : "r"(a))
#define LDSM4T(r, a) asm volatile("ldmatrix.sync.aligned.m8n8.x4.trans.shared.b16 {%0,%1,%2,%3}, [%4];" \
    : "=r"((r)[0]), "=r"((r)[1]), "=r"((r)[2]), "=r"((r)[3]) : "r"(a))

// bf16 helpers (agent path — bit-identical mask)
__device__ __forceinline__ void split_hl(float v, __nv_bfloat16& h, __nv_bfloat16& l) {
    h = __float2bfloat16_rn(v);
    l = __float2bfloat16_rn(v - __bfloat162float(h));
}
__device__ __forceinline__ void cvt_pack(float4 v, uint2& h, uint2& l) {
    __nv_bfloat16 h0,l0,h1,l1,h2,l2,h3,l3;
    split_hl(v.x,h0,l0); split_hl(v.y,h1,l1); split_hl(v.z,h2,l2); split_hl(v.w,h3,l3);
    h.x = ((uint32_t)__bfloat16_as_ushort(h1)<<16)|(uint32_t)__bfloat16_as_ushort(h0);
    h.y = ((uint32_t)__bfloat16_as_ushort(h3)<<16)|(uint32_t)__bfloat16_as_ushort(h2);
    l.x = ((uint32_t)__bfloat16_as_ushort(l1)<<16)|(uint32_t)__bfloat16_as_ushort(l0);
    l.y = ((uint32_t)__bfloat16_as_ushort(l3)<<16)|(uint32_t)__bfloat16_as_ushort(l2);
}
// fp16 helpers
__device__ __forceinline__ uint32_t packh2(float a, float b) {
    __half2 h2 = __floats2half2_rn(a, b);
    return *reinterpret_cast<uint32_t*>(&h2);
}
__device__ __forceinline__ void pack_hl2h(float a, float b, uint32_t& ph, uint32_t& pl) {
    __half ha = __float2half_rn(a), hb = __float2half_rn(b);
    float la = a - __half2float(ha), lb = b - __half2float(hb);
    ph = ((uint32_t)__half_as_ushort(hb)<<16)|(uint32_t)__half_as_ushort(ha);
    pl = ((uint32_t)__half_as_ushort(__float2half_rn(lb))<<16)
       | (uint32_t)__half_as_ushort(__float2half_rn(la));
}

// ---------------- scratch ----------------
__device__ float g_xcat[(size_t)BB*NT*512];
__device__ float g_part[(size_t)BB*NT*4];
__device__ float g_maskf [BB*NT];
__device__ int   g_list[BB*NT];
__device__ int   g_cnt [BB];
__device__ float g_x  [(size_t)2*BB*NT*CD];
__device__ __align__(16) __nv_bfloat16 g_w_ag [2*262144];
__device__ __align__(16) __nv_bfloat16 g_xcat_hl[2*XCAT_PLANE];
__device__ __align__(16) __half g_w16  [3145728];
__device__ __align__(16) __half g_xn_h [XN_PLANE];
__device__ __align__(16) __half g_att_h[ATT_PLANE];
__device__ __align__(16) __half g_hid_h[HID_PLANE];
__device__ __align__(16) __half g_qkv_hl[2*QKV_PLANE];

// ---------------- weight converts ----------------
__global__ void conv_wag(const float* __restrict__ src, __nv_bfloat16* __restrict__ dst, int n)
{
    __nv_bfloat16* dh = dst;
    __nv_bfloat16* dl = dst + n;
    int n4 = n >> 2;
    for (int i = blockIdx.x*256 + threadIdx.x; i < n4; i += gridDim.x*256) {
        float4 v = ((const float4*)src)[i];
        uint2 h, l; cvt_pack(v, h, l);
        *(uint2*)&dh[i*4] = h;
        *(uint2*)&dl[i*4] = l;
    }
}
struct W8 { const float* src[8]; int start[8]; int n[8]; };
__global__ void conv_w16(W8 a, __half* __restrict__ dst)
{
    int w = blockIdx.y;
    int n = a.n[w];
    const float4* s = (const float4*)a.src[w];
    __half* dh = dst + a.start[w];
    __half* dl = dh + n;
    int n4 = n >> 2;
    for (int i = blockIdx.x*256 + threadIdx.x; i < n4; i += gridDim.x*256) {
        float4 v = s[i];
        uint32_t h0,l0,h1,l1;
        pack_hl2h(v.x, v.y, h0, l0);
        pack_hl2h(v.z, v.w, h1, l1);
        *(uint2*)&dh[i*4] = make_uint2(h0, h1);
        *(uint2*)&dl[i*4] = make_uint2(l0, l1);
    }
}

// ---------------- transpose [B,C,N] -> token-major concat + bf16 hi/lo (agent) ----------------
__global__ void transpose_cat(const float* __restrict__ fir, const float* __restrict__ fvis,
                              float* __restrict__ xcat, __nv_bfloat16* __restrict__ xcat_hl)
{
    int src = blockIdx.z & 1;
    int b   = blockIdx.z >> 1;
    const float* f = src ? fvis : fir;
    __shared__ float tile[32][33];
    int n0 = blockIdx.x * 32, c0 = blockIdx.y * 32;
    int tx = threadIdx.x, ty = threadIdx.y;
    #pragma unroll
    for (int i = 0; i < 32; i += 8)
        tile[ty + i][tx] = f[((size_t)b*CD + c0 + ty + i)*NT + n0 + tx];
    __syncthreads();
    #pragma unroll
    for (int i = 0; i < 32; i += 8) {
        float v = tile[tx][ty + i];
        size_t idx = ((size_t)b*NT + n0 + ty + i)*512 + src*CD + c0 + tx;
        xcat[idx] = v;
        __nv_bfloat16 h, l; split_hl(v, h, l);
        xcat_hl[idx] = h;
        xcat_hl[XCAT_PLANE + idx] = l;
    }
}

#define RSB   80
#define MATB  (128*RSB)

__device__ __forceinline__ float actf(float t, int act) {
    if (act == 1) return t / (1.f + expf(-t));
    if (act == 2) return 0.5f*t*(1.f + erff(t*0.70710678118654752f));
    return t;
}

// ================= agent GEMM: bf16 3-term, 2-stage, 2 CTAs/SM, term-major MMA order ============
#define STAGEA (4*MATB)
#define AGEMM_SMEM (2*STAGEA)   // 81920
__global__ void __launch_bounds__(256, 2)
gemm_agent(const __nv_bfloat16* __restrict__ Ahl, size_t aplane,
           const __nv_bfloat16* __restrict__ Wh, size_t wplane,
           const float* __restrict__ bias, int K,
           const float* __restrict__ logit_w, float* __restrict__ part)
{
    int b = blockIdx.z;
    int m0 = blockIdx.y * 128;
    int o0 = blockIdx.x * 128;
    size_t rowbase = (size_t)b * NT;
    const __nv_bfloat16* Ah_g = Ahl + (rowbase + m0) * K;
    const __nv_bfloat16* Al_g = Ah_g + aplane;
    const __nv_bfloat16* Wh_g = Wh + (size_t)o0 * K;
    const __nv_bfloat16* Wl_g = Wh_g + wplane;

    extern __shared__ char smem[];
    uint32_t sbase = smem_u32(smem);
    int tid = threadIdx.x, lane = tid & 31, w = tid >> 5;
    int wm = w & 3, wn = w >> 2;
    int gid = lane >> 2, tig = lane & 3;

    float acc[2][8][4];
    #pragma unroll
    for (int mt=0; mt<2; mt++)
        #pragma unroll
        for (int nt=0; nt<8; nt++)
            #pragma unroll
            for (int q=0; q<4; q++) acc[mt][nt][q] = 0.f;

#define PREFA(cc, st) do { \
    uint32_t sb_ = sbase + (st)*STAGEA; \
    _Pragma("unroll") \
    for (int i_ = 0; i_ < 2; i_++) { \
        int f_ = tid + i_*256; int row_ = f_ >> 2; int jb_ = (f_ & 3) * 16; \
        size_t go_ = (size_t)row_*K + (size_t)(cc)*32; \
        uint32_t so_ = sb_ + (uint32_t)(row_*RSB + jb_); \
        CP16(so_, (const char*)(Ah_g + go_) + jb_); \
        CP16(so_ + MATB, (const char*)(Al_g + go_) + jb_); \
        CP16(so_ + 2*MATB, (const char*)(Wh_g + go_) + jb_); \
        CP16(so_ + 3*MATB, (const char*)(Wl_g + go_) + jb_); \
    } } while (0)

    int nchunk = K >> 5;
    PREFA(0, 0);
    CPCOMMIT();

    for (int c = 0; c < nchunk; c++) {
        if (c + 1 < nchunk) { PREFA(c+1, (c+1)&1); CPCOMMIT(); CPWAIT(1); }
        else { CPWAIT(0); }
        __syncthreads();
        uint32_t stg = sbase + (c & 1) * STAGEA;
        #pragma unroll
        for (int ks = 0; ks < 2; ks++) {
            uint32_t colb = (uint32_t)(ks*32 + ((lane >> 4) << 4));
            uint32_t Ahf[2][4], Alf[2][4];
            #pragma unroll
            for (int mt = 0; mt < 2; mt++) {
                uint32_t sa = stg + (uint32_t)((wm*32 + mt*16 + (lane & 15)) * RSB) + colb;
                LDSM4(Ahf[mt], sa);
                LDSM4(Alf[mt], sa + MATB);
            }
            #pragma unroll
            for (int np = 0; np < 4; np++) {
                uint32_t sb = stg + 2*MATB + (uint32_t)((wn*64 + np*16 + (lane & 15)) * RSB) + colb;
                uint32_t Bh[4], Bl[4];
                LDSM4(Bh, sb);
                LDSM4(Bl, sb + MATB);
                // term-major: 4 independent accs per pass, same-acc spacing = 4
                mma16816(acc[0][2*np],   Ahf[0], Bh[0], Bh[2]);
                mma16816(acc[0][2*np+1], Ahf[0], Bh[1], Bh[3]);
                mma16816(acc[1][2*np],   Ahf[1], Bh[0], Bh[2]);
                mma16816(acc[1][2*np+1], Ahf[1], Bh[1], Bh[3]);
                mma16816(acc[0][2*np],   Ahf[0], Bl[0], Bl[2]);
                mma16816(acc[0][2*np+1], Ahf[0], Bl[1], Bl[3]);
                mma16816(acc[1][2*np],   Ahf[1], Bl[0], Bl[2]);
                mma16816(acc[1][2*np+1], Ahf[1], Bl[1], Bl[3]);
                mma16816(acc[0][2*np],   Alf[0], Bh[0], Bh[2]);
                mma16816(acc[0][2*np+1], Alf[0], Bh[1], Bh[3]);
                mma16816(acc[1][2*np],   Alf[1], Bh[0], Bh[2]);
                mma16816(acc[1][2*np+1], Alf[1], Bh[1], Bh[3]);
            }
        }
        __syncthreads();
    }
#undef PREFA

    // fused agent-logit partials (identical math/order to R8-R11)
    float pr[4] = {0.f, 0.f, 0.f, 0.f};
    #pragma unroll
    for (int mt = 0; mt < 2; mt++) {
        #pragma unroll
        for (int nt = 0; nt < 8; nt++) {
            int col = o0 + wn*64 + nt*8 + 2*tig;
            float b0v = bias[col], b1v = bias[col+1];
            float w0 = logit_w[col], w1 = logit_w[col+1];
            float t0 = actf(acc[mt][nt][0] + b0v, 1);
            float t1 = actf(acc[mt][nt][1] + b1v, 1);
            float t2 = actf(acc[mt][nt][2] + b0v, 1);
            float t3 = actf(acc[mt][nt][3] + b1v, 1);
            pr[mt*2+0] += t0*w0 + t1*w1;
            pr[mt*2+1] += t2*w0 + t3*w1;
        }
    }
    #pragma unroll
    for (int i = 0; i < 4; i++) {
        pr[i] += __shfl_xor_sync(0xffffffffu, pr[i], 1);
        pr[i] += __shfl_xor_sync(0xffffffffu, pr[i], 2);
    }
    __syncthreads();
    float* red = (float*)smem;
    if (tig == 0) {
        #pragma unroll
        for (int mt = 0; mt < 2; mt++) {
            red[wn*128 + wm*32 + mt*16 + gid]     = pr[mt*2+0];
            red[wn*128 + wm*32 + mt*16 + gid + 8] = pr[mt*2+1];
        }
    }
    __syncthreads();
    if (tid < 128)
        part[((size_t)b*NT + m0 + tid)*4 + blockIdx.x] = red[tid] + red[128 + tid];
}

// ================= fp16 2-term GEMM, templated tile (BMT x 128), 3-stage, 2 CTAs/SM =============
template<int BMT>
__global__ void __launch_bounds__(256, 2)
gemm_f16(const __half* __restrict__ Aall,
         const __half* __restrict__ Wah, const __half* __restrict__ Wbh, size_t wplane,
         const float* __restrict__ ba, const float* __restrict__ bbv,
         float* __restrict__ Cf, __half* __restrict__ Ch, size_t cplane,
         const float* __restrict__ R,
         const int* __restrict__ counts, int K, int Ocols, int act)
{
    constexpr int NWM  = (BMT == 128) ? 4 : 2;  // m-warps
    constexpr int NWN  = 8 / NWM;               // n-warps
    constexpr int WCOL = 128 / NWN;             // cols per warp (64 / 32)
    constexpr int NPB  = WCOL / 16;             // B ldsm blocks per warp (4 / 2)
    constexpr int AMATB = BMT * RSB;
    constexpr int WMATB = 128 * RSB;
    constexpr int STG  = AMATB + 2*WMATB;
    constexpr int NITER = ((BMT + 256) * 4) / 256;  // cp.async iters (6 / 5)

    int bz = blockIdx.z;
    int s = (bz >= BB) ? 1 : 0;
    int b = bz & 3;
    int Mb = counts[b];
    int m0 = blockIdx.y * BMT;
    if (m0 >= Mb) return;
    int o0 = blockIdx.x * 128;
    const __half* Wsel = s ? Wbh : Wah;
    const float* bias = s ? bbv : ba;
    size_t rowbase = (size_t)(s*BB + b) * NT;
    const __half* Ah_g = Aall + (rowbase + m0) * K;
    const __half* Wh_g = Wsel + (size_t)o0 * K;
    const __half* Wl_g = Wh_g + wplane;
    float* Cfb = Cf ? Cf + rowbase * Ocols : (float*)0;
    __half* Chb = Ch ? Ch + rowbase * Ocols : (__half*)0;
    const float* Rb = R ? R + rowbase * Ocols : (const float*)0;

    extern __shared__ char smem[];
    uint32_t sbase = smem_u32(smem);
    int tid = threadIdx.x, lane = tid & 31, w = tid >> 5;
    int wm = w % NWM, wn = w / NWM;
    int gid = lane >> 2, tig = lane & 3;

    float acc[2][2*NPB][4];
    #pragma unroll
    for (int mt=0; mt<2; mt++)
        #pragma unroll
        for (int nt=0; nt<2*NPB; nt++)
            #pragma unroll
            for (int q=0; q<4; q++) acc[mt][nt][q] = 0.f;

#define PREF16(cc, st) do { \
    uint32_t sb_ = sbase + (st)*STG; \
    _Pragma("unroll") \
    for (int i_ = 0; i_ < NITER; i_++) { \
        int f_ = tid + i_*256; int row_ = f_ >> 2; int jb_ = (f_ & 3) * 16; \
        const char* p_; uint32_t soff_; \
        if (row_ < BMT)            { p_ = (const char*)(Ah_g + (size_t)row_*K + (size_t)(cc)*32); soff_ = (uint32_t)(row_*RSB); } \
        else if (row_ < BMT + 128) { int r_ = row_ - BMT;       p_ = (const char*)(Wh_g + (size_t)r_*K + (size_t)(cc)*32); soff_ = (uint32_t)(AMATB + r_*RSB); } \
        else                       { int r_ = row_ - BMT - 128; p_ = (const char*)(Wl_g + (size_t)r_*K + (size_t)(cc)*32); soff_ = (uint32_t)(AMATB + WMATB + r_*RSB); } \
        CP16(sb_ + soff_ + jb_, p_ + jb_); \
    } } while (0)

    int nchunk = K >> 5;
    PREF16(0, 0);
    CPCOMMIT();
    if (nchunk > 1) { PREF16(1, 1); CPCOMMIT(); }

    for (int c = 0; c < nchunk; c++) {
        if (c == nchunk - 1) { CPWAIT(0); } else { CPWAIT(1); }
        __syncthreads();
        uint32_t stg = sbase + (c % 3) * STG;
        #pragma unroll
        for (int ks = 0; ks < 2; ks++) {
            uint32_t colb = (uint32_t)(ks*32 + ((lane >> 4) << 4));
            uint32_t Ahf[2][4];
            #pragma unroll
            for (int mt = 0; mt < 2; mt++) {
                uint32_t sa = stg + (uint32_t)((wm*32 + mt*16 + (lane & 15)) * RSB) + colb;
                LDSM4(Ahf[mt], sa);
            }
            #pragma unroll
            for (int np = 0; np < NPB; np++) {
                uint32_t sb = stg + AMATB + (uint32_t)((wn*WCOL + np*16 + (lane & 15)) * RSB) + colb;
                uint32_t Bh[4], Bl[4];
                LDSM4(Bh, sb);
                LDSM4(Bl, sb + WMATB);
                // term-major: same-acc spacing = 4
                mma16816h(acc[0][2*np],   Ahf[0], Bh[0], Bh[2]);
                mma16816h(acc[0][2*np+1], Ahf[0], Bh[1], Bh[3]);
                mma16816h(acc[1][2*np],   Ahf[1], Bh[0], Bh[2]);
                mma16816h(acc[1][2*np+1], Ahf[1], Bh[1], Bh[3]);
                mma16816h(acc[0][2*np],   Ahf[0], Bl[0], Bl[2]);
                mma16816h(acc[0][2*np+1], Ahf[0], Bl[1], Bl[3]);
                mma16816h(acc[1][2*np],   Ahf[1], Bl[0], Bl[2]);
                mma16816h(acc[1][2*np+1], Ahf[1], Bl[1], Bl[3]);
            }
        }
        if (c + 2 < nchunk) { PREF16(c+2, (c+2) % 3); CPCOMMIT(); }
    }
#undef PREF16

    #pragma unroll
    for (int mt = 0; mt < 2; mt++) {
        int r0 = m0 + wm*32 + mt*16 + gid;
        int r1 = r0 + 8;
        #pragma unroll
        for (int nt = 0; nt < 2*NPB; nt++) {
            int col = o0 + wn*WCOL + nt*8 + 2*tig;
            float b0v = bias[col], b1v = bias[col+1];
            float t0 = actf(acc[mt][nt][0] + b0v, act);
            float t1 = actf(acc[mt][nt][1] + b1v, act);
            float t2 = actf(acc[mt][nt][2] + b0v, act);
            float t3 = actf(acc[mt][nt][3] + b1v, act);
            if (Cfb) {
                if (r0 < Mb) {
                    if (Rb) { t0 += Rb[(size_t)r0*Ocols + col]; t1 += Rb[(size_t)r0*Ocols + col + 1]; }
                    *(float2*)&Cfb[(size_t)r0*Ocols + col] = make_float2(t0, t1);
                }
                if (r1 < Mb) {
                    if (Rb) { t2 += Rb[(size_t)r1*Ocols + col]; t3 += Rb[(size_t)r1*Ocols + col + 1]; }
                    *(float2*)&Cfb[(size_t)r1*Ocols + col] = make_float2(t2, t3);
                }
            } else if (cplane) {
                bool wantlo = (col >= 256) && (col < 512);
                if (r0 < Mb) {
                    if (wantlo) {
                        uint32_t ph, pl; pack_hl2h(t0, t1, ph, pl);
                        *(uint32_t*)&Chb[(size_t)r0*Ocols + col] = ph;
                        *(uint32_t*)&Chb[cplane + (size_t)r0*Ocols + col] = pl;
                    } else {
                        *(uint32_t*)&Chb[(size_t)r0*Ocols + col] = packh2(t0, t1);
                    }
                }
                if (r1 < Mb) {
                    if (wantlo) {
                        uint32_t ph, pl; pack_hl2h(t2, t3, ph, pl);
                        *(uint32_t*)&Chb[(size_t)r1*Ocols + col] = ph;
                        *(uint32_t*)&Chb[cplane + (size_t)r1*Ocols + col] = pl;
                    } else {
                        *(uint32_t*)&Chb[(size_t)r1*Ocols + col] = packh2(t2, t3);
                    }
                }
            } else {
                if (r0 < Mb) *(uint32_t*)&Chb[(size_t)r0*Ocols + col] = packh2(t0, t1);
                if (r1 < Mb) *(uint32_t*)&Chb[(size_t)r1*Ocols + col] = packh2(t2, t3);
            }
        }
    }
}

#define GEMM16_SMEM_128 (3*((128+256)*RSB))   // 92160
#define GEMM16_SMEM_64  (3*((64+256)*RSB))    // 76800

// ---------------- selection (logits from partials) ----------------
__global__ void select_kernel(const float* __restrict__ part, const float* __restrict__ ab2,
                              int* __restrict__ list, int* __restrict__ cnt,
                              float* __restrict__ maskf)
{
    int b = blockIdx.x, tid = threadIdx.x;
    const int PER = NT/256;  // 9
    __shared__ int cn[256];
    float ab2v = ab2[0];
    int base = tid*PER;
    float lv[PER];
    bool  sv[PER];
    int c = 0;
    #pragma unroll
    for (int i = 0; i < PER; i++) {
        size_t t4 = ((size_t)b*NT + base + i)*4;
        float lg = ((part[t4] + part[t4+1]) + (part[t4+2] + part[t4+3])) + ab2v;
        lv[i] = lg;
        bool sel = lg > 0.f; sv[i] = sel; c += sel;
        maskf[b*NT + base + i] = sel ? 1.f : 0.f;
    }
    cn[tid] = c; __syncthreads();
    for (int off = 1; off < 256; off <<= 1) {
        int v = (tid >= off) ? cn[tid-off] : 0;
        __syncthreads();
        cn[tid] += v;
        __syncthreads();
    }
    int total = cn[255];
    int pos = cn[tid] - c;
    if (total >= 64) {
        #pragma unroll
        for (int i = 0; i < PER; i++)
            if (sv[i]) { list[b*NT + pos] = base + i; pos++; }
        if (tid == 0) cnt[b] = total;
    } else {
        __shared__ float sl[NT];
        #pragma unroll
        for (int i = 0; i < PER; i++) sl[base+i] = lv[i];
        __syncthreads();
        if (tid == 0) {
            for (int t = 0; t < 64; t++) {
                int am = 0; float mv = sl[0];
                for (int n = 1; n < NT; n++) if (sl[n] > mv) { mv = sl[n]; am = n; }
                list[b*NT + t] = am; sl[am] = -1e30f;
            }
            cnt[b] = 64;
        }
    }
}

// ---------------- fused gather + LayerNorm (both streams) -> fp16 ----------------
__global__ void gather_ln(const float* __restrict__ xcat, const int* __restrict__ list,
                          const int* __restrict__ cnt,
                          float* __restrict__ x, __half* __restrict__ Yh,
                          const float* __restrict__ ga, const float* __restrict__ bba,
                          const float* __restrict__ gb2, const float* __restrict__ bbb)
{
    int b = blockIdx.y, j = blockIdx.x;
    if (j >= cnt[b]) return;
    int idx = list[b*NT + j];
    int tid = threadIdx.x;
    const float* src = xcat + ((size_t)b*NT + idx)*512;
    __shared__ float red[8];
    #pragma unroll
    for (int s = 0; s < 2; s++) {
        const float* gw = s ? gb2 : ga;
        const float* gb = s ? bbb : bba;
        float v = src[s*CD + tid];
        size_t row = ((size_t)(s*BB + b)*NT + j)*CD;
        x[row + tid] = v;
        float ssum = v;
        #pragma unroll
        for (int o = 16; o; o >>= 1) ssum += __shfl_down_sync(0xffffffffu, ssum, o);
        if ((tid & 31) == 0) red[tid>>5] = ssum;
        __syncthreads();
        float mean = 0.f;
        #pragma unroll
        for (int i = 0; i < 8; i++) mean += red[i];
        mean *= (1.f/CD);
        __syncthreads();
        float d = v - mean;
        ssum = d*d;
        #pragma unroll
        for (int o = 16; o; o >>= 1) ssum += __shfl_down_sync(0xffffffffu, ssum, o);
        if ((tid & 31) == 0) red[tid>>5] = ssum;
        __syncthreads();
        float var = 0.f;
        #pragma unroll
        for (int i = 0; i < 8; i++) var += red[i];
        var *= (1.f/CD);
        Yh[row + tid] = __float2half_rn(d * rsqrtf(var + 1e-5f) * gw[tid] + gb[tid]);
        __syncthreads();
    }
}

// ---------------- LayerNorm (dual-stream) -> fp16 ----------------
__global__ void ln2(const float* __restrict__ X, __half* __restrict__ Yh,
                    const float* __restrict__ ga, const float* __restrict__ bba,
                    const float* __restrict__ gb2, const float* __restrict__ bbb,
                    const int* __restrict__ cnt)
{
    int bz = blockIdx.y; int s = bz >> 2, b = bz & 3;
    int n = blockIdx.x;
    if (n >= cnt[b]) return;
    const float* gw = s ? gb2 : ga;
    const float* gb = s ? bbb : bba;
    int tid = threadIdx.x;
    size_t row = ((size_t)(s*BB+b)*NT + n)*CD;
    float v = X[row + tid];
    __shared__ float red[8];
    float ssum = v;
    #pragma unroll
    for (int o = 16; o; o >>= 1) ssum += __shfl_down_sync(0xffffffffu, ssum, o);
    if ((tid & 31) == 0) red[tid>>5] = ssum;
    __syncthreads();
    float mean = 0.f;
    #pragma unroll
    for (int i = 0; i < 8; i++) mean += red[i];
    mean *= (1.f/CD);
    __syncthreads();
    float d = v - mean;
    ssum = d*d;
    #pragma unroll
    for (int o = 16; o; o >>= 1) ssum += __shfl_down_sync(0xffffffffu, ssum, o);
    if ((tid & 31) == 0) red[tid>>5] = ssum;
    __syncthreads();
    float var = 0.f;
    #pragma unroll
    for (int i = 0; i < 8; i++) var += red[i];
    var *= (1.f/CD);
    Yh[row + tid] = __float2half_rn(d * rsqrtf(var + 1e-5f) * gw[tid] + gb[tid]);
}

// ================= flash attention fp16 (max-free softmax), 3-stage, 2 CTAs/SM ======
#define AQR 144
#define AT_KVOFF (128*AQR)               // Q hi plane only
#define AT_STG (3*64*AQR)                // Kh,Kl,Vh
#define ATTN_SMEM (AT_KVOFF + 3*AT_STG)  // 101376

__global__ void __launch_bounds__(256, 2)
attn_mma(const __half* __restrict__ qkvhl, __half* __restrict__ att_h,
         const int* __restrict__ cnt)
{
    extern __shared__ char smc[];
    uint32_t sb = smem_u32(smc);
    int bz = blockIdx.z; int s = bz >> 2, b = bz & 3;
    int h = blockIdx.y, q0 = blockIdx.x*128;
    int Mb = cnt[b];
    if (q0 >= Mb) return;
    int tid = threadIdx.x, lane = tid & 31, w = tid >> 5;
    int gid = lane >> 2, tig = lane & 3;
    size_t rowbase = (size_t)(s*BB + b) * NT;
    const __half* qg = qkvhl;

    // Q hi prefetch
    {
        #pragma unroll
        for (int i = 0; i < 4; i++) {
            int f = tid + i*256;
            int row = f >> 3, c16 = f & 7;
            const char* src = (const char*)(qg + (rowbase + q0 + row)*768 + h*64) + c16*16;
            CP16P(sb + row*AQR + c16*16, src, (q0 + row) < Mb);
        }
    }
#define KV_PREFETCH(kt, st) do { \
    int k0_ = (kt)*64; \
    _Pragma("unroll") \
    for (int i_ = 0; i_ < 6; i_++) { \
        int f_ = tid + i_*256; \
        int pl_ = f_ >> 9, rem_ = f_ & 511; \
        int row_ = rem_ >> 3, c16_ = rem_ & 7; \
        int ko_ = (pl_ < 2) ? 256 : 512; \
        size_t hp_ = (pl_ == 1) ? QKV_PLANE : 0; \
        const char* src_ = (const char*)(qg + (rowbase + k0_ + row_)*768 + ko_ + h*64 + hp_) + c16_*16; \
        uint32_t dst_ = sb + AT_KVOFF + (st)*AT_STG + pl_*(64*AQR) + row_*AQR + c16_*16; \
        CP16P(dst_, src_, (k0_ + row_) < Mb); \
    } } while (0)

    int nkt = (Mb + 63) >> 6;
    KV_PREFETCH(0, 0);
    CPCOMMIT();
    if (nkt > 1) { KV_PREFETCH(1, 1); CPCOMMIT(); }

    uint32_t Qh[4][4];
    float oacc[8][4];
    #pragma unroll
    for (int j=0;j<8;j++)
        #pragma unroll
        for (int q=0;q<4;q++) oacc[j][q] = 0.f;
    float l0 = 0.f, l1 = 0.f;
    bool qload = false;

    for (int c = 0; c < nkt; c++) {
        if (c == nkt - 1) { CPWAIT(0); } else { CPWAIT(1); }
        __syncthreads();
        if (!qload) {
            qload = true;
            #pragma unroll
            for (int ks = 0; ks < 4; ks++) {
                uint32_t qa = sb + (uint32_t)((w*16 + (lane & 15)) * AQR) + ks*32 + ((lane >> 4) << 4);
                LDSM4(Qh[ks], qa);
            }
        }
        uint32_t kb = sb + AT_KVOFF + (c % 3)*AT_STG;
        uint32_t vb = kb + 2*(64*AQR);

        float sacc[8][4];
        #pragma unroll
        for (int j=0;j<8;j++)
            #pragma unroll
            for (int q=0;q<4;q++) sacc[j][q] = 0.f;
        #pragma unroll
        for (int ks = 0; ks < 4; ks++) {
            #pragma unroll
            for (int np = 0; np < 4; np++) {
                uint32_t ka = kb + (uint32_t)((np*16 + ((lane >> 4) << 3) + (lane & 7)) * AQR)
                            + ks*32 + (((lane >> 3) & 1) << 4);
                uint32_t Kh4[4], Kl4[4];
                LDSM4(Kh4, ka);
                LDSM4(Kl4, ka + 64*AQR);
                mma16816h(sacc[2*np],   Qh[ks], Kh4[0], Kh4[1]);
                mma16816h(sacc[2*np+1], Qh[ks], Kh4[2], Kh4[3]);
                mma16816h(sacc[2*np],   Qh[ks], Kl4[0], Kl4[1]);
                mma16816h(sacc[2*np+1], Qh[ks], Kl4[2], Kl4[3]);
            }
        }
        // max-free softmax: P = exp(S/8) (masked -> 0), accumulate row sums
        int kvb = c*64;
        float s0 = 0.f, s1 = 0.f;
        #pragma unroll
        for (int j = 0; j < 8; j++) {
            int t0 = kvb + j*8 + 2*tig;
            bool v0 = t0 < Mb, v1 = (t0 + 1) < Mb;
            sacc[j][0] = v0 ? __expf(sacc[j][0]*0.125f) : 0.f;
            sacc[j][1] = v1 ? __expf(sacc[j][1]*0.125f) : 0.f;
            sacc[j][2] = v0 ? __expf(sacc[j][2]*0.125f) : 0.f;
            sacc[j][3] = v1 ? __expf(sacc[j][3]*0.125f) : 0.f;
            s0 += sacc[j][0] + sacc[j][1];
            s1 += sacc[j][2] + sacc[j][3];
        }
        s0 += __shfl_xor_sync(0xffffffffu, s0, 1);
        s0 += __shfl_xor_sync(0xffffffffu, s0, 2);
        s1 += __shfl_xor_sync(0xffffffffu, s1, 1);
        s1 += __shfl_xor_sync(0xffffffffu, s1, 2);
        l0 += s0; l1 += s1;
        // O += P V (P hi-only fp16, V hi-only)
        #pragma unroll
        for (int kt = 0; kt < 4; kt++) {
            uint32_t aP[4];
            aP[0] = packh2(sacc[2*kt][0],   sacc[2*kt][1]);
            aP[1] = packh2(sacc[2*kt][2],   sacc[2*kt][3]);
            aP[2] = packh2(sacc[2*kt+1][0], sacc[2*kt+1][1]);
            aP[3] = packh2(sacc[2*kt+1][2], sacc[2*kt+1][3]);
            #pragma unroll
            for (int np = 0; np < 4; np++) {
                uint32_t va = vb + (uint32_t)((kt*16 + (((lane >> 3) & 1) << 3) + (lane & 7)) * AQR)
                            + (2*np + (lane >> 4))*16;
                uint32_t Vh4[4];
                LDSM4T(Vh4, va);
                mma16816h(oacc[2*np],   aP, Vh4[0], Vh4[1]);
                mma16816h(oacc[2*np+1], aP, Vh4[2], Vh4[3]);
            }
        }
        if (c + 2 < nkt) { KV_PREFETCH(c+2, (c+2) % 3); CPCOMMIT(); }
    }
#undef KV_PREFETCH

    float inv0 = 1.f / l0, inv1 = 1.f / l1;
    int qr0 = q0 + w*16 + gid;
    int qr1 = qr0 + 8;
    #pragma unroll
    for (int j = 0; j < 8; j++) {
        int col = h*64 + j*8 + 2*tig;
        if (qr0 < Mb)
            *(uint32_t*)&att_h[(rowbase + qr0)*CD + col] = packh2(oacc[j][0]*inv0, oacc[j][1]*inv0);
        if (qr1 < Mb)
            *(uint32_t*)&att_h[(rowbase + qr1)*CD + col] = packh2(oacc[j][2]*inv1, oacc[j][3]*inv1);
    }
}

// ---------------- output ----------------
__global__ void base_out(const float* __restrict__ fir, const float* __restrict__ fvis,
                         float* __restrict__ out)
{
    size_t i = (size_t)blockIdx.x*256 + threadIdx.x;
    float4 a = ((const float4*)fir)[i];
    float4 b = ((const float4*)fvis)[i];
    ((float4*)out)[i] = make_float4(a.x+b.x, a.y+b.y, a.z+b.z, a.w+b.w);
}

__global__ void scatter_out(const float* __restrict__ x0, const float* __restrict__ x1,
                            const int* __restrict__ list, const float* __restrict__ maskf,
                            const int* __restrict__ cnt, float* __restrict__ out)
{
    int b = blockIdx.y, j = blockIdx.x;
    if (j >= cnt[b]) return;
    int idx = list[b*NT + j];
    float mv = maskf[b*NT + idx];
    int c = threadIdx.x;
    float v = (x0[((size_t)b*NT + j)*CD + c] + x1[((size_t)b*NT + j)*CD + c]) * mv;
    out[((size_t)b*CD + c)*NT + idx] = v;
}

// ---------------- host ----------------
extern "C" void kernel_launch(void* const* d_in, const int* in_sizes, int n_in,
                              void* d_out, int out_size)
{
    const float* f_ir  = (const float*)d_in[0];
    const float* f_vis = (const float*)d_in[1];
    const float* aw1   = (const float*)d_in[2];
    const float* ab1   = (const float*)d_in[3];
    const float* aw2   = (const float*)d_in[4];
    const float* ab2   = (const float*)d_in[5];
    const float* ir_lng  = (const float*)d_in[6];
    const float* ir_lnb  = (const float*)d_in[7];
    const float* ir_wqkv = (const float*)d_in[8];
    const float* ir_bqkv = (const float*)d_in[9];
    const float* ir_wo   = (const float*)d_in[10];
    const float* ir_bo   = (const float*)d_in[11];
    const float* ir_w1   = (const float*)d_in[12];
    const float* ir_b1   = (const float*)d_in[13];
    const float* ir_w2   = (const float*)d_in[14];
    const float* ir_b2   = (const float*)d_in[15];
    const float* vi_lng  = (const float*)d_in[16];
    const float* vi_lnb  = (const float*)d_in[17];
    const float* vi_wqkv = (const float*)d_in[18];
    const float* vi_bqkv = (const float*)d_in[19];
    const float* vi_wo   = (const float*)d_in[20];
    const float* vi_bo   = (const float*)d_in[21];
    const float* vi_w1   = (const float*)d_in[22];
    const float* vi_b1   = (const float*)d_in[23];
    const float* vi_w2   = (const float*)d_in[24];
    const float* vi_b2   = (const float*)d_in[25];
    float* out = (float*)d_out;

    float *xcat,*partp,*maskf,*x;
    __nv_bfloat16 *wag,*xcathl;
    __half *w16,*xnh,*atth,*hidh,*qkvhl;
    int *list,*cntp;
    cudaGetSymbolAddress((void**)&xcat,  g_xcat);
    cudaGetSymbolAddress((void**)&partp, g_part);
    cudaGetSymbolAddress((void**)&maskf, g_maskf);
    cudaGetSymbolAddress((void**)&x,     g_x);
    cudaGetSymbolAddress((void**)&wag,   g_w_ag);
    cudaGetSymbolAddress((void**)&xcathl,g_xcat_hl);
    cudaGetSymbolAddress((void**)&w16,   g_w16);
    cudaGetSymbolAddress((void**)&xnh,   g_xn_h);
    cudaGetSymbolAddress((void**)&atth,  g_att_h);
    cudaGetSymbolAddress((void**)&hidh,  g_hid_h);
    cudaGetSymbolAddress((void**)&qkvhl, g_qkv_hl);
    cudaGetSymbolAddress((void**)&list,  g_list);
    cudaGetSymbolAddress((void**)&cntp,  g_cnt);
    float* x0 = x;
    float* x1 = x + (size_t)BB*NT*CD;

    cudaFuncSetAttribute(attn_mma, cudaFuncAttributeMaxDynamicSharedMemorySize, ATTN_SMEM);
    cudaFuncSetAttribute(gemm_agent, cudaFuncAttributeMaxDynamicSharedMemorySize, AGEMM_SMEM);
    cudaFuncSetAttribute(gemm_f16<128>, cudaFuncAttributeMaxDynamicSharedMemorySize, GEMM16_SMEM_128);
    cudaFuncSetAttribute(gemm_f16<64>,  cudaFuncAttributeMaxDynamicSharedMemorySize, GEMM16_SMEM_64);

    // weight conversions
    conv_wag<<<64, 256>>>(aw1, wag, 262144);
    W8 ws;
    const float* wsrc[8] = {ir_wqkv, vi_wqkv, ir_wo, vi_wo, ir_w1, vi_w1, ir_w2, vi_w2};
    const int    wn[8]   = {196608, 196608, 65536, 65536, 262144, 262144, 262144, 262144};
    int start = 0;
    for (int i = 0; i < 8; i++) { ws.src[i] = wsrc[i]; ws.n[i] = wn[i]; ws.start[i] = start; start += 2*wn[i]; }
    conv_w16<<<dim3(64, 8), 256>>>(ws, w16);

    // 1. token-major concat (+bf16 hi/lo for agent)
    transpose_cat<<<dim3(NT/32, CD/32, BB*2), dim3(32,8)>>>(f_ir, f_vis, xcat, xcathl);
    // 2. agent GEMM (bf16 3-term, bit-identical logits)
    gemm_agent<<<dim3(AGH/128, NT/128, BB), 256, AGEMM_SMEM>>>(
        xcathl, XCAT_PLANE, wag, 262144, ab1, 512, aw2, partp);
    // 3. selection
    select_kernel<<<BB, 256>>>(partp, ab2, list, cntp, maskf);
    // 4. fused gather + first LN (fp16 out)
    gather_ln<<<dim3(NT, BB), 256>>>(xcat, list, cntp, x, xnh,
                                     ir_lng, ir_lnb, vi_lng, vi_lnb);

    // 5. both mixers (fp16 2-term)
    gemm_f16<128><<<dim3(768/128, NT/128, 2*BB), 256, GEMM16_SMEM_128>>>(
        xnh, w16 + 0, w16 + 393216, 196608,
        ir_bqkv, vi_bqkv, (float*)0, qkvhl, QKV_PLANE, (const float*)0, cntp, 256, 768, 0);
    attn_mma<<<dim3(NT/128, NH, 2*BB), 256, ATTN_SMEM>>>(qkvhl, atth, cntp);
    gemm_f16<64><<<dim3(CD/128, NT/64, 2*BB), 256, GEMM16_SMEM_64>>>(
        atth, w16 + 786432, w16 + 917504, 65536,
        ir_bo, vi_bo, x, (__half*)0, 0, x, cntp, 256, CD, 0);
    ln2<<<dim3(NT, 2*BB), 256>>>(x, xnh, ir_lng, ir_lnb, vi_lng, vi_lnb, cntp);
    gemm_f16<128><<<dim3(1024/128, NT/128, 2*BB), 256, GEMM16_SMEM_128>>>(
        xnh, w16 + 1048576, w16 + 1572864, 262144,
        ir_b1, vi_b1, (float*)0, hidh, 0, (const float*)0, cntp, 256, 1024, 2);
    gemm_f16<64><<<dim3(CD/128, NT/64, 2*BB), 256, GEMM16_SMEM_64>>>(
        hidh, w16 + 2097152, w16 + 2621440, 262144,
        ir_b2, vi_b2, x, (__half*)0, 0, x, cntp, 1024, CD, 0);

    // 6. output
    base_out<<<(BB*CD*NT)/1024, 256>>>(f_ir, f_vis, out);
    scatter_out<<<dim3(NT, BB), 256>>>(x0, x1, list, maskf, cntp, out);
}

// round 14
// speedup vs baseline: 5.7679x; 1.0078x over previous
#include <cuda_runtime.h>
#include <cuda_bf16.h>
#include <cuda_fp16.h>
#include <math.h>
#include <stdint.h>

#define BB   4
#define NT   2304      // 48*48 tokens
#define CD   256       // DIM
#define AGH  512       // agent hidden
#define NH   4
#define DH   64

// plane sizes (elements)
#define XCAT_PLANE ((size_t)BB*NT*512)
#define XN_PLANE   ((size_t)2*BB*NT*CD)
#define ATT_PLANE  ((size_t)2*BB*NT*CD)
#define HID_PLANE  ((size_t)2*BB*NT*1024)
#define QKV_PLANE  ((size_t)2*BB*NT*768)

// ---------------- HMMA m16n8k16 (bf16 + fp16 variants) ----------------
__device__ __forceinline__ void mma16816(float* c, const uint32_t* a, uint32_t b0, uint32_t b1) {
    asm volatile("mma.sync.aligned.m16n8k16.row.col.f32.bf16.bf16.f32 "
        "{%0,%1,%2,%3}, {%4,%5,%6,%7}, {%8,%9}, {%0,%1,%2,%3};"
        : "+f"(c[0]), "+f"(c[1]), "+f"(c[2]), "+f"(c[3])
        : "r"(a[0]), "r"(a[1]), "r"(a[2]), "r"(a[3]), "r"(b0), "r"(b1));
}
__device__ __forceinline__ void mma16816h(float* c, const uint32_t* a, uint32_t b0, uint32_t b1) {
    asm volatile("mma.sync.aligned.m16n8k16.row.col.f32.f16.f16.f32 "
        "{%0,%1,%2,%3}, {%4,%5,%6,%7}, {%8,%9}, {%0,%1,%2,%3};"
        : "+f"(c[0]), "+f"(c[1]), "+f"(c[2]), "+f"(c[3])
        : "r"(a[0]), "r"(a[1]), "r"(a[2]), "r"(a[3]), "r"(b0), "r"(b1));
}

__device__ __forceinline__ uint32_t smem_u32(const void* p) {
    uint32_t a;
    asm("{ .reg .u64 t; cvta.to.shared.u64 t, %1; cvt.u32.u64 %0, t; }" : "=r"(a) : "l"(p));
    return a;
}
#define CP16(dst, src) asm volatile("cp.async.cg.shared.global [%0], [%1], 16;" :: "r"(dst), "l"(src))
#define CP16P(dst, src, p) asm volatile("cp.async.cg.shared.global [%0], [%1], 16, %2;" :: "r"(dst), "l"(src), "r"((p)?16:0))
#define CPCOMMIT()     asm volatile("cp.async.commit_group;" ::: "memory")
#define CPWAIT(n)      asm volatile("cp.async.wait_group %0;" :: "n"(n) : "memory")
#define LDSM4(r, a) asm volatile("ldmatrix.sync.aligned.m8n8.x4.shared.b16 {%0,%1,%2,%3}, [%4];" \
    : "=r"((r)[0]), "=r"((r)[1]), "=r"((r)[2]), "=r"((r)[3]) : "r"(a))
#define LDSM4T(r, a) asm volatile("ldmatrix.sync.aligned.m8n8.x4.trans.shared.b16 {%0,%1,%2,%3}, [%4];" \
    : "=r"((r)[0]), "=r"((r)[1]), "=r"((r)[2]), "=r"((r)[3]) : "r"(a))

// bf16 helpers (agent path — bit-identical mask)
__device__ __forceinline__ void split_hl(float v, __nv_bfloat16& h, __nv_bfloat16& l) {
    h = __float2bfloat16_rn(v);
    l = __float2bfloat16_rn(v - __bfloat162float(h));
}
__device__ __forceinline__ void cvt_pack(float4 v, uint2& h, uint2& l) {
    __nv_bfloat16 h0,l0,h1,l1,h2,l2,h3,l3;
    split_hl(v.x,h0,l0); split_hl(v.y,h1,l1); split_hl(v.z,h2,l2); split_hl(v.w,h3,l3);
    h.x = ((uint32_t)__bfloat16_as_ushort(h1)<<16)|(uint32_t)__bfloat16_as_ushort(h0);
    h.y = ((uint32_t)__bfloat16_as_ushort(h3)<<16)|(uint32_t)__bfloat16_as_ushort(h2);
    l.x = ((uint32_t)__bfloat16_as_ushort(l1)<<16)|(uint32_t)__bfloat16_as_ushort(l0);
    l.y = ((uint32_t)__bfloat16_as_ushort(l3)<<16)|(uint32_t)__bfloat16_as_ushort(l2);
}
// fp16 helpers
__device__ __forceinline__ uint32_t packh2(float a, float b) {
    __half2 h2 = __floats2half2_rn(a, b);
    return *reinterpret_cast<uint32_t*>(&h2);
}
__device__ __forceinline__ void pack_hl2h(float a, float b, uint32_t& ph, uint32_t& pl) {
    __half ha = __float2half_rn(a), hb = __float2half_rn(b);
    float la = a - __half2float(ha), lb = b - __half2float(hb);
    ph = ((uint32_t)__half_as_ushort(hb)<<16)|(uint32_t)__half_as_ushort(ha);
    pl = ((uint32_t)__half_as_ushort(__float2half_rn(lb))<<16)
       | (uint32_t)__half_as_ushort(__float2half_rn(la));
}

// ---------------- scratch ----------------
__device__ float g_xcat[(size_t)BB*NT*512];
__device__ float g_part[(size_t)BB*NT*4];
__device__ float g_maskf [BB*NT];
__device__ int   g_list[BB*NT];
__device__ int   g_iinv[BB*NT];
__device__ int   g_cnt [BB];
__device__ float g_x  [(size_t)2*BB*NT*CD];
__device__ __align__(16) __nv_bfloat16 g_w_ag [2*262144];
__device__ __align__(16) __nv_bfloat16 g_xcat_hl[2*XCAT_PLANE];
__device__ __align__(16) __half g_w16  [3145728];
__device__ __align__(16) __half g_xn_h [XN_PLANE];
__device__ __align__(16) __half g_att_h[ATT_PLANE];
__device__ __align__(16) __half g_hid_h[HID_PLANE];
__device__ __align__(16) __half g_qkv_hl[2*QKV_PLANE];

// ---------------- weight converts ----------------
__global__ void conv_wag(const float* __restrict__ src, __nv_bfloat16* __restrict__ dst, int n)
{
    __nv_bfloat16* dh = dst;
    __nv_bfloat16* dl = dst + n;
    int n4 = n >> 2;
    for (int i = blockIdx.x*256 + threadIdx.x; i < n4; i += gridDim.x*256) {
        float4 v = ((const float4*)src)[i];
        uint2 h, l; cvt_pack(v, h, l);
        *(uint2*)&dh[i*4] = h;
        *(uint2*)&dl[i*4] = l;
    }
}
struct W8 { const float* src[8]; int start[8]; int n[8]; };
__global__ void conv_w16(W8 a, __half* __restrict__ dst)
{
    int w = blockIdx.y;
    int n = a.n[w];
    const float4* s = (const float4*)a.src[w];
    __half* dh = dst + a.start[w];
    __half* dl = dh + n;
    int n4 = n >> 2;
    for (int i = blockIdx.x*256 + threadIdx.x; i < n4; i += gridDim.x*256) {
        float4 v = s[i];
        uint32_t h0,l0,h1,l1;
        pack_hl2h(v.x, v.y, h0, l0);
        pack_hl2h(v.z, v.w, h1, l1);
        *(uint2*)&dh[i*4] = make_uint2(h0, h1);
        *(uint2*)&dl[i*4] = make_uint2(l0, l1);
    }
}

// ---------------- transpose [B,C,N] -> token-major concat + bf16 hi/lo (agent) ----------------
__global__ void transpose_cat(const float* __restrict__ fir, const float* __restrict__ fvis,
                              float* __restrict__ xcat, __nv_bfloat16* __restrict__ xcat_hl)
{
    int src = blockIdx.z & 1;
    int b   = blockIdx.z >> 1;
    const float* f = src ? fvis : fir;
    __shared__ float tile[32][33];
    int n0 = blockIdx.x * 32, c0 = blockIdx.y * 32;
    int tx = threadIdx.x, ty = threadIdx.y;
    #pragma unroll
    for (int i = 0; i < 32; i += 8)
        tile[ty + i][tx] = f[((size_t)b*CD + c0 + ty + i)*NT + n0 + tx];
    __syncthreads();
    #pragma unroll
    for (int i = 0; i < 32; i += 8) {
        float v = tile[tx][ty + i];
        size_t idx = ((size_t)b*NT + n0 + ty + i)*512 + src*CD + c0 + tx;
        xcat[idx] = v;
        __nv_bfloat16 h, l; split_hl(v, h, l);
        xcat_hl[idx] = h;
        xcat_hl[XCAT_PLANE + idx] = l;
    }
}

#define RSB   80
#define MATB  (128*RSB)

__device__ __forceinline__ float actf(float t, int act) {
    if (act == 1) return t / (1.f + expf(-t));
    if (act == 2) return 0.5f*t*(1.f + erff(t*0.70710678118654752f));
    return t;
}

// ================= agent GEMM: bf16 3-term, 2-stage, 2 CTAs/SM, term-major order ============
#define STAGEA (4*MATB)
#define AGEMM_SMEM (2*STAGEA)   // 81920
__global__ void __launch_bounds__(256, 2)
gemm_agent(const __nv_bfloat16* __restrict__ Ahl, size_t aplane,
           const __nv_bfloat16* __restrict__ Wh, size_t wplane,
           const float* __restrict__ bias, int K,
           const float* __restrict__ logit_w, float* __restrict__ part)
{
    int b = blockIdx.z;
    int m0 = blockIdx.y * 128;
    int o0 = blockIdx.x * 128;
    size_t rowbase = (size_t)b * NT;
    const __nv_bfloat16* Ah_g = Ahl + (rowbase + m0) * K;
    const __nv_bfloat16* Al_g = Ah_g + aplane;
    const __nv_bfloat16* Wh_g = Wh + (size_t)o0 * K;
    const __nv_bfloat16* Wl_g = Wh_g + wplane;

    extern __shared__ char smem[];
    uint32_t sbase = smem_u32(smem);
    int tid = threadIdx.x, lane = tid & 31, w = tid >> 5;
    int wm = w & 3, wn = w >> 2;
    int gid = lane >> 2, tig = lane & 3;

    float acc[2][8][4];
    #pragma unroll
    for (int mt=0; mt<2; mt++)
        #pragma unroll
        for (int nt=0; nt<8; nt++)
            #pragma unroll
            for (int q=0; q<4; q++) acc[mt][nt][q] = 0.f;

#define PREFA(cc, st) do { \
    uint32_t sb_ = sbase + (st)*STAGEA; \
    _Pragma("unroll") \
    for (int i_ = 0; i_ < 2; i_++) { \
        int f_ = tid + i_*256; int row_ = f_ >> 2; int jb_ = (f_ & 3) * 16; \
        size_t go_ = (size_t)row_*K + (size_t)(cc)*32; \
        uint32_t so_ = sb_ + (uint32_t)(row_*RSB + jb_); \
        CP16(so_, (const char*)(Ah_g + go_) + jb_); \
        CP16(so_ + MATB, (const char*)(Al_g + go_) + jb_); \
        CP16(so_ + 2*MATB, (const char*)(Wh_g + go_) + jb_); \
        CP16(so_ + 3*MATB, (const char*)(Wl_g + go_) + jb_); \
    } } while (0)

    int nchunk = K >> 5;
    PREFA(0, 0);
    CPCOMMIT();

    for (int c = 0; c < nchunk; c++) {
        if (c + 1 < nchunk) { PREFA(c+1, (c+1)&1); CPCOMMIT(); CPWAIT(1); }
        else { CPWAIT(0); }
        __syncthreads();
        uint32_t stg = sbase + (c & 1) * STAGEA;
        #pragma unroll
        for (int ks = 0; ks < 2; ks++) {
            uint32_t colb = (uint32_t)(ks*32 + ((lane >> 4) << 4));
            uint32_t Ahf[2][4], Alf[2][4];
            #pragma unroll
            for (int mt = 0; mt < 2; mt++) {
                uint32_t sa = stg + (uint32_t)((wm*32 + mt*16 + (lane & 15)) * RSB) + colb;
                LDSM4(Ahf[mt], sa);
                LDSM4(Alf[mt], sa + MATB);
            }
            #pragma unroll
            for (int np = 0; np < 4; np++) {
                uint32_t sb = stg + 2*MATB + (uint32_t)((wn*64 + np*16 + (lane & 15)) * RSB) + colb;
                uint32_t Bh[4], Bl[4];
                LDSM4(Bh, sb);
                LDSM4(Bl, sb + MATB);
                mma16816(acc[0][2*np],   Ahf[0], Bh[0], Bh[2]);
                mma16816(acc[0][2*np+1], Ahf[0], Bh[1], Bh[3]);
                mma16816(acc[1][2*np],   Ahf[1], Bh[0], Bh[2]);
                mma16816(acc[1][2*np+1], Ahf[1], Bh[1], Bh[3]);
                mma16816(acc[0][2*np],   Ahf[0], Bl[0], Bl[2]);
                mma16816(acc[0][2*np+1], Ahf[0], Bl[1], Bl[3]);
                mma16816(acc[1][2*np],   Ahf[1], Bl[0], Bl[2]);
                mma16816(acc[1][2*np+1], Ahf[1], Bl[1], Bl[3]);
                mma16816(acc[0][2*np],   Alf[0], Bh[0], Bh[2]);
                mma16816(acc[0][2*np+1], Alf[0], Bh[1], Bh[3]);
                mma16816(acc[1][2*np],   Alf[1], Bh[0], Bh[2]);
                mma16816(acc[1][2*np+1], Alf[1], Bh[1], Bh[3]);
            }
        }
        __syncthreads();
    }
#undef PREFA

    // fused agent-logit partials (identical math/order to R8-R12)
    float pr[4] = {0.f, 0.f, 0.f, 0.f};
    #pragma unroll
    for (int mt = 0; mt < 2; mt++) {
        #pragma unroll
        for (int nt = 0; nt < 8; nt++) {
            int col = o0 + wn*64 + nt*8 + 2*tig;
            float b0v = bias[col], b1v = bias[col+1];
            float w0 = logit_w[col], w1 = logit_w[col+1];
            float t0 = actf(acc[mt][nt][0] + b0v, 1);
            float t1 = actf(acc[mt][nt][1] + b1v, 1);
            float t2 = actf(acc[mt][nt][2] + b0v, 1);
            float t3 = actf(acc[mt][nt][3] + b1v, 1);
            pr[mt*2+0] += t0*w0 + t1*w1;
            pr[mt*2+1] += t2*w0 + t3*w1;
        }
    }
    #pragma unroll
    for (int i = 0; i < 4; i++) {
        pr[i] += __shfl_xor_sync(0xffffffffu, pr[i], 1);
        pr[i] += __shfl_xor_sync(0xffffffffu, pr[i], 2);
    }
    __syncthreads();
    float* red = (float*)smem;
    if (tig == 0) {
        #pragma unroll
        for (int mt = 0; mt < 2; mt++) {
            red[wn*128 + wm*32 + mt*16 + gid]     = pr[mt*2+0];
            red[wn*128 + wm*32 + mt*16 + gid + 8] = pr[mt*2+1];
        }
    }
    __syncthreads();
    if (tid < 128)
        part[((size_t)b*NT + m0 + tid)*4 + blockIdx.x] = red[tid] + red[128 + tid];
}

// ======= fp16 2-term GEMM, BMT x 128 block, 64mx32o-class warp tiles (LDSM-balanced) =======
template<int BMT>
__global__ void __launch_bounds__(256, 2)
gemm_f16(const __half* __restrict__ Aall,
         const __half* __restrict__ Wah, const __half* __restrict__ Wbh, size_t wplane,
         const float* __restrict__ ba, const float* __restrict__ bbv,
         float* __restrict__ Cf, __half* __restrict__ Ch, size_t cplane,
         const float* __restrict__ R,
         const int* __restrict__ counts, int K, int Ocols, int act)
{
    constexpr int NWM   = 2;
    constexpr int WMEXT = BMT / NWM;      // 64 or 32 rows per warp
    constexpr int MT    = WMEXT / 16;     // 4 or 2
    constexpr int AMATB = BMT * RSB;
    constexpr int WMATB = 128 * RSB;
    constexpr int STG   = AMATB + 2*WMATB;
    constexpr int NITER = ((BMT + 256) * 4) / 256;

    int bz = blockIdx.z;
    int s = (bz >= BB) ? 1 : 0;
    int b = bz & 3;
    int Mb = counts[b];
    int m0 = blockIdx.y * BMT;
    if (m0 >= Mb) return;
    int o0 = blockIdx.x * 128;
    const __half* Wsel = s ? Wbh : Wah;
    const float* bias = s ? bbv : ba;
    size_t rowbase = (size_t)(s*BB + b) * NT;
    const __half* Ah_g = Aall + (rowbase + m0) * K;
    const __half* Wh_g = Wsel + (size_t)o0 * K;
    const __half* Wl_g = Wh_g + wplane;
    float* Cfb = Cf ? Cf + rowbase * Ocols : (float*)0;
    __half* Chb = Ch ? Ch + rowbase * Ocols : (__half*)0;
    const float* Rb = R ? R + rowbase * Ocols : (const float*)0;

    extern __shared__ char smem[];
    uint32_t sbase = smem_u32(smem);
    int tid = threadIdx.x, lane = tid & 31, w = tid >> 5;
    int wm = w & 1, wn = w >> 1;          // 2 m-warps x 4 n-warps
    int gid = lane >> 2, tig = lane & 3;

    float acc[MT][4][4];
    #pragma unroll
    for (int mt=0; mt<MT; mt++)
        #pragma unroll
        for (int nt=0; nt<4; nt++)
            #pragma unroll
            for (int q=0; q<4; q++) acc[mt][nt][q] = 0.f;

#define PREF16(cc, st) do { \
    uint32_t sb_ = sbase + (st)*STG; \
    _Pragma("unroll") \
    for (int i_ = 0; i_ < NITER; i_++) { \
        int f_ = tid + i_*256; int row_ = f_ >> 2; int jb_ = (f_ & 3) * 16; \
        const char* p_; uint32_t soff_; \
        if (row_ < BMT)            { p_ = (const char*)(Ah_g + (size_t)row_*K + (size_t)(cc)*32); soff_ = (uint32_t)(row_*RSB); } \
        else if (row_ < BMT + 128) { int r_ = row_ - BMT;       p_ = (const char*)(Wh_g + (size_t)r_*K + (size_t)(cc)*32); soff_ = (uint32_t)(AMATB + r_*RSB); } \
        else                       { int r_ = row_ - BMT - 128; p_ = (const char*)(Wl_g + (size_t)r_*K + (size_t)(cc)*32); soff_ = (uint32_t)(AMATB + WMATB + r_*RSB); } \
        CP16(sb_ + soff_ + jb_, p_ + jb_); \
    } } while (0)

    int nchunk = K >> 5;
    PREF16(0, 0);
    CPCOMMIT();
    if (nchunk > 1) { PREF16(1, 1); CPCOMMIT(); }

    for (int c = 0; c < nchunk; c++) {
        if (c == nchunk - 1) { CPWAIT(0); } else { CPWAIT(1); }
        __syncthreads();
        uint32_t stg = sbase + (c % 3) * STG;
        #pragma unroll
        for (int ks = 0; ks < 2; ks++) {
            uint32_t colb = (uint32_t)(ks*32 + ((lane >> 4) << 4));
            uint32_t Ahf[MT][4];
            #pragma unroll
            for (int mt = 0; mt < MT; mt++) {
                uint32_t sa = stg + (uint32_t)((wm*WMEXT + mt*16 + (lane & 15)) * RSB) + colb;
                LDSM4(Ahf[mt], sa);
            }
            #pragma unroll
            for (int np = 0; np < 2; np++) {
                uint32_t sb = stg + AMATB + (uint32_t)((wn*32 + np*16 + (lane & 15)) * RSB) + colb;
                uint32_t Bh[4], Bl[4];
                LDSM4(Bh, sb);
                LDSM4(Bl, sb + WMATB);
                // hi-term pass (2*MT independent), then lo-term pass
                #pragma unroll
                for (int mt = 0; mt < MT; mt++) {
                    mma16816h(acc[mt][2*np],   Ahf[mt], Bh[0], Bh[2]);
                    mma16816h(acc[mt][2*np+1], Ahf[mt], Bh[1], Bh[3]);
                }
                #pragma unroll
                for (int mt = 0; mt < MT; mt++) {
                    mma16816h(acc[mt][2*np],   Ahf[mt], Bl[0], Bl[2]);
                    mma16816h(acc[mt][2*np+1], Ahf[mt], Bl[1], Bl[3]);
                }
            }
        }
        if (c + 2 < nchunk) { PREF16(c+2, (c+2) % 3); CPCOMMIT(); }
    }
#undef PREF16

    #pragma unroll
    for (int mt = 0; mt < MT; mt++) {
        int r0 = m0 + wm*WMEXT + mt*16 + gid;
        int r1 = r0 + 8;
        #pragma unroll
        for (int nt = 0; nt < 4; nt++) {
            int col = o0 + wn*32 + nt*8 + 2*tig;
            float b0v = bias[col], b1v = bias[col+1];
            float t0 = actf(acc[mt][nt][0] + b0v, act);
            float t1 = actf(acc[mt][nt][1] + b1v, act);
            float t2 = actf(acc[mt][nt][2] + b0v, act);
            float t3 = actf(acc[mt][nt][3] + b1v, act);
            if (Cfb) {
                if (r0 < Mb) {
                    if (Rb) { t0 += Rb[(size_t)r0*Ocols + col]; t1 += Rb[(size_t)r0*Ocols + col + 1]; }
                    *(float2*)&Cfb[(size_t)r0*Ocols + col] = make_float2(t0, t1);
                }
                if (r1 < Mb) {
                    if (Rb) { t2 += Rb[(size_t)r1*Ocols + col]; t3 += Rb[(size_t)r1*Ocols + col + 1]; }
                    *(float2*)&Cfb[(size_t)r1*Ocols + col] = make_float2(t2, t3);
                }
            } else if (cplane) {
                bool wantlo = (col >= 256) && (col < 512);
                if (r0 < Mb) {
                    if (wantlo) {
                        uint32_t ph, pl; pack_hl2h(t0, t1, ph, pl);
                        *(uint32_t*)&Chb[(size_t)r0*Ocols + col] = ph;
                        *(uint32_t*)&Chb[cplane + (size_t)r0*Ocols + col] = pl;
                    } else {
                        *(uint32_t*)&Chb[(size_t)r0*Ocols + col] = packh2(t0, t1);
                    }
                }
                if (r1 < Mb) {
                    if (wantlo) {
                        uint32_t ph, pl; pack_hl2h(t2, t3, ph, pl);
                        *(uint32_t*)&Chb[(size_t)r1*Ocols + col] = ph;
                        *(uint32_t*)&Chb[cplane + (size_t)r1*Ocols + col] = pl;
                    } else {
                        *(uint32_t*)&Chb[(size_t)r1*Ocols + col] = packh2(t2, t3);
                    }
                }
            } else {
                if (r0 < Mb) *(uint32_t*)&Chb[(size_t)r0*Ocols + col] = packh2(t0, t1);
                if (r1 < Mb) *(uint32_t*)&Chb[(size_t)r1*Ocols + col] = packh2(t2, t3);
            }
        }
    }
}

#define GEMM16_SMEM_128 (3*((128+256)*RSB))   // 92160
#define GEMM16_SMEM_64  (3*((64+256)*RSB))    // 76800

// ---------------- selection (logits from partials) + inverse index ----------------
__global__ void select_kernel(const float* __restrict__ part, const float* __restrict__ ab2,
                              int* __restrict__ list, int* __restrict__ cnt,
                              float* __restrict__ maskf, int* __restrict__ iinv)
{
    int b = blockIdx.x, tid = threadIdx.x;
    const int PER = NT/256;  // 9
    __shared__ int cn[256];
    float ab2v = ab2[0];
    int base = tid*PER;
    float lv[PER];
    bool  sv[PER];
    int c = 0;
    #pragma unroll
    for (int i = 0; i < PER; i++) {
        size_t t4 = ((size_t)b*NT + base + i)*4;
        float lg = ((part[t4] + part[t4+1]) + (part[t4+2] + part[t4+3])) + ab2v;
        lv[i] = lg;
        bool sel = lg > 0.f; sv[i] = sel; c += sel;
        maskf[b*NT + base + i] = sel ? 1.f : 0.f;
        iinv[b*NT + base + i] = -1;
    }
    cn[tid] = c; __syncthreads();
    for (int off = 1; off < 256; off <<= 1) {
        int v = (tid >= off) ? cn[tid-off] : 0;
        __syncthreads();
        cn[tid] += v;
        __syncthreads();
    }
    int total = cn[255];
    int pos = cn[tid] - c;
    if (total >= 64) {
        #pragma unroll
        for (int i = 0; i < PER; i++)
            if (sv[i]) { list[b*NT + pos] = base + i; iinv[b*NT + base + i] = pos; pos++; }
        if (tid == 0) cnt[b] = total;
    } else {
        __shared__ float sl[NT];
        #pragma unroll
        for (int i = 0; i < PER; i++) sl[base+i] = lv[i];
        __syncthreads();
        if (tid == 0) {
            for (int t = 0; t < 64; t++) {
                int am = 0; float mv = sl[0];
                for (int n = 1; n < NT; n++) if (sl[n] > mv) { mv = sl[n]; am = n; }
                list[b*NT + t] = am; iinv[b*NT + am] = t; sl[am] = -1e30f;
            }
            cnt[b] = 64;
        }
    }
}

// ---------------- fused gather + LayerNorm (both streams) -> fp16 ----------------
__global__ void gather_ln(const float* __restrict__ xcat, const int* __restrict__ list,
                          const int* __restrict__ cnt,
                          float* __restrict__ x, __half* __restrict__ Yh,
                          const float* __restrict__ ga, const float* __restrict__ bba,
                          const float* __restrict__ gb2, const float* __restrict__ bbb)
{
    int b = blockIdx.y, j = blockIdx.x;
    if (j >= cnt[b]) return;
    int idx = list[b*NT + j];
    int tid = threadIdx.x;
    const float* src = xcat + ((size_t)b*NT + idx)*512;
    __shared__ float red[8];
    #pragma unroll
    for (int s = 0; s < 2; s++) {
        const float* gw = s ? gb2 : ga;
        const float* gb = s ? bbb : bba;
        float v = src[s*CD + tid];
        size_t row = ((size_t)(s*BB + b)*NT + j)*CD;
        x[row + tid] = v;
        float ssum = v;
        #pragma unroll
        for (int o = 16; o; o >>= 1) ssum += __shfl_down_sync(0xffffffffu, ssum, o);
        if ((tid & 31) == 0) red[tid>>5] = ssum;
        __syncthreads();
        float mean = 0.f;
        #pragma unroll
        for (int i = 0; i < 8; i++) mean += red[i];
        mean *= (1.f/CD);
        __syncthreads();
        float d = v - mean;
        ssum = d*d;
        #pragma unroll
        for (int o = 16; o; o >>= 1) ssum += __shfl_down_sync(0xffffffffu, ssum, o);
        if ((tid & 31) == 0) red[tid>>5] = ssum;
        __syncthreads();
        float var = 0.f;
        #pragma unroll
        for (int i = 0; i < 8; i++) var += red[i];
        var *= (1.f/CD);
        Yh[row + tid] = __float2half_rn(d * rsqrtf(var + 1e-5f) * gw[tid] + gb[tid]);
        __syncthreads();
    }
}

// ---------------- LayerNorm (dual-stream) -> fp16 ----------------
__global__ void ln2(const float* __restrict__ X, __half* __restrict__ Yh,
                    const float* __restrict__ ga, const float* __restrict__ bba,
                    const float* __restrict__ gb2, const float* __restrict__ bbb,
                    const int* __restrict__ cnt)
{
    int bz = blockIdx.y; int s = bz >> 2, b = bz & 3;
    int n = blockIdx.x;
    if (n >= cnt[b]) return;
    const float* gw = s ? gb2 : ga;
    const float* gb = s ? bbb : bba;
    int tid = threadIdx.x;
    size_t row = ((size_t)(s*BB+b)*NT + n)*CD;
    float v = X[row + tid];
    __shared__ float red[8];
    float ssum = v;
    #pragma unroll
    for (int o = 16; o; o >>= 1) ssum += __shfl_down_sync(0xffffffffu, ssum, o);
    if ((tid & 31) == 0) red[tid>>5] = ssum;
    __syncthreads();
    float mean = 0.f;
    #pragma unroll
    for (int i = 0; i < 8; i++) mean += red[i];
    mean *= (1.f/CD);
    __syncthreads();
    float d = v - mean;
    ssum = d*d;
    #pragma unroll
    for (int o = 16; o; o >>= 1) ssum += __shfl_down_sync(0xffffffffu, ssum, o);
    if ((tid & 31) == 0) red[tid>>5] = ssum;
    __syncthreads();
    float var = 0.f;
    #pragma unroll
    for (int i = 0; i < 8; i++) var += red[i];
    var *= (1.f/CD);
    Yh[row + tid] = __float2half_rn(d * rsqrtf(var + 1e-5f) * gw[tid] + gb[tid]);
}

// ================= flash attention fp16 (max-free softmax), 3-stage, 2 CTAs/SM ======
#define AQR 144
#define AT_KVOFF (128*AQR)
#define AT_STG (3*64*AQR)
#define ATTN_SMEM (AT_KVOFF + 3*AT_STG)  // 101376

__global__ void __launch_bounds__(256, 2)
attn_mma(const __half* __restrict__ qkvhl, __half* __restrict__ att_h,
         const int* __restrict__ cnt)
{
    extern __shared__ char smc[];
    uint32_t sb = smem_u32(smc);
    int bz = blockIdx.z; int s = bz >> 2, b = bz & 3;
    int h = blockIdx.y, q0 = blockIdx.x*128;
    int Mb = cnt[b];
    if (q0 >= Mb) return;
    int tid = threadIdx.x, lane = tid & 31, w = tid >> 5;
    int gid = lane >> 2, tig = lane & 3;
    size_t rowbase = (size_t)(s*BB + b) * NT;
    const __half* qg = qkvhl;

    {
        #pragma unroll
        for (int i = 0; i < 4; i++) {
            int f = tid + i*256;
            int row = f >> 3, c16 = f & 7;
            const char* src = (const char*)(qg + (rowbase + q0 + row)*768 + h*64) + c16*16;
            CP16P(sb + row*AQR + c16*16, src, (q0 + row) < Mb);
        }
    }
#define KV_PREFETCH(kt, st) do { \
    int k0_ = (kt)*64; \
    _Pragma("unroll") \
    for (int i_ = 0; i_ < 6; i_++) { \
        int f_ = tid + i_*256; \
        int pl_ = f_ >> 9, rem_ = f_ & 511; \
        int row_ = rem_ >> 3, c16_ = rem_ & 7; \
        int ko_ = (pl_ < 2) ? 256 : 512; \
        size_t hp_ = (pl_ == 1) ? QKV_PLANE : 0; \
        const char* src_ = (const char*)(qg + (rowbase + k0_ + row_)*768 + ko_ + h*64 + hp_) + c16_*16; \
        uint32_t dst_ = sb + AT_KVOFF + (st)*AT_STG + pl_*(64*AQR) + row_*AQR + c16_*16; \
        CP16P(dst_, src_, (k0_ + row_) < Mb); \
    } } while (0)

    int nkt = (Mb + 63) >> 6;
    KV_PREFETCH(0, 0);
    CPCOMMIT();
    if (nkt > 1) { KV_PREFETCH(1, 1); CPCOMMIT(); }

    uint32_t Qh[4][4];
    float oacc[8][4];
    #pragma unroll
    for (int j=0;j<8;j++)
        #pragma unroll
        for (int q=0;q<4;q++) oacc[j][q] = 0.f;
    float l0 = 0.f, l1 = 0.f;
    bool qload = false;

    for (int c = 0; c < nkt; c++) {
        if (c == nkt - 1) { CPWAIT(0); } else { CPWAIT(1); }
        __syncthreads();
        if (!qload) {
            qload = true;
            #pragma unroll
            for (int ks = 0; ks < 4; ks++) {
                uint32_t qa = sb + (uint32_t)((w*16 + (lane & 15)) * AQR) + ks*32 + ((lane >> 4) << 4);
                LDSM4(Qh[ks], qa);
            }
        }
        uint32_t kb = sb + AT_KVOFF + (c % 3)*AT_STG;
        uint32_t vb = kb + 2*(64*AQR);

        float sacc[8][4];
        #pragma unroll
        for (int j=0;j<8;j++)
            #pragma unroll
            for (int q=0;q<4;q++) sacc[j][q] = 0.f;
        #pragma unroll
        for (int ks = 0; ks < 4; ks++) {
            #pragma unroll
            for (int np = 0; np < 4; np++) {
                uint32_t ka = kb + (uint32_t)((np*16 + ((lane >> 4) << 3) + (lane & 7)) * AQR)
                            + ks*32 + (((lane >> 3) & 1) << 4);
                uint32_t Kh4[4], Kl4[4];
                LDSM4(Kh4, ka);
                LDSM4(Kl4, ka + 64*AQR);
                mma16816h(sacc[2*np],   Qh[ks], Kh4[0], Kh4[1]);
                mma16816h(sacc[2*np+1], Qh[ks], Kh4[2], Kh4[3]);
                mma16816h(sacc[2*np],   Qh[ks], Kl4[0], Kl4[1]);
                mma16816h(sacc[2*np+1], Qh[ks], Kl4[2], Kl4[3]);
            }
        }
        int kvb = c*64;
        float s0 = 0.f, s1 = 0.f;
        #pragma unroll
        for (int j = 0; j < 8; j++) {
            int t0 = kvb + j*8 + 2*tig;
            bool v0 = t0 < Mb, v1 = (t0 + 1) < Mb;
            sacc[j][0] = v0 ? __expf(sacc[j][0]*0.125f) : 0.f;
            sacc[j][1] = v1 ? __expf(sacc[j][1]*0.125f) : 0.f;
            sacc[j][2] = v0 ? __expf(sacc[j][2]*0.125f) : 0.f;
            sacc[j][3] = v1 ? __expf(sacc[j][3]*0.125f) : 0.f;
            s0 += sacc[j][0] + sacc[j][1];
            s1 += sacc[j][2] + sacc[j][3];
        }
        s0 += __shfl_xor_sync(0xffffffffu, s0, 1);
        s0 += __shfl_xor_sync(0xffffffffu, s0, 2);
        s1 += __shfl_xor_sync(0xffffffffu, s1, 1);
        s1 += __shfl_xor_sync(0xffffffffu, s1, 2);
        l0 += s0; l1 += s1;
        #pragma unroll
        for (int kt = 0; kt < 4; kt++) {
            uint32_t aP[4];
            aP[0] = packh2(sacc[2*kt][0],   sacc[2*kt][1]);
            aP[1] = packh2(sacc[2*kt][2],   sacc[2*kt][3]);
            aP[2] = packh2(sacc[2*kt+1][0], sacc[2*kt+1][1]);
            aP[3] = packh2(sacc[2*kt+1][2], sacc[2*kt+1][3]);
            #pragma unroll
            for (int np = 0; np < 4; np++) {
                uint32_t va = vb + (uint32_t)((kt*16 + (((lane >> 3) & 1) << 3) + (lane & 7)) * AQR)
                            + (2*np + (lane >> 4))*16;
                uint32_t Vh4[4];
                LDSM4T(Vh4, va);
                mma16816h(oacc[2*np],   aP, Vh4[0], Vh4[1]);
                mma16816h(oacc[2*np+1], aP, Vh4[2], Vh4[3]);
            }
        }
        if (c + 2 < nkt) { KV_PREFETCH(c+2, (c+2) % 3); CPCOMMIT(); }
    }
#undef KV_PREFETCH

    float inv0 = 1.f / l0, inv1 = 1.f / l1;
    int qr0 = q0 + w*16 + gid;
    int qr1 = qr0 + 8;
    #pragma unroll
    for (int j = 0; j < 8; j++) {
        int col = h*64 + j*8 + 2*tig;
        if (qr0 < Mb)
            *(uint32_t*)&att_h[(rowbase + qr0)*CD + col] = packh2(oacc[j][0]*inv0, oacc[j][1]*inv0);
        if (qr1 < Mb)
            *(uint32_t*)&att_h[(rowbase + qr1)*CD + col] = packh2(oacc[j][2]*inv1, oacc[j][3]*inv1);
    }
}

// ---------------- fused output: base + scatter, all-coalesced via 32x32 tile ----------------
__global__ void out_fuse(const float* __restrict__ fir, const float* __restrict__ fvis,
                         const float* __restrict__ x0, const float* __restrict__ x1,
                         const int* __restrict__ iinv, const float* __restrict__ maskf,
                         float* __restrict__ out)
{
    int b = blockIdx.z;
    int n0 = blockIdx.x*32, c0 = blockIdx.y*32;
    int tx = threadIdx.x, ty = threadIdx.y;  // (32, 8)
    __shared__ float tile[32][33];           // [n_local][c_local]
    // load refined values token-major (coalesced in c)
    #pragma unroll
    for (int i = 0; i < 32; i += 8) {
        int n = n0 + ty + i;
        int j = iinv[b*NT + n];
        float v = 0.f;
        if (j >= 0) {
            float mv = maskf[b*NT + n];
            size_t r = ((size_t)b*NT + j)*CD + c0 + tx;
            v = (x0[r] + x1[r]) * mv;
        }
        tile[ty + i][tx] = v;
    }
    __syncthreads();
    // write channel-major (coalesced in n)
    #pragma unroll
    for (int i = 0; i < 32; i += 8) {
        int c = c0 + ty + i;
        int n = n0 + tx;
        size_t o = ((size_t)b*CD + c)*NT + n;
        int j = iinv[b*NT + n];
        float base = fir[o] + fvis[o];
        out[o] = (j >= 0) ? tile[tx][ty + i] : base;
    }
}

// ---------------- host ----------------
extern "C" void kernel_launch(void* const* d_in, const int* in_sizes, int n_in,
                              void* d_out, int out_size)
{
    const float* f_ir  = (const float*)d_in[0];
    const float* f_vis = (const float*)d_in[1];
    const float* aw1   = (const float*)d_in[2];
    const float* ab1   = (const float*)d_in[3];
    const float* aw2   = (const float*)d_in[4];
    const float* ab2   = (const float*)d_in[5];
    const float* ir_lng  = (const float*)d_in[6];
    const float* ir_lnb  = (const float*)d_in[7];
    const float* ir_wqkv = (const float*)d_in[8];
    const float* ir_bqkv = (const float*)d_in[9];
    const float* ir_wo   = (const float*)d_in[10];
    const float* ir_bo   = (const float*)d_in[11];
    const float* ir_w1   = (const float*)d_in[12];
    const float* ir_b1   = (const float*)d_in[13];
    const float* ir_w2   = (const float*)d_in[14];
    const float* ir_b2   = (const float*)d_in[15];
    const float* vi_lng  = (const float*)d_in[16];
    const float* vi_lnb  = (const float*)d_in[17];
    const float* vi_wqkv = (const float*)d_in[18];
    const float* vi_bqkv = (const float*)d_in[19];
    const float* vi_wo   = (const float*)d_in[20];
    const float* vi_bo   = (const float*)d_in[21];
    const float* vi_w1   = (const float*)d_in[22];
    const float* vi_b1   = (const float*)d_in[23];
    const float* vi_w2   = (const float*)d_in[24];
    const float* vi_b2   = (const float*)d_in[25];
    float* out = (float*)d_out;

    float *xcat,*partp,*maskf,*x;
    __nv_bfloat16 *wag,*xcathl;
    __half *w16,*xnh,*atth,*hidh,*qkvhl;
    int *list,*iinv,*cntp;
    cudaGetSymbolAddress((void**)&xcat,  g_xcat);
    cudaGetSymbolAddress((void**)&partp, g_part);
    cudaGetSymbolAddress((void**)&maskf, g_maskf);
    cudaGetSymbolAddress((void**)&x,     g_x);
    cudaGetSymbolAddress((void**)&wag,   g_w_ag);
    cudaGetSymbolAddress((void**)&xcathl,g_xcat_hl);
    cudaGetSymbolAddress((void**)&w16,   g_w16);
    cudaGetSymbolAddress((void**)&xnh,   g_xn_h);
    cudaGetSymbolAddress((void**)&atth,  g_att_h);
    cudaGetSymbolAddress((void**)&hidh,  g_hid_h);
    cudaGetSymbolAddress((void**)&qkvhl, g_qkv_hl);
    cudaGetSymbolAddress((void**)&list,  g_list);
    cudaGetSymbolAddress((void**)&iinv,  g_iinv);
    cudaGetSymbolAddress((void**)&cntp,  g_cnt);
    float* x0 = x;
    float* x1 = x + (size_t)BB*NT*CD;

    cudaFuncSetAttribute(attn_mma, cudaFuncAttributeMaxDynamicSharedMemorySize, ATTN_SMEM);
    cudaFuncSetAttribute(gemm_agent, cudaFuncAttributeMaxDynamicSharedMemorySize, AGEMM_SMEM);
    cudaFuncSetAttribute(gemm_f16<128>, cudaFuncAttributeMaxDynamicSharedMemorySize, GEMM16_SMEM_128);
    cudaFuncSetAttribute(gemm_f16<64>,  cudaFuncAttributeMaxDynamicSharedMemorySize, GEMM16_SMEM_64);

    // weight conversions
    conv_wag<<<64, 256>>>(aw1, wag, 262144);
    W8 ws;
    const float* wsrc[8] = {ir_wqkv, vi_wqkv, ir_wo, vi_wo, ir_w1, vi_w1, ir_w2, vi_w2};
    const int    wn[8]   = {196608, 196608, 65536, 65536, 262144, 262144, 262144, 262144};
    int start = 0;
    for (int i = 0; i < 8; i++) { ws.src[i] = wsrc[i]; ws.n[i] = wn[i]; ws.start[i] = start; start += 2*wn[i]; }
    conv_w16<<<dim3(64, 8), 256>>>(ws, w16);

    // 1. token-major concat (+bf16 hi/lo for agent)
    transpose_cat<<<dim3(NT/32, CD/32, BB*2), dim3(32,8)>>>(f_ir, f_vis, xcat, xcathl);
    // 2. agent GEMM (bf16 3-term, bit-identical logits)
    gemm_agent<<<dim3(AGH/128, NT/128, BB), 256, AGEMM_SMEM>>>(
        xcathl, XCAT_PLANE, wag, 262144, ab1, 512, aw2, partp);
    // 3. selection (also builds inverse index)
    select_kernel<<<BB, 256>>>(partp, ab2, list, cntp, maskf, iinv);
    // 4. fused gather + first LN (fp16 out)
    gather_ln<<<dim3(NT, BB), 256>>>(xcat, list, cntp, x, xnh,
                                     ir_lng, ir_lnb, vi_lng, vi_lnb);

    // 5. both mixers (fp16 2-term)
    gemm_f16<128><<<dim3(768/128, NT/128, 2*BB), 256, GEMM16_SMEM_128>>>(
        xnh, w16 + 0, w16 + 393216, 196608,
        ir_bqkv, vi_bqkv, (float*)0, qkvhl, QKV_PLANE, (const float*)0, cntp, 256, 768, 0);
    attn_mma<<<dim3(NT/128, NH, 2*BB), 256, ATTN_SMEM>>>(qkvhl, atth, cntp);
    gemm_f16<64><<<dim3(CD/128, NT/64, 2*BB), 256, GEMM16_SMEM_64>>>(
        atth, w16 + 786432, w16 + 917504, 65536,
        ir_bo, vi_bo, x, (__half*)0, 0, x, cntp, 256, CD, 0);
    ln2<<<dim3(NT, 2*BB), 256>>>(x, xnh, ir_lng, ir_lnb, vi_lng, vi_lnb, cntp);
    gemm_f16<128><<<dim3(1024/128, NT/128, 2*BB), 256, GEMM16_SMEM_128>>>(
        xnh, w16 + 1048576, w16 + 1572864, 262144,
        ir_b1, vi_b1, (float*)0, hidh, 0, (const float*)0, cntp, 256, 1024, 2);
    gemm_f16<64><<<dim3(CD/128, NT/64, 2*BB), 256, GEMM16_SMEM_64>>>(
        hidh, w16 + 2097152, w16 + 2621440, 262144,
        ir_b2, vi_b2, x, (__half*)0, 0, x, cntp, 1024, CD, 0);

    // 6. fused output (all-coalesced)
    out_fuse<<<dim3(NT/32, CD/32, BB), dim3(32,8)>>>(f_ir, f_vis, x0, x1, iinv, maskf, out);
}

// round 15
// speedup vs baseline: 7.4995x; 1.3002x over previous
#include <cuda_runtime.h>
#include <cuda_bf16.h>
#include <cuda_fp16.h>
#include <math.h>
#include <stdint.h>

#define BB   4
#define NT   2304      // 48*48 tokens
#define CD   256       // DIM
#define AGH  512       // agent hidden
#define NH   4
#define DH   64

// plane sizes (elements)
#define XCAT_PLANE ((size_t)BB*NT*512)
#define XN_PLANE   ((size_t)2*BB*NT*CD)
#define ATT_PLANE  ((size_t)2*BB*NT*CD)
#define HID_PLANE  ((size_t)2*BB*NT*1024)
#define QKV_PLANE  ((size_t)2*BB*NT*768)

// ---------------- HMMA m16n8k16 (bf16 + fp16 variants) ----------------
__device__ __forceinline__ void mma16816(float* c, const uint32_t* a, uint32_t b0, uint32_t b1) {
    asm volatile("mma.sync.aligned.m16n8k16.row.col.f32.bf16.bf16.f32 "
        "{%0,%1,%2,%3}, {%4,%5,%6,%7}, {%8,%9}, {%0,%1,%2,%3};"
        : "+f"(c[0]), "+f"(c[1]), "+f"(c[2]), "+f"(c[3])
        : "r"(a[0]), "r"(a[1]), "r"(a[2]), "r"(a[3]), "r"(b0), "r"(b1));
}
__device__ __forceinline__ void mma16816h(float* c, const uint32_t* a, uint32_t b0, uint32_t b1) {
    asm volatile("mma.sync.aligned.m16n8k16.row.col.f32.f16.f16.f32 "
        "{%0,%1,%2,%3}, {%4,%5,%6,%7}, {%8,%9}, {%0,%1,%2,%3};"
        : "+f"(c[0]), "+f"(c[1]), "+f"(c[2]), "+f"(c[3])
        : "r"(a[0]), "r"(a[1]), "r"(a[2]), "r"(a[3]), "r"(b0), "r"(b1));
}

__device__ __forceinline__ uint32_t smem_u32(const void* p) {
    uint32_t a;
    asm("{ .reg .u64 t; cvta.to.shared.u64 t, %1; cvt.u32.u64 %0, t; }" : "=r"(a) : "l"(p));
    return a;
}
#define CP16(dst, src) asm volatile("cp.async.cg.shared.global [%0], [%1], 16;" :: "r"(dst), "l"(src))
#define CP16P(dst, src, p) asm volatile("cp.async.cg.shared.global [%0], [%1], 16, %2;" :: "r"(dst), "l"(src), "r"((p)?16:0))
#define CPCOMMIT()     asm volatile("cp.async.commit_group;" ::: "memory")
#define CPWAIT(n)      asm volatile("cp.async.wait_group %0;" :: "n"(n) : "memory")
#define LDSM4(r, a) asm volatile("ldmatrix.sync.aligned.m8n8.x4.shared.b16 {%0,%1,%2,%3}, [%4];" \
    : "=r"((r)[0]), "=r"((r)[1]), "=r"((r)[2]), "=r"((r)[3]) : "r"(a))
#define LDSM4T(r, a) asm volatile("ldmatrix.sync.aligned.m8n8.x4.trans.shared.b16 {%0,%1,%2,%3}, [%4];" \
    : "=r"((r)[0]), "=r"((r)[1]), "=r"((r)[2]), "=r"((r)[3]) : "r"(a))

// bf16 helpers (agent path — bit-identical mask)
__device__ __forceinline__ void split_hl(float v, __nv_bfloat16& h, __nv_bfloat16& l) {
    h = __float2bfloat16_rn(v);
    l = __float2bfloat16_rn(v - __bfloat162float(h));
}
__device__ __forceinline__ void cvt_pack(float4 v, uint2& h, uint2& l) {
    __nv_bfloat16 h0,l0,h1,l1,h2,l2,h3,l3;
    split_hl(v.x,h0,l0); split_hl(v.y,h1,l1); split_hl(v.z,h2,l2); split_hl(v.w,h3,l3);
    h.x = ((uint32_t)__bfloat16_as_ushort(h1)<<16)|(uint32_t)__bfloat16_as_ushort(h0);
    h.y = ((uint32_t)__bfloat16_as_ushort(h3)<<16)|(uint32_t)__bfloat16_as_ushort(h2);
    l.x = ((uint32_t)__bfloat16_as_ushort(l1)<<16)|(uint32_t)__bfloat16_as_ushort(l0);
    l.y = ((uint32_t)__bfloat16_as_ushort(l3)<<16)|(uint32_t)__bfloat16_as_ushort(l2);
}
// fp16 helpers
__device__ __forceinline__ uint32_t packh2(float a, float b) {
    __half2 h2 = __floats2half2_rn(a, b);
    return *reinterpret_cast<uint32_t*>(&h2);
}

// ---------------- scratch ----------------
__device__ float g_xcat[(size_t)BB*NT*512];
__device__ float g_part[(size_t)BB*NT*4];
__device__ float g_maskf [BB*NT];
__device__ int   g_list[BB*NT];
__device__ int   g_iinv[BB*NT];
__device__ int   g_cnt [BB];
__device__ float g_x  [(size_t)2*BB*NT*CD];
__device__ __align__(16) __nv_bfloat16 g_w_ag [2*262144];
__device__ __align__(16) __nv_bfloat16 g_xcat_hl[2*XCAT_PLANE];
__device__ __align__(16) __half g_w16  [1572864];          // hi planes only
__device__ __align__(16) __half g_xn_h [XN_PLANE];
__device__ __align__(16) __half g_att_h[ATT_PLANE];
__device__ __align__(16) __half g_hid_h[HID_PLANE];
__device__ __align__(16) __half g_qkv_h[QKV_PLANE];

// ---------------- weight converts ----------------
__global__ void conv_wag(const float* __restrict__ src, __nv_bfloat16* __restrict__ dst, int n)
{
    __nv_bfloat16* dh = dst;
    __nv_bfloat16* dl = dst + n;
    int n4 = n >> 2;
    for (int i = blockIdx.x*256 + threadIdx.x; i < n4; i += gridDim.x*256) {
        float4 v = ((const float4*)src)[i];
        uint2 h, l; cvt_pack(v, h, l);
        *(uint2*)&dh[i*4] = h;
        *(uint2*)&dl[i*4] = l;
    }
}
struct W8 { const float* src[8]; int start[8]; int n[8]; };
__global__ void conv_w16(W8 a, __half* __restrict__ dst)
{
    int w = blockIdx.y;
    int n = a.n[w];
    const float4* s = (const float4*)a.src[w];
    __half* dh = dst + a.start[w];
    int n4 = n >> 2;
    for (int i = blockIdx.x*256 + threadIdx.x; i < n4; i += gridDim.x*256) {
        float4 v = s[i];
        *(uint2*)&dh[i*4] = make_uint2(packh2(v.x, v.y), packh2(v.z, v.w));
    }
}

// ---------------- transpose [B,C,N] -> token-major concat + bf16 hi/lo (agent) ----------------
__global__ void transpose_cat(const float* __restrict__ fir, const float* __restrict__ fvis,
                              float* __restrict__ xcat, __nv_bfloat16* __restrict__ xcat_hl)
{
    int src = blockIdx.z & 1;
    int b   = blockIdx.z >> 1;
    const float* f = src ? fvis : fir;
    __shared__ float tile[32][33];
    int n0 = blockIdx.x * 32, c0 = blockIdx.y * 32;
    int tx = threadIdx.x, ty = threadIdx.y;
    #pragma unroll
    for (int i = 0; i < 32; i += 8)
        tile[ty + i][tx] = f[((size_t)b*CD + c0 + ty + i)*NT + n0 + tx];
    __syncthreads();
    #pragma unroll
    for (int i = 0; i < 32; i += 8) {
        float v = tile[tx][ty + i];
        size_t idx = ((size_t)b*NT + n0 + ty + i)*512 + src*CD + c0 + tx;
        xcat[idx] = v;
        __nv_bfloat16 h, l; split_hl(v, h, l);
        xcat_hl[idx] = h;
        xcat_hl[XCAT_PLANE + idx] = l;
    }
}

#define RSB   80
#define MATB  (128*RSB)

__device__ __forceinline__ float actf(float t, int act) {
    if (act == 1) return t / (1.f + expf(-t));
    if (act == 2) return 0.5f*t*(1.f + erff(t*0.70710678118654752f));
    return t;
}

// ================= agent GEMM: bf16 3-term (unchanged; bit-identical mask) ============
#define STAGEA (4*MATB)
#define AGEMM_SMEM (2*STAGEA)   // 81920
__global__ void __launch_bounds__(256, 2)
gemm_agent(const __nv_bfloat16* __restrict__ Ahl, size_t aplane,
           const __nv_bfloat16* __restrict__ Wh, size_t wplane,
           const float* __restrict__ bias, int K,
           const float* __restrict__ logit_w, float* __restrict__ part)
{
    int b = blockIdx.z;
    int m0 = blockIdx.y * 128;
    int o0 = blockIdx.x * 128;
    size_t rowbase = (size_t)b * NT;
    const __nv_bfloat16* Ah_g = Ahl + (rowbase + m0) * K;
    const __nv_bfloat16* Al_g = Ah_g + aplane;
    const __nv_bfloat16* Wh_g = Wh + (size_t)o0 * K;
    const __nv_bfloat16* Wl_g = Wh_g + wplane;

    extern __shared__ char smem[];
    uint32_t sbase = smem_u32(smem);
    int tid = threadIdx.x, lane = tid & 31, w = tid >> 5;
    int wm = w & 3, wn = w >> 2;
    int gid = lane >> 2, tig = lane & 3;

    float acc[2][8][4];
    #pragma unroll
    for (int mt=0; mt<2; mt++)
        #pragma unroll
        for (int nt=0; nt<8; nt++)
            #pragma unroll
            for (int q=0; q<4; q++) acc[mt][nt][q] = 0.f;

#define PREFA(cc, st) do { \
    uint32_t sb_ = sbase + (st)*STAGEA; \
    _Pragma("unroll") \
    for (int i_ = 0; i_ < 2; i_++) { \
        int f_ = tid + i_*256; int row_ = f_ >> 2; int jb_ = (f_ & 3) * 16; \
        size_t go_ = (size_t)row_*K + (size_t)(cc)*32; \
        uint32_t so_ = sb_ + (uint32_t)(row_*RSB + jb_); \
        CP16(so_, (const char*)(Ah_g + go_) + jb_); \
        CP16(so_ + MATB, (const char*)(Al_g + go_) + jb_); \
        CP16(so_ + 2*MATB, (const char*)(Wh_g + go_) + jb_); \
        CP16(so_ + 3*MATB, (const char*)(Wl_g + go_) + jb_); \
    } } while (0)

    int nchunk = K >> 5;
    PREFA(0, 0);
    CPCOMMIT();

    for (int c = 0; c < nchunk; c++) {
        if (c + 1 < nchunk) { PREFA(c+1, (c+1)&1); CPCOMMIT(); CPWAIT(1); }
        else { CPWAIT(0); }
        __syncthreads();
        uint32_t stg = sbase + (c & 1) * STAGEA;
        #pragma unroll
        for (int ks = 0; ks < 2; ks++) {
            uint32_t colb = (uint32_t)(ks*32 + ((lane >> 4) << 4));
            uint32_t Ahf[2][4], Alf[2][4];
            #pragma unroll
            for (int mt = 0; mt < 2; mt++) {
                uint32_t sa = stg + (uint32_t)((wm*32 + mt*16 + (lane & 15)) * RSB) + colb;
                LDSM4(Ahf[mt], sa);
                LDSM4(Alf[mt], sa + MATB);
            }
            #pragma unroll
            for (int np = 0; np < 4; np++) {
                uint32_t sb = stg + 2*MATB + (uint32_t)((wn*64 + np*16 + (lane & 15)) * RSB) + colb;
                uint32_t Bh[4], Bl[4];
                LDSM4(Bh, sb);
                LDSM4(Bl, sb + MATB);
                mma16816(acc[0][2*np],   Ahf[0], Bh[0], Bh[2]);
                mma16816(acc[0][2*np+1], Ahf[0], Bh[1], Bh[3]);
                mma16816(acc[1][2*np],   Ahf[1], Bh[0], Bh[2]);
                mma16816(acc[1][2*np+1], Ahf[1], Bh[1], Bh[3]);
                mma16816(acc[0][2*np],   Ahf[0], Bl[0], Bl[2]);
                mma16816(acc[0][2*np+1], Ahf[0], Bl[1], Bl[3]);
                mma16816(acc[1][2*np],   Ahf[1], Bl[0], Bl[2]);
                mma16816(acc[1][2*np+1], Ahf[1], Bl[1], Bl[3]);
                mma16816(acc[0][2*np],   Alf[0], Bh[0], Bh[2]);
                mma16816(acc[0][2*np+1], Alf[0], Bh[1], Bh[3]);
                mma16816(acc[1][2*np],   Alf[1], Bh[0], Bh[2]);
                mma16816(acc[1][2*np+1], Alf[1], Bh[1], Bh[3]);
            }
        }
        __syncthreads();
    }
#undef PREFA

    float pr[4] = {0.f, 0.f, 0.f, 0.f};
    #pragma unroll
    for (int mt = 0; mt < 2; mt++) {
        #pragma unroll
        for (int nt = 0; nt < 8; nt++) {
            int col = o0 + wn*64 + nt*8 + 2*tig;
            float b0v = bias[col], b1v = bias[col+1];
            float w0 = logit_w[col], w1 = logit_w[col+1];
            float t0 = actf(acc[mt][nt][0] + b0v, 1);
            float t1 = actf(acc[mt][nt][1] + b1v, 1);
            float t2 = actf(acc[mt][nt][2] + b0v, 1);
            float t3 = actf(acc[mt][nt][3] + b1v, 1);
            pr[mt*2+0] += t0*w0 + t1*w1;
            pr[mt*2+1] += t2*w0 + t3*w1;
        }
    }
    #pragma unroll
    for (int i = 0; i < 4; i++) {
        pr[i] += __shfl_xor_sync(0xffffffffu, pr[i], 1);
        pr[i] += __shfl_xor_sync(0xffffffffu, pr[i], 2);
    }
    __syncthreads();
    float* red = (float*)smem;
    if (tig == 0) {
        #pragma unroll
        for (int mt = 0; mt < 2; mt++) {
            red[wn*128 + wm*32 + mt*16 + gid]     = pr[mt*2+0];
            red[wn*128 + wm*32 + mt*16 + gid + 8] = pr[mt*2+1];
        }
    }
    __syncthreads();
    if (tid < 128)
        part[((size_t)b*NT + m0 + tid)*4 + blockIdx.x] = red[tid] + red[128 + tid];
}

// ======= fp16 single-term GEMM (W hi only), BMT x 128 block, 3-stage, 2 CTAs/SM =======
template<int BMT>
__global__ void __launch_bounds__(256, 2)
gemm_f16(const __half* __restrict__ Aall,
         const __half* __restrict__ Wah, const __half* __restrict__ Wbh,
         const float* __restrict__ ba, const float* __restrict__ bbv,
         float* __restrict__ Cf, __half* __restrict__ Ch,
         const float* __restrict__ R,
         const int* __restrict__ counts, int K, int Ocols, int act)
{
    constexpr int NWM   = 2;
    constexpr int WMEXT = BMT / NWM;      // 64 or 32 rows per warp
    constexpr int MT    = WMEXT / 16;     // 4 or 2
    constexpr int AMATB = BMT * RSB;
    constexpr int WMATB = 128 * RSB;
    constexpr int STG   = AMATB + WMATB;
    constexpr int NITER = ((BMT + 128) * 4) / 256;

    int bz = blockIdx.z;
    int s = (bz >= BB) ? 1 : 0;
    int b = bz & 3;
    int Mb = counts[b];
    int m0 = blockIdx.y * BMT;
    if (m0 >= Mb) return;
    int o0 = blockIdx.x * 128;
    const __half* Wsel = s ? Wbh : Wah;
    const float* bias = s ? bbv : ba;
    size_t rowbase = (size_t)(s*BB + b) * NT;
    const __half* Ah_g = Aall + (rowbase + m0) * K;
    const __half* Wh_g = Wsel + (size_t)o0 * K;
    float* Cfb = Cf ? Cf + rowbase * Ocols : (float*)0;
    __half* Chb = Ch ? Ch + rowbase * Ocols : (__half*)0;
    const float* Rb = R ? R + rowbase * Ocols : (const float*)0;

    extern __shared__ char smem[];
    uint32_t sbase = smem_u32(smem);
    int tid = threadIdx.x, lane = tid & 31, w = tid >> 5;
    int wm = w & 1, wn = w >> 1;          // 2 m-warps x 4 n-warps
    int gid = lane >> 2, tig = lane & 3;

    float acc[MT][4][4];
    #pragma unroll
    for (int mt=0; mt<MT; mt++)
        #pragma unroll
        for (int nt=0; nt<4; nt++)
            #pragma unroll
            for (int q=0; q<4; q++) acc[mt][nt][q] = 0.f;

#define PREF16(cc, st) do { \
    uint32_t sb_ = sbase + (st)*STG; \
    _Pragma("unroll") \
    for (int i_ = 0; i_ < NITER; i_++) { \
        int f_ = tid + i_*256; int row_ = f_ >> 2; int jb_ = (f_ & 3) * 16; \
        const char* p_; uint32_t soff_; \
        if (row_ < BMT) { p_ = (const char*)(Ah_g + (size_t)row_*K + (size_t)(cc)*32); soff_ = (uint32_t)(row_*RSB); } \
        else            { int r_ = row_ - BMT; p_ = (const char*)(Wh_g + (size_t)r_*K + (size_t)(cc)*32); soff_ = (uint32_t)(AMATB + r_*RSB); } \
        CP16(sb_ + soff_ + jb_, p_ + jb_); \
    } } while (0)

    int nchunk = K >> 5;
    PREF16(0, 0);
    CPCOMMIT();
    if (nchunk > 1) { PREF16(1, 1); CPCOMMIT(); }

    for (int c = 0; c < nchunk; c++) {
        if (c == nchunk - 1) { CPWAIT(0); } else { CPWAIT(1); }
        __syncthreads();
        uint32_t stg = sbase + (c % 3) * STG;
        #pragma unroll
        for (int ks = 0; ks < 2; ks++) {
            uint32_t colb = (uint32_t)(ks*32 + ((lane >> 4) << 4));
            uint32_t Ahf[MT][4];
            #pragma unroll
            for (int mt = 0; mt < MT; mt++) {
                uint32_t sa = stg + (uint32_t)((wm*WMEXT + mt*16 + (lane & 15)) * RSB) + colb;
                LDSM4(Ahf[mt], sa);
            }
            #pragma unroll
            for (int np = 0; np < 2; np++) {
                uint32_t sb = stg + AMATB + (uint32_t)((wn*32 + np*16 + (lane & 15)) * RSB) + colb;
                uint32_t Bh[4];
                LDSM4(Bh, sb);
                #pragma unroll
                for (int mt = 0; mt < MT; mt++) {
                    mma16816h(acc[mt][2*np],   Ahf[mt], Bh[0], Bh[2]);
                    mma16816h(acc[mt][2*np+1], Ahf[mt], Bh[1], Bh[3]);
                }
            }
        }
        if (c + 2 < nchunk) { PREF16(c+2, (c+2) % 3); CPCOMMIT(); }
    }
#undef PREF16

    #pragma unroll
    for (int mt = 0; mt < MT; mt++) {
        int r0 = m0 + wm*WMEXT + mt*16 + gid;
        int r1 = r0 + 8;
        #pragma unroll
        for (int nt = 0; nt < 4; nt++) {
            int col = o0 + wn*32 + nt*8 + 2*tig;
            float b0v = bias[col], b1v = bias[col+1];
            float t0 = actf(acc[mt][nt][0] + b0v, act);
            float t1 = actf(acc[mt][nt][1] + b1v, act);
            float t2 = actf(acc[mt][nt][2] + b0v, act);
            float t3 = actf(acc[mt][nt][3] + b1v, act);
            if (Cfb) {
                if (r0 < Mb) {
                    if (Rb) { t0 += Rb[(size_t)r0*Ocols + col]; t1 += Rb[(size_t)r0*Ocols + col + 1]; }
                    *(float2*)&Cfb[(size_t)r0*Ocols + col] = make_float2(t0, t1);
                }
                if (r1 < Mb) {
                    if (Rb) { t2 += Rb[(size_t)r1*Ocols + col]; t3 += Rb[(size_t)r1*Ocols + col + 1]; }
                    *(float2*)&Cfb[(size_t)r1*Ocols + col] = make_float2(t2, t3);
                }
            } else {
                if (r0 < Mb) *(uint32_t*)&Chb[(size_t)r0*Ocols + col] = packh2(t0, t1);
                if (r1 < Mb) *(uint32_t*)&Chb[(size_t)r1*Ocols + col] = packh2(t2, t3);
            }
        }
    }
}

#define GEMM16_SMEM_128 (3*((128+128)*RSB))   // 61440
#define GEMM16_SMEM_64  (3*((64+128)*RSB))    // 46080

// ---------------- selection (logits from partials) + inverse index ----------------
__global__ void select_kernel(const float* __restrict__ part, const float* __restrict__ ab2,
                              int* __restrict__ list, int* __restrict__ cnt,
                              float* __restrict__ maskf, int* __restrict__ iinv)
{
    int b = blockIdx.x, tid = threadIdx.x;
    const int PER = NT/256;  // 9
    __shared__ int cn[256];
    float ab2v = ab2[0];
    int base = tid*PER;
    float lv[PER];
    bool  sv[PER];
    int c = 0;
    #pragma unroll
    for (int i = 0; i < PER; i++) {
        size_t t4 = ((size_t)b*NT + base + i)*4;
        float lg = ((part[t4] + part[t4+1]) + (part[t4+2] + part[t4+3])) + ab2v;
        lv[i] = lg;
        bool sel = lg > 0.f; sv[i] = sel; c += sel;
        maskf[b*NT + base + i] = sel ? 1.f : 0.f;
        iinv[b*NT + base + i] = -1;
    }
    cn[tid] = c; __syncthreads();
    for (int off = 1; off < 256; off <<= 1) {
        int v = (tid >= off) ? cn[tid-off] : 0;
        __syncthreads();
        cn[tid] += v;
        __syncthreads();
    }
    int total = cn[255];
    int pos = cn[tid] - c;
    if (total >= 64) {
        #pragma unroll
        for (int i = 0; i < PER; i++)
            if (sv[i]) { list[b*NT + pos] = base + i; iinv[b*NT + base + i] = pos; pos++; }
        if (tid == 0) cnt[b] = total;
    } else {
        __shared__ float sl[NT];
        #pragma unroll
        for (int i = 0; i < PER; i++) sl[base+i] = lv[i];
        __syncthreads();
        if (tid == 0) {
            for (int t = 0; t < 64; t++) {
                int am = 0; float mv = sl[0];
                for (int n = 1; n < NT; n++) if (sl[n] > mv) { mv = sl[n]; am = n; }
                list[b*NT + t] = am; iinv[b*NT + am] = t; sl[am] = -1e30f;
            }
            cnt[b] = 64;
        }
    }
}

// ---------------- fused gather + LayerNorm (both streams) -> fp16 ----------------
__global__ void gather_ln(const float* __restrict__ xcat, const int* __restrict__ list,
                          const int* __restrict__ cnt,
                          float* __restrict__ x, __half* __restrict__ Yh,
                          const float* __restrict__ ga, const float* __restrict__ bba,
                          const float* __restrict__ gb2, const float* __restrict__ bbb)
{
    int b = blockIdx.y, j = blockIdx.x;
    if (j >= cnt[b]) return;
    int idx = list[b*NT + j];
    int tid = threadIdx.x;
    const float* src = xcat + ((size_t)b*NT + idx)*512;
    __shared__ float red[8];
    #pragma unroll
    for (int s = 0; s < 2; s++) {
        const float* gw = s ? gb2 : ga;
        const float* gb = s ? bbb : bba;
        float v = src[s*CD + tid];
        size_t row = ((size_t)(s*BB + b)*NT + j)*CD;
        x[row + tid] = v;
        float ssum = v;
        #pragma unroll
        for (int o = 16; o; o >>= 1) ssum += __shfl_down_sync(0xffffffffu, ssum, o);
        if ((tid & 31) == 0) red[tid>>5] = ssum;
        __syncthreads();
        float mean = 0.f;
        #pragma unroll
        for (int i = 0; i < 8; i++) mean += red[i];
        mean *= (1.f/CD);
        __syncthreads();
        float d = v - mean;
        ssum = d*d;
        #pragma unroll
        for (int o = 16; o; o >>= 1) ssum += __shfl_down_sync(0xffffffffu, ssum, o);
        if ((tid & 31) == 0) red[tid>>5] = ssum;
        __syncthreads();
        float var = 0.f;
        #pragma unroll
        for (int i = 0; i < 8; i++) var += red[i];
        var *= (1.f/CD);
        Yh[row + tid] = __float2half_rn(d * rsqrtf(var + 1e-5f) * gw[tid] + gb[tid]);
        __syncthreads();
    }
}

// ---------------- LayerNorm (dual-stream) -> fp16 ----------------
__global__ void ln2(const float* __restrict__ X, __half* __restrict__ Yh,
                    const float* __restrict__ ga, const float* __restrict__ bba,
                    const float* __restrict__ gb2, const float* __restrict__ bbb,
                    const int* __restrict__ cnt)
{
    int bz = blockIdx.y; int s = bz >> 2, b = bz & 3;
    int n = blockIdx.x;
    if (n >= cnt[b]) return;
    const float* gw = s ? gb2 : ga;
    const float* gb = s ? bbb : bba;
    int tid = threadIdx.x;
    size_t row = ((size_t)(s*BB+b)*NT + n)*CD;
    float v = X[row + tid];
    __shared__ float red[8];
    float ssum = v;
    #pragma unroll
    for (int o = 16; o; o >>= 1) ssum += __shfl_down_sync(0xffffffffu, ssum, o);
    if ((tid & 31) == 0) red[tid>>5] = ssum;
    __syncthreads();
    float mean = 0.f;
    #pragma unroll
    for (int i = 0; i < 8; i++) mean += red[i];
    mean *= (1.f/CD);
    __syncthreads();
    float d = v - mean;
    ssum = d*d;
    #pragma unroll
    for (int o = 16; o; o >>= 1) ssum += __shfl_down_sync(0xffffffffu, ssum, o);
    if ((tid & 31) == 0) red[tid>>5] = ssum;
    __syncthreads();
    float var = 0.f;
    #pragma unroll
    for (int i = 0; i < 8; i++) var += red[i];
    var *= (1.f/CD);
    Yh[row + tid] = __float2half_rn(d * rsqrtf(var + 1e-5f) * gw[tid] + gb[tid]);
}

// ================= flash attention fp16 (single-term S, hi-only K/V), 3-stage, 2 CTAs/SM ======
#define AQR 144
#define AT_KVOFF (128*AQR)
#define AT_STG (2*64*AQR)                // Kh, Vh
#define ATTN_SMEM (AT_KVOFF + 3*AT_STG)  // 73728

__global__ void __launch_bounds__(256, 2)
attn_mma(const __half* __restrict__ qkvh, __half* __restrict__ att_h,
         const int* __restrict__ cnt)
{
    extern __shared__ char smc[];
    uint32_t sb = smem_u32(smc);
    int bz = blockIdx.z; int s = bz >> 2, b = bz & 3;
    int h = blockIdx.y, q0 = blockIdx.x*128;
    int Mb = cnt[b];
    if (q0 >= Mb) return;
    int tid = threadIdx.x, lane = tid & 31, w = tid >> 5;
    int gid = lane >> 2, tig = lane & 3;
    size_t rowbase = (size_t)(s*BB + b) * NT;
    const __half* qg = qkvh;

    {
        #pragma unroll
        for (int i = 0; i < 4; i++) {
            int f = tid + i*256;
            int row = f >> 3, c16 = f & 7;
            const char* src = (const char*)(qg + (rowbase + q0 + row)*768 + h*64) + c16*16;
            CP16P(sb + row*AQR + c16*16, src, (q0 + row) < Mb);
        }
    }
#define KV_PREFETCH(kt, st) do { \
    int k0_ = (kt)*64; \
    _Pragma("unroll") \
    for (int i_ = 0; i_ < 4; i_++) { \
        int f_ = tid + i_*256; \
        int pl_ = f_ >> 9, rem_ = f_ & 511; \
        int row_ = rem_ >> 3, c16_ = rem_ & 7; \
        int ko_ = pl_ ? 512 : 256; \
        const char* src_ = (const char*)(qg + (rowbase + k0_ + row_)*768 + ko_ + h*64) + c16_*16; \
        uint32_t dst_ = sb + AT_KVOFF + (st)*AT_STG + pl_*(64*AQR) + row_*AQR + c16_*16; \
        CP16P(dst_, src_, (k0_ + row_) < Mb); \
    } } while (0)

    int nkt = (Mb + 63) >> 6;
    KV_PREFETCH(0, 0);
    CPCOMMIT();
    if (nkt > 1) { KV_PREFETCH(1, 1); CPCOMMIT(); }

    uint32_t Qh[4][4];
    float oacc[8][4];
    #pragma unroll
    for (int j=0;j<8;j++)
        #pragma unroll
        for (int q=0;q<4;q++) oacc[j][q] = 0.f;
    float l0 = 0.f, l1 = 0.f;
    bool qload = false;

    for (int c = 0; c < nkt; c++) {
        if (c == nkt - 1) { CPWAIT(0); } else { CPWAIT(1); }
        __syncthreads();
        if (!qload) {
            qload = true;
            #pragma unroll
            for (int ks = 0; ks < 4; ks++) {
                uint32_t qa = sb + (uint32_t)((w*16 + (lane & 15)) * AQR) + ks*32 + ((lane >> 4) << 4);
                LDSM4(Qh[ks], qa);
            }
        }
        uint32_t kb = sb + AT_KVOFF + (c % 3)*AT_STG;
        uint32_t vb = kb + 64*AQR;

        float sacc[8][4];
        #pragma unroll
        for (int j=0;j<8;j++)
            #pragma unroll
            for (int q=0;q<4;q++) sacc[j][q] = 0.f;
        #pragma unroll
        for (int ks = 0; ks < 4; ks++) {
            #pragma unroll
            for (int np = 0; np < 4; np++) {
                uint32_t ka = kb + (uint32_t)((np*16 + ((lane >> 4) << 3) + (lane & 7)) * AQR)
                            + ks*32 + (((lane >> 3) & 1) << 4);
                uint32_t Kh4[4];
                LDSM4(Kh4, ka);
                mma16816h(sacc[2*np],   Qh[ks], Kh4[0], Kh4[1]);
                mma16816h(sacc[2*np+1], Qh[ks], Kh4[2], Kh4[3]);
            }
        }
        int kvb = c*64;
        float s0 = 0.f, s1 = 0.f;
        #pragma unroll
        for (int j = 0; j < 8; j++) {
            int t0 = kvb + j*8 + 2*tig;
            bool v0 = t0 < Mb, v1 = (t0 + 1) < Mb;
            sacc[j][0] = v0 ? __expf(sacc[j][0]*0.125f) : 0.f;
            sacc[j][1] = v1 ? __expf(sacc[j][1]*0.125f) : 0.f;
            sacc[j][2] = v0 ? __expf(sacc[j][2]*0.125f) : 0.f;
            sacc[j][3] = v1 ? __expf(sacc[j][3]*0.125f) : 0.f;
            s0 += sacc[j][0] + sacc[j][1];
            s1 += sacc[j][2] + sacc[j][3];
        }
        s0 += __shfl_xor_sync(0xffffffffu, s0, 1);
        s0 += __shfl_xor_sync(0xffffffffu, s0, 2);
        s1 += __shfl_xor_sync(0xffffffffu, s1, 1);
        s1 += __shfl_xor_sync(0xffffffffu, s1, 2);
        l0 += s0; l1 += s1;
        #pragma unroll
        for (int kt = 0; kt < 4; kt++) {
            uint32_t aP[4];
            aP[0] = packh2(sacc[2*kt][0],   sacc[2*kt][1]);
            aP[1] = packh2(sacc[2*kt][2],   sacc[2*kt][3]);
            aP[2] = packh2(sacc[2*kt+1][0], sacc[2*kt+1][1]);
            aP[3] = packh2(sacc[2*kt+1][2], sacc[2*kt+1][3]);
            #pragma unroll
            for (int np = 0; np < 4; np++) {
                uint32_t va = vb + (uint32_t)((kt*16 + (((lane >> 3) & 1) << 3) + (lane & 7)) * AQR)
                            + (2*np + (lane >> 4))*16;
                uint32_t Vh4[4];
                LDSM4T(Vh4, va);
                mma16816h(oacc[2*np],   aP, Vh4[0], Vh4[1]);
                mma16816h(oacc[2*np+1], aP, Vh4[2], Vh4[3]);
            }
        }
        if (c + 2 < nkt) { KV_PREFETCH(c+2, (c+2) % 3); CPCOMMIT(); }
    }
#undef KV_PREFETCH

    float inv0 = 1.f / l0, inv1 = 1.f / l1;
    int qr0 = q0 + w*16 + gid;
    int qr1 = qr0 + 8;
    #pragma unroll
    for (int j = 0; j < 8; j++) {
        int col = h*64 + j*8 + 2*tig;
        if (qr0 < Mb)
            *(uint32_t*)&att_h[(rowbase + qr0)*CD + col] = packh2(oacc[j][0]*inv0, oacc[j][1]*inv0);
        if (qr1 < Mb)
            *(uint32_t*)&att_h[(rowbase + qr1)*CD + col] = packh2(oacc[j][2]*inv1, oacc[j][3]*inv1);
    }
}

// ---------------- fused output: base + scatter, all-coalesced via 32x32 tile ----------------
__global__ void out_fuse(const float* __restrict__ fir, const float* __restrict__ fvis,
                         const float* __restrict__ x0, const float* __restrict__ x1,
                         const int* __restrict__ iinv, const float* __restrict__ maskf,
                         float* __restrict__ out)
{
    int b = blockIdx.z;
    int n0 = blockIdx.x*32, c0 = blockIdx.y*32;
    int tx = threadIdx.x, ty = threadIdx.y;  // (32, 8)
    __shared__ float tile[32][33];
    #pragma unroll
    for (int i = 0; i < 32; i += 8) {
        int n = n0 + ty + i;
        int j = iinv[b*NT + n];
        float v = 0.f;
        if (j >= 0) {
            float mv = maskf[b*NT + n];
            size_t r = ((size_t)b*NT + j)*CD + c0 + tx;
            v = (x0[r] + x1[r]) * mv;
        }
        tile[ty + i][tx] = v;
    }
    __syncthreads();
    #pragma unroll
    for (int i = 0; i < 32; i += 8) {
        int c = c0 + ty + i;
        int n = n0 + tx;
        size_t o = ((size_t)b*CD + c)*NT + n;
        int j = iinv[b*NT + n];
        float base = fir[o] + fvis[o];
        out[o] = (j >= 0) ? tile[tx][ty + i] : base;
    }
}

// ---------------- host ----------------
extern "C" void kernel_launch(void* const* d_in, const int* in_sizes, int n_in,
                              void* d_out, int out_size)
{
    const float* f_ir  = (const float*)d_in[0];
    const float* f_vis = (const float*)d_in[1];
    const float* aw1   = (const float*)d_in[2];
    const float* ab1   = (const float*)d_in[3];
    const float* aw2   = (const float*)d_in[4];
    const float* ab2   = (const float*)d_in[5];
    const float* ir_lng  = (const float*)d_in[6];
    const float* ir_lnb  = (const float*)d_in[7];
    const float* ir_wqkv = (const float*)d_in[8];
    const float* ir_bqkv = (const float*)d_in[9];
    const float* ir_wo   = (const float*)d_in[10];
    const float* ir_bo   = (const float*)d_in[11];
    const float* ir_w1   = (const float*)d_in[12];
    const float* ir_b1   = (const float*)d_in[13];
    const float* ir_w2   = (const float*)d_in[14];
    const float* ir_b2   = (const float*)d_in[15];
    const float* vi_lng  = (const float*)d_in[16];
    const float* vi_lnb  = (const float*)d_in[17];
    const float* vi_wqkv = (const float*)d_in[18];
    const float* vi_bqkv = (const float*)d_in[19];
    const float* vi_wo   = (const float*)d_in[20];
    const float* vi_bo   = (const float*)d_in[21];
    const float* vi_w1   = (const float*)d_in[22];
    const float* vi_b1   = (const float*)d_in[23];
    const float* vi_w2   = (const float*)d_in[24];
    const float* vi_b2   = (const float*)d_in[25];
    float* out = (float*)d_out;

    float *xcat,*partp,*maskf,*x;
    __nv_bfloat16 *wag,*xcathl;
    __half *w16,*xnh,*atth,*hidh,*qkvh;
    int *list,*iinv,*cntp;
    cudaGetSymbolAddress((void**)&xcat,  g_xcat);
    cudaGetSymbolAddress((void**)&partp, g_part);
    cudaGetSymbolAddress((void**)&maskf, g_maskf);
    cudaGetSymbolAddress((void**)&x,     g_x);
    cudaGetSymbolAddress((void**)&wag,   g_w_ag);
    cudaGetSymbolAddress((void**)&xcathl,g_xcat_hl);
    cudaGetSymbolAddress((void**)&w16,   g_w16);
    cudaGetSymbolAddress((void**)&xnh,   g_xn_h);
    cudaGetSymbolAddress((void**)&atth,  g_att_h);
    cudaGetSymbolAddress((void**)&hidh,  g_hid_h);
    cudaGetSymbolAddress((void**)&qkvh,  g_qkv_h);
    cudaGetSymbolAddress((void**)&list,  g_list);
    cudaGetSymbolAddress((void**)&iinv,  g_iinv);
    cudaGetSymbolAddress((void**)&cntp,  g_cnt);
    float* x0 = x;
    float* x1 = x + (size_t)BB*NT*CD;

    cudaFuncSetAttribute(attn_mma, cudaFuncAttributeMaxDynamicSharedMemorySize, ATTN_SMEM);
    cudaFuncSetAttribute(gemm_agent, cudaFuncAttributeMaxDynamicSharedMemorySize, AGEMM_SMEM);
    cudaFuncSetAttribute(gemm_f16<128>, cudaFuncAttributeMaxDynamicSharedMemorySize, GEMM16_SMEM_128);
    cudaFuncSetAttribute(gemm_f16<64>,  cudaFuncAttributeMaxDynamicSharedMemorySize, GEMM16_SMEM_64);

    // weight conversions (hi planes only for mixers)
    conv_wag<<<64, 256>>>(aw1, wag, 262144);
    W8 ws;
    const float* wsrc[8] = {ir_wqkv, vi_wqkv, ir_wo, vi_wo, ir_w1, vi_w1, ir_w2, vi_w2};
    const int    wn[8]   = {196608, 196608, 65536, 65536, 262144, 262144, 262144, 262144};
    int start = 0;
    for (int i = 0; i < 8; i++) { ws.src[i] = wsrc[i]; ws.n[i] = wn[i]; ws.start[i] = start; start += wn[i]; }
    conv_w16<<<dim3(64, 8), 256>>>(ws, w16);

    // 1. token-major concat (+bf16 hi/lo for agent)
    transpose_cat<<<dim3(NT/32, CD/32, BB*2), dim3(32,8)>>>(f_ir, f_vis, xcat, xcathl);
    // 2. agent GEMM (bf16 3-term, bit-identical logits)
    gemm_agent<<<dim3(AGH/128, NT/128, BB), 256, AGEMM_SMEM>>>(
        xcathl, XCAT_PLANE, wag, 262144, ab1, 512, aw2, partp);
    // 3. selection (also builds inverse index)
    select_kernel<<<BB, 256>>>(partp, ab2, list, cntp, maskf, iinv);
    // 4. fused gather + first LN (fp16 out)
    gather_ln<<<dim3(NT, BB), 256>>>(xcat, list, cntp, x, xnh,
                                     ir_lng, ir_lnb, vi_lng, vi_lnb);

    // 5. both mixers (fp16 single-term)
    gemm_f16<128><<<dim3(768/128, NT/128, 2*BB), 256, GEMM16_SMEM_128>>>(
        xnh, w16 + 0, w16 + 196608,
        ir_bqkv, vi_bqkv, (float*)0, qkvh, (const float*)0, cntp, 256, 768, 0);
    attn_mma<<<dim3(NT/128, NH, 2*BB), 256, ATTN_SMEM>>>(qkvh, atth, cntp);
    gemm_f16<64><<<dim3(CD/128, NT/64, 2*BB), 256, GEMM16_SMEM_64>>>(
        atth, w16 + 393216, w16 + 458752,
        ir_bo, vi_bo, x, (__half*)0, x, cntp, 256, CD, 0);
    ln2<<<dim3(NT, 2*BB), 256>>>(x, xnh, ir_lng, ir_lnb, vi_lng, vi_lnb, cntp);
    gemm_f16<128><<<dim3(1024/128, NT/128, 2*BB), 256, GEMM16_SMEM_128>>>(
        xnh, w16 + 524288, w16 + 786432,
        ir_b1, vi_b1, (float*)0, hidh, (const float*)0, cntp, 256, 1024, 2);
    gemm_f16<64><<<dim3(CD/128, NT/64, 2*BB), 256, GEMM16_SMEM_64>>>(
        hidh, w16 + 1048576, w16 + 1310720,
        ir_b2, vi_b2, x, (__half*)0, x, cntp, 1024, CD, 0);

    // 6. fused output (all-coalesced)
    out_fuse<<<dim3(NT/32, CD/32, BB), dim3(32,8)>>>(f_ir, f_vis, x0, x1, iinv, maskf, out);
}